// round 3
// baseline (speedup 1.0000x reference)
#include <cuda_runtime.h>
#include <math.h>

// ---------- static scratch (no allocation) ----------
__device__ float g_h1[67108864];   // (32,64,64,512)
__device__ float g_h2[33554432];   // (32,128,32,256)
__device__ float g_h3[16777216];   // (32,256,16,128) == feat (32,4096,128)
__device__ float g_d1[67108864];
__device__ float g_d2[33554432];
__device__ float g_d3[16777216];
__device__ float g_fam[4194304];   // (32,128,1024)
__device__ float g_xm[4194304];
__device__ float g_att[524288];    // (32,128,128)
__device__ float g_dzb[524288];
__device__ float g_alpha[4096];
__device__ float g_dsb[4096];
__device__ float g_mu[131072];
__device__ float g_m2[131072];
__device__ float g_dMu[131072];
__device__ float g_dE2[131072];
__device__ float g_gvec[8192];
__device__ float g_cm[4096];
__device__ float g_tm[32768];
__device__ float g_meanT[4096];
__device__ float g_meanF[32768];
__device__ int   g_sc[4096];
__device__ int   g_st[4096];
__device__ int   g_rstep[4096];
__device__ int   g_cstep[32768];

// ---------- conv forward: stride2, k=3, SAME(pad lo 0 hi 1), +bias+relu ----------
// grid (WOUT/64, HOUT, B). THREADS = OG*16. thread: og=tid%OG (chan group), jt=tid/OG (4 cols).
template<int CIN,int COUT,int HIN,int WIN,int CC,int OG,int OP,int THREADS>
__global__ void __launch_bounds__(THREADS) k_conv_fwd(
    const float* __restrict__ in, const float* __restrict__ W,
    const float* __restrict__ bias, float* __restrict__ out)
{
  constexpr int HOUT=HIN/2, WOUT=WIN/2;
  __shared__ float ins[CC*3*130];
  __shared__ float ws[CC*9*COUT];
  const int n=blockIdx.z, i=blockIdx.y, j0=blockIdx.x*64;
  const int tid=threadIdx.x, og=tid%OG, jt=tid/OG;
  float acc[OP][4];
#pragma unroll
  for(int o=0;o<OP;o++){acc[o][0]=acc[o][1]=acc[o][2]=acc[o][3]=0.f;}
  for(int c0=0;c0<CIN;c0+=CC){
    __syncthreads();
    for(int idx=tid; idx<CC*3*130; idx+=THREADS){
      int c=idx/390, r=(idx/130)%3, col=idx%130;
      int gx=2*i+r, gy=2*j0+col;
      float v=0.f;
      if(gx<HIN && gy<WIN) v=in[(((long)n*CIN+c0+c)*HIN+gx)*WIN+gy];
      ins[idx]=v;
    }
    for(int idx=tid; idx<COUT*CC*9; idx+=THREADS){
      int o=idx/(CC*9), rem=idx%(CC*9);
      ws[rem*COUT+o]=W[(long)o*CIN*9 + c0*9 + rem];
    }
    __syncthreads();
#pragma unroll
    for(int c=0;c<CC;c++)
#pragma unroll
    for(int r=0;r<3;r++){
      float v[9];
#pragma unroll
      for(int m=0;m<9;m++) v[m]=ins[(c*3+r)*130 + 8*jt + m];
#pragma unroll
      for(int kj=0;kj<3;kj++)
#pragma unroll
      for(int oo=0;oo<OP;oo++){
        float w=ws[(c*9+r*3+kj)*COUT + og + OG*oo];
        acc[oo][0]+=w*v[kj];   acc[oo][1]+=w*v[2+kj];
        acc[oo][2]+=w*v[4+kj]; acc[oo][3]+=w*v[6+kj];
      }
    }
  }
  int j=j0+4*jt;
#pragma unroll
  for(int oo=0;oo<OP;oo++){
    int o=og+OG*oo; float bb=bias[o];
    float4 r;
    r.x=fmaxf(acc[oo][0]+bb,0.f); r.y=fmaxf(acc[oo][1]+bb,0.f);
    r.z=fmaxf(acc[oo][2]+bb,0.f); r.w=fmaxf(acc[oo][3]+bb,0.f);
    *(float4*)&out[(((long)n*COUT+o)*HOUT+i)*WOUT+j]=r;
  }
}

// ---------- conv data-grad (transposed conv) with relu mask of `act` ----------
// din[n,c,x,y]=relu'(act)*sum_{o,ki,kj:2i+ki=x,2j+kj=y} W[o,c,ki,kj]*dout[n,o,i,j]
// grid (WIN/64, HIN, B), 256 thr: cg=tid%16 (chan), yt=tid/16 (4 cols).
template<int CIN,int COUT,int HOUT,int WOUT,int OCC,int CP>
__global__ void __launch_bounds__(256) k_conv_bwd(
    const float* __restrict__ dout, const float* __restrict__ W,
    const float* __restrict__ act, float* __restrict__ din)
{
  constexpr int HIN=2*HOUT, WIN=2*WOUT;
  __shared__ float wsm[OCC*CIN*9];
  __shared__ float dsm[OCC*2*34];
  const int n=blockIdx.z, x=blockIdx.y, y0=blockIdx.x*64;
  const int tid=threadIdx.x, cg=tid%16, yt=tid/16;
  int iA,iB,kiA,kiB; bool hasB;
  if((x&1)==0){ iA=x>>1; kiA=0; iB=iA-1; kiB=2; hasB=(iB>=0); }
  else        { iA=(x-1)>>1; kiA=1; iB=0; kiB=0; hasB=false; }
  const int jbase=y0/2-1;
  float aE0[CP],aO0[CP],aE1[CP],aO1[CP];
#pragma unroll
  for(int c=0;c<CP;c++){aE0[c]=aO0[c]=aE1[c]=aO1[c]=0.f;}
  for(int o0=0;o0<COUT;o0+=OCC){
    __syncthreads();
    for(int idx=tid; idx<OCC*CIN*9; idx+=256)
      wsm[idx]=W[(long)o0*CIN*9+idx];
    for(int idx=tid; idx<OCC*2*34; idx+=256){
      int o=idx/68, rs=(idx/34)&1, jj=idx%34;
      int j=jbase+jj; int ir = rs? iB:iA;
      float v=0.f;
      if(j>=0 && j<WOUT && (rs==0 || hasB))
        v=dout[(((long)n*COUT+o0+o)*HOUT+ir)*WOUT+j];
      dsm[idx]=v;
    }
    __syncthreads();
#pragma unroll 2
    for(int o=0;o<OCC;o++){
#pragma unroll
      for(int rs=0;rs<2;rs++){
        if(rs==1 && !hasB) break;
        int ki = rs? kiB:kiA;
        float vm=dsm[(o*2+rs)*34+2*yt], v0=dsm[(o*2+rs)*34+2*yt+1], vp=dsm[(o*2+rs)*34+2*yt+2];
#pragma unroll
        for(int c=0;c<CP;c++){
          const float* wb=&wsm[(o*CIN+cg+16*c)*9+ki*3];
          float w0=wb[0],w1=wb[1],w2=wb[2];
          aE0[c]+=w0*v0+w2*vm; aO0[c]+=w1*v0;
          aE1[c]+=w0*vp+w2*v0; aO1[c]+=w1*vp;
        }
      }
    }
  }
  int y=y0+4*yt;
#pragma unroll
  for(int c=0;c<CP;c++){
    int ci=cg+16*c;
    long base=(((long)n*CIN+ci)*HIN+x)*WIN+y;
    float4 m=*(const float4*)&act[base];
    float4 r;
    r.x = m.x>0.f? aE0[c]:0.f; r.y = m.y>0.f? aO0[c]:0.f;
    r.z = m.z>0.f? aE1[c]:0.f; r.w = m.w>0.f? aO1[c]:0.f;
    *(float4*)&din[base]=r;
  }
}

// ---------- conv1 data-grad -> |dx| (no relu at input) ----------
// grid (2, 128, 32), 256 thr, 2 cols each.
__global__ void __launch_bounds__(256) k_bwd1(
    const float* __restrict__ dz1, const float* __restrict__ W1,
    float* __restrict__ fam)
{
  __shared__ float ws[576];
  __shared__ float dsm[8*2*260];
  const int n=blockIdx.z, x=blockIdx.y, y0=blockIdx.x*512;
  const int tid=threadIdx.x;
  for(int idx=tid; idx<576; idx+=256) ws[idx]=W1[idx];
  int iA,iB,kiA,kiB; bool hasB;
  if((x&1)==0){iA=x>>1;kiA=0;iB=iA-1;kiB=2;hasB=(iB>=0);}
  else{iA=(x-1)>>1;kiA=1;iB=0;kiB=0;hasB=false;}
  const int jbase=y0/2-1;
  float accE=0.f, accO=0.f;
  for(int o0=0;o0<64;o0+=8){
    __syncthreads();
    for(int idx=tid; idx<8*2*260; idx+=256){
      int o=idx/520, rs=(idx/260)&1, jj=idx%260;
      int j=jbase+jj; int ir=rs?iB:iA;
      float v=0.f;
      if(j>=0 && j<512 && (rs==0||hasB))
        v=dz1[(((long)n*64+o0+o)*64+ir)*512+j];
      dsm[idx]=v;
    }
    __syncthreads();
#pragma unroll
    for(int o=0;o<8;o++){
#pragma unroll
      for(int rs=0;rs<2;rs++){
        if(rs==1&&!hasB) break;
        int ki=rs?kiB:kiA;
        const float* wb=&ws[(o0+o)*9+ki*3];
        float vm=dsm[(o*2+rs)*260+tid], v0=dsm[(o*2+rs)*260+tid+1];
        accE+=wb[0]*v0+wb[2]*vm; accO+=wb[1]*v0;
      }
    }
  }
  long base=((long)n*128+x)*1024 + y0 + 2*tid;
  fam[base]=fabsf(accE); fam[base+1]=fabsf(accO);
}

// ---------- att = tanh(Wa@feat + ba): per-batch 128x128x4096 GEMM ----------
__global__ void __launch_bounds__(256) k_att(
    const float* __restrict__ Wa, const float* __restrict__ feat,
    const float* __restrict__ ba, float* __restrict__ att)
{
  __shared__ float As[128][17];
  __shared__ float Fs[16][128];
  const int b=blockIdx.x, tid=threadIdx.x, tx=tid%16, ty=tid/16;
  const float* fb = feat + (long)b*4096*128;
  float acc[8][8];
#pragma unroll
  for(int i=0;i<8;i++)
#pragma unroll
  for(int j=0;j<8;j++) acc[i][j]=0.f;
  for(int k0=0;k0<4096;k0+=16){
    __syncthreads();
#pragma unroll
    for(int l=0;l<8;l++){
      int idx=tid+l*256; int h=idx/16, kk=idx%16;
      As[h][kk]=Wa[(long)h*4096+k0+kk];
    }
#pragma unroll
    for(int l=0;l<8;l++){
      int idx=tid+l*256; int kk=idx/128, t=idx%128;
      Fs[kk][t]=fb[(long)(k0+kk)*128+t];
    }
    __syncthreads();
#pragma unroll
    for(int kk=0;kk<16;kk++){
      float ra[8], rb[8];
#pragma unroll
      for(int i=0;i<8;i++) ra[i]=As[ty*8+i][kk];
      *(float4*)rb     = *(float4*)&Fs[kk][tx*8];
      *(float4*)(rb+4) = *(float4*)&Fs[kk][tx*8+4];
#pragma unroll
      for(int i=0;i<8;i++)
#pragma unroll
      for(int j=0;j<8;j++) acc[i][j]+=ra[i]*rb[j];
    }
  }
#pragma unroll
  for(int i=0;i<8;i++){
    int h=ty*8+i; float bb=ba[h];
#pragma unroll
    for(int j=0;j<8;j++)
      att[((long)b*128+h)*128+tx*8+j]=tanhf(acc[i][j]+bb);
  }
}

// ---------- s = va.att; alpha = softmax_t(s) ----------
__global__ void __launch_bounds__(128) k_salpha(
    const float* __restrict__ att, const float* __restrict__ va,
    float* __restrict__ alpha)
{
  __shared__ float vs[128], buf[128];
  const int b=blockIdx.x, t=threadIdx.x;
  vs[t]=va[t];
  __syncthreads();
  float s=0.f;
#pragma unroll 4
  for(int h=0;h<128;h++) s+=vs[h]*att[((long)b*128+h)*128+t];
  buf[t]=s; __syncthreads();
  for(int off=64;off;off>>=1){ if(t<off) buf[t]=fmaxf(buf[t],buf[t+off]); __syncthreads(); }
  float mx=buf[0]; __syncthreads();
  float e=expf(s-mx);
  buf[t]=e; __syncthreads();
  for(int off=64;off;off>>=1){ if(t<off) buf[t]+=buf[t+off]; __syncthreads(); }
  alpha[b*128+t]=e/buf[0];
}

// ---------- mu, m2 (warp per (b,d)) ----------
__global__ void k_mustats(const float* __restrict__ feat,
    const float* __restrict__ alpha, float* __restrict__ mu, float* __restrict__ m2)
{
  int w=(blockIdx.x*blockDim.x+threadIdx.x)>>5, lane=threadIdx.x&31;
  if(w>=131072) return;
  int b=w>>12;
  const float* fr=feat+(long)w*128;
  const float* ar=alpha+b*128;
  float s1=0.f,s2=0.f;
#pragma unroll
  for(int t=lane;t<128;t+=32){
    float a=ar[t], f=fr[t];
    s1+=a*f; s2+=a*f*f;
  }
  for(int o=16;o;o>>=1){ s1+=__shfl_down_sync(~0u,s1,o); s2+=__shfl_down_sync(~0u,s2,o); }
  if(!lane){ mu[w]=s1; m2[w]=s2; }
}

// ---------- gvec = We @ (Wc[:,1]-Wc[:,0]) ----------
__global__ void k_gvec(const float* __restrict__ We,const float* __restrict__ Wc,
                       float* __restrict__ gvec)
{
  int w=(blockIdx.x*blockDim.x+threadIdx.x)>>5, lane=threadIdx.x&31;
  if(w>=8192) return;
  float s=0.f;
  for(int j=lane;j<256;j+=32) s+=We[(long)w*256+j]*(Wc[j*2+1]-Wc[j*2]);
  for(int o=16;o;o>>=1) s+=__shfl_down_sync(~0u,s,o);
  if(!lane) gvec[w]=s;
}

// ---------- dMu, dE2 per (b,d) ----------
__global__ void k_dcoef(const float* __restrict__ mu,const float* __restrict__ m2,
    const float* __restrict__ gvec, float* __restrict__ dMu,float* __restrict__ dE2)
{
  int i=blockIdx.x*256+threadIdx.x; if(i>=131072) return;
  int d=i&4095;
  float m=mu[i], v=m2[i]-m*m;
  float g2=gvec[4096+d];
  float dE=0.f, dM=gvec[d];
  if(v>1e-5f){ float sg=sqrtf(v); dE=0.5f*g2/sg; dM-=g2*m/sg; }
  dMu[i]=dM; dE2[i]=dE;
}

// ---------- dalpha then softmax-backward -> ds ----------
__global__ void __launch_bounds__(128) k_dalpha(
    const float* __restrict__ feat,const float* __restrict__ dMu,
    const float* __restrict__ dE2,const float* __restrict__ alpha,
    float* __restrict__ ds)
{
  const int b=blockIdx.x, t=threadIdx.x;
  const float* fb=feat+(long)b*4096*128;
  const float* dm=dMu+b*4096; const float* de=dE2+b*4096;
  float acc=0.f;
#pragma unroll 4
  for(int d=0;d<4096;d++){
    float f=fb[(long)d*128+t];
    acc+=dm[d]*f+de[d]*f*f;
  }
  __shared__ float buf[128];
  float a=alpha[b*128+t];
  buf[t]=a*acc; __syncthreads();
  for(int off=64;off;off>>=1){ if(t<off) buf[t]+=buf[t+off]; __syncthreads(); }
  ds[b*128+t]=a*(acc-buf[0]);
}

// ---------- dz = va[h]*ds[b,t]*(1-att^2) ----------
__global__ void k_dz(const float* __restrict__ att,const float* __restrict__ ds,
    const float* __restrict__ va,float* __restrict__ dz)
{
  int i=blockIdx.x*256+threadIdx.x; if(i>=524288) return;
  int t=i&127, h=(i>>7)&127, b=i>>14;
  float a=att[i];
  dz[i]=va[h]*ds[b*128+t]*(1.f-a*a);
}

// ---------- dfeat = Wa^T@dz + alpha*(dMu+2*dE2*feat), masked by feat>0 ----------
__global__ void __launch_bounds__(256) k_dfeat(
    const float* __restrict__ Wa, const float* __restrict__ dz,
    const float* __restrict__ feat, const float* __restrict__ alpha,
    const float* __restrict__ dMu, const float* __restrict__ dE2,
    float* __restrict__ dout3)
{
  __shared__ float As[16][132];
  __shared__ float Bs[16][128];
  __shared__ float al[128];
  const int b=blockIdx.y, d0=blockIdx.x*128;
  const int tid=threadIdx.x, tx=tid%16, ty=tid/16;
  if(tid<128) al[tid]=alpha[b*128+tid];
  float acc[8][8];
#pragma unroll
  for(int i=0;i<8;i++)
#pragma unroll
  for(int j=0;j<8;j++) acc[i][j]=0.f;
  for(int k0=0;k0<128;k0+=16){
    __syncthreads();
#pragma unroll
    for(int l=0;l<8;l++){
      int idx=tid+l*256; int kk=idx/128, dd=idx%128;
      As[kk][dd]=Wa[(long)(k0+kk)*4096+d0+dd];
    }
#pragma unroll
    for(int l=0;l<8;l++){
      int idx=tid+l*256; int kk=idx/128, t=idx%128;
      Bs[kk][t]=dz[((long)b*128+k0+kk)*128+t];
    }
    __syncthreads();
#pragma unroll
    for(int kk=0;kk<16;kk++){
      float ra[8],rb[8];
#pragma unroll
      for(int i=0;i<8;i++) ra[i]=As[kk][ty*8+i];
      *(float4*)rb    =*(float4*)&Bs[kk][tx*8];
      *(float4*)(rb+4)=*(float4*)&Bs[kk][tx*8+4];
#pragma unroll
      for(int i=0;i<8;i++)
#pragma unroll
      for(int j=0;j<8;j++) acc[i][j]+=ra[i]*rb[j];
    }
  }
#pragma unroll
  for(int i=0;i<8;i++){
    int d=d0+ty*8+i;
    float dm=dMu[(long)b*4096+d], de=dE2[(long)b*4096+d];
#pragma unroll
    for(int j=0;j<8;j++){
      int t=tx*8+j;
      long fi=((long)b*4096+d)*128+t;
      float f=feat[fi];
      float val=acc[i][j]+al[t]*(dm+2.f*de*f);
      dout3[fi]= f>0.f? val:0.f;
    }
  }
}

// ---------- row / col stats ----------
__global__ void k_rowstats(const float* __restrict__ fam,const float* __restrict__ x,
    float* __restrict__ cm,float* __restrict__ meanT)
{
  int w=(blockIdx.x*blockDim.x+threadIdx.x)>>5, lane=threadIdx.x&31;
  if(w>=4096) return;
  const float* fr=fam+(long)w*1024; const float* xr=x+(long)w*1024;
  float m=-1e30f, s=0.f;
  for(int t=lane;t<1024;t+=32){ m=fmaxf(m,fr[t]); s+=xr[t]; }
  for(int o=16;o;o>>=1){ m=fmaxf(m,__shfl_down_sync(~0u,m,o)); s+=__shfl_down_sync(~0u,s,o); }
  if(!lane){ cm[w]=m; meanT[w]=s*(1.f/1024.f); }
}
__global__ void k_colstats(const float* __restrict__ fam,const float* __restrict__ x,
    float* __restrict__ tm,float* __restrict__ meanF)
{
  int i=blockIdx.x*256+threadIdx.x; if(i>=32768) return;
  int b=i>>10, t=i&1023;
  const float* fb=fam+(long)b*131072+t; const float* xb=x+(long)b*131072+t;
  float m=-1e30f, s=0.f;
#pragma unroll 4
  for(int f=0;f<128;f++){ m=fmaxf(m,fb[f*1024]); s+=xb[f*1024]; }
  tm[i]=m; meanF[i]=s*(1.f/128.f);
}

// ---------- bitonic argsort: value desc, index asc (stable-equivalent) ----------
template<int N>
__global__ void k_sort(const float* __restrict__ vals, int* __restrict__ idxout)
{
  __shared__ unsigned long long key[N];
  const int b=blockIdx.x, tid=threadIdx.x, TH=N/2;
  for(int i=tid;i<N;i+=TH){
    unsigned u=__float_as_uint(vals[b*N+i]);
    u = (u&0x80000000u)? ~u : (u|0x80000000u);
    key[i]=((unsigned long long)(~u)<<32)|(unsigned)i;
  }
  __syncthreads();
  for(int k=2;k<=N;k<<=1)
    for(int j=k>>1;j;j>>=1){
      for(int i=tid;i<N;i+=TH){
        int ixj=i^j;
        if(ixj>i){
          bool up=((i&k)==0);
          unsigned long long a=key[i],c=key[ixj];
          if((a>c)==up){ key[i]=c; key[ixj]=a; }
        }
      }
      __syncthreads();
    }
  for(int i=tid;i<128;i+=TH) idxout[b*128+i]=(int)(key[i]&0xFFFFFFFFu);
}

// ---------- RFM sequential scan -> rowstep/colstep (thread per batch) ----------
__global__ void k_rfm(const int* __restrict__ sc,const int* __restrict__ st,
    const int* __restrict__ mask_t,const int* __restrict__ s_t,
    const int* __restrict__ is_train,int* __restrict__ rstep,int* __restrict__ cstep)
{
  int b=threadIdx.x; if(b>=32) return;
  int* rs=rstep+b*128; int* cs=cstep+b*1024;
  for(int i=0;i<128;i++) rs[i]=-1;
  for(int i=0;i<1024;i++) cs[i]=-1;
  if(is_train && is_train[0]==0) return;
  int cnt=0;
  for(int s=0;s<128 && cnt<3;s++){
    int pc=sc[b*128+s], pt=st[b*128+s];
    if(rs[pc]!=-1||cs[pt]!=-1) continue;
    int mt=mask_t[b*128+s], ss=s_t[b*128+s];
    rs[pc]=s;
    int l=pt-ss; if(l<0)l=0;
    int r=pt+mt-ss; if(r>1024)r=1024;
    for(int t=l;t<r;t++) cs[t]=s;
    cnt++;
  }
}

// ---------- apply mask ----------
__global__ void k_apply(const float* __restrict__ x,const int* __restrict__ rstep,
    const int* __restrict__ cstep,const float* __restrict__ meanT,
    const float* __restrict__ meanF,float* __restrict__ xm)
{
  long i=(long)blockIdx.x*256+threadIdx.x; if(i>=4194304) return;
  int t=(int)(i&1023); int f=(int)((i>>10)&127); int b=(int)(i>>17);
  int rs=rstep[b*128+f], cs=cstep[b*1024+t];
  float v;
  if(rs<0&&cs<0) v=x[i];
  else v=(cs>=rs)? meanT[b*128+f] : meanF[b*1024+t];
  xm[i]=v;
}

// ---------- final head: emb = [mu,sg]@We+be; out = emb@Wc+bc ----------
__global__ void __launch_bounds__(256) k_emb(
    const float* __restrict__ mu,const float* __restrict__ m2,
    const float* __restrict__ We,const float* __restrict__ be,
    const float* __restrict__ Wc,const float* __restrict__ bc,
    float* __restrict__ out)
{
  const int b=blockIdx.x, j=threadIdx.x;
  const float* mub=mu+b*4096; const float* m2b=m2+b*4096;
  float acc=0.f;
#pragma unroll 4
  for(int i=0;i<4096;i++) acc+=mub[i]*We[(long)i*256+j];
#pragma unroll 4
  for(int i=0;i<4096;i++){
    float m=mub[i];
    float sg=sqrtf(fmaxf(m2b[i]-m*m,1e-5f));
    acc+=sg*We[(long)(4096+i)*256+j];
  }
  __shared__ float es[256];
  es[j]=acc+be[j];
  __syncthreads();
  if(j<2){
    float s=bc[j];
    for(int q=0;q<256;q++) s+=es[q]*Wc[q*2+j];
    out[b*2+j]=s;
  }
}

// ---------- host ----------
static void run_fwd(const float* xin,const float* W1,const float* b1,
                    const float* W2,const float* b2,const float* W3,const float* b3,
                    const float* Wa,const float* ba,const float* va,
                    float* h1,float* h2,float* h3,float* att,float* alpha,
                    float* mu,float* m2)
{
  k_conv_fwd<1,64,128,1024,1,16,4,256><<<dim3(8,64,32),256>>>(xin,W1,b1,h1);
  k_conv_fwd<64,128,64,512,4,16,8,256><<<dim3(4,32,32),256>>>(h1,W2,b2,h2);
  k_conv_fwd<128,256,32,256,4,32,8,512><<<dim3(2,16,32),512>>>(h2,W3,b3,h3);
  k_att<<<32,256>>>(Wa,h3,ba,att);
  k_salpha<<<32,128>>>(att,va,alpha);
  k_mustats<<<16384,256>>>(h3,alpha,mu,m2);
}

extern "C" void kernel_launch(void* const* d_in,const int* in_sizes,int n_in,
                              void* d_out,int out_size)
{
  const float* x =(const float*)d_in[0];
  const float* W1=(const float*)d_in[1]; const float* b1=(const float*)d_in[2];
  const float* W2=(const float*)d_in[3]; const float* b2=(const float*)d_in[4];
  const float* W3=(const float*)d_in[5]; const float* b3=(const float*)d_in[6];
  const float* Wa=(const float*)d_in[7]; const float* ba=(const float*)d_in[8];
  const float* va=(const float*)d_in[9];
  const float* We=(const float*)d_in[10]; const float* be=(const float*)d_in[11];
  const float* Wc=(const float*)d_in[12]; const float* bc=(const float*)d_in[13];
  const int* mask_t=(const int*)d_in[14]; const int* s_t=(const int*)d_in[15];
  const int* is_train = (n_in>16)? (const int*)d_in[16] : nullptr;
  float* out=(float*)d_out;

  float *h1,*h2,*h3,*d1,*d2,*d3,*fam,*xm,*att,*dz,*alpha,*ds,*mu,*m2,*dMu,*dE2,*gvec;
  float *cm,*tm,*meanT,*meanF;
  int *sc,*st,*rstep,*cstep;
  cudaGetSymbolAddress((void**)&h1,g_h1);   cudaGetSymbolAddress((void**)&h2,g_h2);
  cudaGetSymbolAddress((void**)&h3,g_h3);   cudaGetSymbolAddress((void**)&d1,g_d1);
  cudaGetSymbolAddress((void**)&d2,g_d2);   cudaGetSymbolAddress((void**)&d3,g_d3);
  cudaGetSymbolAddress((void**)&fam,g_fam); cudaGetSymbolAddress((void**)&xm,g_xm);
  cudaGetSymbolAddress((void**)&att,g_att); cudaGetSymbolAddress((void**)&dz,g_dzb);
  cudaGetSymbolAddress((void**)&alpha,g_alpha); cudaGetSymbolAddress((void**)&ds,g_dsb);
  cudaGetSymbolAddress((void**)&mu,g_mu);   cudaGetSymbolAddress((void**)&m2,g_m2);
  cudaGetSymbolAddress((void**)&dMu,g_dMu); cudaGetSymbolAddress((void**)&dE2,g_dE2);
  cudaGetSymbolAddress((void**)&gvec,g_gvec);
  cudaGetSymbolAddress((void**)&cm,g_cm);   cudaGetSymbolAddress((void**)&tm,g_tm);
  cudaGetSymbolAddress((void**)&meanT,g_meanT); cudaGetSymbolAddress((void**)&meanF,g_meanF);
  cudaGetSymbolAddress((void**)&sc,g_sc);   cudaGetSymbolAddress((void**)&st,g_st);
  cudaGetSymbolAddress((void**)&rstep,g_rstep); cudaGetSymbolAddress((void**)&cstep,g_cstep);

  // constant head cotangent
  k_gvec<<<1024,256>>>(We,Wc,gvec);
  // pass 1: forward on x (stores activations for backward)
  run_fwd(x,W1,b1,W2,b2,W3,b3,Wa,ba,va,h1,h2,h3,att,alpha,mu,m2);
  // backward to input
  k_dcoef<<<512,256>>>(mu,m2,gvec,dMu,dE2);
  k_dalpha<<<32,128>>>(h3,dMu,dE2,alpha,ds);
  k_dz<<<2048,256>>>(att,ds,va,dz);
  k_dfeat<<<dim3(32,32),256>>>(Wa,dz,h3,alpha,dMu,dE2,d3);
  k_conv_bwd<128,256,16,128,8,8><<<dim3(4,32,32),256>>>(d3,W3,h2,d2);
  k_conv_bwd<64,128,32,256,16,4><<<dim3(8,64,32),256>>>(d2,W2,h1,d1);
  k_bwd1<<<dim3(2,128,32),256>>>(d1,W1,fam);
  // masks
  k_rowstats<<<512,256>>>(fam,x,cm,meanT);
  k_colstats<<<128,256>>>(fam,x,tm,meanF);
  k_sort<128><<<32,64>>>(cm,sc);
  k_sort<1024><<<32,512>>>(tm,st);
  k_rfm<<<1,32>>>(sc,st,mask_t,s_t,is_train,rstep,cstep);
  k_apply<<<16384,256>>>(x,rstep,cstep,meanT,meanF,xm);
  // pass 2: forward on masked input + head
  run_fwd(xm,W1,b1,W2,b2,W3,b3,Wa,ba,va,h1,h2,h3,att,alpha,mu,m2);
  k_emb<<<32,256>>>(mu,m2,We,be,Wc,bc,out);
}

// round 4
// speedup vs baseline: 2.0102x; 2.0102x over previous
#include <cuda_runtime.h>
#include <math.h>

// ---------- static scratch ----------
__device__ float g_h1[67108864];
__device__ float g_h2[33554432];
__device__ float g_h3[16777216];
__device__ float g_d1[67108864];
__device__ float g_d2[33554432];
__device__ float g_d3[16777216];
__device__ float g_fam[4194304];
__device__ float g_xm[4194304];
__device__ float g_att[524288];
__device__ float g_attp[4194304];
__device__ float g_dzb[524288];
__device__ float g_alpha[4096];
__device__ float g_dsb[4096];
__device__ float g_dap[32768];
__device__ float g_mu[131072];
__device__ float g_m2[131072];
__device__ float g_dMu[131072];
__device__ float g_dE2[131072];
__device__ float g_gvec[8192];
__device__ float g_cat[262144];
__device__ float g_ep[1048576];
__device__ float g_cm[4096];
__device__ float g_tm[32768];
__device__ float g_meanT[4096];
__device__ float g_meanF[32768];
__device__ int   g_sc[4096];
__device__ int   g_st[4096];
__device__ int   g_rstep[4096];
__device__ int   g_cstep[32768];
__device__ float g_wtf2[73728];
__device__ float g_wtb2[73728];
__device__ float g_wtf3[294912];
__device__ float g_wtb3[294912];

// ---------- weight transposes: WTf[(c*9+k)*COUT+o], WTb[(o*9+k)*CIN+c] ----------
__global__ void k_wt(const float* __restrict__ W, float* __restrict__ WTf,
                     float* __restrict__ WTb, int CIN, int COUT)
{
  int idx=blockIdx.x*256+threadIdx.x;
  int tot=CIN*COUT*9; if(idx>=tot) return;
  int k=idx%9, c=(idx/9)%CIN, o=idx/(9*CIN);
  float v=W[idx];
  WTf[((long)c*9+k)*COUT+o]=v;
  WTb[((long)o*9+k)*CIN+c]=v;
}

// ---------- conv1 fwd (CIN=1, small) ----------
template<int CIN,int COUT,int HIN,int WIN,int CC,int OG,int OP,int THREADS>
__global__ void __launch_bounds__(THREADS) k_conv_fwd(
    const float* __restrict__ in, const float* __restrict__ W,
    const float* __restrict__ bias, float* __restrict__ out)
{
  constexpr int HOUT=HIN/2, WOUT=WIN/2;
  __shared__ float ins[CC*3*130];
  __shared__ float ws[CC*9*COUT];
  const int n=blockIdx.z, i=blockIdx.y, j0=blockIdx.x*64;
  const int tid=threadIdx.x, og=tid%OG, jt=tid/OG;
  float acc[OP][4];
#pragma unroll
  for(int o=0;o<OP;o++){acc[o][0]=acc[o][1]=acc[o][2]=acc[o][3]=0.f;}
  for(int c0=0;c0<CIN;c0+=CC){
    __syncthreads();
    for(int idx=tid; idx<CC*3*130; idx+=THREADS){
      int c=idx/390, r=(idx/130)%3, col=idx%130;
      int gx=2*i+r, gy=2*j0+col;
      float v=0.f;
      if(gx<HIN && gy<WIN) v=in[(((long)n*CIN+c0+c)*HIN+gx)*WIN+gy];
      ins[idx]=v;
    }
    for(int idx=tid; idx<COUT*CC*9; idx+=THREADS){
      int o=idx/(CC*9), rem=idx%(CC*9);
      ws[rem*COUT+o]=W[(long)o*CIN*9 + c0*9 + rem];
    }
    __syncthreads();
#pragma unroll
    for(int c=0;c<CC;c++)
#pragma unroll
    for(int r=0;r<3;r++){
      float v[9];
#pragma unroll
      for(int m=0;m<9;m++) v[m]=ins[(c*3+r)*130 + 8*jt + m];
#pragma unroll
      for(int kj=0;kj<3;kj++)
#pragma unroll
      for(int oo=0;oo<OP;oo++){
        float w=ws[(c*9+r*3+kj)*COUT + og + OG*oo];
        acc[oo][0]+=w*v[kj];   acc[oo][1]+=w*v[2+kj];
        acc[oo][2]+=w*v[4+kj]; acc[oo][3]+=w*v[6+kj];
      }
    }
  }
  int j=j0+4*jt;
#pragma unroll
  for(int oo=0;oo<OP;oo++){
    int o=og+OG*oo; float bb=bias[o];
    float4 r;
    r.x=fmaxf(acc[oo][0]+bb,0.f); r.y=fmaxf(acc[oo][1]+bb,0.f);
    r.z=fmaxf(acc[oo][2]+bb,0.f); r.w=fmaxf(acc[oo][3]+bb,0.f);
    *(float4*)&out[(((long)n*COUT+o)*HOUT+i)*WOUT+j]=r;
  }
}

// ---------- big conv fwd: 8x8 register tile, deinterleaved smem ----------
// block tile: 128 out-chans x 128 out-cols, one row i, one batch.
template<int CIN,int COUT,int HIN,int WIN,int CC>
__global__ void __launch_bounds__(256,2) k_cfwd(
    const float* __restrict__ in, const float* __restrict__ WT,
    const float* __restrict__ bias, float* __restrict__ out)
{
  constexpr int HOUT=HIN/2, WOUT=WIN/2;
  constexpr int NJT=WOUT/128;
  __shared__ __align__(16) float ev[CC*3][136];
  __shared__ __align__(16) float od[CC*3][136];
  __shared__ __align__(16) float ws[CC*9][128];
  const int n=blockIdx.z, i=blockIdx.y;
  const int jt_=blockIdx.x%NJT, ot=blockIdx.x/NJT;
  const int j0=jt_*128, o0=ot*128;
  const int tid=threadIdx.x, tx=tid%16, ty=tid/16;
  float acc[8][8];
#pragma unroll
  for(int a=0;a<8;a++)
#pragma unroll
  for(int b=0;b<8;b++) acc[a][b]=0.f;

  for(int c0=0;c0<CIN;c0+=CC){
    __syncthreads();
    for(int idx=tid; idx<CC*3*129; idx+=256){
      int c=idx/387, rem=idx%387, r=rem/129, p=rem%129;
      int gx=2*i+r, gy=2*j0+2*p;
      float a=0.f,b=0.f;
      if(gx<HIN && gy<WIN){
        const float2 s=*(const float2*)&in[(((long)n*CIN+c0+c)*HIN+gx)*WIN+gy];
        a=s.x; b=s.y;
      }
      ev[c*3+r][p]=a;
      if(p<128) od[c*3+r][p]=b;
    }
    for(int idx=tid; idx<CC*9*32; idx+=256){
      int k=idx/32, oq=idx%32;
      *(float4*)&ws[k][oq*4] = *(const float4*)&WT[((long)c0*9 + k)*COUT + o0 + oq*4];
    }
    __syncthreads();
#pragma unroll
    for(int k=0;k<CC*3;k++){
      float e[9], oV[8];
      *(float4*)e     = *(float4*)&ev[k][tx*8];
      *(float4*)(e+4) = *(float4*)&ev[k][tx*8+4];
      e[8]            = ev[k][tx*8+8];
      *(float4*)oV    = *(float4*)&od[k][tx*8];
      *(float4*)(oV+4)= *(float4*)&od[k][tx*8+4];
#pragma unroll
      for(int kj=0;kj<3;kj++){
        float w[8];
        *(float4*)w    =*(float4*)&ws[k*3+kj][ty*8];
        *(float4*)(w+4)=*(float4*)&ws[k*3+kj][ty*8+4];
#pragma unroll
        for(int ii=0;ii<8;ii++)
#pragma unroll
        for(int jj=0;jj<8;jj++){
          float v = (kj==0)? e[jj] : (kj==1)? oV[jj] : e[jj+1];
          acc[ii][jj] += w[ii]*v;
        }
      }
    }
  }
#pragma unroll
  for(int ii=0;ii<8;ii++){
    int o=o0+ty*8+ii;
    float bb=bias[o];
    float4 r0,r1;
    r0.x=fmaxf(acc[ii][0]+bb,0.f); r0.y=fmaxf(acc[ii][1]+bb,0.f);
    r0.z=fmaxf(acc[ii][2]+bb,0.f); r0.w=fmaxf(acc[ii][3]+bb,0.f);
    r1.x=fmaxf(acc[ii][4]+bb,0.f); r1.y=fmaxf(acc[ii][5]+bb,0.f);
    r1.z=fmaxf(acc[ii][6]+bb,0.f); r1.w=fmaxf(acc[ii][7]+bb,0.f);
    long base=(((long)n*COUT+o)*HOUT+i)*WOUT + j0 + tx*8;
    *(float4*)&out[base]=r0; *(float4*)&out[base+4]=r1;
  }
}

// ---------- big conv bwd: x-row-pair, 4chan x 8col x 2row tile ----------
// din[c,x,y] = relu'(act) * sum W[o,c,ki,kj]*dout[o,(x-ki)/2,(y-kj)/2]
template<int CIN,int COUT,int HOUT,int WOUT,int OCC>
__global__ void __launch_bounds__(256,2) k_cbwd(
    const float* __restrict__ dout, const float* __restrict__ WT,
    const float* __restrict__ act, float* __restrict__ din)
{
  constexpr int HIN=2*HOUT, WIN=2*WOUT;
  constexpr int NJT=WIN/128;
  __shared__ __align__(16) float dsA[OCC][72];
  __shared__ __align__(16) float dsB[OCC][72];
  __shared__ __align__(16) float ws[OCC*9][64];
  const int n=blockIdx.z, q=blockIdx.y;          // rows x=2q, 2q+1
  const int jt_=blockIdx.x%NJT, ct=blockIdx.x/NJT;
  const int y0=jt_*128, c0=ct*64;
  const int tid=threadIdx.x, tx=tid%16, ty=tid/16;
  const int jbase=y0/2-1;
  float accE[4][8], accO[4][8];
#pragma unroll
  for(int c=0;c<4;c++)
#pragma unroll
  for(int u=0;u<8;u++){accE[c][u]=0.f; accO[c][u]=0.f;}

  for(int o0=0;o0<COUT;o0+=OCC){
    __syncthreads();
    for(int idx=tid; idx<OCC*66; idx+=256){
      int o=idx/66, jl=idx%66, j=jbase+jl;
      float a=0.f,b=0.f;
      if(j>=0 && j<WOUT){
        a = dout[(((long)n*COUT+o0+o)*HOUT+q)*WOUT+j];
        if(q>0) b = dout[(((long)n*COUT+o0+o)*HOUT+q-1)*WOUT+j];
      }
      dsA[o][jl]=a; dsB[o][jl]=b;
    }
    for(int idx=tid; idx<OCC*9*16; idx+=256){
      int k=idx/16, cq=idx%16;
      *(float4*)&ws[k][cq*4] = *(const float4*)&WT[((long)o0*9 + k)*CIN + c0 + cq*4];
    }
    __syncthreads();
#pragma unroll
    for(int o=0;o<OCC;o++){
      float a[5], b[5];
      *(float4*)a=*(float4*)&dsA[o][tx*4]; a[4]=dsA[o][tx*4+4];
      *(float4*)b=*(float4*)&dsB[o][tx*4]; b[4]=dsB[o][tx*4+4];
#pragma unroll
      for(int ki=0;ki<3;ki++){
        const float* s = (ki==2)? b : a;
#pragma unroll
        for(int kj=0;kj<3;kj++){
          float w[4];
          *(float4*)w=*(float4*)&ws[o*9+ki*3+kj][ty*4];
#pragma unroll
          for(int c=0;c<4;c++)
#pragma unroll
          for(int e=0;e<4;e++){
            float v = w[c]*((kj==2)? s[e] : s[e+1]);
            int u = (kj==1)? 2*e+1 : 2*e;
            if(ki==1) accO[c][u]+=v; else accE[c][u]+=v;
          }
        }
      }
    }
  }
  const int xE=2*q;
#pragma unroll
  for(int c=0;c<4;c++){
    int ci=c0+ty*4+c;
    long bE=(((long)n*CIN+ci)*HIN+xE)*WIN + y0 + tx*8;
    long bO=bE+WIN;
    float4 mE0=*(const float4*)&act[bE],  mE1=*(const float4*)&act[bE+4];
    float4 mO0=*(const float4*)&act[bO],  mO1=*(const float4*)&act[bO+4];
    float4 r;
    r.x=mE0.x>0.f?accE[c][0]:0.f; r.y=mE0.y>0.f?accE[c][1]:0.f;
    r.z=mE0.z>0.f?accE[c][2]:0.f; r.w=mE0.w>0.f?accE[c][3]:0.f;
    *(float4*)&din[bE]=r;
    r.x=mE1.x>0.f?accE[c][4]:0.f; r.y=mE1.y>0.f?accE[c][5]:0.f;
    r.z=mE1.z>0.f?accE[c][6]:0.f; r.w=mE1.w>0.f?accE[c][7]:0.f;
    *(float4*)&din[bE+4]=r;
    r.x=mO0.x>0.f?accO[c][0]:0.f; r.y=mO0.y>0.f?accO[c][1]:0.f;
    r.z=mO0.z>0.f?accO[c][2]:0.f; r.w=mO0.w>0.f?accO[c][3]:0.f;
    *(float4*)&din[bO]=r;
    r.x=mO1.x>0.f?accO[c][4]:0.f; r.y=mO1.y>0.f?accO[c][5]:0.f;
    r.z=mO1.z>0.f?accO[c][6]:0.f; r.w=mO1.w>0.f?accO[c][7]:0.f;
    *(float4*)&din[bO+4]=r;
  }
}

// ---------- conv1 data-grad -> |dx| ----------
__global__ void __launch_bounds__(256) k_bwd1(
    const float* __restrict__ dz1, const float* __restrict__ W1,
    float* __restrict__ fam)
{
  __shared__ float ws[576];
  __shared__ float dsm[8*2*260];
  const int n=blockIdx.z, x=blockIdx.y, y0=blockIdx.x*512;
  const int tid=threadIdx.x;
  for(int idx=tid; idx<576; idx+=256) ws[idx]=W1[idx];
  int iA,iB,kiA,kiB; bool hasB;
  if((x&1)==0){iA=x>>1;kiA=0;iB=iA-1;kiB=2;hasB=(iB>=0);}
  else{iA=(x-1)>>1;kiA=1;iB=0;kiB=0;hasB=false;}
  const int jbase=y0/2-1;
  float accE=0.f, accO=0.f;
  for(int o0=0;o0<64;o0+=8){
    __syncthreads();
    for(int idx=tid; idx<8*2*260; idx+=256){
      int o=idx/520, rs=(idx/260)&1, jj=idx%260;
      int j=jbase+jj; int ir=rs?iB:iA;
      float v=0.f;
      if(j>=0 && j<512 && (rs==0||hasB))
        v=dz1[(((long)n*64+o0+o)*64+ir)*512+j];
      dsm[idx]=v;
    }
    __syncthreads();
#pragma unroll
    for(int o=0;o<8;o++){
#pragma unroll
      for(int rs=0;rs<2;rs++){
        if(rs==1&&!hasB) break;
        int ki=rs?kiB:kiA;
        const float* wb=&ws[(o0+o)*9+ki*3];
        float vm=dsm[(o*2+rs)*260+tid], v0=dsm[(o*2+rs)*260+tid+1];
        accE+=wb[0]*v0+wb[2]*vm; accO+=wb[1]*v0;
      }
    }
  }
  long base=((long)n*128+x)*1024 + y0 + 2*tid;
  fam[base]=fabsf(accE); fam[base+1]=fabsf(accO);
}

// ---------- att partial GEMM: 128x128x512 per block, grid(8 ks, 32 b) ----------
__global__ void __launch_bounds__(256) k_attp(
    const float* __restrict__ Wa, const float* __restrict__ feat,
    float* __restrict__ attp)
{
  __shared__ float As[128][17];
  __shared__ float Fs[16][128];
  const int ks=blockIdx.x, b=blockIdx.y, tid=threadIdx.x, tx=tid%16, ty=tid/16;
  const float* fb = feat + (long)b*524288;
  float acc[8][8];
#pragma unroll
  for(int i=0;i<8;i++)
#pragma unroll
  for(int j=0;j<8;j++) acc[i][j]=0.f;
  for(int k0=ks*512;k0<ks*512+512;k0+=16){
    __syncthreads();
#pragma unroll
    for(int l=0;l<8;l++){
      int idx=tid+l*256; int h=idx/16, kk=idx%16;
      As[h][kk]=Wa[(long)h*4096+k0+kk];
    }
#pragma unroll
    for(int l=0;l<8;l++){
      int idx=tid+l*256; int kk=idx/128, t=idx%128;
      Fs[kk][t]=fb[(long)(k0+kk)*128+t];
    }
    __syncthreads();
#pragma unroll
    for(int kk=0;kk<16;kk++){
      float ra[8], rb[8];
#pragma unroll
      for(int i=0;i<8;i++) ra[i]=As[ty*8+i][kk];
      *(float4*)rb     = *(float4*)&Fs[kk][tx*8];
      *(float4*)(rb+4) = *(float4*)&Fs[kk][tx*8+4];
#pragma unroll
      for(int i=0;i<8;i++)
#pragma unroll
      for(int j=0;j<8;j++) acc[i][j]+=ra[i]*rb[j];
    }
  }
#pragma unroll
  for(int i=0;i<8;i++){
    int h=ty*8+i;
#pragma unroll
    for(int j=0;j<8;j++)
      attp[(long)ks*524288 + ((long)b*128+h)*128+tx*8+j]=acc[i][j];
  }
}
__global__ void k_attf(const float* __restrict__ attp, const float* __restrict__ ba,
                       float* __restrict__ att)
{
  int i=blockIdx.x*256+threadIdx.x; if(i>=524288) return;
  int h=(i>>7)&127;
  float s=0.f;
#pragma unroll
  for(int ks=0;ks<8;ks++) s+=attp[(long)ks*524288+i];
  att[i]=tanhf(s+ba[h]);
}

// ---------- softmax over t ----------
__global__ void __launch_bounds__(128) k_salpha(
    const float* __restrict__ att, const float* __restrict__ va,
    float* __restrict__ alpha)
{
  __shared__ float vs[128], buf[128];
  const int b=blockIdx.x, t=threadIdx.x;
  vs[t]=va[t];
  __syncthreads();
  float s=0.f;
#pragma unroll 4
  for(int h=0;h<128;h++) s+=vs[h]*att[((long)b*128+h)*128+t];
  buf[t]=s; __syncthreads();
  for(int off=64;off;off>>=1){ if(t<off) buf[t]=fmaxf(buf[t],buf[t+off]); __syncthreads(); }
  float mx=buf[0]; __syncthreads();
  float e=expf(s-mx);
  buf[t]=e; __syncthreads();
  for(int off=64;off;off>>=1){ if(t<off) buf[t]+=buf[t+off]; __syncthreads(); }
  alpha[b*128+t]=e/buf[0];
}

// ---------- mu, m2 ----------
__global__ void k_mustats(const float* __restrict__ feat,
    const float* __restrict__ alpha, float* __restrict__ mu, float* __restrict__ m2)
{
  int w=(blockIdx.x*blockDim.x+threadIdx.x)>>5, lane=threadIdx.x&31;
  if(w>=131072) return;
  int b=w>>12;
  const float* fr=feat+(long)w*128;
  const float* ar=alpha+b*128;
  float s1=0.f,s2=0.f;
#pragma unroll
  for(int t=lane;t<128;t+=32){
    float a=ar[t], f=fr[t];
    s1+=a*f; s2+=a*f*f;
  }
  for(int o=16;o;o>>=1){ s1+=__shfl_down_sync(~0u,s1,o); s2+=__shfl_down_sync(~0u,s2,o); }
  if(!lane){ mu[w]=s1; m2[w]=s2; }
}

// ---------- gvec = We @ (Wc[:,1]-Wc[:,0]) ----------
__global__ void k_gvec(const float* __restrict__ We,const float* __restrict__ Wc,
                       float* __restrict__ gvec)
{
  int w=(blockIdx.x*blockDim.x+threadIdx.x)>>5, lane=threadIdx.x&31;
  if(w>=8192) return;
  float s=0.f;
  for(int j=lane;j<256;j+=32) s+=We[(long)w*256+j]*(Wc[j*2+1]-Wc[j*2]);
  for(int o=16;o;o>>=1) s+=__shfl_down_sync(~0u,s,o);
  if(!lane) gvec[w]=s;
}

// ---------- dMu,dE2 ----------
__global__ void k_dcoef(const float* __restrict__ mu,const float* __restrict__ m2,
    const float* __restrict__ gvec, float* __restrict__ dMu,float* __restrict__ dE2)
{
  int i=blockIdx.x*256+threadIdx.x; if(i>=131072) return;
  int d=i&4095;
  float m=mu[i], v=m2[i]-m*m;
  float g2=gvec[4096+d];
  float dE=0.f, dM=gvec[d];
  if(v>1e-5f){ float sg=sqrtf(v); dE=0.5f*g2/sg; dM-=g2*m/sg; }
  dMu[i]=dM; dE2[i]=dE;
}

// ---------- dalpha split ----------
__global__ void __launch_bounds__(128) k_dalp(
    const float* __restrict__ feat,const float* __restrict__ dMu,
    const float* __restrict__ dE2,float* __restrict__ part)
{
  const int ks=blockIdx.x, b=blockIdx.y, t=threadIdx.x;
  const float* fb=feat+(long)b*524288;
  const float* dm=dMu+b*4096; const float* de=dE2+b*4096;
  float acc=0.f;
  int d0=ks*512;
#pragma unroll 4
  for(int d=d0;d<d0+512;d++){
    float f=fb[(long)d*128+t];
    acc+=dm[d]*f+de[d]*f*f;
  }
  part[(ks*32+b)*128+t]=acc;
}
__global__ void __launch_bounds__(128) k_dalf(
    const float* __restrict__ part,const float* __restrict__ alpha,
    float* __restrict__ ds)
{
  const int b=blockIdx.x, t=threadIdx.x;
  float acc=0.f;
#pragma unroll
  for(int ks=0;ks<8;ks++) acc+=part[(ks*32+b)*128+t];
  __shared__ float buf[128];
  float a=alpha[b*128+t];
  buf[t]=a*acc; __syncthreads();
  for(int off=64;off;off>>=1){ if(t<off) buf[t]+=buf[t+off]; __syncthreads(); }
  ds[b*128+t]=a*(acc-buf[0]);
}

// ---------- dz ----------
__global__ void k_dz(const float* __restrict__ att,const float* __restrict__ ds,
    const float* __restrict__ va,float* __restrict__ dz)
{
  int i=blockIdx.x*256+threadIdx.x; if(i>=524288) return;
  int t=i&127, h=(i>>7)&127, b=i>>14;
  float a=att[i];
  dz[i]=va[h]*ds[b*128+t]*(1.f-a*a);
}

// ---------- dfeat ----------
__global__ void __launch_bounds__(256) k_dfeat(
    const float* __restrict__ Wa, const float* __restrict__ dz,
    const float* __restrict__ feat, const float* __restrict__ alpha,
    const float* __restrict__ dMu, const float* __restrict__ dE2,
    float* __restrict__ dout3)
{
  __shared__ float As[16][132];
  __shared__ float Bs[16][128];
  __shared__ float al[128];
  const int b=blockIdx.y, d0=blockIdx.x*128;
  const int tid=threadIdx.x, tx=tid%16, ty=tid/16;
  if(tid<128) al[tid]=alpha[b*128+tid];
  float acc[8][8];
#pragma unroll
  for(int i=0;i<8;i++)
#pragma unroll
  for(int j=0;j<8;j++) acc[i][j]=0.f;
  for(int k0=0;k0<128;k0+=16){
    __syncthreads();
#pragma unroll
    for(int l=0;l<8;l++){
      int idx=tid+l*256; int kk=idx/128, dd=idx%128;
      As[kk][dd]=Wa[(long)(k0+kk)*4096+d0+dd];
    }
#pragma unroll
    for(int l=0;l<8;l++){
      int idx=tid+l*256; int kk=idx/128, t=idx%128;
      Bs[kk][t]=dz[((long)b*128+k0+kk)*128+t];
    }
    __syncthreads();
#pragma unroll
    for(int kk=0;kk<16;kk++){
      float ra[8],rb[8];
#pragma unroll
      for(int i=0;i<8;i++) ra[i]=As[kk][ty*8+i];
      *(float4*)rb    =*(float4*)&Bs[kk][tx*8];
      *(float4*)(rb+4)=*(float4*)&Bs[kk][tx*8+4];
#pragma unroll
      for(int i=0;i<8;i++)
#pragma unroll
      for(int j=0;j<8;j++) acc[i][j]+=ra[i]*rb[j];
    }
  }
#pragma unroll
  for(int i=0;i<8;i++){
    int d=d0+ty*8+i;
    float dm=dMu[(long)b*4096+d], de=dE2[(long)b*4096+d];
#pragma unroll
    for(int j=0;j<8;j++){
      int t=tx*8+j;
      long fi=((long)b*4096+d)*128+t;
      float f=feat[fi];
      float val=acc[i][j]+al[t]*(dm+2.f*de*f);
      dout3[fi]= f>0.f? val:0.f;
    }
  }
}

// ---------- row/col stats ----------
__global__ void k_rowstats(const float* __restrict__ fam,const float* __restrict__ x,
    float* __restrict__ cm,float* __restrict__ meanT)
{
  int w=(blockIdx.x*blockDim.x+threadIdx.x)>>5, lane=threadIdx.x&31;
  if(w>=4096) return;
  const float* fr=fam+(long)w*1024; const float* xr=x+(long)w*1024;
  float m=-1e30f, s=0.f;
  for(int t=lane;t<1024;t+=32){ m=fmaxf(m,fr[t]); s+=xr[t]; }
  for(int o=16;o;o>>=1){ m=fmaxf(m,__shfl_down_sync(~0u,m,o)); s+=__shfl_down_sync(~0u,s,o); }
  if(!lane){ cm[w]=m; meanT[w]=s*(1.f/1024.f); }
}
__global__ void k_colstats(const float* __restrict__ fam,const float* __restrict__ x,
    float* __restrict__ tm,float* __restrict__ meanF)
{
  int i=blockIdx.x*256+threadIdx.x; if(i>=32768) return;
  int b=i>>10, t=i&1023;
  const float* fb=fam+(long)b*131072+t; const float* xb=x+(long)b*131072+t;
  float m=-1e30f, s=0.f;
#pragma unroll 4
  for(int f=0;f<128;f++){ m=fmaxf(m,fb[f*1024]); s+=xb[f*1024]; }
  tm[i]=m; meanF[i]=s*(1.f/128.f);
}

// ---------- bitonic argsort (value desc, index asc) ----------
template<int N>
__global__ void k_sort(const float* __restrict__ vals, int* __restrict__ idxout)
{
  __shared__ unsigned long long key[N];
  const int b=blockIdx.x, tid=threadIdx.x, TH=N/2;
  for(int i=tid;i<N;i+=TH){
    unsigned u=__float_as_uint(vals[b*N+i]);
    u = (u&0x80000000u)? ~u : (u|0x80000000u);
    key[i]=((unsigned long long)(~u)<<32)|(unsigned)i;
  }
  __syncthreads();
  for(int k=2;k<=N;k<<=1)
    for(int j=k>>1;j;j>>=1){
      for(int i=tid;i<N;i+=TH){
        int ixj=i^j;
        if(ixj>i){
          bool up=((i&k)==0);
          unsigned long long a=key[i],c=key[ixj];
          if((a>c)==up){ key[i]=c; key[ixj]=a; }
        }
      }
      __syncthreads();
    }
  for(int i=tid;i<128;i+=TH) idxout[b*128+i]=(int)(key[i]&0xFFFFFFFFu);
}

// ---------- RFM scan ----------
__global__ void k_rfm(const int* __restrict__ sc,const int* __restrict__ st,
    const int* __restrict__ mask_t,const int* __restrict__ s_t,
    const int* __restrict__ is_train,int* __restrict__ rstep,int* __restrict__ cstep)
{
  int b=threadIdx.x; if(b>=32) return;
  int* rs=rstep+b*128; int* cs=cstep+b*1024;
  for(int i=0;i<128;i++) rs[i]=-1;
  for(int i=0;i<1024;i++) cs[i]=-1;
  if(is_train && is_train[0]==0) return;
  int cnt=0;
  for(int s=0;s<128 && cnt<3;s++){
    int pc=sc[b*128+s], pt=st[b*128+s];
    if(rs[pc]!=-1||cs[pt]!=-1) continue;
    int mt=mask_t[b*128+s], ss=s_t[b*128+s];
    rs[pc]=s;
    int l=pt-ss; if(l<0)l=0;
    int r=pt+mt-ss; if(r>1024)r=1024;
    for(int t=l;t<r;t++) cs[t]=s;
    cnt++;
  }
}

// ---------- apply mask ----------
__global__ void k_apply(const float* __restrict__ x,const int* __restrict__ rstep,
    const int* __restrict__ cstep,const float* __restrict__ meanT,
    const float* __restrict__ meanF,float* __restrict__ xm)
{
  long i=(long)blockIdx.x*256+threadIdx.x; if(i>=4194304) return;
  int t=(int)(i&1023); int f=(int)((i>>10)&127); int b=(int)(i>>17);
  int rs=rstep[b*128+f], cs=cstep[b*1024+t];
  float v;
  if(rs<0&&cs<0) v=x[i];
  else v=(cs>=rs)? meanT[b*128+f] : meanF[b*1024+t];
  xm[i]=v;
}

// ---------- emb head: cat, split-K GEMM, finalize ----------
__global__ void k_cat(const float* __restrict__ mu,const float* __restrict__ m2,
                      float* __restrict__ cat)
{
  int i=blockIdx.x*256+threadIdx.x; if(i>=131072) return;
  int b=i>>12, d=i&4095;
  float m=mu[i];
  cat[(long)b*8192+d]=m;
  cat[(long)b*8192+4096+d]=sqrtf(fmaxf(m2[i]-m*m,1e-5f));
}
__global__ void __launch_bounds__(256) k_embp(
    const float* __restrict__ cat,const float* __restrict__ We,
    float* __restrict__ part)
{
  __shared__ float cs[32][64];
  const int ks=blockIdx.x, j=threadIdx.x;
  for(int idx=j; idx<32*64; idx+=256){
    int b=idx>>6, ii=idx&63;
    cs[b][ii]=cat[(long)b*8192 + ks*64 + ii];
  }
  __syncthreads();
  float acc[32];
#pragma unroll
  for(int b=0;b<32;b++) acc[b]=0.f;
  for(int ii=0;ii<64;ii++){
    float w=We[((long)ks*64+ii)*256+j];
#pragma unroll
    for(int b=0;b<32;b++) acc[b]+=cs[b][ii]*w;
  }
#pragma unroll
  for(int b=0;b<32;b++) part[((long)ks*32+b)*256+j]=acc[b];
}
__global__ void __launch_bounds__(256) k_embf(
    const float* __restrict__ part,const float* __restrict__ be,
    const float* __restrict__ Wc,const float* __restrict__ bc,
    float* __restrict__ out)
{
  const int b=blockIdx.x, j=threadIdx.x;
  float s=be[j];
  for(int ks=0;ks<128;ks++) s+=part[((long)ks*32+b)*256+j];
  __shared__ float es[256];
  es[j]=s; __syncthreads();
  if(j<2){
    float acc=bc[j];
    for(int q=0;q<256;q++) acc+=es[q]*Wc[q*2+j];
    out[b*2+j]=acc;
  }
}

// ---------- host ----------
static void run_fwd(const float* xin,const float* W1,const float* b1,
                    const float* wtf2,const float* b2,const float* wtf3,const float* b3,
                    const float* Wa,const float* ba,const float* va,
                    float* h1,float* h2,float* h3,float* attp,float* att,
                    float* alpha,float* mu,float* m2)
{
  k_conv_fwd<1,64,128,1024,1,16,4,256><<<dim3(8,64,32),256>>>(xin,W1,b1,h1);
  k_cfwd<64,128,64,512,4><<<dim3(2,32,32),256>>>(h1,wtf2,b2,h2);
  k_cfwd<128,256,32,256,4><<<dim3(2,16,32),256>>>(h2,wtf3,b3,h3);
  k_attp<<<dim3(8,32),256>>>(Wa,h3,attp);
  k_attf<<<2048,256>>>(attp,ba,att);
  k_salpha<<<32,128>>>(att,va,alpha);
  k_mustats<<<16384,256>>>(h3,alpha,mu,m2);
}

extern "C" void kernel_launch(void* const* d_in,const int* in_sizes,int n_in,
                              void* d_out,int out_size)
{
  const float* x =(const float*)d_in[0];
  const float* W1=(const float*)d_in[1]; const float* b1=(const float*)d_in[2];
  const float* W2=(const float*)d_in[3]; const float* b2=(const float*)d_in[4];
  const float* W3=(const float*)d_in[5]; const float* b3=(const float*)d_in[6];
  const float* Wa=(const float*)d_in[7]; const float* ba=(const float*)d_in[8];
  const float* va=(const float*)d_in[9];
  const float* We=(const float*)d_in[10]; const float* be=(const float*)d_in[11];
  const float* Wc=(const float*)d_in[12]; const float* bc=(const float*)d_in[13];
  const int* mask_t=(const int*)d_in[14]; const int* s_t=(const int*)d_in[15];
  const int* is_train = (n_in>16)? (const int*)d_in[16] : nullptr;
  float* out=(float*)d_out;

  float *h1,*h2,*h3,*d1,*d2,*d3,*fam,*xm,*att,*attp,*dz,*alpha,*ds,*dap,*mu,*m2,*dMu,*dE2,*gvec;
  float *cat,*ep,*cm,*tm,*meanT,*meanF,*wtf2,*wtb2,*wtf3,*wtb3;
  int *sc,*st,*rstep,*cstep;
  cudaGetSymbolAddress((void**)&h1,g_h1);   cudaGetSymbolAddress((void**)&h2,g_h2);
  cudaGetSymbolAddress((void**)&h3,g_h3);   cudaGetSymbolAddress((void**)&d1,g_d1);
  cudaGetSymbolAddress((void**)&d2,g_d2);   cudaGetSymbolAddress((void**)&d3,g_d3);
  cudaGetSymbolAddress((void**)&fam,g_fam); cudaGetSymbolAddress((void**)&xm,g_xm);
  cudaGetSymbolAddress((void**)&att,g_att); cudaGetSymbolAddress((void**)&attp,g_attp);
  cudaGetSymbolAddress((void**)&dz,g_dzb);
  cudaGetSymbolAddress((void**)&alpha,g_alpha); cudaGetSymbolAddress((void**)&ds,g_dsb);
  cudaGetSymbolAddress((void**)&dap,g_dap);
  cudaGetSymbolAddress((void**)&mu,g_mu);   cudaGetSymbolAddress((void**)&m2,g_m2);
  cudaGetSymbolAddress((void**)&dMu,g_dMu); cudaGetSymbolAddress((void**)&dE2,g_dE2);
  cudaGetSymbolAddress((void**)&gvec,g_gvec);
  cudaGetSymbolAddress((void**)&cat,g_cat); cudaGetSymbolAddress((void**)&ep,g_ep);
  cudaGetSymbolAddress((void**)&cm,g_cm);   cudaGetSymbolAddress((void**)&tm,g_tm);
  cudaGetSymbolAddress((void**)&meanT,g_meanT); cudaGetSymbolAddress((void**)&meanF,g_meanF);
  cudaGetSymbolAddress((void**)&sc,g_sc);   cudaGetSymbolAddress((void**)&st,g_st);
  cudaGetSymbolAddress((void**)&rstep,g_rstep); cudaGetSymbolAddress((void**)&cstep,g_cstep);
  cudaGetSymbolAddress((void**)&wtf2,g_wtf2); cudaGetSymbolAddress((void**)&wtb2,g_wtb2);
  cudaGetSymbolAddress((void**)&wtf3,g_wtf3); cudaGetSymbolAddress((void**)&wtb3,g_wtb3);

  // weight transposes + constant head cotangent
  k_wt<<<288,256>>>(W2,wtf2,wtb2,64,128);
  k_wt<<<1152,256>>>(W3,wtf3,wtb3,128,256);
  k_gvec<<<1024,256>>>(We,Wc,gvec);
  // pass 1: forward on x
  run_fwd(x,W1,b1,wtf2,b2,wtf3,b3,Wa,ba,va,h1,h2,h3,attp,att,alpha,mu,m2);
  // backward to input
  k_dcoef<<<512,256>>>(mu,m2,gvec,dMu,dE2);
  k_dalp<<<dim3(8,32),128>>>(h3,dMu,dE2,dap);
  k_dalf<<<32,128>>>(dap,alpha,ds);
  k_dz<<<2048,256>>>(att,ds,va,dz);
  k_dfeat<<<dim3(32,32),256>>>(Wa,dz,h3,alpha,dMu,dE2,d3);
  k_cbwd<128,256,16,128,8><<<dim3(4,16,32),256>>>(d3,wtb3,h2,d2);
  k_cbwd<64,128,32,256,8><<<dim3(4,32,32),256>>>(d2,wtb2,h1,d1);
  k_bwd1<<<dim3(2,128,32),256>>>(d1,W1,fam);
  // masking
  k_rowstats<<<512,256>>>(fam,x,cm,meanT);
  k_colstats<<<128,256>>>(fam,x,tm,meanF);
  k_sort<128><<<32,64>>>(cm,sc);
  k_sort<1024><<<32,512>>>(tm,st);
  k_rfm<<<1,32>>>(sc,st,mask_t,s_t,is_train,rstep,cstep);
  k_apply<<<16384,256>>>(x,rstep,cstep,meanT,meanF,xm);
  // pass 2: forward on masked input + head
  run_fwd(xm,W1,b1,wtf2,b2,wtf3,b3,Wa,ba,va,h1,h2,h3,attp,att,alpha,mu,m2);
  k_cat<<<512,256>>>(mu,m2,cat);
  k_embp<<<128,256>>>(cat,We,ep);
  k_embf<<<32,256>>>(ep,be,Wc,bc,out);
}

// round 5
// speedup vs baseline: 2.1319x; 1.0605x over previous
#include <cuda_runtime.h>
#include <math.h>

// ---------- static scratch ----------
__device__ float g_h1[67108864];
__device__ float g_h2[33554432];
__device__ float g_h3[16777216];
__device__ float g_d1[67108864];
__device__ float g_d2[33554432];
__device__ float g_d3[16777216];
__device__ float g_fam[4194304];
__device__ float g_xm[4194304];
__device__ float g_att[524288];
__device__ float g_attp[4194304];
__device__ float g_dzb[524288];
__device__ float g_alpha[4096];
__device__ float g_dsb[4096];
__device__ float g_dap[32768];
__device__ float g_mu[131072];
__device__ float g_m2[131072];
__device__ float g_dMu[131072];
__device__ float g_dE2[131072];
__device__ float g_gvec[8192];
__device__ float g_cat[262144];
__device__ float g_ep[1048576];
__device__ float g_cm[4096];
__device__ float g_tm[32768];
__device__ float g_meanT[4096];
__device__ float g_meanF[32768];
__device__ int   g_sc[4096];
__device__ int   g_st[4096];
__device__ int   g_rstep[4096];
__device__ int   g_cstep[32768];
__device__ float g_wtf2[73728];
__device__ float g_wtb2[73728];
__device__ float g_wtf3[294912];
__device__ float g_wtb3[294912];

// ---------- weight transposes ----------
__global__ void k_wt(const float* __restrict__ W, float* __restrict__ WTf,
                     float* __restrict__ WTb, int CIN, int COUT)
{
  int idx=blockIdx.x*256+threadIdx.x;
  int tot=CIN*COUT*9; if(idx>=tot) return;
  int k=idx%9, c=(idx/9)%CIN, o=idx/(9*CIN);
  float v=W[idx];
  WTf[((long)c*9+k)*COUT+o]=v;
  WTb[((long)o*9+k)*CIN+c]=v;
}

// ---------- conv1 fwd (CIN=1) ----------
template<int CIN,int COUT,int HIN,int WIN,int CC,int OG,int OP,int THREADS>
__global__ void __launch_bounds__(THREADS) k_conv_fwd(
    const float* __restrict__ in, const float* __restrict__ W,
    const float* __restrict__ bias, float* __restrict__ out)
{
  constexpr int HOUT=HIN/2, WOUT=WIN/2;
  __shared__ float ins[CC*3*130];
  __shared__ float ws[CC*9*COUT];
  const int n=blockIdx.z, i=blockIdx.y, j0=blockIdx.x*64;
  const int tid=threadIdx.x, og=tid%OG, jt=tid/OG;
  float acc[OP][4];
#pragma unroll
  for(int o=0;o<OP;o++){acc[o][0]=acc[o][1]=acc[o][2]=acc[o][3]=0.f;}
  for(int c0=0;c0<CIN;c0+=CC){
    __syncthreads();
    for(int idx=tid; idx<CC*3*130; idx+=THREADS){
      int c=idx/390, r=(idx/130)%3, col=idx%130;
      int gx=2*i+r, gy=2*j0+col;
      float v=0.f;
      if(gx<HIN && gy<WIN) v=in[(((long)n*CIN+c0+c)*HIN+gx)*WIN+gy];
      ins[idx]=v;
    }
    for(int idx=tid; idx<COUT*CC*9; idx+=THREADS){
      int o=idx/(CC*9), rem=idx%(CC*9);
      ws[rem*COUT+o]=W[(long)o*CIN*9 + c0*9 + rem];
    }
    __syncthreads();
#pragma unroll
    for(int c=0;c<CC;c++)
#pragma unroll
    for(int r=0;r<3;r++){
      float v[9];
#pragma unroll
      for(int m=0;m<9;m++) v[m]=ins[(c*3+r)*130 + 8*jt + m];
#pragma unroll
      for(int kj=0;kj<3;kj++)
#pragma unroll
      for(int oo=0;oo<OP;oo++){
        float w=ws[(c*9+r*3+kj)*COUT + og + OG*oo];
        acc[oo][0]+=w*v[kj];   acc[oo][1]+=w*v[2+kj];
        acc[oo][2]+=w*v[4+kj]; acc[oo][3]+=w*v[6+kj];
      }
    }
  }
  int j=j0+4*jt;
#pragma unroll
  for(int oo=0;oo<OP;oo++){
    int o=og+OG*oo; float bb=bias[o];
    float4 r;
    r.x=fmaxf(acc[oo][0]+bb,0.f); r.y=fmaxf(acc[oo][1]+bb,0.f);
    r.z=fmaxf(acc[oo][2]+bb,0.f); r.w=fmaxf(acc[oo][3]+bb,0.f);
    *(float4*)&out[(((long)n*COUT+o)*HOUT+i)*WOUT+j]=r;
  }
}

// ---------- fp32 big conv fwd (pass 1, argsort-critical) ----------
template<int CIN,int COUT,int HIN,int WIN,int CC>
__global__ void __launch_bounds__(256,2) k_cfwd(
    const float* __restrict__ in, const float* __restrict__ WT,
    const float* __restrict__ bias, float* __restrict__ out)
{
  constexpr int HOUT=HIN/2, WOUT=WIN/2;
  constexpr int NJT=WOUT/128;
  __shared__ __align__(16) float ev[CC*3][136];
  __shared__ __align__(16) float od[CC*3][136];
  __shared__ __align__(16) float ws[CC*9][128];
  const int n=blockIdx.z, i=blockIdx.y;
  const int jt_=blockIdx.x%NJT, ot=blockIdx.x/NJT;
  const int j0=jt_*128, o0=ot*128;
  const int tid=threadIdx.x, tx=tid%16, ty=tid/16;
  float acc[8][8];
#pragma unroll
  for(int a=0;a<8;a++)
#pragma unroll
  for(int b=0;b<8;b++) acc[a][b]=0.f;

  for(int c0=0;c0<CIN;c0+=CC){
    __syncthreads();
    for(int idx=tid; idx<CC*3*129; idx+=256){
      int c=idx/387, rem=idx%387, r=rem/129, p=rem%129;
      int gx=2*i+r, gy=2*j0+2*p;
      float a=0.f,b=0.f;
      if(gx<HIN && gy<WIN){
        const float2 s=*(const float2*)&in[(((long)n*CIN+c0+c)*HIN+gx)*WIN+gy];
        a=s.x; b=s.y;
      }
      ev[c*3+r][p]=a;
      if(p<128) od[c*3+r][p]=b;
    }
    for(int idx=tid; idx<CC*9*32; idx+=256){
      int k=idx/32, oq=idx%32;
      *(float4*)&ws[k][oq*4] = *(const float4*)&WT[((long)c0*9 + k)*COUT + o0 + oq*4];
    }
    __syncthreads();
#pragma unroll
    for(int k=0;k<CC*3;k++){
      float e[9], oV[8];
      *(float4*)e     = *(float4*)&ev[k][tx*8];
      *(float4*)(e+4) = *(float4*)&ev[k][tx*8+4];
      e[8]            = ev[k][tx*8+8];
      *(float4*)oV    = *(float4*)&od[k][tx*8];
      *(float4*)(oV+4)= *(float4*)&od[k][tx*8+4];
#pragma unroll
      for(int kj=0;kj<3;kj++){
        float w[8];
        *(float4*)w    =*(float4*)&ws[k*3+kj][ty*8];
        *(float4*)(w+4)=*(float4*)&ws[k*3+kj][ty*8+4];
#pragma unroll
        for(int ii=0;ii<8;ii++)
#pragma unroll
        for(int jj=0;jj<8;jj++){
          float v = (kj==0)? e[jj] : (kj==1)? oV[jj] : e[jj+1];
          acc[ii][jj] += w[ii]*v;
        }
      }
    }
  }
#pragma unroll
  for(int ii=0;ii<8;ii++){
    int o=o0+ty*8+ii;
    float bb=bias[o];
    float4 r0,r1;
    r0.x=fmaxf(acc[ii][0]+bb,0.f); r0.y=fmaxf(acc[ii][1]+bb,0.f);
    r0.z=fmaxf(acc[ii][2]+bb,0.f); r0.w=fmaxf(acc[ii][3]+bb,0.f);
    r1.x=fmaxf(acc[ii][4]+bb,0.f); r1.y=fmaxf(acc[ii][5]+bb,0.f);
    r1.z=fmaxf(acc[ii][6]+bb,0.f); r1.w=fmaxf(acc[ii][7]+bb,0.f);
    long base=(((long)n*COUT+o)*HOUT+i)*WOUT + j0 + tx*8;
    *(float4*)&out[base]=r0; *(float4*)&out[base+4]=r1;
  }
}

// ---------- tf32 mma implicit-GEMM conv fwd (pass 2 only) ----------
// M=COUT tile 128, N=cols tile 128, K=CIN*9 (chunks of CC=8 chans -> 72)
__device__ __forceinline__ float to_tf32(float v){
  unsigned r; asm("cvt.rna.tf32.f32 %0, %1;" : "=r"(r) : "f"(v));
  return __uint_as_float(r);
}
template<int CIN,int COUT,int HIN,int WIN>
__global__ void __launch_bounds__(256) k_cfwd_mma(
    const float* __restrict__ in, const float* __restrict__ WT,
    const float* __restrict__ bias, float* __restrict__ out)
{
  constexpr int HOUT=HIN/2, WOUT=WIN/2;
  constexpr int NJT=WOUT/128;
  constexpr int CC=8, KK=72, LDB=136;
  extern __shared__ float sm[];
  float* Bt = sm;            // [KK][LDB] im2col tile
  float* Ws = sm + KK*LDB;   // [KK][LDB] weights [k][o]
  const int n=blockIdx.z, i=blockIdx.y;
  const int jt_=blockIdx.x%NJT, ot=blockIdx.x/NJT;
  const int j0=jt_*128, o0=ot*128;
  const int tid=threadIdx.x, wid=tid/32, lane=tid%32;
  const int gid=lane/4, tig=lane%4;
  const int m0=(wid%4)*32, n0w=(wid/4)*64;
  float acc[2][8][4];
#pragma unroll
  for(int a=0;a<2;a++)
#pragma unroll
  for(int b=0;b<8;b++)
#pragma unroll
  for(int c=0;c<4;c++) acc[a][b][c]=0.f;

  for(int c0=0;c0<CIN;c0+=CC){
    __syncthreads();
    for(int idx=tid; idx<KK*128; idx+=256){
      int kk=idx>>7, j=idx&127;
      int c=kk/9, tap=kk%9, r=tap/3, kj=tap%3;
      int gx=2*i+r, gy=2*(j0+j)+kj;
      float v=0.f;
      if(gx<HIN && gy<WIN) v=in[(((long)n*CIN+c0+c)*HIN+gx)*WIN+gy];
      Bt[kk*LDB+j]=to_tf32(v);
    }
    for(int idx=tid; idx<KK*128; idx+=256){
      int kk=idx>>7, o=idx&127;
      Ws[kk*LDB+o]=to_tf32(WT[((long)c0*9 + kk)*COUT + o0 + o]);
    }
    __syncthreads();
#pragma unroll
    for(int kc=0;kc<9;kc++){
      const int kb=kc*8;
      unsigned bf[8][2];
#pragma unroll
      for(int f=0;f<8;f++){
        bf[f][0]=__float_as_uint(Bt[(kb+tig)*LDB + n0w + f*8 + gid]);
        bf[f][1]=__float_as_uint(Bt[(kb+tig+4)*LDB + n0w + f*8 + gid]);
      }
#pragma unroll
      for(int mf=0;mf<2;mf++){
        unsigned a0=__float_as_uint(Ws[(kb+tig)*LDB + m0+mf*16+gid]);
        unsigned a1=__float_as_uint(Ws[(kb+tig)*LDB + m0+mf*16+gid+8]);
        unsigned a2=__float_as_uint(Ws[(kb+tig+4)*LDB + m0+mf*16+gid]);
        unsigned a3=__float_as_uint(Ws[(kb+tig+4)*LDB + m0+mf*16+gid+8]);
#pragma unroll
        for(int f=0;f<8;f++){
          asm volatile(
            "mma.sync.aligned.m16n8k8.row.col.f32.tf32.tf32.f32 "
            "{%0,%1,%2,%3},{%4,%5,%6,%7},{%8,%9},{%0,%1,%2,%3};"
            : "+f"(acc[mf][f][0]),"+f"(acc[mf][f][1]),
              "+f"(acc[mf][f][2]),"+f"(acc[mf][f][3])
            : "r"(a0),"r"(a1),"r"(a2),"r"(a3),"r"(bf[f][0]),"r"(bf[f][1]));
        }
      }
    }
  }
#pragma unroll
  for(int mf=0;mf<2;mf++){
    int oA=o0+m0+mf*16+gid, oB=oA+8;
    float bA=bias[oA], bB=bias[oB];
#pragma unroll
    for(int f=0;f<8;f++){
      int jj=j0 + n0w + f*8 + tig*2;
      long baseA=(((long)n*COUT+oA)*HOUT+i)*WOUT + jj;
      long baseB=(((long)n*COUT+oB)*HOUT+i)*WOUT + jj;
      float2 rA, rB;
      rA.x=fmaxf(acc[mf][f][0]+bA,0.f); rA.y=fmaxf(acc[mf][f][1]+bA,0.f);
      rB.x=fmaxf(acc[mf][f][2]+bB,0.f); rB.y=fmaxf(acc[mf][f][3]+bB,0.f);
      *(float2*)&out[baseA]=rA;
      *(float2*)&out[baseB]=rB;
    }
  }
}

// ---------- big conv bwd (fp32, pass 1) ----------
template<int CIN,int COUT,int HOUT,int WOUT,int OCC>
__global__ void __launch_bounds__(256,2) k_cbwd(
    const float* __restrict__ dout, const float* __restrict__ WT,
    const float* __restrict__ act, float* __restrict__ din)
{
  constexpr int HIN=2*HOUT, WIN=2*WOUT;
  constexpr int NJT=WIN/128;
  __shared__ __align__(16) float dsA[OCC][72];
  __shared__ __align__(16) float dsB[OCC][72];
  __shared__ __align__(16) float ws[OCC*9][64];
  const int n=blockIdx.z, q=blockIdx.y;
  const int jt_=blockIdx.x%NJT, ct=blockIdx.x/NJT;
  const int y0=jt_*128, c0=ct*64;
  const int tid=threadIdx.x, tx=tid%16, ty=tid/16;
  const int jbase=y0/2-1;
  float accE[4][8], accO[4][8];
#pragma unroll
  for(int c=0;c<4;c++)
#pragma unroll
  for(int u=0;u<8;u++){accE[c][u]=0.f; accO[c][u]=0.f;}

  for(int o0=0;o0<COUT;o0+=OCC){
    __syncthreads();
    for(int idx=tid; idx<OCC*66; idx+=256){
      int o=idx/66, jl=idx%66, j=jbase+jl;
      float a=0.f,b=0.f;
      if(j>=0 && j<WOUT){
        a = dout[(((long)n*COUT+o0+o)*HOUT+q)*WOUT+j];
        if(q>0) b = dout[(((long)n*COUT+o0+o)*HOUT+q-1)*WOUT+j];
      }
      dsA[o][jl]=a; dsB[o][jl]=b;
    }
    for(int idx=tid; idx<OCC*9*16; idx+=256){
      int k=idx/16, cq=idx%16;
      *(float4*)&ws[k][cq*4] = *(const float4*)&WT[((long)o0*9 + k)*CIN + c0 + cq*4];
    }
    __syncthreads();
#pragma unroll
    for(int o=0;o<OCC;o++){
      float a[5], b[5];
      *(float4*)a=*(float4*)&dsA[o][tx*4]; a[4]=dsA[o][tx*4+4];
      *(float4*)b=*(float4*)&dsB[o][tx*4]; b[4]=dsB[o][tx*4+4];
#pragma unroll
      for(int ki=0;ki<3;ki++){
        const float* s = (ki==2)? b : a;
#pragma unroll
        for(int kj=0;kj<3;kj++){
          float w[4];
          *(float4*)w=*(float4*)&ws[o*9+ki*3+kj][ty*4];
#pragma unroll
          for(int c=0;c<4;c++)
#pragma unroll
          for(int e=0;e<4;e++){
            float v = w[c]*((kj==2)? s[e] : s[e+1]);
            int u = (kj==1)? 2*e+1 : 2*e;
            if(ki==1) accO[c][u]+=v; else accE[c][u]+=v;
          }
        }
      }
    }
  }
  const int xE=2*q;
#pragma unroll
  for(int c=0;c<4;c++){
    int ci=c0+ty*4+c;
    long bE=(((long)n*CIN+ci)*HIN+xE)*WIN + y0 + tx*8;
    long bO=bE+WIN;
    float4 mE0=*(const float4*)&act[bE],  mE1=*(const float4*)&act[bE+4];
    float4 mO0=*(const float4*)&act[bO],  mO1=*(const float4*)&act[bO+4];
    float4 r;
    r.x=mE0.x>0.f?accE[c][0]:0.f; r.y=mE0.y>0.f?accE[c][1]:0.f;
    r.z=mE0.z>0.f?accE[c][2]:0.f; r.w=mE0.w>0.f?accE[c][3]:0.f;
    *(float4*)&din[bE]=r;
    r.x=mE1.x>0.f?accE[c][4]:0.f; r.y=mE1.y>0.f?accE[c][5]:0.f;
    r.z=mE1.z>0.f?accE[c][6]:0.f; r.w=mE1.w>0.f?accE[c][7]:0.f;
    *(float4*)&din[bE+4]=r;
    r.x=mO0.x>0.f?accO[c][0]:0.f; r.y=mO0.y>0.f?accO[c][1]:0.f;
    r.z=mO0.z>0.f?accO[c][2]:0.f; r.w=mO0.w>0.f?accO[c][3]:0.f;
    *(float4*)&din[bO]=r;
    r.x=mO1.x>0.f?accO[c][4]:0.f; r.y=mO1.y>0.f?accO[c][5]:0.f;
    r.z=mO1.z>0.f?accO[c][6]:0.f; r.w=mO1.w>0.f?accO[c][7]:0.f;
    *(float4*)&din[bO+4]=r;
  }
}

// ---------- conv1 data-grad -> |dx| ----------
__global__ void __launch_bounds__(256) k_bwd1(
    const float* __restrict__ dz1, const float* __restrict__ W1,
    float* __restrict__ fam)
{
  __shared__ float ws[576];
  __shared__ float dsm[8*2*260];
  const int n=blockIdx.z, x=blockIdx.y, y0=blockIdx.x*512;
  const int tid=threadIdx.x;
  for(int idx=tid; idx<576; idx+=256) ws[idx]=W1[idx];
  int iA,iB,kiA,kiB; bool hasB;
  if((x&1)==0){iA=x>>1;kiA=0;iB=iA-1;kiB=2;hasB=(iB>=0);}
  else{iA=(x-1)>>1;kiA=1;iB=0;kiB=0;hasB=false;}
  const int jbase=y0/2-1;
  float accE=0.f, accO=0.f;
  for(int o0=0;o0<64;o0+=8){
    __syncthreads();
    for(int idx=tid; idx<8*2*260; idx+=256){
      int o=idx/520, rs=(idx/260)&1, jj=idx%260;
      int j=jbase+jj; int ir=rs?iB:iA;
      float v=0.f;
      if(j>=0 && j<512 && (rs==0||hasB))
        v=dz1[(((long)n*64+o0+o)*64+ir)*512+j];
      dsm[idx]=v;
    }
    __syncthreads();
#pragma unroll
    for(int o=0;o<8;o++){
#pragma unroll
      for(int rs=0;rs<2;rs++){
        if(rs==1&&!hasB) break;
        int ki=rs?kiB:kiA;
        const float* wb=&ws[(o0+o)*9+ki*3];
        float vm=dsm[(o*2+rs)*260+tid], v0=dsm[(o*2+rs)*260+tid+1];
        accE+=wb[0]*v0+wb[2]*vm; accO+=wb[1]*v0;
      }
    }
  }
  long base=((long)n*128+x)*1024 + y0 + 2*tid;
  fam[base]=fabsf(accE); fam[base+1]=fabsf(accO);
}

// ---------- att partial GEMM ----------
__global__ void __launch_bounds__(256) k_attp(
    const float* __restrict__ Wa, const float* __restrict__ feat,
    float* __restrict__ attp)
{
  __shared__ float As[128][17];
  __shared__ float Fs[16][128];
  const int ks=blockIdx.x, b=blockIdx.y, tid=threadIdx.x, tx=tid%16, ty=tid/16;
  const float* fb = feat + (long)b*524288;
  float acc[8][8];
#pragma unroll
  for(int i=0;i<8;i++)
#pragma unroll
  for(int j=0;j<8;j++) acc[i][j]=0.f;
  for(int k0=ks*512;k0<ks*512+512;k0+=16){
    __syncthreads();
#pragma unroll
    for(int l=0;l<8;l++){
      int idx=tid+l*256; int h=idx/16, kk=idx%16;
      As[h][kk]=Wa[(long)h*4096+k0+kk];
    }
#pragma unroll
    for(int l=0;l<8;l++){
      int idx=tid+l*256; int kk=idx/128, t=idx%128;
      Fs[kk][t]=fb[(long)(k0+kk)*128+t];
    }
    __syncthreads();
#pragma unroll
    for(int kk=0;kk<16;kk++){
      float ra[8], rb[8];
#pragma unroll
      for(int i=0;i<8;i++) ra[i]=As[ty*8+i][kk];
      *(float4*)rb     = *(float4*)&Fs[kk][tx*8];
      *(float4*)(rb+4) = *(float4*)&Fs[kk][tx*8+4];
#pragma unroll
      for(int i=0;i<8;i++)
#pragma unroll
      for(int j=0;j<8;j++) acc[i][j]+=ra[i]*rb[j];
    }
  }
#pragma unroll
  for(int i=0;i<8;i++){
    int h=ty*8+i;
#pragma unroll
    for(int j=0;j<8;j++)
      attp[(long)ks*524288 + ((long)b*128+h)*128+tx*8+j]=acc[i][j];
  }
}
__global__ void k_attf(const float* __restrict__ attp, const float* __restrict__ ba,
                       float* __restrict__ att)
{
  int i=blockIdx.x*256+threadIdx.x; if(i>=524288) return;
  int h=(i>>7)&127;
  float s=0.f;
#pragma unroll
  for(int ks=0;ks<8;ks++) s+=attp[(long)ks*524288+i];
  att[i]=tanhf(s+ba[h]);
}

// ---------- softmax ----------
__global__ void __launch_bounds__(128) k_salpha(
    const float* __restrict__ att, const float* __restrict__ va,
    float* __restrict__ alpha)
{
  __shared__ float vs[128], buf[128];
  const int b=blockIdx.x, t=threadIdx.x;
  vs[t]=va[t];
  __syncthreads();
  float s=0.f;
#pragma unroll 4
  for(int h=0;h<128;h++) s+=vs[h]*att[((long)b*128+h)*128+t];
  buf[t]=s; __syncthreads();
  for(int off=64;off;off>>=1){ if(t<off) buf[t]=fmaxf(buf[t],buf[t+off]); __syncthreads(); }
  float mx=buf[0]; __syncthreads();
  float e=expf(s-mx);
  buf[t]=e; __syncthreads();
  for(int off=64;off;off>>=1){ if(t<off) buf[t]+=buf[t+off]; __syncthreads(); }
  alpha[b*128+t]=e/buf[0];
}

// ---------- mu, m2 ----------
__global__ void k_mustats(const float* __restrict__ feat,
    const float* __restrict__ alpha, float* __restrict__ mu, float* __restrict__ m2)
{
  int w=(blockIdx.x*blockDim.x+threadIdx.x)>>5, lane=threadIdx.x&31;
  if(w>=131072) return;
  int b=w>>12;
  const float* fr=feat+(long)w*128;
  const float* ar=alpha+b*128;
  float s1=0.f,s2=0.f;
#pragma unroll
  for(int t=lane;t<128;t+=32){
    float a=ar[t], f=fr[t];
    s1+=a*f; s2+=a*f*f;
  }
  for(int o=16;o;o>>=1){ s1+=__shfl_down_sync(~0u,s1,o); s2+=__shfl_down_sync(~0u,s2,o); }
  if(!lane){ mu[w]=s1; m2[w]=s2; }
}

// ---------- gvec ----------
__global__ void k_gvec(const float* __restrict__ We,const float* __restrict__ Wc,
                       float* __restrict__ gvec)
{
  int w=(blockIdx.x*blockDim.x+threadIdx.x)>>5, lane=threadIdx.x&31;
  if(w>=8192) return;
  float s=0.f;
  for(int j=lane;j<256;j+=32) s+=We[(long)w*256+j]*(Wc[j*2+1]-Wc[j*2]);
  for(int o=16;o;o>>=1) s+=__shfl_down_sync(~0u,s,o);
  if(!lane) gvec[w]=s;
}

// ---------- dMu,dE2 ----------
__global__ void k_dcoef(const float* __restrict__ mu,const float* __restrict__ m2,
    const float* __restrict__ gvec, float* __restrict__ dMu,float* __restrict__ dE2)
{
  int i=blockIdx.x*256+threadIdx.x; if(i>=131072) return;
  int d=i&4095;
  float m=mu[i], v=m2[i]-m*m;
  float g2=gvec[4096+d];
  float dE=0.f, dM=gvec[d];
  if(v>1e-5f){ float sg=sqrtf(v); dE=0.5f*g2/sg; dM-=g2*m/sg; }
  dMu[i]=dM; dE2[i]=dE;
}

// ---------- dalpha ----------
__global__ void __launch_bounds__(128) k_dalp(
    const float* __restrict__ feat,const float* __restrict__ dMu,
    const float* __restrict__ dE2,float* __restrict__ part)
{
  const int ks=blockIdx.x, b=blockIdx.y, t=threadIdx.x;
  const float* fb=feat+(long)b*524288;
  const float* dm=dMu+b*4096; const float* de=dE2+b*4096;
  float acc=0.f;
  int d0=ks*512;
#pragma unroll 4
  for(int d=d0;d<d0+512;d++){
    float f=fb[(long)d*128+t];
    acc+=dm[d]*f+de[d]*f*f;
  }
  part[(ks*32+b)*128+t]=acc;
}
__global__ void __launch_bounds__(128) k_dalf(
    const float* __restrict__ part,const float* __restrict__ alpha,
    float* __restrict__ ds)
{
  const int b=blockIdx.x, t=threadIdx.x;
  float acc=0.f;
#pragma unroll
  for(int ks=0;ks<8;ks++) acc+=part[(ks*32+b)*128+t];
  __shared__ float buf[128];
  float a=alpha[b*128+t];
  buf[t]=a*acc; __syncthreads();
  for(int off=64;off;off>>=1){ if(t<off) buf[t]+=buf[t+off]; __syncthreads(); }
  ds[b*128+t]=a*(acc-buf[0]);
}

// ---------- dz ----------
__global__ void k_dz(const float* __restrict__ att,const float* __restrict__ ds,
    const float* __restrict__ va,float* __restrict__ dz)
{
  int i=blockIdx.x*256+threadIdx.x; if(i>=524288) return;
  int t=i&127, h=(i>>7)&127, b=i>>14;
  float a=att[i];
  dz[i]=va[h]*ds[b*128+t]*(1.f-a*a);
}

// ---------- dfeat ----------
__global__ void __launch_bounds__(256) k_dfeat(
    const float* __restrict__ Wa, const float* __restrict__ dz,
    const float* __restrict__ feat, const float* __restrict__ alpha,
    const float* __restrict__ dMu, const float* __restrict__ dE2,
    float* __restrict__ dout3)
{
  __shared__ float As[16][132];
  __shared__ float Bs[16][128];
  __shared__ float al[128];
  const int b=blockIdx.y, d0=blockIdx.x*128;
  const int tid=threadIdx.x, tx=tid%16, ty=tid/16;
  if(tid<128) al[tid]=alpha[b*128+tid];
  float acc[8][8];
#pragma unroll
  for(int i=0;i<8;i++)
#pragma unroll
  for(int j=0;j<8;j++) acc[i][j]=0.f;
  for(int k0=0;k0<128;k0+=16){
    __syncthreads();
#pragma unroll
    for(int l=0;l<8;l++){
      int idx=tid+l*256; int kk=idx/128, dd=idx%128;
      As[kk][dd]=Wa[(long)(k0+kk)*4096+d0+dd];
    }
#pragma unroll
    for(int l=0;l<8;l++){
      int idx=tid+l*256; int kk=idx/128, t=idx%128;
      Bs[kk][t]=dz[((long)b*128+k0+kk)*128+t];
    }
    __syncthreads();
#pragma unroll
    for(int kk=0;kk<16;kk++){
      float ra[8],rb[8];
#pragma unroll
      for(int i=0;i<8;i++) ra[i]=As[kk][ty*8+i];
      *(float4*)rb    =*(float4*)&Bs[kk][tx*8];
      *(float4*)(rb+4)=*(float4*)&Bs[kk][tx*8+4];
#pragma unroll
      for(int i=0;i<8;i++)
#pragma unroll
      for(int j=0;j<8;j++) acc[i][j]+=ra[i]*rb[j];
    }
  }
#pragma unroll
  for(int i=0;i<8;i++){
    int d=d0+ty*8+i;
    float dm=dMu[(long)b*4096+d], de=dE2[(long)b*4096+d];
#pragma unroll
    for(int j=0;j<8;j++){
      int t=tx*8+j;
      long fi=((long)b*4096+d)*128+t;
      float f=feat[fi];
      float val=acc[i][j]+al[t]*(dm+2.f*de*f);
      dout3[fi]= f>0.f? val:0.f;
    }
  }
}

// ---------- row/col stats ----------
__global__ void k_rowstats(const float* __restrict__ fam,const float* __restrict__ x,
    float* __restrict__ cm,float* __restrict__ meanT)
{
  int w=(blockIdx.x*blockDim.x+threadIdx.x)>>5, lane=threadIdx.x&31;
  if(w>=4096) return;
  const float* fr=fam+(long)w*1024; const float* xr=x+(long)w*1024;
  float m=-1e30f, s=0.f;
  for(int t=lane;t<1024;t+=32){ m=fmaxf(m,fr[t]); s+=xr[t]; }
  for(int o=16;o;o>>=1){ m=fmaxf(m,__shfl_down_sync(~0u,m,o)); s+=__shfl_down_sync(~0u,s,o); }
  if(!lane){ cm[w]=m; meanT[w]=s*(1.f/1024.f); }
}
__global__ void k_colstats(const float* __restrict__ fam,const float* __restrict__ x,
    float* __restrict__ tm,float* __restrict__ meanF)
{
  int i=blockIdx.x*256+threadIdx.x; if(i>=32768) return;
  int b=i>>10, t=i&1023;
  const float* fb=fam+(long)b*131072+t; const float* xb=x+(long)b*131072+t;
  float m=-1e30f, s=0.f;
#pragma unroll 4
  for(int f=0;f<128;f++){ m=fmaxf(m,fb[f*1024]); s+=xb[f*1024]; }
  tm[i]=m; meanF[i]=s*(1.f/128.f);
}

// ---------- bitonic argsort ----------
template<int N>
__global__ void k_sort(const float* __restrict__ vals, int* __restrict__ idxout)
{
  __shared__ unsigned long long key[N];
  const int b=blockIdx.x, tid=threadIdx.x, TH=N/2;
  for(int i=tid;i<N;i+=TH){
    unsigned u=__float_as_uint(vals[b*N+i]);
    u = (u&0x80000000u)? ~u : (u|0x80000000u);
    key[i]=((unsigned long long)(~u)<<32)|(unsigned)i;
  }
  __syncthreads();
  for(int k=2;k<=N;k<<=1)
    for(int j=k>>1;j;j>>=1){
      for(int i=tid;i<N;i+=TH){
        int ixj=i^j;
        if(ixj>i){
          bool up=((i&k)==0);
          unsigned long long a=key[i],c=key[ixj];
          if((a>c)==up){ key[i]=c; key[ixj]=a; }
        }
      }
      __syncthreads();
    }
  for(int i=tid;i<128;i+=TH) idxout[b*128+i]=(int)(key[i]&0xFFFFFFFFu);
}

// ---------- RFM scan ----------
__global__ void k_rfm(const int* __restrict__ sc,const int* __restrict__ st,
    const int* __restrict__ mask_t,const int* __restrict__ s_t,
    const int* __restrict__ is_train,int* __restrict__ rstep,int* __restrict__ cstep)
{
  int b=threadIdx.x; if(b>=32) return;
  int* rs=rstep+b*128; int* cs=cstep+b*1024;
  for(int i=0;i<128;i++) rs[i]=-1;
  for(int i=0;i<1024;i++) cs[i]=-1;
  if(is_train && is_train[0]==0) return;
  int cnt=0;
  for(int s=0;s<128 && cnt<3;s++){
    int pc=sc[b*128+s], pt=st[b*128+s];
    if(rs[pc]!=-1||cs[pt]!=-1) continue;
    int mt=mask_t[b*128+s], ss=s_t[b*128+s];
    rs[pc]=s;
    int l=pt-ss; if(l<0)l=0;
    int r=pt+mt-ss; if(r>1024)r=1024;
    for(int t=l;t<r;t++) cs[t]=s;
    cnt++;
  }
}

// ---------- apply mask ----------
__global__ void k_apply(const float* __restrict__ x,const int* __restrict__ rstep,
    const int* __restrict__ cstep,const float* __restrict__ meanT,
    const float* __restrict__ meanF,float* __restrict__ xm)
{
  long i=(long)blockIdx.x*256+threadIdx.x; if(i>=4194304) return;
  int t=(int)(i&1023); int f=(int)((i>>10)&127); int b=(int)(i>>17);
  int rs=rstep[b*128+f], cs=cstep[b*1024+t];
  float v;
  if(rs<0&&cs<0) v=x[i];
  else v=(cs>=rs)? meanT[b*128+f] : meanF[b*1024+t];
  xm[i]=v;
}

// ---------- emb head ----------
__global__ void k_cat(const float* __restrict__ mu,const float* __restrict__ m2,
                      float* __restrict__ cat)
{
  int i=blockIdx.x*256+threadIdx.x; if(i>=131072) return;
  int b=i>>12, d=i&4095;
  float m=mu[i];
  cat[(long)b*8192+d]=m;
  cat[(long)b*8192+4096+d]=sqrtf(fmaxf(m2[i]-m*m,1e-5f));
}
__global__ void __launch_bounds__(256) k_embp(
    const float* __restrict__ cat,const float* __restrict__ We,
    float* __restrict__ part)
{
  __shared__ float cs[32][64];
  const int ks=blockIdx.x, j=threadIdx.x;
  for(int idx=j; idx<32*64; idx+=256){
    int b=idx>>6, ii=idx&63;
    cs[b][ii]=cat[(long)b*8192 + ks*64 + ii];
  }
  __syncthreads();
  float acc[32];
#pragma unroll
  for(int b=0;b<32;b++) acc[b]=0.f;
  for(int ii=0;ii<64;ii++){
    float w=We[((long)ks*64+ii)*256+j];
#pragma unroll
    for(int b=0;b<32;b++) acc[b]+=cs[b][ii]*w;
  }
#pragma unroll
  for(int b=0;b<32;b++) part[((long)ks*32+b)*256+j]=acc[b];
}
__global__ void __launch_bounds__(256) k_embf(
    const float* __restrict__ part,const float* __restrict__ be,
    const float* __restrict__ Wc,const float* __restrict__ bc,
    float* __restrict__ out)
{
  const int b=blockIdx.x, j=threadIdx.x;
  float s=be[j];
  for(int ks=0;ks<128;ks++) s+=part[((long)ks*32+b)*256+j];
  __shared__ float es[256];
  es[j]=s; __syncthreads();
  if(j<2){
    float acc=bc[j];
    for(int q=0;q<256;q++) acc+=es[q]*Wc[q*2+j];
    out[b*2+j]=acc;
  }
}

// ---------- host ----------
static void run_tail(const float* h3,const float* Wa,const float* ba,const float* va,
                     float* attp,float* att,float* alpha,float* mu,float* m2)
{
  k_attp<<<dim3(8,32),256>>>(Wa,h3,attp);
  k_attf<<<2048,256>>>(attp,ba,att);
  k_salpha<<<32,128>>>(att,va,alpha);
  k_mustats<<<16384,256>>>(h3,alpha,mu,m2);
}

extern "C" void kernel_launch(void* const* d_in,const int* in_sizes,int n_in,
                              void* d_out,int out_size)
{
  const float* x =(const float*)d_in[0];
  const float* W1=(const float*)d_in[1]; const float* b1=(const float*)d_in[2];
  const float* W2=(const float*)d_in[3]; const float* b2=(const float*)d_in[4];
  const float* W3=(const float*)d_in[5]; const float* b3=(const float*)d_in[6];
  const float* Wa=(const float*)d_in[7]; const float* ba=(const float*)d_in[8];
  const float* va=(const float*)d_in[9];
  const float* We=(const float*)d_in[10]; const float* be=(const float*)d_in[11];
  const float* Wc=(const float*)d_in[12]; const float* bc=(const float*)d_in[13];
  const int* mask_t=(const int*)d_in[14]; const int* s_t=(const int*)d_in[15];
  const int* is_train = (n_in>16)? (const int*)d_in[16] : nullptr;
  float* out=(float*)d_out;

  float *h1,*h2,*h3,*d1,*d2,*d3,*fam,*xm,*att,*attp,*dz,*alpha,*ds,*dap,*mu,*m2,*dMu,*dE2,*gvec;
  float *cat,*ep,*cm,*tm,*meanT,*meanF,*wtf2,*wtb2,*wtf3,*wtb3;
  int *sc,*st,*rstep,*cstep;
  cudaGetSymbolAddress((void**)&h1,g_h1);   cudaGetSymbolAddress((void**)&h2,g_h2);
  cudaGetSymbolAddress((void**)&h3,g_h3);   cudaGetSymbolAddress((void**)&d1,g_d1);
  cudaGetSymbolAddress((void**)&d2,g_d2);   cudaGetSymbolAddress((void**)&d3,g_d3);
  cudaGetSymbolAddress((void**)&fam,g_fam); cudaGetSymbolAddress((void**)&xm,g_xm);
  cudaGetSymbolAddress((void**)&att,g_att); cudaGetSymbolAddress((void**)&attp,g_attp);
  cudaGetSymbolAddress((void**)&dz,g_dzb);
  cudaGetSymbolAddress((void**)&alpha,g_alpha); cudaGetSymbolAddress((void**)&ds,g_dsb);
  cudaGetSymbolAddress((void**)&dap,g_dap);
  cudaGetSymbolAddress((void**)&mu,g_mu);   cudaGetSymbolAddress((void**)&m2,g_m2);
  cudaGetSymbolAddress((void**)&dMu,g_dMu); cudaGetSymbolAddress((void**)&dE2,g_dE2);
  cudaGetSymbolAddress((void**)&gvec,g_gvec);
  cudaGetSymbolAddress((void**)&cat,g_cat); cudaGetSymbolAddress((void**)&ep,g_ep);
  cudaGetSymbolAddress((void**)&cm,g_cm);   cudaGetSymbolAddress((void**)&tm,g_tm);
  cudaGetSymbolAddress((void**)&meanT,g_meanT); cudaGetSymbolAddress((void**)&meanF,g_meanF);
  cudaGetSymbolAddress((void**)&sc,g_sc);   cudaGetSymbolAddress((void**)&st,g_st);
  cudaGetSymbolAddress((void**)&rstep,g_rstep); cudaGetSymbolAddress((void**)&cstep,g_cstep);
  cudaGetSymbolAddress((void**)&wtf2,g_wtf2); cudaGetSymbolAddress((void**)&wtb2,g_wtb2);
  cudaGetSymbolAddress((void**)&wtf3,g_wtf3); cudaGetSymbolAddress((void**)&wtb3,g_wtb3);

  const int MMA_SMEM = 2*72*136*4;
  cudaFuncSetAttribute(k_cfwd_mma<64,128,64,512>,
      cudaFuncAttributeMaxDynamicSharedMemorySize, MMA_SMEM);
  cudaFuncSetAttribute(k_cfwd_mma<128,256,32,256>,
      cudaFuncAttributeMaxDynamicSharedMemorySize, MMA_SMEM);

  // prep
  k_wt<<<288,256>>>(W2,wtf2,wtb2,64,128);
  k_wt<<<1152,256>>>(W3,wtf3,wtb3,128,256);
  k_gvec<<<1024,256>>>(We,Wc,gvec);
  // pass 1 (fp32: argsort-critical)
  k_conv_fwd<1,64,128,1024,1,16,4,256><<<dim3(8,64,32),256>>>(x,W1,b1,h1);
  k_cfwd<64,128,64,512,4><<<dim3(2,32,32),256>>>(h1,wtf2,b2,h2);
  k_cfwd<128,256,32,256,4><<<dim3(2,16,32),256>>>(h2,wtf3,b3,h3);
  run_tail(h3,Wa,ba,va,attp,att,alpha,mu,m2);
  // backward to input (fp32)
  k_dcoef<<<512,256>>>(mu,m2,gvec,dMu,dE2);
  k_dalp<<<dim3(8,32),128>>>(h3,dMu,dE2,dap);
  k_dalf<<<32,128>>>(dap,alpha,ds);
  k_dz<<<2048,256>>>(att,ds,va,dz);
  k_dfeat<<<dim3(32,32),256>>>(Wa,dz,h3,alpha,dMu,dE2,d3);
  k_cbwd<128,256,16,128,8><<<dim3(4,16,32),256>>>(d3,wtb3,h2,d2);
  k_cbwd<64,128,32,256,8><<<dim3(4,32,32),256>>>(d2,wtb2,h1,d1);
  k_bwd1<<<dim3(2,128,32),256>>>(d1,W1,fam);
  // masking
  k_rowstats<<<512,256>>>(fam,x,cm,meanT);
  k_colstats<<<128,256>>>(fam,x,tm,meanF);
  k_sort<128><<<32,64>>>(cm,sc);
  k_sort<1024><<<32,512>>>(tm,st);
  k_rfm<<<1,32>>>(sc,st,mask_t,s_t,is_train,rstep,cstep);
  k_apply<<<16384,256>>>(x,rstep,cstep,meanT,meanF,xm);
  // pass 2 (tf32 tensor-core convs: continuous output path)
  k_conv_fwd<1,64,128,1024,1,16,4,256><<<dim3(8,64,32),256>>>(xm,W1,b1,h1);
  k_cfwd_mma<64,128,64,512><<<dim3(2,32,32),256,MMA_SMEM>>>(h1,wtf2,b2,h2);
  k_cfwd_mma<128,256,32,256><<<dim3(2,16,32),256,MMA_SMEM>>>(h2,wtf3,b3,h3);
  run_tail(h3,Wa,ba,va,attp,att,alpha,mu,m2);
  k_cat<<<512,256>>>(mu,m2,cat);
  k_embp<<<128,256>>>(cat,We,ep);
  k_embf<<<32,256>>>(ep,be,Wc,bc,out);
}

// round 6
// speedup vs baseline: 2.7785x; 1.3033x over previous
#include <cuda_runtime.h>
#include <math.h>

// ---------- static scratch ----------
__device__ float g_h1[67108864];
__device__ float g_h2[33554432];
__device__ float g_h3[16777216];
__device__ float g_d1[67108864];
__device__ float g_d2[33554432];
__device__ float g_d3[16777216];
__device__ float g_fam[4194304];
__device__ float g_xm[4194304];
__device__ float g_att[524288];
__device__ float g_attp[4194304];
__device__ float g_dzb[524288];
__device__ float g_alpha[4096];
__device__ float g_dsb[4096];
__device__ float g_dap[32768];
__device__ float g_mu[131072];
__device__ float g_m2[131072];
__device__ float g_dMu[131072];
__device__ float g_dE2[131072];
__device__ float g_gvec[8192];
__device__ float g_cat[262144];
__device__ float g_ep[1048576];
__device__ float g_cm[4096];
__device__ float g_tm[32768];
__device__ float g_meanT[4096];
__device__ float g_meanF[32768];
__device__ int   g_sc[4096];
__device__ int   g_st[4096];
__device__ int   g_rstep[4096];
__device__ int   g_cstep[32768];
__device__ float g_wtf2[73728];
__device__ float g_wtb2[73728];
__device__ float g_wtf3[294912];
__device__ float g_wtb3[294912];

// ---------- weight transposes ----------
// WTf: mma layout, row = (c/8)*72 + tap*8 + (c%8), cols = COUT
// WTb: [(o*9+k)*CIN + c] for bwd
__global__ void k_wt(const float* __restrict__ W, float* __restrict__ WTf,
                     float* __restrict__ WTb, int CIN, int COUT)
{
  int idx=blockIdx.x*256+threadIdx.x;
  int tot=CIN*COUT*9; if(idx>=tot) return;
  int k=idx%9, c=(idx/9)%CIN, o=idx/(9*CIN);
  float v=W[idx];
  int row=(c>>3)*72 + k*8 + (c&7);
  WTf[(long)row*COUT+o]=v;
  WTb[((long)o*9+k)*CIN+c]=v;
}

// ---------- conv1 fwd (CIN=1) ----------
template<int CIN,int COUT,int HIN,int WIN,int CC,int OG,int OP,int THREADS>
__global__ void __launch_bounds__(THREADS) k_conv_fwd(
    const float* __restrict__ in, const float* __restrict__ W,
    const float* __restrict__ bias, float* __restrict__ out)
{
  constexpr int HOUT=HIN/2, WOUT=WIN/2;
  __shared__ float ins[CC*3*130];
  __shared__ float ws[CC*9*COUT];
  const int n=blockIdx.z, i=blockIdx.y, j0=blockIdx.x*64;
  const int tid=threadIdx.x, og=tid%OG, jt=tid/OG;
  float acc[OP][4];
#pragma unroll
  for(int o=0;o<OP;o++){acc[o][0]=acc[o][1]=acc[o][2]=acc[o][3]=0.f;}
  for(int c0=0;c0<CIN;c0+=CC){
    __syncthreads();
    for(int idx=tid; idx<CC*3*130; idx+=THREADS){
      int c=idx/390, r=(idx/130)%3, col=idx%130;
      int gx=2*i+r, gy=2*j0+col;
      float v=0.f;
      if(gx<HIN && gy<WIN) v=in[(((long)n*CIN+c0+c)*HIN+gx)*WIN+gy];
      ins[idx]=v;
    }
    for(int idx=tid; idx<COUT*CC*9; idx+=THREADS){
      int o=idx/(CC*9), rem=idx%(CC*9);
      ws[rem*COUT+o]=W[(long)o*CIN*9 + c0*9 + rem];
    }
    __syncthreads();
#pragma unroll
    for(int c=0;c<CC;c++)
#pragma unroll
    for(int r=0;r<3;r++){
      float v[9];
#pragma unroll
      for(int m=0;m<9;m++) v[m]=ins[(c*3+r)*130 + 8*jt + m];
#pragma unroll
      for(int kj=0;kj<3;kj++)
#pragma unroll
      for(int oo=0;oo<OP;oo++){
        float w=ws[(c*9+r*3+kj)*COUT + og + OG*oo];
        acc[oo][0]+=w*v[kj];   acc[oo][1]+=w*v[2+kj];
        acc[oo][2]+=w*v[4+kj]; acc[oo][3]+=w*v[6+kj];
      }
    }
  }
  int j=j0+4*jt;
#pragma unroll
  for(int oo=0;oo<OP;oo++){
    int o=og+OG*oo; float bb=bias[o];
    float4 r;
    r.x=fmaxf(acc[oo][0]+bb,0.f); r.y=fmaxf(acc[oo][1]+bb,0.f);
    r.z=fmaxf(acc[oo][2]+bb,0.f); r.w=fmaxf(acc[oo][3]+bb,0.f);
    *(float4*)&out[(((long)n*COUT+o)*HOUT+i)*WOUT+j]=r;
  }
}

// ---------- tf32 mma conv fwd (SPLIT=1: tf32; SPLIT=3: 3xTF32 ~ fp32) ----------
__device__ __forceinline__ float to_tf32(float v){
  unsigned r; asm("cvt.rna.tf32.f32 %0, %1;" : "=r"(r) : "f"(v));
  return __uint_as_float(r);
}
__device__ __forceinline__ void mma_tf32(float* c4,
    unsigned a0,unsigned a1,unsigned a2,unsigned a3,unsigned b0,unsigned b1){
  asm volatile(
    "mma.sync.aligned.m16n8k8.row.col.f32.tf32.tf32.f32 "
    "{%0,%1,%2,%3},{%4,%5,%6,%7},{%8,%9},{%0,%1,%2,%3};"
    : "+f"(c4[0]),"+f"(c4[1]),"+f"(c4[2]),"+f"(c4[3])
    : "r"(a0),"r"(a1),"r"(a2),"r"(a3),"r"(b0),"r"(b1));
}
template<int CIN,int COUT,int HIN,int WIN,int SPLIT>
__global__ void __launch_bounds__(256,2) k_cmma(
    const float* __restrict__ in, const float* __restrict__ WT,
    const float* __restrict__ bias, float* __restrict__ out)
{
  constexpr int HOUT=HIN/2, WOUT=WIN/2;
  constexpr int NJT=WOUT/128;
  constexpr int LD=136;
  extern __shared__ float sm[];
  float* ev = sm;             // [24][LD] even cols, raw fp32
  float* od = sm + 24*LD;     // [24][LD] odd cols
  float* ws = sm + 48*LD;     // [72][LD] weights (tap-major, chan-minor rows)
  const int n=blockIdx.z, i=blockIdx.y;
  const int jt_=blockIdx.x%NJT, ot=blockIdx.x/NJT;
  const int j0=jt_*128, o0=ot*128;
  const int tid=threadIdx.x, wid=tid>>5, lane=tid&31;
  const int gid=lane>>2, tig=lane&3;
  const int m0=(wid&3)*32, n0w=(wid>>2)*64;
  float acc[2][8][4];
#pragma unroll
  for(int a=0;a<2;a++)
#pragma unroll
  for(int b=0;b<8;b++)
#pragma unroll
  for(int c=0;c<4;c++) acc[a][b][c]=0.f;

  for(int c0=0;c0<CIN;c0+=8){
    __syncthreads();
    // raw input staging (deinterleaved even/odd columns), fp32
    for(int idx=tid; idx<8*3*129; idx+=256){
      int c=idx/387, rem=idx%387, r=rem/129, p=rem%129;
      int gx=2*i+r, gy=2*j0+2*p;
      float a=0.f,bv=0.f;
      if(gx<HIN && gy<WIN){
        const float2 s=*(const float2*)&in[(((long)n*CIN+c0+c)*HIN+gx)*WIN+gy];
        a=s.x; bv=s.y;
      }
      ev[(c*3+r)*LD+p]=a;
      od[(c*3+r)*LD+p]=bv;
    }
    // weight staging: straight float4 copy (layout matches smem order)
    {
      const float* wsrc = WT + (long)(c0>>3)*72*COUT + o0;
      for(int idx=tid; idx<72*32; idx+=256){
        int kk=idx>>5, o4=(idx&31)*4;
        float4 v=*(const float4*)&wsrc[(long)kk*COUT + o4];
        *(float4*)&ws[kk*LD + o4]=v;
      }
    }
    __syncthreads();
#pragma unroll
    for(int kc=0;kc<9;kc++){
      const int r=kc/3, kj=kc%3;
      const float* src = (kj==1)? od : ev;
      const int co = (kj==2)? 1:0;
      unsigned bh[8][2], bl[8][2];
#pragma unroll
      for(int f=0;f<8;f++){
        float v0 = src[(tig*3+r)*LD + n0w + f*8 + gid + co];
        float v1 = src[((tig+4)*3+r)*LD + n0w + f*8 + gid + co];
        float h0=to_tf32(v0), h1=to_tf32(v1);
        bh[f][0]=__float_as_uint(h0); bh[f][1]=__float_as_uint(h1);
        if(SPLIT==3){
          bl[f][0]=__float_as_uint(to_tf32(v0-h0));
          bl[f][1]=__float_as_uint(to_tf32(v1-h1));
        }
      }
#pragma unroll
      for(int mf=0;mf<2;mf++){
        float w0=ws[(kc*8+tig)*LD + m0+mf*16+gid];
        float w1=ws[(kc*8+tig)*LD + m0+mf*16+gid+8];
        float w2=ws[(kc*8+tig+4)*LD + m0+mf*16+gid];
        float w3=ws[(kc*8+tig+4)*LD + m0+mf*16+gid+8];
        float h0=to_tf32(w0),h1=to_tf32(w1),h2=to_tf32(w2),h3=to_tf32(w3);
        unsigned ah0=__float_as_uint(h0),ah1=__float_as_uint(h1),
                 ah2=__float_as_uint(h2),ah3=__float_as_uint(h3);
        unsigned al0=0,al1=0,al2=0,al3=0;
        if(SPLIT==3){
          al0=__float_as_uint(to_tf32(w0-h0)); al1=__float_as_uint(to_tf32(w1-h1));
          al2=__float_as_uint(to_tf32(w2-h2)); al3=__float_as_uint(to_tf32(w3-h3));
        }
#pragma unroll
        for(int f=0;f<8;f++){
          mma_tf32(acc[mf][f], ah0,ah1,ah2,ah3, bh[f][0],bh[f][1]);
          if(SPLIT==3){
            mma_tf32(acc[mf][f], ah0,ah1,ah2,ah3, bl[f][0],bl[f][1]);
            mma_tf32(acc[mf][f], al0,al1,al2,al3, bh[f][0],bh[f][1]);
          }
        }
      }
    }
  }
#pragma unroll
  for(int mf=0;mf<2;mf++){
    int oA=o0+m0+mf*16+gid, oB=oA+8;
    float bA=bias[oA], bB=bias[oB];
#pragma unroll
    for(int f=0;f<8;f++){
      int jj=j0 + n0w + f*8 + tig*2;
      long baseA=(((long)n*COUT+oA)*HOUT+i)*WOUT + jj;
      long baseB=(((long)n*COUT+oB)*HOUT+i)*WOUT + jj;
      float2 rA, rB;
      rA.x=fmaxf(acc[mf][f][0]+bA,0.f); rA.y=fmaxf(acc[mf][f][1]+bA,0.f);
      rB.x=fmaxf(acc[mf][f][2]+bB,0.f); rB.y=fmaxf(acc[mf][f][3]+bB,0.f);
      *(float2*)&out[baseA]=rA;
      *(float2*)&out[baseB]=rB;
    }
  }
}

// ---------- big conv bwd (fp32) ----------
template<int CIN,int COUT,int HOUT,int WOUT,int OCC>
__global__ void __launch_bounds__(256,2) k_cbwd(
    const float* __restrict__ dout, const float* __restrict__ WT,
    const float* __restrict__ act, float* __restrict__ din)
{
  constexpr int HIN=2*HOUT, WIN=2*WOUT;
  constexpr int NJT=WIN/128;
  __shared__ __align__(16) float dsA[OCC][72];
  __shared__ __align__(16) float dsB[OCC][72];
  __shared__ __align__(16) float ws[OCC*9][64];
  const int n=blockIdx.z, q=blockIdx.y;
  const int jt_=blockIdx.x%NJT, ct=blockIdx.x/NJT;
  const int y0=jt_*128, c0=ct*64;
  const int tid=threadIdx.x, tx=tid%16, ty=tid/16;
  const int jbase=y0/2-1;
  float accE[4][8], accO[4][8];
#pragma unroll
  for(int c=0;c<4;c++)
#pragma unroll
  for(int u=0;u<8;u++){accE[c][u]=0.f; accO[c][u]=0.f;}

  for(int o0=0;o0<COUT;o0+=OCC){
    __syncthreads();
    for(int idx=tid; idx<OCC*66; idx+=256){
      int o=idx/66, jl=idx%66, j=jbase+jl;
      float a=0.f,b=0.f;
      if(j>=0 && j<WOUT){
        a = dout[(((long)n*COUT+o0+o)*HOUT+q)*WOUT+j];
        if(q>0) b = dout[(((long)n*COUT+o0+o)*HOUT+q-1)*WOUT+j];
      }
      dsA[o][jl]=a; dsB[o][jl]=b;
    }
    for(int idx=tid; idx<OCC*9*16; idx+=256){
      int k=idx/16, cq=idx%16;
      *(float4*)&ws[k][cq*4] = *(const float4*)&WT[((long)o0*9 + k)*CIN + c0 + cq*4];
    }
    __syncthreads();
#pragma unroll
    for(int o=0;o<OCC;o++){
      float a[5], b[5];
      *(float4*)a=*(float4*)&dsA[o][tx*4]; a[4]=dsA[o][tx*4+4];
      *(float4*)b=*(float4*)&dsB[o][tx*4]; b[4]=dsB[o][tx*4+4];
#pragma unroll
      for(int ki=0;ki<3;ki++){
        const float* s = (ki==2)? b : a;
#pragma unroll
        for(int kj=0;kj<3;kj++){
          float w[4];
          *(float4*)w=*(float4*)&ws[o*9+ki*3+kj][ty*4];
#pragma unroll
          for(int c=0;c<4;c++)
#pragma unroll
          for(int e=0;e<4;e++){
            float v = w[c]*((kj==2)? s[e] : s[e+1]);
            int u = (kj==1)? 2*e+1 : 2*e;
            if(ki==1) accO[c][u]+=v; else accE[c][u]+=v;
          }
        }
      }
    }
  }
  const int xE=2*q;
#pragma unroll
  for(int c=0;c<4;c++){
    int ci=c0+ty*4+c;
    long bE=(((long)n*CIN+ci)*HIN+xE)*WIN + y0 + tx*8;
    long bO=bE+WIN;
    float4 mE0=*(const float4*)&act[bE],  mE1=*(const float4*)&act[bE+4];
    float4 mO0=*(const float4*)&act[bO],  mO1=*(const float4*)&act[bO+4];
    float4 r;
    r.x=mE0.x>0.f?accE[c][0]:0.f; r.y=mE0.y>0.f?accE[c][1]:0.f;
    r.z=mE0.z>0.f?accE[c][2]:0.f; r.w=mE0.w>0.f?accE[c][3]:0.f;
    *(float4*)&din[bE]=r;
    r.x=mE1.x>0.f?accE[c][4]:0.f; r.y=mE1.y>0.f?accE[c][5]:0.f;
    r.z=mE1.z>0.f?accE[c][6]:0.f; r.w=mE1.w>0.f?accE[c][7]:0.f;
    *(float4*)&din[bE+4]=r;
    r.x=mO0.x>0.f?accO[c][0]:0.f; r.y=mO0.y>0.f?accO[c][1]:0.f;
    r.z=mO0.z>0.f?accO[c][2]:0.f; r.w=mO0.w>0.f?accO[c][3]:0.f;
    *(float4*)&din[bO]=r;
    r.x=mO1.x>0.f?accO[c][4]:0.f; r.y=mO1.y>0.f?accO[c][5]:0.f;
    r.z=mO1.z>0.f?accO[c][6]:0.f; r.w=mO1.w>0.f?accO[c][7]:0.f;
    *(float4*)&din[bO+4]=r;
  }
}

// ---------- conv1 data-grad -> |dx| ----------
__global__ void __launch_bounds__(256) k_bwd1(
    const float* __restrict__ dz1, const float* __restrict__ W1,
    float* __restrict__ fam)
{
  __shared__ float ws[576];
  __shared__ float dsm[8*2*260];
  const int n=blockIdx.z, x=blockIdx.y, y0=blockIdx.x*512;
  const int tid=threadIdx.x;
  for(int idx=tid; idx<576; idx+=256) ws[idx]=W1[idx];
  int iA,iB,kiA,kiB; bool hasB;
  if((x&1)==0){iA=x>>1;kiA=0;iB=iA-1;kiB=2;hasB=(iB>=0);}
  else{iA=(x-1)>>1;kiA=1;iB=0;kiB=0;hasB=false;}
  const int jbase=y0/2-1;
  float accE=0.f, accO=0.f;
  for(int o0=0;o0<64;o0+=8){
    __syncthreads();
    for(int idx=tid; idx<8*2*260; idx+=256){
      int o=idx/520, rs=(idx/260)&1, jj=idx%260;
      int j=jbase+jj; int ir=rs?iB:iA;
      float v=0.f;
      if(j>=0 && j<512 && (rs==0||hasB))
        v=dz1[(((long)n*64+o0+o)*64+ir)*512+j];
      dsm[idx]=v;
    }
    __syncthreads();
#pragma unroll
    for(int o=0;o<8;o++){
#pragma unroll
      for(int rs=0;rs<2;rs++){
        if(rs==1&&!hasB) break;
        int ki=rs?kiB:kiA;
        const float* wb=&ws[(o0+o)*9+ki*3];
        float vm=dsm[(o*2+rs)*260+tid], v0=dsm[(o*2+rs)*260+tid+1];
        accE+=wb[0]*v0+wb[2]*vm; accO+=wb[1]*v0;
      }
    }
  }
  long base=((long)n*128+x)*1024 + y0 + 2*tid;
  fam[base]=fabsf(accE); fam[base+1]=fabsf(accO);
}

// ---------- att partial GEMM ----------
__global__ void __launch_bounds__(256) k_attp(
    const float* __restrict__ Wa, const float* __restrict__ feat,
    float* __restrict__ attp)
{
  __shared__ float As[128][17];
  __shared__ float Fs[16][128];
  const int ks=blockIdx.x, b=blockIdx.y, tid=threadIdx.x, tx=tid%16, ty=tid/16;
  const float* fb = feat + (long)b*524288;
  float acc[8][8];
#pragma unroll
  for(int i=0;i<8;i++)
#pragma unroll
  for(int j=0;j<8;j++) acc[i][j]=0.f;
  for(int k0=ks*512;k0<ks*512+512;k0+=16){
    __syncthreads();
#pragma unroll
    for(int l=0;l<8;l++){
      int idx=tid+l*256; int h=idx/16, kk=idx%16;
      As[h][kk]=Wa[(long)h*4096+k0+kk];
    }
#pragma unroll
    for(int l=0;l<8;l++){
      int idx=tid+l*256; int kk=idx/128, t=idx%128;
      Fs[kk][t]=fb[(long)(k0+kk)*128+t];
    }
    __syncthreads();
#pragma unroll
    for(int kk=0;kk<16;kk++){
      float ra[8], rb[8];
#pragma unroll
      for(int i=0;i<8;i++) ra[i]=As[ty*8+i][kk];
      *(float4*)rb     = *(float4*)&Fs[kk][tx*8];
      *(float4*)(rb+4) = *(float4*)&Fs[kk][tx*8+4];
#pragma unroll
      for(int i=0;i<8;i++)
#pragma unroll
      for(int j=0;j<8;j++) acc[i][j]+=ra[i]*rb[j];
    }
  }
#pragma unroll
  for(int i=0;i<8;i++){
    int h=ty*8+i;
#pragma unroll
    for(int j=0;j<8;j++)
      attp[(long)ks*524288 + ((long)b*128+h)*128+tx*8+j]=acc[i][j];
  }
}
__global__ void k_attf(const float* __restrict__ attp, const float* __restrict__ ba,
                       float* __restrict__ att)
{
  int i=blockIdx.x*256+threadIdx.x; if(i>=524288) return;
  int h=(i>>7)&127;
  float s=0.f;
#pragma unroll
  for(int ks=0;ks<8;ks++) s+=attp[(long)ks*524288+i];
  att[i]=tanhf(s+ba[h]);
}

// ---------- softmax ----------
__global__ void __launch_bounds__(128) k_salpha(
    const float* __restrict__ att, const float* __restrict__ va,
    float* __restrict__ alpha)
{
  __shared__ float vs[128], buf[128];
  const int b=blockIdx.x, t=threadIdx.x;
  vs[t]=va[t];
  __syncthreads();
  float s=0.f;
#pragma unroll 4
  for(int h=0;h<128;h++) s+=vs[h]*att[((long)b*128+h)*128+t];
  buf[t]=s; __syncthreads();
  for(int off=64;off;off>>=1){ if(t<off) buf[t]=fmaxf(buf[t],buf[t+off]); __syncthreads(); }
  float mx=buf[0]; __syncthreads();
  float e=expf(s-mx);
  buf[t]=e; __syncthreads();
  for(int off=64;off;off>>=1){ if(t<off) buf[t]+=buf[t+off]; __syncthreads(); }
  alpha[b*128+t]=e/buf[0];
}

// ---------- mu, m2 ----------
__global__ void k_mustats(const float* __restrict__ feat,
    const float* __restrict__ alpha, float* __restrict__ mu, float* __restrict__ m2)
{
  int w=(blockIdx.x*blockDim.x+threadIdx.x)>>5, lane=threadIdx.x&31;
  if(w>=131072) return;
  int b=w>>12;
  const float* fr=feat+(long)w*128;
  const float* ar=alpha+b*128;
  float s1=0.f,s2=0.f;
#pragma unroll
  for(int t=lane;t<128;t+=32){
    float a=ar[t], f=fr[t];
    s1+=a*f; s2+=a*f*f;
  }
  for(int o=16;o;o>>=1){ s1+=__shfl_down_sync(~0u,s1,o); s2+=__shfl_down_sync(~0u,s2,o); }
  if(!lane){ mu[w]=s1; m2[w]=s2; }
}

// ---------- gvec ----------
__global__ void k_gvec(const float* __restrict__ We,const float* __restrict__ Wc,
                       float* __restrict__ gvec)
{
  int w=(blockIdx.x*blockDim.x+threadIdx.x)>>5, lane=threadIdx.x&31;
  if(w>=8192) return;
  float s=0.f;
  for(int j=lane;j<256;j+=32) s+=We[(long)w*256+j]*(Wc[j*2+1]-Wc[j*2]);
  for(int o=16;o;o>>=1) s+=__shfl_down_sync(~0u,s,o);
  if(!lane) gvec[w]=s;
}

// ---------- dMu,dE2 ----------
__global__ void k_dcoef(const float* __restrict__ mu,const float* __restrict__ m2,
    const float* __restrict__ gvec, float* __restrict__ dMu,float* __restrict__ dE2)
{
  int i=blockIdx.x*256+threadIdx.x; if(i>=131072) return;
  int d=i&4095;
  float m=mu[i], v=m2[i]-m*m;
  float g2=gvec[4096+d];
  float dE=0.f, dM=gvec[d];
  if(v>1e-5f){ float sg=sqrtf(v); dE=0.5f*g2/sg; dM-=g2*m/sg; }
  dMu[i]=dM; dE2[i]=dE;
}

// ---------- dalpha ----------
__global__ void __launch_bounds__(128) k_dalp(
    const float* __restrict__ feat,const float* __restrict__ dMu,
    const float* __restrict__ dE2,float* __restrict__ part)
{
  const int ks=blockIdx.x, b=blockIdx.y, t=threadIdx.x;
  const float* fb=feat+(long)b*524288;
  const float* dm=dMu+b*4096; const float* de=dE2+b*4096;
  float acc=0.f;
  int d0=ks*512;
#pragma unroll 4
  for(int d=d0;d<d0+512;d++){
    float f=fb[(long)d*128+t];
    acc+=dm[d]*f+de[d]*f*f;
  }
  part[(ks*32+b)*128+t]=acc;
}
__global__ void __launch_bounds__(128) k_dalf(
    const float* __restrict__ part,const float* __restrict__ alpha,
    float* __restrict__ ds)
{
  const int b=blockIdx.x, t=threadIdx.x;
  float acc=0.f;
#pragma unroll
  for(int ks=0;ks<8;ks++) acc+=part[(ks*32+b)*128+t];
  __shared__ float buf[128];
  float a=alpha[b*128+t];
  buf[t]=a*acc; __syncthreads();
  for(int off=64;off;off>>=1){ if(t<off) buf[t]+=buf[t+off]; __syncthreads(); }
  ds[b*128+t]=a*(acc-buf[0]);
}

// ---------- dz ----------
__global__ void k_dz(const float* __restrict__ att,const float* __restrict__ ds,
    const float* __restrict__ va,float* __restrict__ dz)
{
  int i=blockIdx.x*256+threadIdx.x; if(i>=524288) return;
  int t=i&127, h=(i>>7)&127, b=i>>14;
  float a=att[i];
  dz[i]=va[h]*ds[b*128+t]*(1.f-a*a);
}

// ---------- dfeat ----------
__global__ void __launch_bounds__(256) k_dfeat(
    const float* __restrict__ Wa, const float* __restrict__ dz,
    const float* __restrict__ feat, const float* __restrict__ alpha,
    const float* __restrict__ dMu, const float* __restrict__ dE2,
    float* __restrict__ dout3)
{
  __shared__ float As[16][132];
  __shared__ float Bs[16][128];
  __shared__ float al[128];
  const int b=blockIdx.y, d0=blockIdx.x*128;
  const int tid=threadIdx.x, tx=tid%16, ty=tid/16;
  if(tid<128) al[tid]=alpha[b*128+tid];
  float acc[8][8];
#pragma unroll
  for(int i=0;i<8;i++)
#pragma unroll
  for(int j=0;j<8;j++) acc[i][j]=0.f;
  for(int k0=0;k0<128;k0+=16){
    __syncthreads();
#pragma unroll
    for(int l=0;l<8;l++){
      int idx=tid+l*256; int kk=idx/128, dd=idx%128;
      As[kk][dd]=Wa[(long)(k0+kk)*4096+d0+dd];
    }
#pragma unroll
    for(int l=0;l<8;l++){
      int idx=tid+l*256; int kk=idx/128, t=idx%128;
      Bs[kk][t]=dz[((long)b*128+k0+kk)*128+t];
    }
    __syncthreads();
#pragma unroll
    for(int kk=0;kk<16;kk++){
      float ra[8],rb[8];
#pragma unroll
      for(int i=0;i<8;i++) ra[i]=As[kk][ty*8+i];
      *(float4*)rb    =*(float4*)&Bs[kk][tx*8];
      *(float4*)(rb+4)=*(float4*)&Bs[kk][tx*8+4];
#pragma unroll
      for(int i=0;i<8;i++)
#pragma unroll
      for(int j=0;j<8;j++) acc[i][j]+=ra[i]*rb[j];
    }
  }
#pragma unroll
  for(int i=0;i<8;i++){
    int d=d0+ty*8+i;
    float dm=dMu[(long)b*4096+d], de=dE2[(long)b*4096+d];
#pragma unroll
    for(int j=0;j<8;j++){
      int t=tx*8+j;
      long fi=((long)b*4096+d)*128+t;
      float f=feat[fi];
      float val=acc[i][j]+al[t]*(dm+2.f*de*f);
      dout3[fi]= f>0.f? val:0.f;
    }
  }
}

// ---------- row/col stats ----------
__global__ void k_rowstats(const float* __restrict__ fam,const float* __restrict__ x,
    float* __restrict__ cm,float* __restrict__ meanT)
{
  int w=(blockIdx.x*blockDim.x+threadIdx.x)>>5, lane=threadIdx.x&31;
  if(w>=4096) return;
  const float* fr=fam+(long)w*1024; const float* xr=x+(long)w*1024;
  float m=-1e30f, s=0.f;
  for(int t=lane;t<1024;t+=32){ m=fmaxf(m,fr[t]); s+=xr[t]; }
  for(int o=16;o;o>>=1){ m=fmaxf(m,__shfl_down_sync(~0u,m,o)); s+=__shfl_down_sync(~0u,s,o); }
  if(!lane){ cm[w]=m; meanT[w]=s*(1.f/1024.f); }
}
__global__ void k_colstats(const float* __restrict__ fam,const float* __restrict__ x,
    float* __restrict__ tm,float* __restrict__ meanF)
{
  int i=blockIdx.x*256+threadIdx.x; if(i>=32768) return;
  int b=i>>10, t=i&1023;
  const float* fb=fam+(long)b*131072+t; const float* xb=x+(long)b*131072+t;
  float m=-1e30f, s=0.f;
#pragma unroll 4
  for(int f=0;f<128;f++){ m=fmaxf(m,fb[f*1024]); s+=xb[f*1024]; }
  tm[i]=m; meanF[i]=s*(1.f/128.f);
}

// ---------- bitonic argsort ----------
template<int N>
__global__ void k_sort(const float* __restrict__ vals, int* __restrict__ idxout)
{
  __shared__ unsigned long long key[N];
  const int b=blockIdx.x, tid=threadIdx.x, TH=N/2;
  for(int i=tid;i<N;i+=TH){
    unsigned u=__float_as_uint(vals[b*N+i]);
    u = (u&0x80000000u)? ~u : (u|0x80000000u);
    key[i]=((unsigned long long)(~u)<<32)|(unsigned)i;
  }
  __syncthreads();
  for(int k=2;k<=N;k<<=1)
    for(int j=k>>1;j;j>>=1){
      for(int i=tid;i<N;i+=TH){
        int ixj=i^j;
        if(ixj>i){
          bool up=((i&k)==0);
          unsigned long long a=key[i],c=key[ixj];
          if((a>c)==up){ key[i]=c; key[ixj]=a; }
        }
      }
      __syncthreads();
    }
  for(int i=tid;i<128;i+=TH) idxout[b*128+i]=(int)(key[i]&0xFFFFFFFFu);
}

// ---------- RFM scan ----------
__global__ void k_rfm(const int* __restrict__ sc,const int* __restrict__ st,
    const int* __restrict__ mask_t,const int* __restrict__ s_t,
    const int* __restrict__ is_train,int* __restrict__ rstep,int* __restrict__ cstep)
{
  int b=threadIdx.x; if(b>=32) return;
  int* rs=rstep+b*128; int* cs=cstep+b*1024;
  for(int i=0;i<128;i++) rs[i]=-1;
  for(int i=0;i<1024;i++) cs[i]=-1;
  if(is_train && is_train[0]==0) return;
  int cnt=0;
  for(int s=0;s<128 && cnt<3;s++){
    int pc=sc[b*128+s], pt=st[b*128+s];
    if(rs[pc]!=-1||cs[pt]!=-1) continue;
    int mt=mask_t[b*128+s], ss=s_t[b*128+s];
    rs[pc]=s;
    int l=pt-ss; if(l<0)l=0;
    int r=pt+mt-ss; if(r>1024)r=1024;
    for(int t=l;t<r;t++) cs[t]=s;
    cnt++;
  }
}

// ---------- apply mask ----------
__global__ void k_apply(const float* __restrict__ x,const int* __restrict__ rstep,
    const int* __restrict__ cstep,const float* __restrict__ meanT,
    const float* __restrict__ meanF,float* __restrict__ xm)
{
  long i=(long)blockIdx.x*256+threadIdx.x; if(i>=4194304) return;
  int t=(int)(i&1023); int f=(int)((i>>10)&127); int b=(int)(i>>17);
  int rs=rstep[b*128+f], cs=cstep[b*1024+t];
  float v;
  if(rs<0&&cs<0) v=x[i];
  else v=(cs>=rs)? meanT[b*128+f] : meanF[b*1024+t];
  xm[i]=v;
}

// ---------- emb head ----------
__global__ void k_cat(const float* __restrict__ mu,const float* __restrict__ m2,
                      float* __restrict__ cat)
{
  int i=blockIdx.x*256+threadIdx.x; if(i>=131072) return;
  int b=i>>12, d=i&4095;
  float m=mu[i];
  cat[(long)b*8192+d]=m;
  cat[(long)b*8192+4096+d]=sqrtf(fmaxf(m2[i]-m*m,1e-5f));
}
__global__ void __launch_bounds__(256) k_embp(
    const float* __restrict__ cat,const float* __restrict__ We,
    float* __restrict__ part)
{
  __shared__ float cs[32][64];
  const int ks=blockIdx.x, j=threadIdx.x;
  for(int idx=j; idx<32*64; idx+=256){
    int b=idx>>6, ii=idx&63;
    cs[b][ii]=cat[(long)b*8192 + ks*64 + ii];
  }
  __syncthreads();
  float acc[32];
#pragma unroll
  for(int b=0;b<32;b++) acc[b]=0.f;
  for(int ii=0;ii<64;ii++){
    float w=We[((long)ks*64+ii)*256+j];
#pragma unroll
    for(int b=0;b<32;b++) acc[b]+=cs[b][ii]*w;
  }
#pragma unroll
  for(int b=0;b<32;b++) part[((long)ks*32+b)*256+j]=acc[b];
}
__global__ void __launch_bounds__(256) k_embf(
    const float* __restrict__ part,const float* __restrict__ be,
    const float* __restrict__ Wc,const float* __restrict__ bc,
    float* __restrict__ out)
{
  const int b=blockIdx.x, j=threadIdx.x;
  float s=be[j];
  for(int ks=0;ks<128;ks++) s+=part[((long)ks*32+b)*256+j];
  __shared__ float es[256];
  es[j]=s; __syncthreads();
  if(j<2){
    float acc=bc[j];
    for(int q=0;q<256;q++) acc+=es[q]*Wc[q*2+j];
    out[b*2+j]=acc;
  }
}

// ---------- host ----------
static void run_tail(const float* h3,const float* Wa,const float* ba,const float* va,
                     float* attp,float* att,float* alpha,float* mu,float* m2)
{
  k_attp<<<dim3(8,32),256>>>(Wa,h3,attp);
  k_attf<<<2048,256>>>(attp,ba,att);
  k_salpha<<<32,128>>>(att,va,alpha);
  k_mustats<<<16384,256>>>(h3,alpha,mu,m2);
}

extern "C" void kernel_launch(void* const* d_in,const int* in_sizes,int n_in,
                              void* d_out,int out_size)
{
  const float* x =(const float*)d_in[0];
  const float* W1=(const float*)d_in[1]; const float* b1=(const float*)d_in[2];
  const float* W2=(const float*)d_in[3]; const float* b2=(const float*)d_in[4];
  const float* W3=(const float*)d_in[5]; const float* b3=(const float*)d_in[6];
  const float* Wa=(const float*)d_in[7]; const float* ba=(const float*)d_in[8];
  const float* va=(const float*)d_in[9];
  const float* We=(const float*)d_in[10]; const float* be=(const float*)d_in[11];
  const float* Wc=(const float*)d_in[12]; const float* bc=(const float*)d_in[13];
  const int* mask_t=(const int*)d_in[14]; const int* s_t=(const int*)d_in[15];
  const int* is_train = (n_in>16)? (const int*)d_in[16] : nullptr;
  float* out=(float*)d_out;

  float *h1,*h2,*h3,*d1,*d2,*d3,*fam,*xm,*att,*attp,*dz,*alpha,*ds,*dap,*mu,*m2,*dMu,*dE2,*gvec;
  float *cat,*ep,*cm,*tm,*meanT,*meanF,*wtf2,*wtb2,*wtf3,*wtb3;
  int *sc,*st,*rstep,*cstep;
  cudaGetSymbolAddress((void**)&h1,g_h1);   cudaGetSymbolAddress((void**)&h2,g_h2);
  cudaGetSymbolAddress((void**)&h3,g_h3);   cudaGetSymbolAddress((void**)&d1,g_d1);
  cudaGetSymbolAddress((void**)&d2,g_d2);   cudaGetSymbolAddress((void**)&d3,g_d3);
  cudaGetSymbolAddress((void**)&fam,g_fam); cudaGetSymbolAddress((void**)&xm,g_xm);
  cudaGetSymbolAddress((void**)&att,g_att); cudaGetSymbolAddress((void**)&attp,g_attp);
  cudaGetSymbolAddress((void**)&dz,g_dzb);
  cudaGetSymbolAddress((void**)&alpha,g_alpha); cudaGetSymbolAddress((void**)&ds,g_dsb);
  cudaGetSymbolAddress((void**)&dap,g_dap);
  cudaGetSymbolAddress((void**)&mu,g_mu);   cudaGetSymbolAddress((void**)&m2,g_m2);
  cudaGetSymbolAddress((void**)&dMu,g_dMu); cudaGetSymbolAddress((void**)&dE2,g_dE2);
  cudaGetSymbolAddress((void**)&gvec,g_gvec);
  cudaGetSymbolAddress((void**)&cat,g_cat); cudaGetSymbolAddress((void**)&ep,g_ep);
  cudaGetSymbolAddress((void**)&cm,g_cm);   cudaGetSymbolAddress((void**)&tm,g_tm);
  cudaGetSymbolAddress((void**)&meanT,g_meanT); cudaGetSymbolAddress((void**)&meanF,g_meanF);
  cudaGetSymbolAddress((void**)&sc,g_sc);   cudaGetSymbolAddress((void**)&st,g_st);
  cudaGetSymbolAddress((void**)&rstep,g_rstep); cudaGetSymbolAddress((void**)&cstep,g_cstep);
  cudaGetSymbolAddress((void**)&wtf2,g_wtf2); cudaGetSymbolAddress((void**)&wtb2,g_wtb2);
  cudaGetSymbolAddress((void**)&wtf3,g_wtf3); cudaGetSymbolAddress((void**)&wtb3,g_wtb3);

  const int MMA_SMEM = 120*136*4; // ev+od (48 rows) + ws (72 rows), LD=136
  cudaFuncSetAttribute(k_cmma<64,128,64,512,1>,  cudaFuncAttributeMaxDynamicSharedMemorySize, MMA_SMEM);
  cudaFuncSetAttribute(k_cmma<64,128,64,512,3>,  cudaFuncAttributeMaxDynamicSharedMemorySize, MMA_SMEM);
  cudaFuncSetAttribute(k_cmma<128,256,32,256,1>, cudaFuncAttributeMaxDynamicSharedMemorySize, MMA_SMEM);
  cudaFuncSetAttribute(k_cmma<128,256,32,256,3>, cudaFuncAttributeMaxDynamicSharedMemorySize, MMA_SMEM);

  // prep
  k_wt<<<288,256>>>(W2,wtf2,wtb2,64,128);
  k_wt<<<1152,256>>>(W3,wtf3,wtb3,128,256);
  k_gvec<<<1024,256>>>(We,Wc,gvec);
  // pass 1 (3xTF32: fp32-accurate, argsort-safe)
  k_conv_fwd<1,64,128,1024,1,16,4,256><<<dim3(8,64,32),256>>>(x,W1,b1,h1);
  k_cmma<64,128,64,512,3><<<dim3(2,32,32),256,MMA_SMEM>>>(h1,wtf2,b2,h2);
  k_cmma<128,256,32,256,3><<<dim3(2,16,32),256,MMA_SMEM>>>(h2,wtf3,b3,h3);
  run_tail(h3,Wa,ba,va,attp,att,alpha,mu,m2);
  // backward to input (fp32)
  k_dcoef<<<512,256>>>(mu,m2,gvec,dMu,dE2);
  k_dalp<<<dim3(8,32),128>>>(h3,dMu,dE2,dap);
  k_dalf<<<32,128>>>(dap,alpha,ds);
  k_dz<<<2048,256>>>(att,ds,va,dz);
  k_dfeat<<<dim3(32,32),256>>>(Wa,dz,h3,alpha,dMu,dE2,d3);
  k_cbwd<128,256,16,128,8><<<dim3(4,16,32),256>>>(d3,wtb3,h2,d2);
  k_cbwd<64,128,32,256,8><<<dim3(4,32,32),256>>>(d2,wtb2,h1,d1);
  k_bwd1<<<dim3(2,128,32),256>>>(d1,W1,fam);
  // masking
  k_rowstats<<<512,256>>>(fam,x,cm,meanT);
  k_colstats<<<128,256>>>(fam,x,tm,meanF);
  k_sort<128><<<32,64>>>(cm,sc);
  k_sort<1024><<<32,512>>>(tm,st);
  k_rfm<<<1,32>>>(sc,st,mask_t,s_t,is_train,rstep,cstep);
  k_apply<<<16384,256>>>(x,rstep,cstep,meanT,meanF,xm);
  // pass 2 (single tf32: continuous output path)
  k_conv_fwd<1,64,128,1024,1,16,4,256><<<dim3(8,64,32),256>>>(xm,W1,b1,h1);
  k_cmma<64,128,64,512,1><<<dim3(2,32,32),256,MMA_SMEM>>>(h1,wtf2,b2,h2);
  k_cmma<128,256,32,256,1><<<dim3(2,16,32),256,MMA_SMEM>>>(h2,wtf3,b3,h3);
  run_tail(h3,Wa,ba,va,attp,att,alpha,mu,m2);
  k_cat<<<512,256>>>(mu,m2,cat);
  k_embp<<<128,256>>>(cat,We,ep);
  k_embf<<<32,256>>>(ep,be,Wc,bc,out);
}

// round 7
// speedup vs baseline: 2.8864x; 1.0388x over previous
#include <cuda_runtime.h>
#include <math.h>

// ---------- static scratch ----------
__device__ float g_h1[67108864];
__device__ float g_h2[33554432];
__device__ float g_h3[16777216];
__device__ float g_d1[67108864];
__device__ float g_d2[33554432];
__device__ float g_d3[16777216];
__device__ float g_fam[4194304];
__device__ float g_xm[4194304];
__device__ float g_att[524288];
__device__ float g_attp[4194304];
__device__ float g_dzb[524288];
__device__ float g_alpha[4096];
__device__ float g_dsb[4096];
__device__ float g_dap[32768];
__device__ float g_mu[131072];
__device__ float g_m2[131072];
__device__ float g_dMu[131072];
__device__ float g_dE2[131072];
__device__ float g_gvec[8192];
__device__ float g_cat[262144];
__device__ float g_ep[1048576];
__device__ float g_cm[4096];
__device__ float g_tm[32768];
__device__ float g_meanT[4096];
__device__ float g_meanF[32768];
__device__ int   g_sc[4096];
__device__ int   g_st[4096];
__device__ int   g_rstep[4096];
__device__ int   g_cstep[32768];
__device__ float g_wtf2[73728];
__device__ float g_wtb2[73728];
__device__ float g_wtf3[294912];
__device__ float g_wtb3[294912];

// ---------- weight transposes ----------
// WTf: fwd mma layout, row = (c/8)*72 + tap*8 + (c%8), cols = COUT
// WTb: bwd mma layout, row = (o/8)*72 + tap*8 + (o%8), cols = CIN
__global__ void k_wt(const float* __restrict__ W, float* __restrict__ WTf,
                     float* __restrict__ WTb, int CIN, int COUT)
{
  int idx=blockIdx.x*256+threadIdx.x;
  int tot=CIN*COUT*9; if(idx>=tot) return;
  int k=idx%9, c=(idx/9)%CIN, o=idx/(9*CIN);
  float v=W[idx];
  int rf=(c>>3)*72 + k*8 + (c&7);
  WTf[(long)rf*COUT+o]=v;
  int rb=(o>>3)*72 + k*8 + (o&7);
  WTb[(long)rb*CIN+c]=v;
}

// ---------- conv1 fwd (CIN=1) ----------
template<int CIN,int COUT,int HIN,int WIN,int CC,int OG,int OP,int THREADS>
__global__ void __launch_bounds__(THREADS) k_conv_fwd(
    const float* __restrict__ in, const float* __restrict__ W,
    const float* __restrict__ bias, float* __restrict__ out)
{
  constexpr int HOUT=HIN/2, WOUT=WIN/2;
  __shared__ float ins[CC*3*130];
  __shared__ float ws[CC*9*COUT];
  const int n=blockIdx.z, i=blockIdx.y, j0=blockIdx.x*64;
  const int tid=threadIdx.x, og=tid%OG, jt=tid/OG;
  float acc[OP][4];
#pragma unroll
  for(int o=0;o<OP;o++){acc[o][0]=acc[o][1]=acc[o][2]=acc[o][3]=0.f;}
  for(int c0=0;c0<CIN;c0+=CC){
    __syncthreads();
    for(int idx=tid; idx<CC*3*130; idx+=THREADS){
      int c=idx/390, r=(idx/130)%3, col=idx%130;
      int gx=2*i+r, gy=2*j0+col;
      float v=0.f;
      if(gx<HIN && gy<WIN) v=in[(((long)n*CIN+c0+c)*HIN+gx)*WIN+gy];
      ins[idx]=v;
    }
    for(int idx=tid; idx<COUT*CC*9; idx+=THREADS){
      int o=idx/(CC*9), rem=idx%(CC*9);
      ws[rem*COUT+o]=W[(long)o*CIN*9 + c0*9 + rem];
    }
    __syncthreads();
#pragma unroll
    for(int c=0;c<CC;c++)
#pragma unroll
    for(int r=0;r<3;r++){
      float v[9];
#pragma unroll
      for(int m=0;m<9;m++) v[m]=ins[(c*3+r)*130 + 8*jt + m];
#pragma unroll
      for(int kj=0;kj<3;kj++)
#pragma unroll
      for(int oo=0;oo<OP;oo++){
        float w=ws[(c*9+r*3+kj)*COUT + og + OG*oo];
        acc[oo][0]+=w*v[kj];   acc[oo][1]+=w*v[2+kj];
        acc[oo][2]+=w*v[4+kj]; acc[oo][3]+=w*v[6+kj];
      }
    }
  }
  int j=j0+4*jt;
#pragma unroll
  for(int oo=0;oo<OP;oo++){
    int o=og+OG*oo; float bb=bias[o];
    float4 r;
    r.x=fmaxf(acc[oo][0]+bb,0.f); r.y=fmaxf(acc[oo][1]+bb,0.f);
    r.z=fmaxf(acc[oo][2]+bb,0.f); r.w=fmaxf(acc[oo][3]+bb,0.f);
    *(float4*)&out[(((long)n*COUT+o)*HOUT+i)*WOUT+j]=r;
  }
}

// ---------- tf32 helpers ----------
__device__ __forceinline__ float to_tf32(float v){
  unsigned r; asm("cvt.rna.tf32.f32 %0, %1;" : "=r"(r) : "f"(v));
  return __uint_as_float(r);
}
__device__ __forceinline__ void mma_tf32(float* c4,
    unsigned a0,unsigned a1,unsigned a2,unsigned a3,unsigned b0,unsigned b1){
  asm volatile(
    "mma.sync.aligned.m16n8k8.row.col.f32.tf32.tf32.f32 "
    "{%0,%1,%2,%3},{%4,%5,%6,%7},{%8,%9},{%0,%1,%2,%3};"
    : "+f"(c4[0]),"+f"(c4[1]),"+f"(c4[2]),"+f"(c4[3])
    : "r"(a0),"r"(a1),"r"(a2),"r"(a3),"r"(b0),"r"(b1));
}

// ---------- tf32 mma conv fwd (SPLIT=1: tf32; SPLIT=3: ~fp32) ----------
template<int CIN,int COUT,int HIN,int WIN,int SPLIT>
__global__ void __launch_bounds__(256,2) k_cmma(
    const float* __restrict__ in, const float* __restrict__ WT,
    const float* __restrict__ bias, float* __restrict__ out)
{
  constexpr int HOUT=HIN/2, WOUT=WIN/2;
  constexpr int NJT=WOUT/128;
  constexpr int LD=136;
  extern __shared__ float sm[];
  float* ev = sm;
  float* od = sm + 24*LD;
  float* ws = sm + 48*LD;
  const int n=blockIdx.z, i=blockIdx.y;
  const int jt_=blockIdx.x%NJT, ot=blockIdx.x/NJT;
  const int j0=jt_*128, o0=ot*128;
  const int tid=threadIdx.x, wid=tid>>5, lane=tid&31;
  const int gid=lane>>2, tig=lane&3;
  const int m0=(wid&3)*32, n0w=(wid>>2)*64;
  float acc[2][8][4];
#pragma unroll
  for(int a=0;a<2;a++)
#pragma unroll
  for(int b=0;b<8;b++)
#pragma unroll
  for(int c=0;c<4;c++) acc[a][b][c]=0.f;

  for(int c0=0;c0<CIN;c0+=8){
    __syncthreads();
    for(int idx=tid; idx<8*3*129; idx+=256){
      int c=idx/387, rem=idx%387, r=rem/129, p=rem%129;
      int gx=2*i+r, gy=2*j0+2*p;
      float a=0.f,bv=0.f;
      if(gx<HIN && gy<WIN){
        const float2 s=*(const float2*)&in[(((long)n*CIN+c0+c)*HIN+gx)*WIN+gy];
        a=s.x; bv=s.y;
      }
      ev[(c*3+r)*LD+p]=a;
      od[(c*3+r)*LD+p]=bv;
    }
    {
      const float* wsrc = WT + (long)(c0>>3)*72*COUT + o0;
      for(int idx=tid; idx<72*32; idx+=256){
        int kk=idx>>5, o4=(idx&31)*4;
        float4 v=*(const float4*)&wsrc[(long)kk*COUT + o4];
        *(float4*)&ws[kk*LD + o4]=v;
      }
    }
    __syncthreads();
#pragma unroll
    for(int kc=0;kc<9;kc++){
      const int r=kc/3, kj=kc%3;
      const float* src = (kj==1)? od : ev;
      const int co = (kj==2)? 1:0;
      unsigned bh[8][2], bl[8][2];
#pragma unroll
      for(int f=0;f<8;f++){
        float v0 = src[(tig*3+r)*LD + n0w + f*8 + gid + co];
        float v1 = src[((tig+4)*3+r)*LD + n0w + f*8 + gid + co];
        float h0=to_tf32(v0), h1=to_tf32(v1);
        bh[f][0]=__float_as_uint(h0); bh[f][1]=__float_as_uint(h1);
        if(SPLIT==3){
          bl[f][0]=__float_as_uint(to_tf32(v0-h0));
          bl[f][1]=__float_as_uint(to_tf32(v1-h1));
        }
      }
#pragma unroll
      for(int mf=0;mf<2;mf++){
        float w0=ws[(kc*8+tig)*LD + m0+mf*16+gid];
        float w1=ws[(kc*8+tig)*LD + m0+mf*16+gid+8];
        float w2=ws[(kc*8+tig+4)*LD + m0+mf*16+gid];
        float w3=ws[(kc*8+tig+4)*LD + m0+mf*16+gid+8];
        float h0=to_tf32(w0),h1=to_tf32(w1),h2=to_tf32(w2),h3=to_tf32(w3);
        unsigned ah0=__float_as_uint(h0),ah1=__float_as_uint(h1),
                 ah2=__float_as_uint(h2),ah3=__float_as_uint(h3);
        unsigned al0=0,al1=0,al2=0,al3=0;
        if(SPLIT==3){
          al0=__float_as_uint(to_tf32(w0-h0)); al1=__float_as_uint(to_tf32(w1-h1));
          al2=__float_as_uint(to_tf32(w2-h2)); al3=__float_as_uint(to_tf32(w3-h3));
        }
#pragma unroll
        for(int f=0;f<8;f++){
          mma_tf32(acc[mf][f], ah0,ah1,ah2,ah3, bh[f][0],bh[f][1]);
          if(SPLIT==3){
            mma_tf32(acc[mf][f], ah0,ah1,ah2,ah3, bl[f][0],bl[f][1]);
            mma_tf32(acc[mf][f], al0,al1,al2,al3, bh[f][0],bh[f][1]);
          }
        }
      }
    }
  }
#pragma unroll
  for(int mf=0;mf<2;mf++){
    int oA=o0+m0+mf*16+gid, oB=oA+8;
    float bA=bias[oA], bB=bias[oB];
#pragma unroll
    for(int f=0;f<8;f++){
      int jj=j0 + n0w + f*8 + tig*2;
      long baseA=(((long)n*COUT+oA)*HOUT+i)*WOUT + jj;
      long baseB=(((long)n*COUT+oB)*HOUT+i)*WOUT + jj;
      float2 rA, rB;
      rA.x=fmaxf(acc[mf][f][0]+bA,0.f); rA.y=fmaxf(acc[mf][f][1]+bA,0.f);
      rB.x=fmaxf(acc[mf][f][2]+bB,0.f); rB.y=fmaxf(acc[mf][f][3]+bB,0.f);
      *(float2*)&out[baseA]=rA;
      *(float2*)&out[baseB]=rB;
    }
  }
}

// ---------- tf32 mma transposed-conv bwd (SPLIT=3 for argsort safety) ----------
// din[n,c,x,y] = relu'(act) * sum_{o,ki,kj: x=2i+ki, y=2j+kj} W[o,c,ki,kj]*dout[n,o,i,j]
// Block: one (n,x), M = CIN, N = NT y-positions. Even/odd-y accumulator groups.
template<int CIN,int COUT,int HOUT,int WOUT,int NT,int SPLIT>
__global__ void __launch_bounds__(256,2) k_cbmma(
    const float* __restrict__ dout, const float* __restrict__ WT,
    const float* __restrict__ act, float* __restrict__ din)
{
  constexpr int HIN=2*HOUT, WIN=2*WOUT;
  constexpr int LDW=CIN+8, LDD=NT/2+4, JL=NT/2+2;
  constexpr int NW_M=CIN/32;
  __shared__ float ws[72*LDW];
  __shared__ float dsA[8*LDD];
  __shared__ float dsB[8*LDD];
  const int n=blockIdx.z, x=blockIdx.y, y0=blockIdx.x*NT;
  const int tid=threadIdx.x, wid=tid>>5, lane=tid&31;
  const int gid=lane>>2, tig=lane&3;
  const int m0=(wid%NW_M)*32, n0=(wid/NW_M)*64;
  const bool xe=((x&1)==0);
  const int iA = xe ? (x>>1) : ((x-1)>>1);
  const int iB = (x>>1)-1;
  const bool hasB = xe && iB>=0;
  const int jb = y0/2 - 1;
  float acc_e[2][4][4], acc_o[2][4][4];
#pragma unroll
  for(int a=0;a<2;a++)
#pragma unroll
  for(int b=0;b<4;b++)
#pragma unroll
  for(int c=0;c<4;c++){acc_e[a][b][c]=0.f; acc_o[a][b][c]=0.f;}

  for(int o0=0;o0<COUT;o0+=8){
    __syncthreads();
    {
      const float* wsrc = WT + (long)(o0>>3)*72*CIN;
      for(int idx=tid; idx<72*(CIN/4); idx+=256){
        int r=idx/(CIN/4), c4=(idx%(CIN/4))*4;
        float4 v=*(const float4*)&wsrc[(long)r*CIN+c4];
        *(float4*)&ws[r*LDW+c4]=v;
      }
    }
    for(int idx=tid; idx<8*JL; idx+=256){
      int o=idx/JL, jl=idx%JL; int j=jb+jl;
      float a=0.f,bv=0.f;
      if(j>=0 && j<WOUT){
        long base=((long)n*COUT+o0+o)*HOUT;
        a = dout[(base+iA)*WOUT+j];
        if(hasB) bv = dout[(base+iB)*WOUT+j];
      }
      dsA[o*LDD+jl]=a; dsB[o*LDD+jl]=bv;
    }
    __syncthreads();

    auto proc = [&](const float* ds, const int tapBase){
      unsigned b1h[4][2], b0h[4][2], b1l[4][2], b0l[4][2];
#pragma unroll
      for(int f=0;f<4;f++){
        int cbase = n0/2 + f*8 + gid;
        float v1a = ds[tig*LDD + cbase + 1];
        float v1b = ds[(tig+4)*LDD + cbase + 1];
        float v0a = ds[tig*LDD + cbase];
        float v0b = ds[(tig+4)*LDD + cbase];
        float h1a=to_tf32(v1a), h1b=to_tf32(v1b);
        float h0a=to_tf32(v0a), h0b=to_tf32(v0b);
        b1h[f][0]=__float_as_uint(h1a); b1h[f][1]=__float_as_uint(h1b);
        b0h[f][0]=__float_as_uint(h0a); b0h[f][1]=__float_as_uint(h0b);
        if(SPLIT==3){
          b1l[f][0]=__float_as_uint(to_tf32(v1a-h1a));
          b1l[f][1]=__float_as_uint(to_tf32(v1b-h1b));
          b0l[f][0]=__float_as_uint(to_tf32(v0a-h0a));
          b0l[f][1]=__float_as_uint(to_tf32(v0b-h0b));
        }
      }
#pragma unroll
      for(int kj=0;kj<3;kj++){
        const int tap=tapBase+kj;
#pragma unroll
        for(int mf=0;mf<2;mf++){
          float w0=ws[(tap*8+tig)*LDW + m0+mf*16+gid];
          float w1=ws[(tap*8+tig)*LDW + m0+mf*16+gid+8];
          float w2=ws[(tap*8+tig+4)*LDW + m0+mf*16+gid];
          float w3=ws[(tap*8+tig+4)*LDW + m0+mf*16+gid+8];
          float h0=to_tf32(w0),h1=to_tf32(w1),h2=to_tf32(w2),h3=to_tf32(w3);
          unsigned ah0=__float_as_uint(h0),ah1=__float_as_uint(h1),
                   ah2=__float_as_uint(h2),ah3=__float_as_uint(h3);
          unsigned al0=0,al1=0,al2=0,al3=0;
          if(SPLIT==3){
            al0=__float_as_uint(to_tf32(w0-h0)); al1=__float_as_uint(to_tf32(w1-h1));
            al2=__float_as_uint(to_tf32(w2-h2)); al3=__float_as_uint(to_tf32(w3-h3));
          }
#pragma unroll
          for(int f=0;f<4;f++){
            float* c4 = (kj==1)? acc_o[mf][f] : acc_e[mf][f];
            const unsigned* bh = (kj==2)? b0h[f] : b1h[f];
            const unsigned* bl = (kj==2)? b0l[f] : b1l[f];
            mma_tf32(c4, ah0,ah1,ah2,ah3, bh[0],bh[1]);
            if(SPLIT==3){
              mma_tf32(c4, ah0,ah1,ah2,ah3, bl[0],bl[1]);
              mma_tf32(c4, al0,al1,al2,al3, bh[0],bh[1]);
            }
          }
        }
      }
    };
    proc(dsA, xe?0:3);
    if(hasB) proc(dsB, 6);
  }

#pragma unroll
  for(int mf=0;mf<2;mf++){
    int c0_=m0+mf*16+gid;
#pragma unroll
    for(int f=0;f<4;f++){
      int Y = y0 + n0 + 2*(f*8 + 2*tig);
      long b0i=(((long)n*CIN+c0_)*HIN+x)*WIN + Y;
      long b1i=(((long)n*CIN+c0_+8)*HIN+x)*WIN + Y;
      float2 m, r;
      m=*(const float2*)&act[b0i];
      r.x = m.x>0.f? acc_e[mf][f][0]:0.f; r.y = m.y>0.f? acc_o[mf][f][0]:0.f;
      *(float2*)&din[b0i]=r;
      m=*(const float2*)&act[b0i+2];
      r.x = m.x>0.f? acc_e[mf][f][1]:0.f; r.y = m.y>0.f? acc_o[mf][f][1]:0.f;
      *(float2*)&din[b0i+2]=r;
      m=*(const float2*)&act[b1i];
      r.x = m.x>0.f? acc_e[mf][f][2]:0.f; r.y = m.y>0.f? acc_o[mf][f][2]:0.f;
      *(float2*)&din[b1i]=r;
      m=*(const float2*)&act[b1i+2];
      r.x = m.x>0.f? acc_e[mf][f][3]:0.f; r.y = m.y>0.f? acc_o[mf][f][3]:0.f;
      *(float2*)&din[b1i+2]=r;
    }
  }
}

// ---------- conv1 data-grad -> |dx| ----------
__global__ void __launch_bounds__(256) k_bwd1(
    const float* __restrict__ dz1, const float* __restrict__ W1,
    float* __restrict__ fam)
{
  __shared__ float ws[576];
  __shared__ float dsm[8*2*260];
  const int n=blockIdx.z, x=blockIdx.y, y0=blockIdx.x*512;
  const int tid=threadIdx.x;
  for(int idx=tid; idx<576; idx+=256) ws[idx]=W1[idx];
  int iA,iB,kiA,kiB; bool hasB;
  if((x&1)==0){iA=x>>1;kiA=0;iB=iA-1;kiB=2;hasB=(iB>=0);}
  else{iA=(x-1)>>1;kiA=1;iB=0;kiB=0;hasB=false;}
  const int jbase=y0/2-1;
  float accE=0.f, accO=0.f;
  for(int o0=0;o0<64;o0+=8){
    __syncthreads();
    for(int idx=tid; idx<8*2*260; idx+=256){
      int o=idx/520, rs=(idx/260)&1, jj=idx%260;
      int j=jbase+jj; int ir=rs?iB:iA;
      float v=0.f;
      if(j>=0 && j<512 && (rs==0||hasB))
        v=dz1[(((long)n*64+o0+o)*64+ir)*512+j];
      dsm[idx]=v;
    }
    __syncthreads();
#pragma unroll
    for(int o=0;o<8;o++){
#pragma unroll
      for(int rs=0;rs<2;rs++){
        if(rs==1&&!hasB) break;
        int ki=rs?kiB:kiA;
        const float* wb=&ws[(o0+o)*9+ki*3];
        float vm=dsm[(o*2+rs)*260+tid], v0=dsm[(o*2+rs)*260+tid+1];
        accE+=wb[0]*v0+wb[2]*vm; accO+=wb[1]*v0;
      }
    }
  }
  long base=((long)n*128+x)*1024 + y0 + 2*tid;
  fam[base]=fabsf(accE); fam[base+1]=fabsf(accO);
}

// ---------- att partial GEMM ----------
__global__ void __launch_bounds__(256) k_attp(
    const float* __restrict__ Wa, const float* __restrict__ feat,
    float* __restrict__ attp)
{
  __shared__ float As[128][17];
  __shared__ float Fs[16][128];
  const int ks=blockIdx.x, b=blockIdx.y, tid=threadIdx.x, tx=tid%16, ty=tid/16;
  const float* fb = feat + (long)b*524288;
  float acc[8][8];
#pragma unroll
  for(int i=0;i<8;i++)
#pragma unroll
  for(int j=0;j<8;j++) acc[i][j]=0.f;
  for(int k0=ks*512;k0<ks*512+512;k0+=16){
    __syncthreads();
#pragma unroll
    for(int l=0;l<8;l++){
      int idx=tid+l*256; int h=idx/16, kk=idx%16;
      As[h][kk]=Wa[(long)h*4096+k0+kk];
    }
#pragma unroll
    for(int l=0;l<8;l++){
      int idx=tid+l*256; int kk=idx/128, t=idx%128;
      Fs[kk][t]=fb[(long)(k0+kk)*128+t];
    }
    __syncthreads();
#pragma unroll
    for(int kk=0;kk<16;kk++){
      float ra[8], rb[8];
#pragma unroll
      for(int i=0;i<8;i++) ra[i]=As[ty*8+i][kk];
      *(float4*)rb     = *(float4*)&Fs[kk][tx*8];
      *(float4*)(rb+4) = *(float4*)&Fs[kk][tx*8+4];
#pragma unroll
      for(int i=0;i<8;i++)
#pragma unroll
      for(int j=0;j<8;j++) acc[i][j]+=ra[i]*rb[j];
    }
  }
#pragma unroll
  for(int i=0;i<8;i++){
    int h=ty*8+i;
#pragma unroll
    for(int j=0;j<8;j++)
      attp[(long)ks*524288 + ((long)b*128+h)*128+tx*8+j]=acc[i][j];
  }
}
__global__ void k_attf(const float* __restrict__ attp, const float* __restrict__ ba,
                       float* __restrict__ att)
{
  int i=blockIdx.x*256+threadIdx.x; if(i>=524288) return;
  int h=(i>>7)&127;
  float s=0.f;
#pragma unroll
  for(int ks=0;ks<8;ks++) s+=attp[(long)ks*524288+i];
  att[i]=tanhf(s+ba[h]);
}

// ---------- softmax ----------
__global__ void __launch_bounds__(128) k_salpha(
    const float* __restrict__ att, const float* __restrict__ va,
    float* __restrict__ alpha)
{
  __shared__ float vs[128], buf[128];
  const int b=blockIdx.x, t=threadIdx.x;
  vs[t]=va[t];
  __syncthreads();
  float s=0.f;
#pragma unroll 4
  for(int h=0;h<128;h++) s+=vs[h]*att[((long)b*128+h)*128+t];
  buf[t]=s; __syncthreads();
  for(int off=64;off;off>>=1){ if(t<off) buf[t]=fmaxf(buf[t],buf[t+off]); __syncthreads(); }
  float mx=buf[0]; __syncthreads();
  float e=expf(s-mx);
  buf[t]=e; __syncthreads();
  for(int off=64;off;off>>=1){ if(t<off) buf[t]+=buf[t+off]; __syncthreads(); }
  alpha[b*128+t]=e/buf[0];
}

// ---------- mu, m2 ----------
__global__ void k_mustats(const float* __restrict__ feat,
    const float* __restrict__ alpha, float* __restrict__ mu, float* __restrict__ m2)
{
  int w=(blockIdx.x*blockDim.x+threadIdx.x)>>5, lane=threadIdx.x&31;
  if(w>=131072) return;
  int b=w>>12;
  const float* fr=feat+(long)w*128;
  const float* ar=alpha+b*128;
  float s1=0.f,s2=0.f;
#pragma unroll
  for(int t=lane;t<128;t+=32){
    float a=ar[t], f=fr[t];
    s1+=a*f; s2+=a*f*f;
  }
  for(int o=16;o;o>>=1){ s1+=__shfl_down_sync(~0u,s1,o); s2+=__shfl_down_sync(~0u,s2,o); }
  if(!lane){ mu[w]=s1; m2[w]=s2; }
}

// ---------- gvec ----------
__global__ void k_gvec(const float* __restrict__ We,const float* __restrict__ Wc,
                       float* __restrict__ gvec)
{
  int w=(blockIdx.x*blockDim.x+threadIdx.x)>>5, lane=threadIdx.x&31;
  if(w>=8192) return;
  float s=0.f;
  for(int j=lane;j<256;j+=32) s+=We[(long)w*256+j]*(Wc[j*2+1]-Wc[j*2]);
  for(int o=16;o;o>>=1) s+=__shfl_down_sync(~0u,s,o);
  if(!lane) gvec[w]=s;
}

// ---------- dMu,dE2 ----------
__global__ void k_dcoef(const float* __restrict__ mu,const float* __restrict__ m2,
    const float* __restrict__ gvec, float* __restrict__ dMu,float* __restrict__ dE2)
{
  int i=blockIdx.x*256+threadIdx.x; if(i>=131072) return;
  int d=i&4095;
  float m=mu[i], v=m2[i]-m*m;
  float g2=gvec[4096+d];
  float dE=0.f, dM=gvec[d];
  if(v>1e-5f){ float sg=sqrtf(v); dE=0.5f*g2/sg; dM-=g2*m/sg; }
  dMu[i]=dM; dE2[i]=dE;
}

// ---------- dalpha ----------
__global__ void __launch_bounds__(128) k_dalp(
    const float* __restrict__ feat,const float* __restrict__ dMu,
    const float* __restrict__ dE2,float* __restrict__ part)
{
  const int ks=blockIdx.x, b=blockIdx.y, t=threadIdx.x;
  const float* fb=feat+(long)b*524288;
  const float* dm=dMu+b*4096; const float* de=dE2+b*4096;
  float acc=0.f;
  int d0=ks*512;
#pragma unroll 4
  for(int d=d0;d<d0+512;d++){
    float f=fb[(long)d*128+t];
    acc+=dm[d]*f+de[d]*f*f;
  }
  part[(ks*32+b)*128+t]=acc;
}
__global__ void __launch_bounds__(128) k_dalf(
    const float* __restrict__ part,const float* __restrict__ alpha,
    float* __restrict__ ds)
{
  const int b=blockIdx.x, t=threadIdx.x;
  float acc=0.f;
#pragma unroll
  for(int ks=0;ks<8;ks++) acc+=part[(ks*32+b)*128+t];
  __shared__ float buf[128];
  float a=alpha[b*128+t];
  buf[t]=a*acc; __syncthreads();
  for(int off=64;off;off>>=1){ if(t<off) buf[t]+=buf[t+off]; __syncthreads(); }
  ds[b*128+t]=a*(acc-buf[0]);
}

// ---------- dz ----------
__global__ void k_dz(const float* __restrict__ att,const float* __restrict__ ds,
    const float* __restrict__ va,float* __restrict__ dz)
{
  int i=blockIdx.x*256+threadIdx.x; if(i>=524288) return;
  int t=i&127, h=(i>>7)&127, b=i>>14;
  float a=att[i];
  dz[i]=va[h]*ds[b*128+t]*(1.f-a*a);
}

// ---------- dfeat ----------
__global__ void __launch_bounds__(256) k_dfeat(
    const float* __restrict__ Wa, const float* __restrict__ dz,
    const float* __restrict__ feat, const float* __restrict__ alpha,
    const float* __restrict__ dMu, const float* __restrict__ dE2,
    float* __restrict__ dout3)
{
  __shared__ float As[16][132];
  __shared__ float Bs[16][128];
  __shared__ float al[128];
  const int b=blockIdx.y, d0=blockIdx.x*128;
  const int tid=threadIdx.x, tx=tid%16, ty=tid/16;
  if(tid<128) al[tid]=alpha[b*128+tid];
  float acc[8][8];
#pragma unroll
  for(int i=0;i<8;i++)
#pragma unroll
  for(int j=0;j<8;j++) acc[i][j]=0.f;
  for(int k0=0;k0<128;k0+=16){
    __syncthreads();
#pragma unroll
    for(int l=0;l<8;l++){
      int idx=tid+l*256; int kk=idx/128, dd=idx%128;
      As[kk][dd]=Wa[(long)(k0+kk)*4096+d0+dd];
    }
#pragma unroll
    for(int l=0;l<8;l++){
      int idx=tid+l*256; int kk=idx/128, t=idx%128;
      Bs[kk][t]=dz[((long)b*128+k0+kk)*128+t];
    }
    __syncthreads();
#pragma unroll
    for(int kk=0;kk<16;kk++){
      float ra[8],rb[8];
#pragma unroll
      for(int i=0;i<8;i++) ra[i]=As[kk][ty*8+i];
      *(float4*)rb    =*(float4*)&Bs[kk][tx*8];
      *(float4*)(rb+4)=*(float4*)&Bs[kk][tx*8+4];
#pragma unroll
      for(int i=0;i<8;i++)
#pragma unroll
      for(int j=0;j<8;j++) acc[i][j]+=ra[i]*rb[j];
    }
  }
#pragma unroll
  for(int i=0;i<8;i++){
    int d=d0+ty*8+i;
    float dm=dMu[(long)b*4096+d], de=dE2[(long)b*4096+d];
#pragma unroll
    for(int j=0;j<8;j++){
      int t=tx*8+j;
      long fi=((long)b*4096+d)*128+t;
      float f=feat[fi];
      float val=acc[i][j]+al[t]*(dm+2.f*de*f);
      dout3[fi]= f>0.f? val:0.f;
    }
  }
}

// ---------- row/col stats ----------
__global__ void k_rowstats(const float* __restrict__ fam,const float* __restrict__ x,
    float* __restrict__ cm,float* __restrict__ meanT)
{
  int w=(blockIdx.x*blockDim.x+threadIdx.x)>>5, lane=threadIdx.x&31;
  if(w>=4096) return;
  const float* fr=fam+(long)w*1024; const float* xr=x+(long)w*1024;
  float m=-1e30f, s=0.f;
  for(int t=lane;t<1024;t+=32){ m=fmaxf(m,fr[t]); s+=xr[t]; }
  for(int o=16;o;o>>=1){ m=fmaxf(m,__shfl_down_sync(~0u,m,o)); s+=__shfl_down_sync(~0u,s,o); }
  if(!lane){ cm[w]=m; meanT[w]=s*(1.f/1024.f); }
}
__global__ void k_colstats(const float* __restrict__ fam,const float* __restrict__ x,
    float* __restrict__ tm,float* __restrict__ meanF)
{
  int i=blockIdx.x*256+threadIdx.x; if(i>=32768) return;
  int b=i>>10, t=i&1023;
  const float* fb=fam+(long)b*131072+t; const float* xb=x+(long)b*131072+t;
  float m=-1e30f, s=0.f;
#pragma unroll 4
  for(int f=0;f<128;f++){ m=fmaxf(m,fb[f*1024]); s+=xb[f*1024]; }
  tm[i]=m; meanF[i]=s*(1.f/128.f);
}

// ---------- bitonic argsort ----------
template<int N>
__global__ void k_sort(const float* __restrict__ vals, int* __restrict__ idxout)
{
  __shared__ unsigned long long key[N];
  const int b=blockIdx.x, tid=threadIdx.x, TH=N/2;
  for(int i=tid;i<N;i+=TH){
    unsigned u=__float_as_uint(vals[b*N+i]);
    u = (u&0x80000000u)? ~u : (u|0x80000000u);
    key[i]=((unsigned long long)(~u)<<32)|(unsigned)i;
  }
  __syncthreads();
  for(int k=2;k<=N;k<<=1)
    for(int j=k>>1;j;j>>=1){
      for(int i=tid;i<N;i+=TH){
        int ixj=i^j;
        if(ixj>i){
          bool up=((i&k)==0);
          unsigned long long a=key[i],c=key[ixj];
          if((a>c)==up){ key[i]=c; key[ixj]=a; }
        }
      }
      __syncthreads();
    }
  for(int i=tid;i<128;i+=TH) idxout[b*128+i]=(int)(key[i]&0xFFFFFFFFu);
}

// ---------- RFM scan ----------
__global__ void k_rfm(const int* __restrict__ sc,const int* __restrict__ st,
    const int* __restrict__ mask_t,const int* __restrict__ s_t,
    const int* __restrict__ is_train,int* __restrict__ rstep,int* __restrict__ cstep)
{
  int b=threadIdx.x; if(b>=32) return;
  int* rs=rstep+b*128; int* cs=cstep+b*1024;
  for(int i=0;i<128;i++) rs[i]=-1;
  for(int i=0;i<1024;i++) cs[i]=-1;
  if(is_train && is_train[0]==0) return;
  int cnt=0;
  for(int s=0;s<128 && cnt<3;s++){
    int pc=sc[b*128+s], pt=st[b*128+s];
    if(rs[pc]!=-1||cs[pt]!=-1) continue;
    int mt=mask_t[b*128+s], ss=s_t[b*128+s];
    rs[pc]=s;
    int l=pt-ss; if(l<0)l=0;
    int r=pt+mt-ss; if(r>1024)r=1024;
    for(int t=l;t<r;t++) cs[t]=s;
    cnt++;
  }
}

// ---------- apply mask ----------
__global__ void k_apply(const float* __restrict__ x,const int* __restrict__ rstep,
    const int* __restrict__ cstep,const float* __restrict__ meanT,
    const float* __restrict__ meanF,float* __restrict__ xm)
{
  long i=(long)blockIdx.x*256+threadIdx.x; if(i>=4194304) return;
  int t=(int)(i&1023); int f=(int)((i>>10)&127); int b=(int)(i>>17);
  int rs=rstep[b*128+f], cs=cstep[b*1024+t];
  float v;
  if(rs<0&&cs<0) v=x[i];
  else v=(cs>=rs)? meanT[b*128+f] : meanF[b*1024+t];
  xm[i]=v;
}

// ---------- emb head ----------
__global__ void k_cat(const float* __restrict__ mu,const float* __restrict__ m2,
                      float* __restrict__ cat)
{
  int i=blockIdx.x*256+threadIdx.x; if(i>=131072) return;
  int b=i>>12, d=i&4095;
  float m=mu[i];
  cat[(long)b*8192+d]=m;
  cat[(long)b*8192+4096+d]=sqrtf(fmaxf(m2[i]-m*m,1e-5f));
}
__global__ void __launch_bounds__(256) k_embp(
    const float* __restrict__ cat,const float* __restrict__ We,
    float* __restrict__ part)
{
  __shared__ float cs[32][64];
  const int ks=blockIdx.x, j=threadIdx.x;
  for(int idx=j; idx<32*64; idx+=256){
    int b=idx>>6, ii=idx&63;
    cs[b][ii]=cat[(long)b*8192 + ks*64 + ii];
  }
  __syncthreads();
  float acc[32];
#pragma unroll
  for(int b=0;b<32;b++) acc[b]=0.f;
  for(int ii=0;ii<64;ii++){
    float w=We[((long)ks*64+ii)*256+j];
#pragma unroll
    for(int b=0;b<32;b++) acc[b]+=cs[b][ii]*w;
  }
#pragma unroll
  for(int b=0;b<32;b++) part[((long)ks*32+b)*256+j]=acc[b];
}
__global__ void __launch_bounds__(256) k_embf(
    const float* __restrict__ part,const float* __restrict__ be,
    const float* __restrict__ Wc,const float* __restrict__ bc,
    float* __restrict__ out)
{
  const int b=blockIdx.x, j=threadIdx.x;
  float s=be[j];
  for(int ks=0;ks<128;ks++) s+=part[((long)ks*32+b)*256+j];
  __shared__ float es[256];
  es[j]=s; __syncthreads();
  if(j<2){
    float acc=bc[j];
    for(int q=0;q<256;q++) acc+=es[q]*Wc[q*2+j];
    out[b*2+j]=acc;
  }
}

// ---------- host ----------
static void run_tail(const float* h3,const float* Wa,const float* ba,const float* va,
                     float* attp,float* att,float* alpha,float* mu,float* m2)
{
  k_attp<<<dim3(8,32),256>>>(Wa,h3,attp);
  k_attf<<<2048,256>>>(attp,ba,att);
  k_salpha<<<32,128>>>(att,va,alpha);
  k_mustats<<<16384,256>>>(h3,alpha,mu,m2);
}

extern "C" void kernel_launch(void* const* d_in,const int* in_sizes,int n_in,
                              void* d_out,int out_size)
{
  const float* x =(const float*)d_in[0];
  const float* W1=(const float*)d_in[1]; const float* b1=(const float*)d_in[2];
  const float* W2=(const float*)d_in[3]; const float* b2=(const float*)d_in[4];
  const float* W3=(const float*)d_in[5]; const float* b3=(const float*)d_in[6];
  const float* Wa=(const float*)d_in[7]; const float* ba=(const float*)d_in[8];
  const float* va=(const float*)d_in[9];
  const float* We=(const float*)d_in[10]; const float* be=(const float*)d_in[11];
  const float* Wc=(const float*)d_in[12]; const float* bc=(const float*)d_in[13];
  const int* mask_t=(const int*)d_in[14]; const int* s_t=(const int*)d_in[15];
  const int* is_train = (n_in>16)? (const int*)d_in[16] : nullptr;
  float* out=(float*)d_out;

  float *h1,*h2,*h3,*d1,*d2,*d3,*fam,*xm,*att,*attp,*dz,*alpha,*ds,*dap,*mu,*m2,*dMu,*dE2,*gvec;
  float *cat,*ep,*cm,*tm,*meanT,*meanF,*wtf2,*wtb2,*wtf3,*wtb3;
  int *sc,*st,*rstep,*cstep;
  cudaGetSymbolAddress((void**)&h1,g_h1);   cudaGetSymbolAddress((void**)&h2,g_h2);
  cudaGetSymbolAddress((void**)&h3,g_h3);   cudaGetSymbolAddress((void**)&d1,g_d1);
  cudaGetSymbolAddress((void**)&d2,g_d2);   cudaGetSymbolAddress((void**)&d3,g_d3);
  cudaGetSymbolAddress((void**)&fam,g_fam); cudaGetSymbolAddress((void**)&xm,g_xm);
  cudaGetSymbolAddress((void**)&att,g_att); cudaGetSymbolAddress((void**)&attp,g_attp);
  cudaGetSymbolAddress((void**)&dz,g_dzb);
  cudaGetSymbolAddress((void**)&alpha,g_alpha); cudaGetSymbolAddress((void**)&ds,g_dsb);
  cudaGetSymbolAddress((void**)&dap,g_dap);
  cudaGetSymbolAddress((void**)&mu,g_mu);   cudaGetSymbolAddress((void**)&m2,g_m2);
  cudaGetSymbolAddress((void**)&dMu,g_dMu); cudaGetSymbolAddress((void**)&dE2,g_dE2);
  cudaGetSymbolAddress((void**)&gvec,g_gvec);
  cudaGetSymbolAddress((void**)&cat,g_cat); cudaGetSymbolAddress((void**)&ep,g_ep);
  cudaGetSymbolAddress((void**)&cm,g_cm);   cudaGetSymbolAddress((void**)&tm,g_tm);
  cudaGetSymbolAddress((void**)&meanT,g_meanT); cudaGetSymbolAddress((void**)&meanF,g_meanF);
  cudaGetSymbolAddress((void**)&sc,g_sc);   cudaGetSymbolAddress((void**)&st,g_st);
  cudaGetSymbolAddress((void**)&rstep,g_rstep); cudaGetSymbolAddress((void**)&cstep,g_cstep);
  cudaGetSymbolAddress((void**)&wtf2,g_wtf2); cudaGetSymbolAddress((void**)&wtb2,g_wtb2);
  cudaGetSymbolAddress((void**)&wtf3,g_wtf3); cudaGetSymbolAddress((void**)&wtb3,g_wtb3);

  const int MMA_SMEM = 120*136*4;
  cudaFuncSetAttribute(k_cmma<64,128,64,512,1>,  cudaFuncAttributeMaxDynamicSharedMemorySize, MMA_SMEM);
  cudaFuncSetAttribute(k_cmma<64,128,64,512,3>,  cudaFuncAttributeMaxDynamicSharedMemorySize, MMA_SMEM);
  cudaFuncSetAttribute(k_cmma<128,256,32,256,1>, cudaFuncAttributeMaxDynamicSharedMemorySize, MMA_SMEM);
  cudaFuncSetAttribute(k_cmma<128,256,32,256,3>, cudaFuncAttributeMaxDynamicSharedMemorySize, MMA_SMEM);

  // prep
  k_wt<<<288,256>>>(W2,wtf2,wtb2,64,128);
  k_wt<<<1152,256>>>(W3,wtf3,wtb3,128,256);
  k_gvec<<<1024,256>>>(We,Wc,gvec);
  // pass 1 (3xTF32: fp32-accurate, argsort-safe)
  k_conv_fwd<1,64,128,1024,1,16,4,256><<<dim3(8,64,32),256>>>(x,W1,b1,h1);
  k_cmma<64,128,64,512,3><<<dim3(2,32,32),256,MMA_SMEM>>>(h1,wtf2,b2,h2);
  k_cmma<128,256,32,256,3><<<dim3(2,16,32),256,MMA_SMEM>>>(h2,wtf3,b3,h3);
  run_tail(h3,Wa,ba,va,attp,att,alpha,mu,m2);
  // backward to input (3xTF32 mma transposed convs)
  k_dcoef<<<512,256>>>(mu,m2,gvec,dMu,dE2);
  k_dalp<<<dim3(8,32),128>>>(h3,dMu,dE2,dap);
  k_dalf<<<32,128>>>(dap,alpha,ds);
  k_dz<<<2048,256>>>(att,ds,va,dz);
  k_dfeat<<<dim3(32,32),256>>>(Wa,dz,h3,alpha,dMu,dE2,d3);
  k_cbmma<128,256,16,128,128,3><<<dim3(2,32,32),256>>>(d3,wtb3,h2,d2);
  k_cbmma<64,128,32,256,256,3><<<dim3(2,64,32),256>>>(d2,wtb2,h1,d1);
  k_bwd1<<<dim3(2,128,32),256>>>(d1,W1,fam);
  // masking
  k_rowstats<<<512,256>>>(fam,x,cm,meanT);
  k_colstats<<<128,256>>>(fam,x,tm,meanF);
  k_sort<128><<<32,64>>>(cm,sc);
  k_sort<1024><<<32,512>>>(tm,st);
  k_rfm<<<1,32>>>(sc,st,mask_t,s_t,is_train,rstep,cstep);
  k_apply<<<16384,256>>>(x,rstep,cstep,meanT,meanF,xm);
  // pass 2 (single tf32: continuous output path)
  k_conv_fwd<1,64,128,1024,1,16,4,256><<<dim3(8,64,32),256>>>(xm,W1,b1,h1);
  k_cmma<64,128,64,512,1><<<dim3(2,32,32),256,MMA_SMEM>>>(h1,wtf2,b2,h2);
  k_cmma<128,256,32,256,1><<<dim3(2,16,32),256,MMA_SMEM>>>(h2,wtf3,b3,h3);
  run_tail(h3,Wa,ba,va,attp,att,alpha,mu,m2);
  k_cat<<<512,256>>>(mu,m2,cat);
  k_embp<<<128,256>>>(cat,We,ep);
  k_embf<<<32,256>>>(ep,be,Wc,bc,out);
}

// round 8
// speedup vs baseline: 2.9118x; 1.0088x over previous
#include <cuda_runtime.h>
#include <math.h>

// ---------- static scratch ----------
__device__ float g_h1[67108864];
__device__ float g_h2[33554432];
__device__ float g_h3[16777216];
__device__ float g_d1[67108864];
__device__ float g_d2[33554432];
__device__ float g_d3[16777216];
__device__ float g_fam[4194304];
__device__ float g_xm[4194304];
__device__ float g_att[524288];
__device__ float g_attp[4194304];
__device__ float g_dzb[524288];
__device__ float g_alpha[4096];
__device__ float g_dsb[4096];
__device__ float g_dap[32768];
__device__ float g_mu[131072];
__device__ float g_m2[131072];
__device__ float g_dMu[131072];
__device__ float g_dE2[131072];
__device__ float g_gvec[8192];
__device__ float g_cat[262144];
__device__ float g_ep[1048576];
__device__ float g_cm[4096];
__device__ float g_tm[32768];
__device__ float g_meanT[4096];
__device__ float g_meanF[32768];
__device__ int   g_sc[4096];
__device__ int   g_st[4096];
__device__ int   g_rstep[4096];
__device__ int   g_cstep[32768];
__device__ float g_wtf2[73728];
__device__ float g_wtb2[73728];
__device__ float g_wtf3[294912];
__device__ float g_wtb3[294912];

// ---------- weight transposes ----------
__global__ void k_wt(const float* __restrict__ W, float* __restrict__ WTf,
                     float* __restrict__ WTb, int CIN, int COUT)
{
  int idx=blockIdx.x*256+threadIdx.x;
  int tot=CIN*COUT*9; if(idx>=tot) return;
  int k=idx%9, c=(idx/9)%CIN, o=idx/(9*CIN);
  float v=W[idx];
  int rf=(c>>3)*72 + k*8 + (c&7);
  WTf[(long)rf*COUT+o]=v;
  int rb=(o>>3)*72 + k*8 + (o&7);
  WTb[(long)rb*CIN+c]=v;
}

// ---------- conv1 fwd (CIN=1) ----------
template<int CIN,int COUT,int HIN,int WIN,int CC,int OG,int OP,int THREADS>
__global__ void __launch_bounds__(THREADS) k_conv_fwd(
    const float* __restrict__ in, const float* __restrict__ W,
    const float* __restrict__ bias, float* __restrict__ out)
{
  constexpr int HOUT=HIN/2, WOUT=WIN/2;
  __shared__ float ins[CC*3*130];
  __shared__ float ws[CC*9*COUT];
  const int n=blockIdx.z, i=blockIdx.y, j0=blockIdx.x*64;
  const int tid=threadIdx.x, og=tid%OG, jt=tid/OG;
  float acc[OP][4];
#pragma unroll
  for(int o=0;o<OP;o++){acc[o][0]=acc[o][1]=acc[o][2]=acc[o][3]=0.f;}
  for(int c0=0;c0<CIN;c0+=CC){
    __syncthreads();
    for(int idx=tid; idx<CC*3*130; idx+=THREADS){
      int c=idx/390, r=(idx/130)%3, col=idx%130;
      int gx=2*i+r, gy=2*j0+col;
      float v=0.f;
      if(gx<HIN && gy<WIN) v=in[(((long)n*CIN+c0+c)*HIN+gx)*WIN+gy];
      ins[idx]=v;
    }
    for(int idx=tid; idx<COUT*CC*9; idx+=THREADS){
      int o=idx/(CC*9), rem=idx%(CC*9);
      ws[rem*COUT+o]=W[(long)o*CIN*9 + c0*9 + rem];
    }
    __syncthreads();
#pragma unroll
    for(int c=0;c<CC;c++)
#pragma unroll
    for(int r=0;r<3;r++){
      float v[9];
#pragma unroll
      for(int m=0;m<9;m++) v[m]=ins[(c*3+r)*130 + 8*jt + m];
#pragma unroll
      for(int kj=0;kj<3;kj++)
#pragma unroll
      for(int oo=0;oo<OP;oo++){
        float w=ws[(c*9+r*3+kj)*COUT + og + OG*oo];
        acc[oo][0]+=w*v[kj];   acc[oo][1]+=w*v[2+kj];
        acc[oo][2]+=w*v[4+kj]; acc[oo][3]+=w*v[6+kj];
      }
    }
  }
  int j=j0+4*jt;
#pragma unroll
  for(int oo=0;oo<OP;oo++){
    int o=og+OG*oo; float bb=bias[o];
    float4 r;
    r.x=fmaxf(acc[oo][0]+bb,0.f); r.y=fmaxf(acc[oo][1]+bb,0.f);
    r.z=fmaxf(acc[oo][2]+bb,0.f); r.w=fmaxf(acc[oo][3]+bb,0.f);
    *(float4*)&out[(((long)n*COUT+o)*HOUT+i)*WOUT+j]=r;
  }
}

// ---------- tf32 helpers ----------
__device__ __forceinline__ float to_tf32(float v){
  unsigned r; asm("cvt.rna.tf32.f32 %0, %1;" : "=r"(r) : "f"(v));
  return __uint_as_float(r);
}
__device__ __forceinline__ void mma_tf32(float* c4,
    unsigned a0,unsigned a1,unsigned a2,unsigned a3,unsigned b0,unsigned b1){
  asm volatile(
    "mma.sync.aligned.m16n8k8.row.col.f32.tf32.tf32.f32 "
    "{%0,%1,%2,%3},{%4,%5,%6,%7},{%8,%9},{%0,%1,%2,%3};"
    : "+f"(c4[0]),"+f"(c4[1]),"+f"(c4[2]),"+f"(c4[3])
    : "r"(a0),"r"(a1),"r"(a2),"r"(a3),"r"(b0),"r"(b1));
}

// ---------- tf32 mma conv fwd ----------
template<int CIN,int COUT,int HIN,int WIN,int SPLIT>
__global__ void __launch_bounds__(256,2) k_cmma(
    const float* __restrict__ in, const float* __restrict__ WT,
    const float* __restrict__ bias, float* __restrict__ out)
{
  constexpr int HOUT=HIN/2, WOUT=WIN/2;
  constexpr int NJT=WOUT/128;
  constexpr int LD=136;
  extern __shared__ float sm[];
  float* ev = sm;
  float* od = sm + 24*LD;
  float* ws = sm + 48*LD;
  const int n=blockIdx.z, i=blockIdx.y;
  const int jt_=blockIdx.x%NJT, ot=blockIdx.x/NJT;
  const int j0=jt_*128, o0=ot*128;
  const int tid=threadIdx.x, wid=tid>>5, lane=tid&31;
  const int gid=lane>>2, tig=lane&3;
  const int m0=(wid&3)*32, n0w=(wid>>2)*64;
  float acc[2][8][4];
#pragma unroll
  for(int a=0;a<2;a++)
#pragma unroll
  for(int b=0;b<8;b++)
#pragma unroll
  for(int c=0;c<4;c++) acc[a][b][c]=0.f;

  for(int c0=0;c0<CIN;c0+=8){
    __syncthreads();
    for(int idx=tid; idx<8*3*129; idx+=256){
      int c=idx/387, rem=idx%387, r=rem/129, p=rem%129;
      int gx=2*i+r, gy=2*j0+2*p;
      float a=0.f,bv=0.f;
      if(gx<HIN && gy<WIN){
        const float2 s=*(const float2*)&in[(((long)n*CIN+c0+c)*HIN+gx)*WIN+gy];
        a=s.x; bv=s.y;
      }
      ev[(c*3+r)*LD+p]=a;
      od[(c*3+r)*LD+p]=bv;
    }
    {
      const float* wsrc = WT + (long)(c0>>3)*72*COUT + o0;
      for(int idx=tid; idx<72*32; idx+=256){
        int kk=idx>>5, o4=(idx&31)*4;
        float4 v=*(const float4*)&wsrc[(long)kk*COUT + o4];
        *(float4*)&ws[kk*LD + o4]=v;
      }
    }
    __syncthreads();
#pragma unroll
    for(int kc=0;kc<9;kc++){
      const int r=kc/3, kj=kc%3;
      const float* src = (kj==1)? od : ev;
      const int co = (kj==2)? 1:0;
      unsigned bh[8][2], bl[8][2];
#pragma unroll
      for(int f=0;f<8;f++){
        float v0 = src[(tig*3+r)*LD + n0w + f*8 + gid + co];
        float v1 = src[((tig+4)*3+r)*LD + n0w + f*8 + gid + co];
        float h0=to_tf32(v0), h1=to_tf32(v1);
        bh[f][0]=__float_as_uint(h0); bh[f][1]=__float_as_uint(h1);
        if(SPLIT==3){
          bl[f][0]=__float_as_uint(to_tf32(v0-h0));
          bl[f][1]=__float_as_uint(to_tf32(v1-h1));
        }
      }
#pragma unroll
      for(int mf=0;mf<2;mf++){
        float w0=ws[(kc*8+tig)*LD + m0+mf*16+gid];
        float w1=ws[(kc*8+tig)*LD + m0+mf*16+gid+8];
        float w2=ws[(kc*8+tig+4)*LD + m0+mf*16+gid];
        float w3=ws[(kc*8+tig+4)*LD + m0+mf*16+gid+8];
        float h0=to_tf32(w0),h1=to_tf32(w1),h2=to_tf32(w2),h3=to_tf32(w3);
        unsigned ah0=__float_as_uint(h0),ah1=__float_as_uint(h1),
                 ah2=__float_as_uint(h2),ah3=__float_as_uint(h3);
        unsigned al0=0,al1=0,al2=0,al3=0;
        if(SPLIT==3){
          al0=__float_as_uint(to_tf32(w0-h0)); al1=__float_as_uint(to_tf32(w1-h1));
          al2=__float_as_uint(to_tf32(w2-h2)); al3=__float_as_uint(to_tf32(w3-h3));
        }
#pragma unroll
        for(int f=0;f<8;f++){
          mma_tf32(acc[mf][f], ah0,ah1,ah2,ah3, bh[f][0],bh[f][1]);
          if(SPLIT==3){
            mma_tf32(acc[mf][f], ah0,ah1,ah2,ah3, bl[f][0],bl[f][1]);
            mma_tf32(acc[mf][f], al0,al1,al2,al3, bh[f][0],bh[f][1]);
          }
        }
      }
    }
  }
#pragma unroll
  for(int mf=0;mf<2;mf++){
    int oA=o0+m0+mf*16+gid, oB=oA+8;
    float bA=bias[oA], bB=bias[oB];
#pragma unroll
    for(int f=0;f<8;f++){
      int jj=j0 + n0w + f*8 + tig*2;
      long baseA=(((long)n*COUT+oA)*HOUT+i)*WOUT + jj;
      long baseB=(((long)n*COUT+oB)*HOUT+i)*WOUT + jj;
      float2 rA, rB;
      rA.x=fmaxf(acc[mf][f][0]+bA,0.f); rA.y=fmaxf(acc[mf][f][1]+bA,0.f);
      rB.x=fmaxf(acc[mf][f][2]+bB,0.f); rB.y=fmaxf(acc[mf][f][3]+bB,0.f);
      *(float2*)&out[baseA]=rA;
      *(float2*)&out[baseB]=rB;
    }
  }
}

// ---------- tf32 mma transposed-conv bwd ----------
template<int CIN,int COUT,int HOUT,int WOUT,int NT,int SPLIT>
__global__ void __launch_bounds__(256,2) k_cbmma(
    const float* __restrict__ dout, const float* __restrict__ WT,
    const float* __restrict__ act, float* __restrict__ din)
{
  constexpr int HIN=2*HOUT, WIN=2*WOUT;
  constexpr int LDW=CIN+8, LDD=NT/2+4, JL=NT/2+2;
  constexpr int NW_M=CIN/32;
  __shared__ float ws[72*LDW];
  __shared__ float dsA[8*LDD];
  __shared__ float dsB[8*LDD];
  const int n=blockIdx.z, x=blockIdx.y, y0=blockIdx.x*NT;
  const int tid=threadIdx.x, wid=tid>>5, lane=tid&31;
  const int gid=lane>>2, tig=lane&3;
  const int m0=(wid%NW_M)*32, n0=(wid/NW_M)*64;
  const bool xe=((x&1)==0);
  const int iA = xe ? (x>>1) : ((x-1)>>1);
  const int iB = (x>>1)-1;
  const bool hasB = xe && iB>=0;
  const int jb = y0/2 - 1;
  float acc_e[2][4][4], acc_o[2][4][4];
#pragma unroll
  for(int a=0;a<2;a++)
#pragma unroll
  for(int b=0;b<4;b++)
#pragma unroll
  for(int c=0;c<4;c++){acc_e[a][b][c]=0.f; acc_o[a][b][c]=0.f;}

  for(int o0=0;o0<COUT;o0+=8){
    __syncthreads();
    {
      const float* wsrc = WT + (long)(o0>>3)*72*CIN;
      for(int idx=tid; idx<72*(CIN/4); idx+=256){
        int r=idx/(CIN/4), c4=(idx%(CIN/4))*4;
        float4 v=*(const float4*)&wsrc[(long)r*CIN+c4];
        *(float4*)&ws[r*LDW+c4]=v;
      }
    }
    for(int idx=tid; idx<8*JL; idx+=256){
      int o=idx/JL, jl=idx%JL; int j=jb+jl;
      float a=0.f,bv=0.f;
      if(j>=0 && j<WOUT){
        long base=((long)n*COUT+o0+o)*HOUT;
        a = dout[(base+iA)*WOUT+j];
        if(hasB) bv = dout[(base+iB)*WOUT+j];
      }
      dsA[o*LDD+jl]=a; dsB[o*LDD+jl]=bv;
    }
    __syncthreads();

    auto proc = [&](const float* ds, const int tapBase){
      unsigned b1h[4][2], b0h[4][2], b1l[4][2], b0l[4][2];
#pragma unroll
      for(int f=0;f<4;f++){
        int cbase = n0/2 + f*8 + gid;
        float v1a = ds[tig*LDD + cbase + 1];
        float v1b = ds[(tig+4)*LDD + cbase + 1];
        float v0a = ds[tig*LDD + cbase];
        float v0b = ds[(tig+4)*LDD + cbase];
        float h1a=to_tf32(v1a), h1b=to_tf32(v1b);
        float h0a=to_tf32(v0a), h0b=to_tf32(v0b);
        b1h[f][0]=__float_as_uint(h1a); b1h[f][1]=__float_as_uint(h1b);
        b0h[f][0]=__float_as_uint(h0a); b0h[f][1]=__float_as_uint(h0b);
        if(SPLIT==3){
          b1l[f][0]=__float_as_uint(to_tf32(v1a-h1a));
          b1l[f][1]=__float_as_uint(to_tf32(v1b-h1b));
          b0l[f][0]=__float_as_uint(to_tf32(v0a-h0a));
          b0l[f][1]=__float_as_uint(to_tf32(v0b-h0b));
        }
      }
#pragma unroll
      for(int kj=0;kj<3;kj++){
        const int tap=tapBase+kj;
#pragma unroll
        for(int mf=0;mf<2;mf++){
          float w0=ws[(tap*8+tig)*LDW + m0+mf*16+gid];
          float w1=ws[(tap*8+tig)*LDW + m0+mf*16+gid+8];
          float w2=ws[(tap*8+tig+4)*LDW + m0+mf*16+gid];
          float w3=ws[(tap*8+tig+4)*LDW + m0+mf*16+gid+8];
          float h0=to_tf32(w0),h1=to_tf32(w1),h2=to_tf32(w2),h3=to_tf32(w3);
          unsigned ah0=__float_as_uint(h0),ah1=__float_as_uint(h1),
                   ah2=__float_as_uint(h2),ah3=__float_as_uint(h3);
          unsigned al0=0,al1=0,al2=0,al3=0;
          if(SPLIT==3){
            al0=__float_as_uint(to_tf32(w0-h0)); al1=__float_as_uint(to_tf32(w1-h1));
            al2=__float_as_uint(to_tf32(w2-h2)); al3=__float_as_uint(to_tf32(w3-h3));
          }
#pragma unroll
          for(int f=0;f<4;f++){
            float* c4 = (kj==1)? acc_o[mf][f] : acc_e[mf][f];
            const unsigned* bh = (kj==2)? b0h[f] : b1h[f];
            const unsigned* bl = (kj==2)? b0l[f] : b1l[f];
            mma_tf32(c4, ah0,ah1,ah2,ah3, bh[0],bh[1]);
            if(SPLIT==3){
              mma_tf32(c4, ah0,ah1,ah2,ah3, bl[0],bl[1]);
              mma_tf32(c4, al0,al1,al2,al3, bh[0],bh[1]);
            }
          }
        }
      }
    };
    proc(dsA, xe?0:3);
    if(hasB) proc(dsB, 6);
  }

#pragma unroll
  for(int mf=0;mf<2;mf++){
    int c0_=m0+mf*16+gid;
#pragma unroll
    for(int f=0;f<4;f++){
      int Y = y0 + n0 + 2*(f*8 + 2*tig);
      long b0i=(((long)n*CIN+c0_)*HIN+x)*WIN + Y;
      long b1i=(((long)n*CIN+c0_+8)*HIN+x)*WIN + Y;
      float2 m, r;
      m=*(const float2*)&act[b0i];
      r.x = m.x>0.f? acc_e[mf][f][0]:0.f; r.y = m.y>0.f? acc_o[mf][f][0]:0.f;
      *(float2*)&din[b0i]=r;
      m=*(const float2*)&act[b0i+2];
      r.x = m.x>0.f? acc_e[mf][f][1]:0.f; r.y = m.y>0.f? acc_o[mf][f][1]:0.f;
      *(float2*)&din[b0i+2]=r;
      m=*(const float2*)&act[b1i];
      r.x = m.x>0.f? acc_e[mf][f][2]:0.f; r.y = m.y>0.f? acc_o[mf][f][2]:0.f;
      *(float2*)&din[b1i]=r;
      m=*(const float2*)&act[b1i+2];
      r.x = m.x>0.f? acc_e[mf][f][3]:0.f; r.y = m.y>0.f? acc_o[mf][f][3]:0.f;
      *(float2*)&din[b1i+2]=r;
    }
  }
}

// ---------- conv1 data-grad -> |dx| ----------
__global__ void __launch_bounds__(256) k_bwd1(
    const float* __restrict__ dz1, const float* __restrict__ W1,
    float* __restrict__ fam)
{
  __shared__ float ws[576];
  __shared__ float dsm[8*2*260];
  const int n=blockIdx.z, x=blockIdx.y, y0=blockIdx.x*512;
  const int tid=threadIdx.x;
  for(int idx=tid; idx<576; idx+=256) ws[idx]=W1[idx];
  int iA,iB,kiA,kiB; bool hasB;
  if((x&1)==0){iA=x>>1;kiA=0;iB=iA-1;kiB=2;hasB=(iB>=0);}
  else{iA=(x-1)>>1;kiA=1;iB=0;kiB=0;hasB=false;}
  const int jbase=y0/2-1;
  float accE=0.f, accO=0.f;
  for(int o0=0;o0<64;o0+=8){
    __syncthreads();
    for(int idx=tid; idx<8*2*260; idx+=256){
      int o=idx/520, rs=(idx/260)&1, jj=idx%260;
      int j=jbase+jj; int ir=rs?iB:iA;
      float v=0.f;
      if(j>=0 && j<512 && (rs==0||hasB))
        v=dz1[(((long)n*64+o0+o)*64+ir)*512+j];
      dsm[idx]=v;
    }
    __syncthreads();
#pragma unroll
    for(int o=0;o<8;o++){
#pragma unroll
      for(int rs=0;rs<2;rs++){
        if(rs==1&&!hasB) break;
        int ki=rs?kiB:kiA;
        const float* wb=&ws[(o0+o)*9+ki*3];
        float vm=dsm[(o*2+rs)*260+tid], v0=dsm[(o*2+rs)*260+tid+1];
        accE+=wb[0]*v0+wb[2]*vm; accO+=wb[1]*v0;
      }
    }
  }
  long base=((long)n*128+x)*1024 + y0 + 2*tid;
  fam[base]=fabsf(accE); fam[base+1]=fabsf(accO);
}

// ---------- att partial GEMM (tf32 mma, split-K) ----------
template<int SPLIT>
__global__ void __launch_bounds__(256) k_attp_mma(
    const float* __restrict__ Wa, const float* __restrict__ feat,
    float* __restrict__ attp)
{
  constexpr int LDA=129, LDB=132;
  __shared__ float As[32*LDA];   // [k][h]
  __shared__ float Bs[32*LDB];   // [k][t]
  const int ks=blockIdx.x, b=blockIdx.y;
  const int tid=threadIdx.x, wid=tid>>5, lane=tid&31;
  const int gid=lane>>2, tig=lane&3;
  const int m0=(wid&3)*32, n0=(wid>>2)*64;
  const float* fb = feat + (long)b*524288;
  float acc[2][8][4];
#pragma unroll
  for(int a=0;a<2;a++)
#pragma unroll
  for(int bq=0;bq<8;bq++)
#pragma unroll
  for(int c=0;c<4;c++) acc[a][bq][c]=0.f;

  for(int k0=ks*512; k0<ks*512+512; k0+=32){
    __syncthreads();
    for(int idx=tid; idx<4096; idx+=256){
      int h=idx>>5, kk=idx&31;
      As[kk*LDA+h]=Wa[(long)h*4096+k0+kk];
    }
    for(int idx=tid; idx<4096; idx+=256){
      int kk=idx>>7, t=idx&127;
      Bs[kk*LDB+t]=fb[(long)(k0+kk)*128+t];
    }
    __syncthreads();
#pragma unroll
    for(int kc=0;kc<4;kc++){
      const int kb=kc*8;
      unsigned bh[8][2], bl[8][2];
#pragma unroll
      for(int f=0;f<8;f++){
        float v0=Bs[(kb+tig)*LDB + n0+f*8+gid];
        float v1=Bs[(kb+tig+4)*LDB + n0+f*8+gid];
        float h0=to_tf32(v0), h1=to_tf32(v1);
        bh[f][0]=__float_as_uint(h0); bh[f][1]=__float_as_uint(h1);
        if(SPLIT==3){
          bl[f][0]=__float_as_uint(to_tf32(v0-h0));
          bl[f][1]=__float_as_uint(to_tf32(v1-h1));
        }
      }
#pragma unroll
      for(int mf=0;mf<2;mf++){
        float w0=As[(kb+tig)*LDA + m0+mf*16+gid];
        float w1=As[(kb+tig)*LDA + m0+mf*16+gid+8];
        float w2=As[(kb+tig+4)*LDA + m0+mf*16+gid];
        float w3=As[(kb+tig+4)*LDA + m0+mf*16+gid+8];
        float h0=to_tf32(w0),h1=to_tf32(w1),h2=to_tf32(w2),h3=to_tf32(w3);
        unsigned ah0=__float_as_uint(h0),ah1=__float_as_uint(h1),
                 ah2=__float_as_uint(h2),ah3=__float_as_uint(h3);
        unsigned al0=0,al1=0,al2=0,al3=0;
        if(SPLIT==3){
          al0=__float_as_uint(to_tf32(w0-h0)); al1=__float_as_uint(to_tf32(w1-h1));
          al2=__float_as_uint(to_tf32(w2-h2)); al3=__float_as_uint(to_tf32(w3-h3));
        }
#pragma unroll
        for(int f=0;f<8;f++){
          mma_tf32(acc[mf][f], ah0,ah1,ah2,ah3, bh[f][0],bh[f][1]);
          if(SPLIT==3){
            mma_tf32(acc[mf][f], ah0,ah1,ah2,ah3, bl[f][0],bl[f][1]);
            mma_tf32(acc[mf][f], al0,al1,al2,al3, bh[f][0],bh[f][1]);
          }
        }
      }
    }
  }
#pragma unroll
  for(int mf=0;mf<2;mf++){
    int hA=m0+mf*16+gid, hB=hA+8;
#pragma unroll
    for(int f=0;f<8;f++){
      int t=n0+f*8+tig*2;
      float2 rA, rB;
      rA.x=acc[mf][f][0]; rA.y=acc[mf][f][1];
      rB.x=acc[mf][f][2]; rB.y=acc[mf][f][3];
      *(float2*)&attp[(long)ks*524288 + ((long)b*128+hA)*128+t]=rA;
      *(float2*)&attp[(long)ks*524288 + ((long)b*128+hB)*128+t]=rB;
    }
  }
}
__global__ void k_attf(const float* __restrict__ attp, const float* __restrict__ ba,
                       float* __restrict__ att)
{
  int i=blockIdx.x*256+threadIdx.x; if(i>=524288) return;
  int h=(i>>7)&127;
  float s=0.f;
#pragma unroll
  for(int ks=0;ks<8;ks++) s+=attp[(long)ks*524288+i];
  att[i]=tanhf(s+ba[h]);
}

// ---------- softmax ----------
__global__ void __launch_bounds__(128) k_salpha(
    const float* __restrict__ att, const float* __restrict__ va,
    float* __restrict__ alpha)
{
  __shared__ float vs[128], buf[128];
  const int b=blockIdx.x, t=threadIdx.x;
  vs[t]=va[t];
  __syncthreads();
  float s=0.f;
#pragma unroll 4
  for(int h=0;h<128;h++) s+=vs[h]*att[((long)b*128+h)*128+t];
  buf[t]=s; __syncthreads();
  for(int off=64;off;off>>=1){ if(t<off) buf[t]=fmaxf(buf[t],buf[t+off]); __syncthreads(); }
  float mx=buf[0]; __syncthreads();
  float e=expf(s-mx);
  buf[t]=e; __syncthreads();
  for(int off=64;off;off>>=1){ if(t<off) buf[t]+=buf[t+off]; __syncthreads(); }
  alpha[b*128+t]=e/buf[0];
}

// ---------- mu, m2 ----------
__global__ void k_mustats(const float* __restrict__ feat,
    const float* __restrict__ alpha, float* __restrict__ mu, float* __restrict__ m2)
{
  int w=(blockIdx.x*blockDim.x+threadIdx.x)>>5, lane=threadIdx.x&31;
  if(w>=131072) return;
  int b=w>>12;
  const float* fr=feat+(long)w*128;
  const float* ar=alpha+b*128;
  float s1=0.f,s2=0.f;
#pragma unroll
  for(int t=lane;t<128;t+=32){
    float a=ar[t], f=fr[t];
    s1+=a*f; s2+=a*f*f;
  }
  for(int o=16;o;o>>=1){ s1+=__shfl_down_sync(~0u,s1,o); s2+=__shfl_down_sync(~0u,s2,o); }
  if(!lane){ mu[w]=s1; m2[w]=s2; }
}

// ---------- gvec ----------
__global__ void k_gvec(const float* __restrict__ We,const float* __restrict__ Wc,
                       float* __restrict__ gvec)
{
  int w=(blockIdx.x*blockDim.x+threadIdx.x)>>5, lane=threadIdx.x&31;
  if(w>=8192) return;
  float s=0.f;
  for(int j=lane;j<256;j+=32) s+=We[(long)w*256+j]*(Wc[j*2+1]-Wc[j*2]);
  for(int o=16;o;o>>=1) s+=__shfl_down_sync(~0u,s,o);
  if(!lane) gvec[w]=s;
}

// ---------- dMu,dE2 ----------
__global__ void k_dcoef(const float* __restrict__ mu,const float* __restrict__ m2,
    const float* __restrict__ gvec, float* __restrict__ dMu,float* __restrict__ dE2)
{
  int i=blockIdx.x*256+threadIdx.x; if(i>=131072) return;
  int d=i&4095;
  float m=mu[i], v=m2[i]-m*m;
  float g2=gvec[4096+d];
  float dE=0.f, dM=gvec[d];
  if(v>1e-5f){ float sg=sqrtf(v); dE=0.5f*g2/sg; dM-=g2*m/sg; }
  dMu[i]=dM; dE2[i]=dE;
}

// ---------- dalpha ----------
__global__ void __launch_bounds__(128) k_dalp(
    const float* __restrict__ feat,const float* __restrict__ dMu,
    const float* __restrict__ dE2,float* __restrict__ part)
{
  const int ks=blockIdx.x, b=blockIdx.y, t=threadIdx.x;
  const float* fb=feat+(long)b*524288;
  const float* dm=dMu+b*4096; const float* de=dE2+b*4096;
  float acc=0.f;
  int d0=ks*512;
#pragma unroll 4
  for(int d=d0;d<d0+512;d++){
    float f=fb[(long)d*128+t];
    acc+=dm[d]*f+de[d]*f*f;
  }
  part[(ks*32+b)*128+t]=acc;
}
__global__ void __launch_bounds__(128) k_dalf(
    const float* __restrict__ part,const float* __restrict__ alpha,
    float* __restrict__ ds)
{
  const int b=blockIdx.x, t=threadIdx.x;
  float acc=0.f;
#pragma unroll
  for(int ks=0;ks<8;ks++) acc+=part[(ks*32+b)*128+t];
  __shared__ float buf[128];
  float a=alpha[b*128+t];
  buf[t]=a*acc; __syncthreads();
  for(int off=64;off;off>>=1){ if(t<off) buf[t]+=buf[t+off]; __syncthreads(); }
  ds[b*128+t]=a*(acc-buf[0]);
}

// ---------- dz ----------
__global__ void k_dz(const float* __restrict__ att,const float* __restrict__ ds,
    const float* __restrict__ va,float* __restrict__ dz)
{
  int i=blockIdx.x*256+threadIdx.x; if(i>=524288) return;
  int t=i&127, h=(i>>7)&127, b=i>>14;
  float a=att[i];
  dz[i]=va[h]*ds[b*128+t]*(1.f-a*a);
}

// ---------- dfeat (tf32 mma, SPLIT=3) + fused pointwise/mask epilogue ----------
template<int SPLIT>
__global__ void __launch_bounds__(256) k_dfeat_mma(
    const float* __restrict__ Wa, const float* __restrict__ dz,
    const float* __restrict__ feat, const float* __restrict__ alpha,
    const float* __restrict__ dMu, const float* __restrict__ dE2,
    float* __restrict__ dout3)
{
  constexpr int LDA=132, LDB=132;
  __shared__ float As[32*LDA];  // [k][d]
  __shared__ float Bs[32*LDB];  // [k][t]
  __shared__ float al[128];
  const int d0=blockIdx.x*128, b=blockIdx.y;
  const int tid=threadIdx.x, wid=tid>>5, lane=tid&31;
  const int gid=lane>>2, tig=lane&3;
  const int m0=(wid&3)*32, n0=(wid>>2)*64;
  if(tid<128) al[tid]=alpha[b*128+tid];
  float acc[2][8][4];
#pragma unroll
  for(int a=0;a<2;a++)
#pragma unroll
  for(int bq=0;bq<8;bq++)
#pragma unroll
  for(int c=0;c<4;c++) acc[a][bq][c]=0.f;

  for(int k0=0;k0<128;k0+=32){
    __syncthreads();
    for(int idx=tid; idx<4096; idx+=256){
      int kk=idx>>7, dd=idx&127;
      As[kk*LDA+dd]=Wa[(long)(k0+kk)*4096+d0+dd];
    }
    for(int idx=tid; idx<4096; idx+=256){
      int kk=idx>>7, t=idx&127;
      Bs[kk*LDB+t]=dz[((long)b*128+k0+kk)*128+t];
    }
    __syncthreads();
#pragma unroll
    for(int kc=0;kc<4;kc++){
      const int kb=kc*8;
      unsigned bh[8][2], bl[8][2];
#pragma unroll
      for(int f=0;f<8;f++){
        float v0=Bs[(kb+tig)*LDB + n0+f*8+gid];
        float v1=Bs[(kb+tig+4)*LDB + n0+f*8+gid];
        float h0=to_tf32(v0), h1=to_tf32(v1);
        bh[f][0]=__float_as_uint(h0); bh[f][1]=__float_as_uint(h1);
        if(SPLIT==3){
          bl[f][0]=__float_as_uint(to_tf32(v0-h0));
          bl[f][1]=__float_as_uint(to_tf32(v1-h1));
        }
      }
#pragma unroll
      for(int mf=0;mf<2;mf++){
        float w0=As[(kb+tig)*LDA + m0+mf*16+gid];
        float w1=As[(kb+tig)*LDA + m0+mf*16+gid+8];
        float w2=As[(kb+tig+4)*LDA + m0+mf*16+gid];
        float w3=As[(kb+tig+4)*LDA + m0+mf*16+gid+8];
        float h0=to_tf32(w0),h1=to_tf32(w1),h2=to_tf32(w2),h3=to_tf32(w3);
        unsigned ah0=__float_as_uint(h0),ah1=__float_as_uint(h1),
                 ah2=__float_as_uint(h2),ah3=__float_as_uint(h3);
        unsigned al0=0,al1=0,al2=0,al3=0;
        if(SPLIT==3){
          al0=__float_as_uint(to_tf32(w0-h0)); al1=__float_as_uint(to_tf32(w1-h1));
          al2=__float_as_uint(to_tf32(w2-h2)); al3=__float_as_uint(to_tf32(w3-h3));
        }
#pragma unroll
        for(int f=0;f<8;f++){
          mma_tf32(acc[mf][f], ah0,ah1,ah2,ah3, bh[f][0],bh[f][1]);
          if(SPLIT==3){
            mma_tf32(acc[mf][f], ah0,ah1,ah2,ah3, bl[f][0],bl[f][1]);
            mma_tf32(acc[mf][f], al0,al1,al2,al3, bh[f][0],bh[f][1]);
          }
        }
      }
    }
  }
#pragma unroll
  for(int mf=0;mf<2;mf++){
    int dA=d0+m0+mf*16+gid, dB=dA+8;
    float dmA=dMu[(long)b*4096+dA], deA=dE2[(long)b*4096+dA];
    float dmB=dMu[(long)b*4096+dB], deB=dE2[(long)b*4096+dB];
#pragma unroll
    for(int f=0;f<8;f++){
      int t=n0+f*8+tig*2;
      long fiA=((long)b*4096+dA)*128+t;
      long fiB=((long)b*4096+dB)*128+t;
      float2 fvA=*(const float2*)&feat[fiA];
      float2 fvB=*(const float2*)&feat[fiB];
      float2 rA, rB;
      rA.x = fvA.x>0.f? (acc[mf][f][0]+al[t]*(dmA+2.f*deA*fvA.x)) : 0.f;
      rA.y = fvA.y>0.f? (acc[mf][f][1]+al[t+1]*(dmA+2.f*deA*fvA.y)) : 0.f;
      rB.x = fvB.x>0.f? (acc[mf][f][2]+al[t]*(dmB+2.f*deB*fvB.x)) : 0.f;
      rB.y = fvB.y>0.f? (acc[mf][f][3]+al[t+1]*(dmB+2.f*deB*fvB.y)) : 0.f;
      *(float2*)&dout3[fiA]=rA;
      *(float2*)&dout3[fiB]=rB;
    }
  }
}

// ---------- row/col stats ----------
__global__ void k_rowstats(const float* __restrict__ fam,const float* __restrict__ x,
    float* __restrict__ cm,float* __restrict__ meanT)
{
  int w=(blockIdx.x*blockDim.x+threadIdx.x)>>5, lane=threadIdx.x&31;
  if(w>=4096) return;
  const float* fr=fam+(long)w*1024; const float* xr=x+(long)w*1024;
  float m=-1e30f, s=0.f;
  for(int t=lane;t<1024;t+=32){ m=fmaxf(m,fr[t]); s+=xr[t]; }
  for(int o=16;o;o>>=1){ m=fmaxf(m,__shfl_down_sync(~0u,m,o)); s+=__shfl_down_sync(~0u,s,o); }
  if(!lane){ cm[w]=m; meanT[w]=s*(1.f/1024.f); }
}
__global__ void k_colstats(const float* __restrict__ fam,const float* __restrict__ x,
    float* __restrict__ tm,float* __restrict__ meanF)
{
  int i=blockIdx.x*256+threadIdx.x; if(i>=32768) return;
  int b=i>>10, t=i&1023;
  const float* fb=fam+(long)b*131072+t; const float* xb=x+(long)b*131072+t;
  float m=-1e30f, s=0.f;
#pragma unroll 4
  for(int f=0;f<128;f++){ m=fmaxf(m,fb[f*1024]); s+=xb[f*1024]; }
  tm[i]=m; meanF[i]=s*(1.f/128.f);
}

// ---------- bitonic argsort ----------
template<int N>
__global__ void k_sort(const float* __restrict__ vals, int* __restrict__ idxout)
{
  __shared__ unsigned long long key[N];
  const int b=blockIdx.x, tid=threadIdx.x, TH=N/2;
  for(int i=tid;i<N;i+=TH){
    unsigned u=__float_as_uint(vals[b*N+i]);
    u = (u&0x80000000u)? ~u : (u|0x80000000u);
    key[i]=((unsigned long long)(~u)<<32)|(unsigned)i;
  }
  __syncthreads();
  for(int k=2;k<=N;k<<=1)
    for(int j=k>>1;j;j>>=1){
      for(int i=tid;i<N;i+=TH){
        int ixj=i^j;
        if(ixj>i){
          bool up=((i&k)==0);
          unsigned long long a=key[i],c=key[ixj];
          if((a>c)==up){ key[i]=c; key[ixj]=a; }
        }
      }
      __syncthreads();
    }
  for(int i=tid;i<128;i+=TH) idxout[b*128+i]=(int)(key[i]&0xFFFFFFFFu);
}

// ---------- RFM scan ----------
__global__ void k_rfm(const int* __restrict__ sc,const int* __restrict__ st,
    const int* __restrict__ mask_t,const int* __restrict__ s_t,
    const int* __restrict__ is_train,int* __restrict__ rstep,int* __restrict__ cstep)
{
  int b=threadIdx.x; if(b>=32) return;
  int* rs=rstep+b*128; int* cs=cstep+b*1024;
  for(int i=0;i<128;i++) rs[i]=-1;
  for(int i=0;i<1024;i++) cs[i]=-1;
  if(is_train && is_train[0]==0) return;
  int cnt=0;
  for(int s=0;s<128 && cnt<3;s++){
    int pc=sc[b*128+s], pt=st[b*128+s];
    if(rs[pc]!=-1||cs[pt]!=-1) continue;
    int mt=mask_t[b*128+s], ss=s_t[b*128+s];
    rs[pc]=s;
    int l=pt-ss; if(l<0)l=0;
    int r=pt+mt-ss; if(r>1024)r=1024;
    for(int t=l;t<r;t++) cs[t]=s;
    cnt++;
  }
}

// ---------- apply mask ----------
__global__ void k_apply(const float* __restrict__ x,const int* __restrict__ rstep,
    const int* __restrict__ cstep,const float* __restrict__ meanT,
    const float* __restrict__ meanF,float* __restrict__ xm)
{
  long i=(long)blockIdx.x*256+threadIdx.x; if(i>=4194304) return;
  int t=(int)(i&1023); int f=(int)((i>>10)&127); int b=(int)(i>>17);
  int rs=rstep[b*128+f], cs=cstep[b*1024+t];
  float v;
  if(rs<0&&cs<0) v=x[i];
  else v=(cs>=rs)? meanT[b*128+f] : meanF[b*1024+t];
  xm[i]=v;
}

// ---------- emb head ----------
__global__ void k_cat(const float* __restrict__ mu,const float* __restrict__ m2,
                      float* __restrict__ cat)
{
  int i=blockIdx.x*256+threadIdx.x; if(i>=131072) return;
  int b=i>>12, d=i&4095;
  float m=mu[i];
  cat[(long)b*8192+d]=m;
  cat[(long)b*8192+4096+d]=sqrtf(fmaxf(m2[i]-m*m,1e-5f));
}
__global__ void __launch_bounds__(256) k_embp(
    const float* __restrict__ cat,const float* __restrict__ We,
    float* __restrict__ part)
{
  __shared__ float cs[32][64];
  const int ks=blockIdx.x, j=threadIdx.x;
  for(int idx=j; idx<32*64; idx+=256){
    int b=idx>>6, ii=idx&63;
    cs[b][ii]=cat[(long)b*8192 + ks*64 + ii];
  }
  __syncthreads();
  float acc[32];
#pragma unroll
  for(int b=0;b<32;b++) acc[b]=0.f;
  for(int ii=0;ii<64;ii++){
    float w=We[((long)ks*64+ii)*256+j];
#pragma unroll
    for(int b=0;b<32;b++) acc[b]+=cs[b][ii]*w;
  }
#pragma unroll
  for(int b=0;b<32;b++) part[((long)ks*32+b)*256+j]=acc[b];
}
__global__ void __launch_bounds__(256) k_embf(
    const float* __restrict__ part,const float* __restrict__ be,
    const float* __restrict__ Wc,const float* __restrict__ bc,
    float* __restrict__ out)
{
  const int b=blockIdx.x, j=threadIdx.x;
  float s=be[j];
  for(int ks=0;ks<128;ks++) s+=part[((long)ks*32+b)*256+j];
  __shared__ float es[256];
  es[j]=s; __syncthreads();
  if(j<2){
    float acc=bc[j];
    for(int q=0;q<256;q++) acc+=es[q]*Wc[q*2+j];
    out[b*2+j]=acc;
  }
}

// ---------- host ----------
template<int SPLIT>
static void run_tail(const float* h3,const float* Wa,const float* ba,const float* va,
                     float* attp,float* att,float* alpha,float* mu,float* m2)
{
  k_attp_mma<SPLIT><<<dim3(8,32),256>>>(Wa,h3,attp);
  k_attf<<<2048,256>>>(attp,ba,att);
  k_salpha<<<32,128>>>(att,va,alpha);
  k_mustats<<<16384,256>>>(h3,alpha,mu,m2);
}

extern "C" void kernel_launch(void* const* d_in,const int* in_sizes,int n_in,
                              void* d_out,int out_size)
{
  const float* x =(const float*)d_in[0];
  const float* W1=(const float*)d_in[1]; const float* b1=(const float*)d_in[2];
  const float* W2=(const float*)d_in[3]; const float* b2=(const float*)d_in[4];
  const float* W3=(const float*)d_in[5]; const float* b3=(const float*)d_in[6];
  const float* Wa=(const float*)d_in[7]; const float* ba=(const float*)d_in[8];
  const float* va=(const float*)d_in[9];
  const float* We=(const float*)d_in[10]; const float* be=(const float*)d_in[11];
  const float* Wc=(const float*)d_in[12]; const float* bc=(const float*)d_in[13];
  const int* mask_t=(const int*)d_in[14]; const int* s_t=(const int*)d_in[15];
  const int* is_train = (n_in>16)? (const int*)d_in[16] : nullptr;
  float* out=(float*)d_out;

  float *h1,*h2,*h3,*d1,*d2,*d3,*fam,*xm,*att,*attp,*dz,*alpha,*ds,*dap,*mu,*m2,*dMu,*dE2,*gvec;
  float *cat,*ep,*cm,*tm,*meanT,*meanF,*wtf2,*wtb2,*wtf3,*wtb3;
  int *sc,*st,*rstep,*cstep;
  cudaGetSymbolAddress((void**)&h1,g_h1);   cudaGetSymbolAddress((void**)&h2,g_h2);
  cudaGetSymbolAddress((void**)&h3,g_h3);   cudaGetSymbolAddress((void**)&d1,g_d1);
  cudaGetSymbolAddress((void**)&d2,g_d2);   cudaGetSymbolAddress((void**)&d3,g_d3);
  cudaGetSymbolAddress((void**)&fam,g_fam); cudaGetSymbolAddress((void**)&xm,g_xm);
  cudaGetSymbolAddress((void**)&att,g_att); cudaGetSymbolAddress((void**)&attp,g_attp);
  cudaGetSymbolAddress((void**)&dz,g_dzb);
  cudaGetSymbolAddress((void**)&alpha,g_alpha); cudaGetSymbolAddress((void**)&ds,g_dsb);
  cudaGetSymbolAddress((void**)&dap,g_dap);
  cudaGetSymbolAddress((void**)&mu,g_mu);   cudaGetSymbolAddress((void**)&m2,g_m2);
  cudaGetSymbolAddress((void**)&dMu,g_dMu); cudaGetSymbolAddress((void**)&dE2,g_dE2);
  cudaGetSymbolAddress((void**)&gvec,g_gvec);
  cudaGetSymbolAddress((void**)&cat,g_cat); cudaGetSymbolAddress((void**)&ep,g_ep);
  cudaGetSymbolAddress((void**)&cm,g_cm);   cudaGetSymbolAddress((void**)&tm,g_tm);
  cudaGetSymbolAddress((void**)&meanT,g_meanT); cudaGetSymbolAddress((void**)&meanF,g_meanF);
  cudaGetSymbolAddress((void**)&sc,g_sc);   cudaGetSymbolAddress((void**)&st,g_st);
  cudaGetSymbolAddress((void**)&rstep,g_rstep); cudaGetSymbolAddress((void**)&cstep,g_cstep);
  cudaGetSymbolAddress((void**)&wtf2,g_wtf2); cudaGetSymbolAddress((void**)&wtb2,g_wtb2);
  cudaGetSymbolAddress((void**)&wtf3,g_wtf3); cudaGetSymbolAddress((void**)&wtb3,g_wtb3);

  const int MMA_SMEM = 120*136*4;
  cudaFuncSetAttribute(k_cmma<64,128,64,512,1>,  cudaFuncAttributeMaxDynamicSharedMemorySize, MMA_SMEM);
  cudaFuncSetAttribute(k_cmma<64,128,64,512,3>,  cudaFuncAttributeMaxDynamicSharedMemorySize, MMA_SMEM);
  cudaFuncSetAttribute(k_cmma<128,256,32,256,1>, cudaFuncAttributeMaxDynamicSharedMemorySize, MMA_SMEM);
  cudaFuncSetAttribute(k_cmma<128,256,32,256,3>, cudaFuncAttributeMaxDynamicSharedMemorySize, MMA_SMEM);

  // prep
  k_wt<<<288,256>>>(W2,wtf2,wtb2,64,128);
  k_wt<<<1152,256>>>(W3,wtf3,wtb3,128,256);
  k_gvec<<<1024,256>>>(We,Wc,gvec);
  // pass 1 (3xTF32: fp32-accurate, argsort-safe)
  k_conv_fwd<1,64,128,1024,1,16,4,256><<<dim3(8,64,32),256>>>(x,W1,b1,h1);
  k_cmma<64,128,64,512,3><<<dim3(2,32,32),256,MMA_SMEM>>>(h1,wtf2,b2,h2);
  k_cmma<128,256,32,256,3><<<dim3(2,16,32),256,MMA_SMEM>>>(h2,wtf3,b3,h3);
  run_tail<3>(h3,Wa,ba,va,attp,att,alpha,mu,m2);
  // backward to input
  k_dcoef<<<512,256>>>(mu,m2,gvec,dMu,dE2);
  k_dalp<<<dim3(8,32),128>>>(h3,dMu,dE2,dap);
  k_dalf<<<32,128>>>(dap,alpha,ds);
  k_dz<<<2048,256>>>(att,ds,va,dz);
  k_dfeat_mma<3><<<dim3(32,32),256>>>(Wa,dz,h3,alpha,dMu,dE2,d3);
  k_cbmma<128,256,16,128,128,3><<<dim3(2,32,32),256>>>(d3,wtb3,h2,d2);
  k_cbmma<64,128,32,256,256,3><<<dim3(2,64,32),256>>>(d2,wtb2,h1,d1);
  k_bwd1<<<dim3(2,128,32),256>>>(d1,W1,fam);
  // masking
  k_rowstats<<<512,256>>>(fam,x,cm,meanT);
  k_colstats<<<128,256>>>(fam,x,tm,meanF);
  k_sort<128><<<32,64>>>(cm,sc);
  k_sort<1024><<<32,512>>>(tm,st);
  k_rfm<<<1,32>>>(sc,st,mask_t,s_t,is_train,rstep,cstep);
  k_apply<<<16384,256>>>(x,rstep,cstep,meanT,meanF,xm);
  // pass 2 (single tf32: continuous output path)
  k_conv_fwd<1,64,128,1024,1,16,4,256><<<dim3(8,64,32),256>>>(xm,W1,b1,h1);
  k_cmma<64,128,64,512,1><<<dim3(2,32,32),256,MMA_SMEM>>>(h1,wtf2,b2,h2);
  k_cmma<128,256,32,256,1><<<dim3(2,16,32),256,MMA_SMEM>>>(h2,wtf3,b3,h3);
  run_tail<1>(h3,Wa,ba,va,attp,att,alpha,mu,m2);
  k_cat<<<512,256>>>(mu,m2,cat);
  k_embp<<<128,256>>>(cat,We,ep);
  k_embf<<<32,256>>>(ep,be,Wc,bc,out);
}

// round 9
// speedup vs baseline: 3.3044x; 1.1348x over previous
#include <cuda_runtime.h>
#include <math.h>

// ---------- static scratch ----------
__device__ float g_h1[67108864];
__device__ float g_h2[33554432];
__device__ float g_h3[16777216];
__device__ float g_d1[67108864];
__device__ float g_d2[33554432];
__device__ float g_d3[16777216];
__device__ float g_fam[4194304];
__device__ float g_xm[4194304];
__device__ float g_att[524288];
__device__ float g_attp[4194304];
__device__ float g_dzb[524288];
__device__ float g_alpha[4096];
__device__ float g_dsb[4096];
__device__ float g_dap[32768];
__device__ float g_mu[131072];
__device__ float g_m2[131072];
__device__ float g_dMu[131072];
__device__ float g_dE2[131072];
__device__ float g_gvec[8192];
__device__ float g_cat[262144];
__device__ float g_ep[1048576];
__device__ float g_cm[4096];
__device__ float g_tm[32768];
__device__ float g_meanT[4096];
__device__ float g_meanF[32768];
__device__ int   g_sc[4096];
__device__ int   g_st[4096];
__device__ int   g_rstep[4096];
__device__ int   g_cstep[32768];
__device__ float g_wtf2[73728];
__device__ float g_wtb2[73728];
__device__ float g_wtf3[294912];
__device__ float g_wtb3[294912];

// ---------- weight transposes ----------
__global__ void k_wt(const float* __restrict__ W, float* __restrict__ WTf,
                     float* __restrict__ WTb, int CIN, int COUT)
{
  int idx=blockIdx.x*256+threadIdx.x;
  int tot=CIN*COUT*9; if(idx>=tot) return;
  int k=idx%9, c=(idx/9)%CIN, o=idx/(9*CIN);
  float v=W[idx];
  int rf=(c>>3)*72 + k*8 + (c&7);
  WTf[(long)rf*COUT+o]=v;
  int rb=(o>>3)*72 + k*8 + (o&7);
  WTb[(long)rb*CIN+c]=v;
}

// ---------- conv1 fwd (CIN=1) ----------
template<int CIN,int COUT,int HIN,int WIN,int CC,int OG,int OP,int THREADS>
__global__ void __launch_bounds__(THREADS) k_conv_fwd(
    const float* __restrict__ in, const float* __restrict__ W,
    const float* __restrict__ bias, float* __restrict__ out)
{
  constexpr int HOUT=HIN/2, WOUT=WIN/2;
  __shared__ float ins[CC*3*130];
  __shared__ float ws[CC*9*COUT];
  const int n=blockIdx.z, i=blockIdx.y, j0=blockIdx.x*64;
  const int tid=threadIdx.x, og=tid%OG, jt=tid/OG;
  float acc[OP][4];
#pragma unroll
  for(int o=0;o<OP;o++){acc[o][0]=acc[o][1]=acc[o][2]=acc[o][3]=0.f;}
  for(int c0=0;c0<CIN;c0+=CC){
    __syncthreads();
    for(int idx=tid; idx<CC*3*130; idx+=THREADS){
      int c=idx/390, r=(idx/130)%3, col=idx%130;
      int gx=2*i+r, gy=2*j0+col;
      float v=0.f;
      if(gx<HIN && gy<WIN) v=in[(((long)n*CIN+c0+c)*HIN+gx)*WIN+gy];
      ins[idx]=v;
    }
    for(int idx=tid; idx<COUT*CC*9; idx+=THREADS){
      int o=idx/(CC*9), rem=idx%(CC*9);
      ws[rem*COUT+o]=W[(long)o*CIN*9 + c0*9 + rem];
    }
    __syncthreads();
#pragma unroll
    for(int c=0;c<CC;c++)
#pragma unroll
    for(int r=0;r<3;r++){
      float v[9];
#pragma unroll
      for(int m=0;m<9;m++) v[m]=ins[(c*3+r)*130 + 8*jt + m];
#pragma unroll
      for(int kj=0;kj<3;kj++)
#pragma unroll
      for(int oo=0;oo<OP;oo++){
        float w=ws[(c*9+r*3+kj)*COUT + og + OG*oo];
        acc[oo][0]+=w*v[kj];   acc[oo][1]+=w*v[2+kj];
        acc[oo][2]+=w*v[4+kj]; acc[oo][3]+=w*v[6+kj];
      }
    }
  }
  int j=j0+4*jt;
#pragma unroll
  for(int oo=0;oo<OP;oo++){
    int o=og+OG*oo; float bb=bias[o];
    float4 r;
    r.x=fmaxf(acc[oo][0]+bb,0.f); r.y=fmaxf(acc[oo][1]+bb,0.f);
    r.z=fmaxf(acc[oo][2]+bb,0.f); r.w=fmaxf(acc[oo][3]+bb,0.f);
    *(float4*)&out[(((long)n*COUT+o)*HOUT+i)*WOUT+j]=r;
  }
}

// ---------- tf32 helpers ----------
__device__ __forceinline__ float to_tf32(float v){
  unsigned r; asm("cvt.rna.tf32.f32 %0, %1;" : "=r"(r) : "f"(v));
  return __uint_as_float(r);
}
__device__ __forceinline__ void mma_tf32(float* c4,
    unsigned a0,unsigned a1,unsigned a2,unsigned a3,unsigned b0,unsigned b1){
  asm volatile(
    "mma.sync.aligned.m16n8k8.row.col.f32.tf32.tf32.f32 "
    "{%0,%1,%2,%3},{%4,%5,%6,%7},{%8,%9},{%0,%1,%2,%3};"
    : "+f"(c4[0]),"+f"(c4[1]),"+f"(c4[2]),"+f"(c4[3])
    : "r"(a0),"r"(a1),"r"(a2),"r"(a3),"r"(b0),"r"(b1));
}

// ---------- tf32 mma conv fwd ----------
template<int CIN,int COUT,int HIN,int WIN,int SPLIT>
__global__ void __launch_bounds__(256,2) k_cmma(
    const float* __restrict__ in, const float* __restrict__ WT,
    const float* __restrict__ bias, float* __restrict__ out)
{
  constexpr int HOUT=HIN/2, WOUT=WIN/2;
  constexpr int NJT=WOUT/128;
  constexpr int LD=136;
  extern __shared__ float sm[];
  float* ev = sm;
  float* od = sm + 24*LD;
  float* ws = sm + 48*LD;
  const int n=blockIdx.z, i=blockIdx.y;
  const int jt_=blockIdx.x%NJT, ot=blockIdx.x/NJT;
  const int j0=jt_*128, o0=ot*128;
  const int tid=threadIdx.x, wid=tid>>5, lane=tid&31;
  const int gid=lane>>2, tig=lane&3;
  const int m0=(wid&3)*32, n0w=(wid>>2)*64;
  float acc[2][8][4];
#pragma unroll
  for(int a=0;a<2;a++)
#pragma unroll
  for(int b=0;b<8;b++)
#pragma unroll
  for(int c=0;c<4;c++) acc[a][b][c]=0.f;

  for(int c0=0;c0<CIN;c0+=8){
    __syncthreads();
    for(int idx=tid; idx<8*3*129; idx+=256){
      int c=idx/387, rem=idx%387, r=rem/129, p=rem%129;
      int gx=2*i+r, gy=2*j0+2*p;
      float a=0.f,bv=0.f;
      if(gx<HIN && gy<WIN){
        const float2 s=*(const float2*)&in[(((long)n*CIN+c0+c)*HIN+gx)*WIN+gy];
        a=s.x; bv=s.y;
      }
      ev[(c*3+r)*LD+p]=a;
      od[(c*3+r)*LD+p]=bv;
    }
    {
      const float* wsrc = WT + (long)(c0>>3)*72*COUT + o0;
      for(int idx=tid; idx<72*32; idx+=256){
        int kk=idx>>5, o4=(idx&31)*4;
        float4 v=*(const float4*)&wsrc[(long)kk*COUT + o4];
        *(float4*)&ws[kk*LD + o4]=v;
      }
    }
    __syncthreads();
#pragma unroll
    for(int kc=0;kc<9;kc++){
      const int r=kc/3, kj=kc%3;
      const float* src = (kj==1)? od : ev;
      const int co = (kj==2)? 1:0;
      unsigned bh[8][2], bl[8][2];
#pragma unroll
      for(int f=0;f<8;f++){
        float v0 = src[(tig*3+r)*LD + n0w + f*8 + gid + co];
        float v1 = src[((tig+4)*3+r)*LD + n0w + f*8 + gid + co];
        float h0=to_tf32(v0), h1=to_tf32(v1);
        bh[f][0]=__float_as_uint(h0); bh[f][1]=__float_as_uint(h1);
        if(SPLIT==3){
          bl[f][0]=__float_as_uint(to_tf32(v0-h0));
          bl[f][1]=__float_as_uint(to_tf32(v1-h1));
        }
      }
#pragma unroll
      for(int mf=0;mf<2;mf++){
        float w0=ws[(kc*8+tig)*LD + m0+mf*16+gid];
        float w1=ws[(kc*8+tig)*LD + m0+mf*16+gid+8];
        float w2=ws[(kc*8+tig+4)*LD + m0+mf*16+gid];
        float w3=ws[(kc*8+tig+4)*LD + m0+mf*16+gid+8];
        float h0=to_tf32(w0),h1=to_tf32(w1),h2=to_tf32(w2),h3=to_tf32(w3);
        unsigned ah0=__float_as_uint(h0),ah1=__float_as_uint(h1),
                 ah2=__float_as_uint(h2),ah3=__float_as_uint(h3);
        unsigned al0=0,al1=0,al2=0,al3=0;
        if(SPLIT==3){
          al0=__float_as_uint(to_tf32(w0-h0)); al1=__float_as_uint(to_tf32(w1-h1));
          al2=__float_as_uint(to_tf32(w2-h2)); al3=__float_as_uint(to_tf32(w3-h3));
        }
#pragma unroll
        for(int f=0;f<8;f++){
          mma_tf32(acc[mf][f], ah0,ah1,ah2,ah3, bh[f][0],bh[f][1]);
          if(SPLIT==3){
            mma_tf32(acc[mf][f], ah0,ah1,ah2,ah3, bl[f][0],bl[f][1]);
            mma_tf32(acc[mf][f], al0,al1,al2,al3, bh[f][0],bh[f][1]);
          }
        }
      }
    }
  }
#pragma unroll
  for(int mf=0;mf<2;mf++){
    int oA=o0+m0+mf*16+gid, oB=oA+8;
    float bA=bias[oA], bB=bias[oB];
#pragma unroll
    for(int f=0;f<8;f++){
      int jj=j0 + n0w + f*8 + tig*2;
      long baseA=(((long)n*COUT+oA)*HOUT+i)*WOUT + jj;
      long baseB=(((long)n*COUT+oB)*HOUT+i)*WOUT + jj;
      float2 rA, rB;
      rA.x=fmaxf(acc[mf][f][0]+bA,0.f); rA.y=fmaxf(acc[mf][f][1]+bA,0.f);
      rB.x=fmaxf(acc[mf][f][2]+bB,0.f); rB.y=fmaxf(acc[mf][f][3]+bB,0.f);
      *(float2*)&out[baseA]=rA;
      *(float2*)&out[baseB]=rB;
    }
  }
}

// ---------- tf32 mma transposed-conv bwd ----------
template<int CIN,int COUT,int HOUT,int WOUT,int NT,int SPLIT>
__global__ void __launch_bounds__(256,2) k_cbmma(
    const float* __restrict__ dout, const float* __restrict__ WT,
    const float* __restrict__ act, float* __restrict__ din)
{
  constexpr int HIN=2*HOUT, WIN=2*WOUT;
  constexpr int LDW=CIN+8, LDD=NT/2+4, JL=NT/2+2;
  constexpr int NW_M=CIN/32;
  __shared__ float ws[72*LDW];
  __shared__ float dsA[8*LDD];
  __shared__ float dsB[8*LDD];
  const int n=blockIdx.z, x=blockIdx.y, y0=blockIdx.x*NT;
  const int tid=threadIdx.x, wid=tid>>5, lane=tid&31;
  const int gid=lane>>2, tig=lane&3;
  const int m0=(wid%NW_M)*32, n0=(wid/NW_M)*64;
  const bool xe=((x&1)==0);
  const int iA = xe ? (x>>1) : ((x-1)>>1);
  const int iB = (x>>1)-1;
  const bool hasB = xe && iB>=0;
  const int jb = y0/2 - 1;
  float acc_e[2][4][4], acc_o[2][4][4];
#pragma unroll
  for(int a=0;a<2;a++)
#pragma unroll
  for(int b=0;b<4;b++)
#pragma unroll
  for(int c=0;c<4;c++){acc_e[a][b][c]=0.f; acc_o[a][b][c]=0.f;}

  for(int o0=0;o0<COUT;o0+=8){
    __syncthreads();
    {
      const float* wsrc = WT + (long)(o0>>3)*72*CIN;
      for(int idx=tid; idx<72*(CIN/4); idx+=256){
        int r=idx/(CIN/4), c4=(idx%(CIN/4))*4;
        float4 v=*(const float4*)&wsrc[(long)r*CIN+c4];
        *(float4*)&ws[r*LDW+c4]=v;
      }
    }
    for(int idx=tid; idx<8*JL; idx+=256){
      int o=idx/JL, jl=idx%JL; int j=jb+jl;
      float a=0.f,bv=0.f;
      if(j>=0 && j<WOUT){
        long base=((long)n*COUT+o0+o)*HOUT;
        a = dout[(base+iA)*WOUT+j];
        if(hasB) bv = dout[(base+iB)*WOUT+j];
      }
      dsA[o*LDD+jl]=a; dsB[o*LDD+jl]=bv;
    }
    __syncthreads();

    auto proc = [&](const float* ds, const int tapBase){
      unsigned b1h[4][2], b0h[4][2], b1l[4][2], b0l[4][2];
#pragma unroll
      for(int f=0;f<4;f++){
        int cbase = n0/2 + f*8 + gid;
        float v1a = ds[tig*LDD + cbase + 1];
        float v1b = ds[(tig+4)*LDD + cbase + 1];
        float v0a = ds[tig*LDD + cbase];
        float v0b = ds[(tig+4)*LDD + cbase];
        float h1a=to_tf32(v1a), h1b=to_tf32(v1b);
        float h0a=to_tf32(v0a), h0b=to_tf32(v0b);
        b1h[f][0]=__float_as_uint(h1a); b1h[f][1]=__float_as_uint(h1b);
        b0h[f][0]=__float_as_uint(h0a); b0h[f][1]=__float_as_uint(h0b);
        if(SPLIT==3){
          b1l[f][0]=__float_as_uint(to_tf32(v1a-h1a));
          b1l[f][1]=__float_as_uint(to_tf32(v1b-h1b));
          b0l[f][0]=__float_as_uint(to_tf32(v0a-h0a));
          b0l[f][1]=__float_as_uint(to_tf32(v0b-h0b));
        }
      }
#pragma unroll
      for(int kj=0;kj<3;kj++){
        const int tap=tapBase+kj;
#pragma unroll
        for(int mf=0;mf<2;mf++){
          float w0=ws[(tap*8+tig)*LDW + m0+mf*16+gid];
          float w1=ws[(tap*8+tig)*LDW + m0+mf*16+gid+8];
          float w2=ws[(tap*8+tig+4)*LDW + m0+mf*16+gid];
          float w3=ws[(tap*8+tig+4)*LDW + m0+mf*16+gid+8];
          float h0=to_tf32(w0),h1=to_tf32(w1),h2=to_tf32(w2),h3=to_tf32(w3);
          unsigned ah0=__float_as_uint(h0),ah1=__float_as_uint(h1),
                   ah2=__float_as_uint(h2),ah3=__float_as_uint(h3);
          unsigned al0=0,al1=0,al2=0,al3=0;
          if(SPLIT==3){
            al0=__float_as_uint(to_tf32(w0-h0)); al1=__float_as_uint(to_tf32(w1-h1));
            al2=__float_as_uint(to_tf32(w2-h2)); al3=__float_as_uint(to_tf32(w3-h3));
          }
#pragma unroll
          for(int f=0;f<4;f++){
            float* c4 = (kj==1)? acc_o[mf][f] : acc_e[mf][f];
            const unsigned* bh = (kj==2)? b0h[f] : b1h[f];
            const unsigned* bl = (kj==2)? b0l[f] : b1l[f];
            mma_tf32(c4, ah0,ah1,ah2,ah3, bh[0],bh[1]);
            if(SPLIT==3){
              mma_tf32(c4, ah0,ah1,ah2,ah3, bl[0],bl[1]);
              mma_tf32(c4, al0,al1,al2,al3, bh[0],bh[1]);
            }
          }
        }
      }
    };
    proc(dsA, xe?0:3);
    if(hasB) proc(dsB, 6);
  }

#pragma unroll
  for(int mf=0;mf<2;mf++){
    int c0_=m0+mf*16+gid;
#pragma unroll
    for(int f=0;f<4;f++){
      int Y = y0 + n0 + 2*(f*8 + 2*tig);
      long b0i=(((long)n*CIN+c0_)*HIN+x)*WIN + Y;
      long b1i=(((long)n*CIN+c0_+8)*HIN+x)*WIN + Y;
      float2 m, r;
      m=*(const float2*)&act[b0i];
      r.x = m.x>0.f? acc_e[mf][f][0]:0.f; r.y = m.y>0.f? acc_o[mf][f][0]:0.f;
      *(float2*)&din[b0i]=r;
      m=*(const float2*)&act[b0i+2];
      r.x = m.x>0.f? acc_e[mf][f][1]:0.f; r.y = m.y>0.f? acc_o[mf][f][1]:0.f;
      *(float2*)&din[b0i+2]=r;
      m=*(const float2*)&act[b1i];
      r.x = m.x>0.f? acc_e[mf][f][2]:0.f; r.y = m.y>0.f? acc_o[mf][f][2]:0.f;
      *(float2*)&din[b1i]=r;
      m=*(const float2*)&act[b1i+2];
      r.x = m.x>0.f? acc_e[mf][f][3]:0.f; r.y = m.y>0.f? acc_o[mf][f][3]:0.f;
      *(float2*)&din[b1i+2]=r;
    }
  }
}

// ---------- conv1 data-grad -> |dx| ----------
__global__ void __launch_bounds__(256) k_bwd1(
    const float* __restrict__ dz1, const float* __restrict__ W1,
    float* __restrict__ fam)
{
  __shared__ float ws[576];
  __shared__ float dsm[8*2*260];
  const int n=blockIdx.z, x=blockIdx.y, y0=blockIdx.x*512;
  const int tid=threadIdx.x;
  for(int idx=tid; idx<576; idx+=256) ws[idx]=W1[idx];
  int iA,iB,kiA,kiB; bool hasB;
  if((x&1)==0){iA=x>>1;kiA=0;iB=iA-1;kiB=2;hasB=(iB>=0);}
  else{iA=(x-1)>>1;kiA=1;iB=0;kiB=0;hasB=false;}
  const int jbase=y0/2-1;
  float accE=0.f, accO=0.f;
  for(int o0=0;o0<64;o0+=8){
    __syncthreads();
    for(int idx=tid; idx<8*2*260; idx+=256){
      int o=idx/520, rs=(idx/260)&1, jj=idx%260;
      int j=jbase+jj; int ir=rs?iB:iA;
      float v=0.f;
      if(j>=0 && j<512 && (rs==0||hasB))
        v=dz1[(((long)n*64+o0+o)*64+ir)*512+j];
      dsm[idx]=v;
    }
    __syncthreads();
#pragma unroll
    for(int o=0;o<8;o++){
#pragma unroll
      for(int rs=0;rs<2;rs++){
        if(rs==1&&!hasB) break;
        int ki=rs?kiB:kiA;
        const float* wb=&ws[(o0+o)*9+ki*3];
        float vm=dsm[(o*2+rs)*260+tid], v0=dsm[(o*2+rs)*260+tid+1];
        accE+=wb[0]*v0+wb[2]*vm; accO+=wb[1]*v0;
      }
    }
  }
  long base=((long)n*128+x)*1024 + y0 + 2*tid;
  fam[base]=fabsf(accE); fam[base+1]=fabsf(accO);
}

// ---------- att partial GEMM (tf32 mma, split-K) ----------
template<int SPLIT>
__global__ void __launch_bounds__(256) k_attp_mma(
    const float* __restrict__ Wa, const float* __restrict__ feat,
    float* __restrict__ attp)
{
  constexpr int LDA=129, LDB=132;
  __shared__ float As[32*LDA];   // [k][h]
  __shared__ float Bs[32*LDB];   // [k][t]
  const int ks=blockIdx.x, b=blockIdx.y;
  const int tid=threadIdx.x, wid=tid>>5, lane=tid&31;
  const int gid=lane>>2, tig=lane&3;
  const int m0=(wid&3)*32, n0=(wid>>2)*64;
  const float* fb = feat + (long)b*524288;
  float acc[2][8][4];
#pragma unroll
  for(int a=0;a<2;a++)
#pragma unroll
  for(int bq=0;bq<8;bq++)
#pragma unroll
  for(int c=0;c<4;c++) acc[a][bq][c]=0.f;

  for(int k0=ks*512; k0<ks*512+512; k0+=32){
    __syncthreads();
    for(int idx=tid; idx<4096; idx+=256){
      int h=idx>>5, kk=idx&31;
      As[kk*LDA+h]=Wa[(long)h*4096+k0+kk];
    }
    for(int idx=tid; idx<4096; idx+=256){
      int kk=idx>>7, t=idx&127;
      Bs[kk*LDB+t]=fb[(long)(k0+kk)*128+t];
    }
    __syncthreads();
#pragma unroll
    for(int kc=0;kc<4;kc++){
      const int kb=kc*8;
      unsigned bh[8][2], bl[8][2];
#pragma unroll
      for(int f=0;f<8;f++){
        float v0=Bs[(kb+tig)*LDB + n0+f*8+gid];
        float v1=Bs[(kb+tig+4)*LDB + n0+f*8+gid];
        float h0=to_tf32(v0), h1=to_tf32(v1);
        bh[f][0]=__float_as_uint(h0); bh[f][1]=__float_as_uint(h1);
        if(SPLIT==3){
          bl[f][0]=__float_as_uint(to_tf32(v0-h0));
          bl[f][1]=__float_as_uint(to_tf32(v1-h1));
        }
      }
#pragma unroll
      for(int mf=0;mf<2;mf++){
        float w0=As[(kb+tig)*LDA + m0+mf*16+gid];
        float w1=As[(kb+tig)*LDA + m0+mf*16+gid+8];
        float w2=As[(kb+tig+4)*LDA + m0+mf*16+gid];
        float w3=As[(kb+tig+4)*LDA + m0+mf*16+gid+8];
        float h0=to_tf32(w0),h1=to_tf32(w1),h2=to_tf32(w2),h3=to_tf32(w3);
        unsigned ah0=__float_as_uint(h0),ah1=__float_as_uint(h1),
                 ah2=__float_as_uint(h2),ah3=__float_as_uint(h3);
        unsigned al0=0,al1=0,al2=0,al3=0;
        if(SPLIT==3){
          al0=__float_as_uint(to_tf32(w0-h0)); al1=__float_as_uint(to_tf32(w1-h1));
          al2=__float_as_uint(to_tf32(w2-h2)); al3=__float_as_uint(to_tf32(w3-h3));
        }
#pragma unroll
        for(int f=0;f<8;f++){
          mma_tf32(acc[mf][f], ah0,ah1,ah2,ah3, bh[f][0],bh[f][1]);
          if(SPLIT==3){
            mma_tf32(acc[mf][f], ah0,ah1,ah2,ah3, bl[f][0],bl[f][1]);
            mma_tf32(acc[mf][f], al0,al1,al2,al3, bh[f][0],bh[f][1]);
          }
        }
      }
    }
  }
#pragma unroll
  for(int mf=0;mf<2;mf++){
    int hA=m0+mf*16+gid, hB=hA+8;
#pragma unroll
    for(int f=0;f<8;f++){
      int t=n0+f*8+tig*2;
      float2 rA, rB;
      rA.x=acc[mf][f][0]; rA.y=acc[mf][f][1];
      rB.x=acc[mf][f][2]; rB.y=acc[mf][f][3];
      *(float2*)&attp[(long)ks*524288 + ((long)b*128+hA)*128+t]=rA;
      *(float2*)&attp[(long)ks*524288 + ((long)b*128+hB)*128+t]=rB;
    }
  }
}
__global__ void k_attf(const float* __restrict__ attp, const float* __restrict__ ba,
                       float* __restrict__ att)
{
  int i=blockIdx.x*256+threadIdx.x; if(i>=524288) return;
  int h=(i>>7)&127;
  float s=0.f;
#pragma unroll
  for(int ks=0;ks<8;ks++) s+=attp[(long)ks*524288+i];
  att[i]=tanhf(s+ba[h]);
}

// ---------- softmax ----------
__global__ void __launch_bounds__(128) k_salpha(
    const float* __restrict__ att, const float* __restrict__ va,
    float* __restrict__ alpha)
{
  __shared__ float vs[128], buf[128];
  const int b=blockIdx.x, t=threadIdx.x;
  vs[t]=va[t];
  __syncthreads();
  float s=0.f;
#pragma unroll 4
  for(int h=0;h<128;h++) s+=vs[h]*att[((long)b*128+h)*128+t];
  buf[t]=s; __syncthreads();
  for(int off=64;off;off>>=1){ if(t<off) buf[t]=fmaxf(buf[t],buf[t+off]); __syncthreads(); }
  float mx=buf[0]; __syncthreads();
  float e=expf(s-mx);
  buf[t]=e; __syncthreads();
  for(int off=64;off;off>>=1){ if(t<off) buf[t]+=buf[t+off]; __syncthreads(); }
  alpha[b*128+t]=e/buf[0];
}

// ---------- mu, m2 ----------
__global__ void k_mustats(const float* __restrict__ feat,
    const float* __restrict__ alpha, float* __restrict__ mu, float* __restrict__ m2)
{
  int w=(blockIdx.x*blockDim.x+threadIdx.x)>>5, lane=threadIdx.x&31;
  if(w>=131072) return;
  int b=w>>12;
  const float* fr=feat+(long)w*128;
  const float* ar=alpha+b*128;
  float s1=0.f,s2=0.f;
#pragma unroll
  for(int t=lane;t<128;t+=32){
    float a=ar[t], f=fr[t];
    s1+=a*f; s2+=a*f*f;
  }
  for(int o=16;o;o>>=1){ s1+=__shfl_down_sync(~0u,s1,o); s2+=__shfl_down_sync(~0u,s2,o); }
  if(!lane){ mu[w]=s1; m2[w]=s2; }
}

// ---------- gvec ----------
__global__ void k_gvec(const float* __restrict__ We,const float* __restrict__ Wc,
                       float* __restrict__ gvec)
{
  int w=(blockIdx.x*blockDim.x+threadIdx.x)>>5, lane=threadIdx.x&31;
  if(w>=8192) return;
  float s=0.f;
  for(int j=lane;j<256;j+=32) s+=We[(long)w*256+j]*(Wc[j*2+1]-Wc[j*2]);
  for(int o=16;o;o>>=1) s+=__shfl_down_sync(~0u,s,o);
  if(!lane) gvec[w]=s;
}

// ---------- dMu,dE2 ----------
__global__ void k_dcoef(const float* __restrict__ mu,const float* __restrict__ m2,
    const float* __restrict__ gvec, float* __restrict__ dMu,float* __restrict__ dE2)
{
  int i=blockIdx.x*256+threadIdx.x; if(i>=131072) return;
  int d=i&4095;
  float m=mu[i], v=m2[i]-m*m;
  float g2=gvec[4096+d];
  float dE=0.f, dM=gvec[d];
  if(v>1e-5f){ float sg=sqrtf(v); dE=0.5f*g2/sg; dM-=g2*m/sg; }
  dMu[i]=dM; dE2[i]=dE;
}

// ---------- dalpha ----------
__global__ void __launch_bounds__(128) k_dalp(
    const float* __restrict__ feat,const float* __restrict__ dMu,
    const float* __restrict__ dE2,float* __restrict__ part)
{
  const int ks=blockIdx.x, b=blockIdx.y, t=threadIdx.x;
  const float* fb=feat+(long)b*524288;
  const float* dm=dMu+b*4096; const float* de=dE2+b*4096;
  float acc=0.f;
  int d0=ks*512;
#pragma unroll 4
  for(int d=d0;d<d0+512;d++){
    float f=fb[(long)d*128+t];
    acc+=dm[d]*f+de[d]*f*f;
  }
  part[(ks*32+b)*128+t]=acc;
}
__global__ void __launch_bounds__(128) k_dalf(
    const float* __restrict__ part,const float* __restrict__ alpha,
    float* __restrict__ ds)
{
  const int b=blockIdx.x, t=threadIdx.x;
  float acc=0.f;
#pragma unroll
  for(int ks=0;ks<8;ks++) acc+=part[(ks*32+b)*128+t];
  __shared__ float buf[128];
  float a=alpha[b*128+t];
  buf[t]=a*acc; __syncthreads();
  for(int off=64;off;off>>=1){ if(t<off) buf[t]+=buf[t+off]; __syncthreads(); }
  ds[b*128+t]=a*(acc-buf[0]);
}

// ---------- dz ----------
__global__ void k_dz(const float* __restrict__ att,const float* __restrict__ ds,
    const float* __restrict__ va,float* __restrict__ dz)
{
  int i=blockIdx.x*256+threadIdx.x; if(i>=524288) return;
  int t=i&127, h=(i>>7)&127, b=i>>14;
  float a=att[i];
  dz[i]=va[h]*ds[b*128+t]*(1.f-a*a);
}

// ---------- dfeat (tf32 mma) + fused pointwise/mask epilogue ----------
template<int SPLIT>
__global__ void __launch_bounds__(256) k_dfeat_mma(
    const float* __restrict__ Wa, const float* __restrict__ dz,
    const float* __restrict__ feat, const float* __restrict__ alpha,
    const float* __restrict__ dMu, const float* __restrict__ dE2,
    float* __restrict__ dout3)
{
  constexpr int LDA=132, LDB=132;
  __shared__ float As[32*LDA];  // [k][d]
  __shared__ float Bs[32*LDB];  // [k][t]
  __shared__ float al[128];
  const int d0=blockIdx.x*128, b=blockIdx.y;
  const int tid=threadIdx.x, wid=tid>>5, lane=tid&31;
  const int gid=lane>>2, tig=lane&3;
  const int m0=(wid&3)*32, n0=(wid>>2)*64;
  if(tid<128) al[tid]=alpha[b*128+tid];
  float acc[2][8][4];
#pragma unroll
  for(int a=0;a<2;a++)
#pragma unroll
  for(int bq=0;bq<8;bq++)
#pragma unroll
  for(int c=0;c<4;c++) acc[a][bq][c]=0.f;

  for(int k0=0;k0<128;k0+=32){
    __syncthreads();
    for(int idx=tid; idx<4096; idx+=256){
      int kk=idx>>7, dd=idx&127;
      As[kk*LDA+dd]=Wa[(long)(k0+kk)*4096+d0+dd];
    }
    for(int idx=tid; idx<4096; idx+=256){
      int kk=idx>>7, t=idx&127;
      Bs[kk*LDB+t]=dz[((long)b*128+k0+kk)*128+t];
    }
    __syncthreads();
#pragma unroll
    for(int kc=0;kc<4;kc++){
      const int kb=kc*8;
      unsigned bh[8][2], bl[8][2];
#pragma unroll
      for(int f=0;f<8;f++){
        float v0=Bs[(kb+tig)*LDB + n0+f*8+gid];
        float v1=Bs[(kb+tig+4)*LDB + n0+f*8+gid];
        float h0=to_tf32(v0), h1=to_tf32(v1);
        bh[f][0]=__float_as_uint(h0); bh[f][1]=__float_as_uint(h1);
        if(SPLIT==3){
          bl[f][0]=__float_as_uint(to_tf32(v0-h0));
          bl[f][1]=__float_as_uint(to_tf32(v1-h1));
        }
      }
#pragma unroll
      for(int mf=0;mf<2;mf++){
        float w0=As[(kb+tig)*LDA + m0+mf*16+gid];
        float w1=As[(kb+tig)*LDA + m0+mf*16+gid+8];
        float w2=As[(kb+tig+4)*LDA + m0+mf*16+gid];
        float w3=As[(kb+tig+4)*LDA + m0+mf*16+gid+8];
        float h0=to_tf32(w0),h1=to_tf32(w1),h2=to_tf32(w2),h3=to_tf32(w3);
        unsigned ah0=__float_as_uint(h0),ah1=__float_as_uint(h1),
                 ah2=__float_as_uint(h2),ah3=__float_as_uint(h3);
        unsigned al0=0,al1=0,al2=0,al3=0;
        if(SPLIT==3){
          al0=__float_as_uint(to_tf32(w0-h0)); al1=__float_as_uint(to_tf32(w1-h1));
          al2=__float_as_uint(to_tf32(w2-h2)); al3=__float_as_uint(to_tf32(w3-h3));
        }
#pragma unroll
        for(int f=0;f<8;f++){
          mma_tf32(acc[mf][f], ah0,ah1,ah2,ah3, bh[f][0],bh[f][1]);
          if(SPLIT==3){
            mma_tf32(acc[mf][f], ah0,ah1,ah2,ah3, bl[f][0],bl[f][1]);
            mma_tf32(acc[mf][f], al0,al1,al2,al3, bh[f][0],bh[f][1]);
          }
        }
      }
    }
  }
#pragma unroll
  for(int mf=0;mf<2;mf++){
    int dA=d0+m0+mf*16+gid, dB=dA+8;
    float dmA=dMu[(long)b*4096+dA], deA=dE2[(long)b*4096+dA];
    float dmB=dMu[(long)b*4096+dB], deB=dE2[(long)b*4096+dB];
#pragma unroll
    for(int f=0;f<8;f++){
      int t=n0+f*8+tig*2;
      long fiA=((long)b*4096+dA)*128+t;
      long fiB=((long)b*4096+dB)*128+t;
      float2 fvA=*(const float2*)&feat[fiA];
      float2 fvB=*(const float2*)&feat[fiB];
      float2 rA, rB;
      rA.x = fvA.x>0.f? (acc[mf][f][0]+al[t]*(dmA+2.f*deA*fvA.x)) : 0.f;
      rA.y = fvA.y>0.f? (acc[mf][f][1]+al[t+1]*(dmA+2.f*deA*fvA.y)) : 0.f;
      rB.x = fvB.x>0.f? (acc[mf][f][2]+al[t]*(dmB+2.f*deB*fvB.x)) : 0.f;
      rB.y = fvB.y>0.f? (acc[mf][f][3]+al[t+1]*(dmB+2.f*deB*fvB.y)) : 0.f;
      *(float2*)&dout3[fiA]=rA;
      *(float2*)&dout3[fiB]=rB;
    }
  }
}

// ---------- row/col stats ----------
__global__ void k_rowstats(const float* __restrict__ fam,const float* __restrict__ x,
    float* __restrict__ cm,float* __restrict__ meanT)
{
  int w=(blockIdx.x*blockDim.x+threadIdx.x)>>5, lane=threadIdx.x&31;
  if(w>=4096) return;
  const float* fr=fam+(long)w*1024; const float* xr=x+(long)w*1024;
  float m=-1e30f, s=0.f;
  for(int t=lane;t<1024;t+=32){ m=fmaxf(m,fr[t]); s+=xr[t]; }
  for(int o=16;o;o>>=1){ m=fmaxf(m,__shfl_down_sync(~0u,m,o)); s+=__shfl_down_sync(~0u,s,o); }
  if(!lane){ cm[w]=m; meanT[w]=s*(1.f/1024.f); }
}
__global__ void k_colstats(const float* __restrict__ fam,const float* __restrict__ x,
    float* __restrict__ tm,float* __restrict__ meanF)
{
  int i=blockIdx.x*256+threadIdx.x; if(i>=32768) return;
  int b=i>>10, t=i&1023;
  const float* fb=fam+(long)b*131072+t; const float* xb=x+(long)b*131072+t;
  float m=-1e30f, s=0.f;
#pragma unroll 4
  for(int f=0;f<128;f++){ m=fmaxf(m,fb[f*1024]); s+=xb[f*1024]; }
  tm[i]=m; meanF[i]=s*(1.f/128.f);
}

// ---------- bitonic argsort ----------
template<int N>
__global__ void k_sort(const float* __restrict__ vals, int* __restrict__ idxout)
{
  __shared__ unsigned long long key[N];
  const int b=blockIdx.x, tid=threadIdx.x, TH=N/2;
  for(int i=tid;i<N;i+=TH){
    unsigned u=__float_as_uint(vals[b*N+i]);
    u = (u&0x80000000u)? ~u : (u|0x80000000u);
    key[i]=((unsigned long long)(~u)<<32)|(unsigned)i;
  }
  __syncthreads();
  for(int k=2;k<=N;k<<=1)
    for(int j=k>>1;j;j>>=1){
      for(int i=tid;i<N;i+=TH){
        int ixj=i^j;
        if(ixj>i){
          bool up=((i&k)==0);
          unsigned long long a=key[i],c=key[ixj];
          if((a>c)==up){ key[i]=c; key[ixj]=a; }
        }
      }
      __syncthreads();
    }
  for(int i=tid;i<128;i+=TH) idxout[b*128+i]=(int)(key[i]&0xFFFFFFFFu);
}

// ---------- RFM scan ----------
__global__ void k_rfm(const int* __restrict__ sc,const int* __restrict__ st,
    const int* __restrict__ mask_t,const int* __restrict__ s_t,
    const int* __restrict__ is_train,int* __restrict__ rstep,int* __restrict__ cstep)
{
  int b=threadIdx.x; if(b>=32) return;
  int* rs=rstep+b*128; int* cs=cstep+b*1024;
  for(int i=0;i<128;i++) rs[i]=-1;
  for(int i=0;i<1024;i++) cs[i]=-1;
  if(is_train && is_train[0]==0) return;
  int cnt=0;
  for(int s=0;s<128 && cnt<3;s++){
    int pc=sc[b*128+s], pt=st[b*128+s];
    if(rs[pc]!=-1||cs[pt]!=-1) continue;
    int mt=mask_t[b*128+s], ss=s_t[b*128+s];
    rs[pc]=s;
    int l=pt-ss; if(l<0)l=0;
    int r=pt+mt-ss; if(r>1024)r=1024;
    for(int t=l;t<r;t++) cs[t]=s;
    cnt++;
  }
}

// ---------- apply mask ----------
__global__ void k_apply(const float* __restrict__ x,const int* __restrict__ rstep,
    const int* __restrict__ cstep,const float* __restrict__ meanT,
    const float* __restrict__ meanF,float* __restrict__ xm)
{
  long i=(long)blockIdx.x*256+threadIdx.x; if(i>=4194304) return;
  int t=(int)(i&1023); int f=(int)((i>>10)&127); int b=(int)(i>>17);
  int rs=rstep[b*128+f], cs=cstep[b*1024+t];
  float v;
  if(rs<0&&cs<0) v=x[i];
  else v=(cs>=rs)? meanT[b*128+f] : meanF[b*1024+t];
  xm[i]=v;
}

// ---------- emb head ----------
__global__ void k_cat(const float* __restrict__ mu,const float* __restrict__ m2,
                      float* __restrict__ cat)
{
  int i=blockIdx.x*256+threadIdx.x; if(i>=131072) return;
  int b=i>>12, d=i&4095;
  float m=mu[i];
  cat[(long)b*8192+d]=m;
  cat[(long)b*8192+4096+d]=sqrtf(fmaxf(m2[i]-m*m,1e-5f));
}
__global__ void __launch_bounds__(256) k_embp(
    const float* __restrict__ cat,const float* __restrict__ We,
    float* __restrict__ part)
{
  __shared__ float cs[32][64];
  const int ks=blockIdx.x, j=threadIdx.x;
  for(int idx=j; idx<32*64; idx+=256){
    int b=idx>>6, ii=idx&63;
    cs[b][ii]=cat[(long)b*8192 + ks*64 + ii];
  }
  __syncthreads();
  float acc[32];
#pragma unroll
  for(int b=0;b<32;b++) acc[b]=0.f;
  for(int ii=0;ii<64;ii++){
    float w=We[((long)ks*64+ii)*256+j];
#pragma unroll
    for(int b=0;b<32;b++) acc[b]+=cs[b][ii]*w;
  }
#pragma unroll
  for(int b=0;b<32;b++) part[((long)ks*32+b)*256+j]=acc[b];
}
__global__ void __launch_bounds__(256) k_embf(
    const float* __restrict__ part,const float* __restrict__ be,
    const float* __restrict__ Wc,const float* __restrict__ bc,
    float* __restrict__ out)
{
  const int b=blockIdx.x, j=threadIdx.x;
  float s=be[j];
  for(int ks=0;ks<128;ks++) s+=part[((long)ks*32+b)*256+j];
  __shared__ float es[256];
  es[j]=s; __syncthreads();
  if(j<2){
    float acc=bc[j];
    for(int q=0;q<256;q++) acc+=es[q]*Wc[q*2+j];
    out[b*2+j]=acc;
  }
}

// ---------- host ----------
template<int SPLIT>
static void run_tail(const float* h3,const float* Wa,const float* ba,const float* va,
                     float* attp,float* att,float* alpha,float* mu,float* m2)
{
  k_attp_mma<SPLIT><<<dim3(8,32),256>>>(Wa,h3,attp);
  k_attf<<<2048,256>>>(attp,ba,att);
  k_salpha<<<32,128>>>(att,va,alpha);
  k_mustats<<<16384,256>>>(h3,alpha,mu,m2);
}

extern "C" void kernel_launch(void* const* d_in,const int* in_sizes,int n_in,
                              void* d_out,int out_size)
{
  const float* x =(const float*)d_in[0];
  const float* W1=(const float*)d_in[1]; const float* b1=(const float*)d_in[2];
  const float* W2=(const float*)d_in[3]; const float* b2=(const float*)d_in[4];
  const float* W3=(const float*)d_in[5]; const float* b3=(const float*)d_in[6];
  const float* Wa=(const float*)d_in[7]; const float* ba=(const float*)d_in[8];
  const float* va=(const float*)d_in[9];
  const float* We=(const float*)d_in[10]; const float* be=(const float*)d_in[11];
  const float* Wc=(const float*)d_in[12]; const float* bc=(const float*)d_in[13];
  const int* mask_t=(const int*)d_in[14]; const int* s_t=(const int*)d_in[15];
  const int* is_train = (n_in>16)? (const int*)d_in[16] : nullptr;
  float* out=(float*)d_out;

  float *h1,*h2,*h3,*d1,*d2,*d3,*fam,*xm,*att,*attp,*dz,*alpha,*ds,*dap,*mu,*m2,*dMu,*dE2,*gvec;
  float *cat,*ep,*cm,*tm,*meanT,*meanF,*wtf2,*wtb2,*wtf3,*wtb3;
  int *sc,*st,*rstep,*cstep;
  cudaGetSymbolAddress((void**)&h1,g_h1);   cudaGetSymbolAddress((void**)&h2,g_h2);
  cudaGetSymbolAddress((void**)&h3,g_h3);   cudaGetSymbolAddress((void**)&d1,g_d1);
  cudaGetSymbolAddress((void**)&d2,g_d2);   cudaGetSymbolAddress((void**)&d3,g_d3);
  cudaGetSymbolAddress((void**)&fam,g_fam); cudaGetSymbolAddress((void**)&xm,g_xm);
  cudaGetSymbolAddress((void**)&att,g_att); cudaGetSymbolAddress((void**)&attp,g_attp);
  cudaGetSymbolAddress((void**)&dz,g_dzb);
  cudaGetSymbolAddress((void**)&alpha,g_alpha); cudaGetSymbolAddress((void**)&ds,g_dsb);
  cudaGetSymbolAddress((void**)&dap,g_dap);
  cudaGetSymbolAddress((void**)&mu,g_mu);   cudaGetSymbolAddress((void**)&m2,g_m2);
  cudaGetSymbolAddress((void**)&dMu,g_dMu); cudaGetSymbolAddress((void**)&dE2,g_dE2);
  cudaGetSymbolAddress((void**)&gvec,g_gvec);
  cudaGetSymbolAddress((void**)&cat,g_cat); cudaGetSymbolAddress((void**)&ep,g_ep);
  cudaGetSymbolAddress((void**)&cm,g_cm);   cudaGetSymbolAddress((void**)&tm,g_tm);
  cudaGetSymbolAddress((void**)&meanT,g_meanT); cudaGetSymbolAddress((void**)&meanF,g_meanF);
  cudaGetSymbolAddress((void**)&sc,g_sc);   cudaGetSymbolAddress((void**)&st,g_st);
  cudaGetSymbolAddress((void**)&rstep,g_rstep); cudaGetSymbolAddress((void**)&cstep,g_cstep);
  cudaGetSymbolAddress((void**)&wtf2,g_wtf2); cudaGetSymbolAddress((void**)&wtb2,g_wtb2);
  cudaGetSymbolAddress((void**)&wtf3,g_wtf3); cudaGetSymbolAddress((void**)&wtb3,g_wtb3);

  const int MMA_SMEM = 120*136*4;
  cudaFuncSetAttribute(k_cmma<64,128,64,512,1>,  cudaFuncAttributeMaxDynamicSharedMemorySize, MMA_SMEM);
  cudaFuncSetAttribute(k_cmma<64,128,64,512,3>,  cudaFuncAttributeMaxDynamicSharedMemorySize, MMA_SMEM);
  cudaFuncSetAttribute(k_cmma<128,256,32,256,1>, cudaFuncAttributeMaxDynamicSharedMemorySize, MMA_SMEM);
  cudaFuncSetAttribute(k_cmma<128,256,32,256,3>, cudaFuncAttributeMaxDynamicSharedMemorySize, MMA_SMEM);

  // prep
  k_wt<<<288,256>>>(W2,wtf2,wtb2,64,128);
  k_wt<<<1152,256>>>(W3,wtf3,wtb3,128,256);
  k_gvec<<<1024,256>>>(We,Wc,gvec);
  // pass 1 forward convs stay 3xTF32 (exact ReLU masks + argsort-safe activations)
  k_conv_fwd<1,64,128,1024,1,16,4,256><<<dim3(8,64,32),256>>>(x,W1,b1,h1);
  k_cmma<64,128,64,512,3><<<dim3(2,32,32),256,MMA_SMEM>>>(h1,wtf2,b2,h2);
  k_cmma<128,256,32,256,3><<<dim3(2,16,32),256,MMA_SMEM>>>(h2,wtf3,b3,h3);
  run_tail<1>(h3,Wa,ba,va,attp,att,alpha,mu,m2);
  // backward to input: single-tf32 (additive noise only into fam)
  k_dcoef<<<512,256>>>(mu,m2,gvec,dMu,dE2);
  k_dalp<<<dim3(8,32),128>>>(h3,dMu,dE2,dap);
  k_dalf<<<32,128>>>(dap,alpha,ds);
  k_dz<<<2048,256>>>(att,ds,va,dz);
  k_dfeat_mma<1><<<dim3(32,32),256>>>(Wa,dz,h3,alpha,dMu,dE2,d3);
  k_cbmma<128,256,16,128,128,1><<<dim3(2,32,32),256>>>(d3,wtb3,h2,d2);
  k_cbmma<64,128,32,256,256,1><<<dim3(2,64,32),256>>>(d2,wtb2,h1,d1);
  k_bwd1<<<dim3(2,128,32),256>>>(d1,W1,fam);
  // masking
  k_rowstats<<<512,256>>>(fam,x,cm,meanT);
  k_colstats<<<128,256>>>(fam,x,tm,meanF);
  k_sort<128><<<32,64>>>(cm,sc);
  k_sort<1024><<<32,512>>>(tm,st);
  k_rfm<<<1,32>>>(sc,st,mask_t,s_t,is_train,rstep,cstep);
  k_apply<<<16384,256>>>(x,rstep,cstep,meanT,meanF,xm);
  // pass 2 (single tf32: continuous output path)
  k_conv_fwd<1,64,128,1024,1,16,4,256><<<dim3(8,64,32),256>>>(xm,W1,b1,h1);
  k_cmma<64,128,64,512,1><<<dim3(2,32,32),256,MMA_SMEM>>>(h1,wtf2,b2,h2);
  k_cmma<128,256,32,256,1><<<dim3(2,16,32),256,MMA_SMEM>>>(h2,wtf3,b3,h3);
  run_tail<1>(h3,Wa,ba,va,attp,att,alpha,mu,m2);
  k_cat<<<512,256>>>(mu,m2,cat);
  k_embp<<<128,256>>>(cat,We,ep);
  k_embf<<<32,256>>>(ep,be,Wc,bc,out);
}

// round 11
// speedup vs baseline: 3.3275x; 1.0070x over previous
#include <cuda_runtime.h>
#include <math.h>

// ---------- static scratch ----------
__device__ float g_h1[67108864];
__device__ float g_h2[33554432];
__device__ float g_h3[16777216];
__device__ float g_d1[67108864];
__device__ float g_d2[33554432];
__device__ float g_d3[16777216];
__device__ float g_fam[4194304];
__device__ float g_xm[4194304];
__device__ float g_att[524288];
__device__ float g_attp[4194304];
__device__ float g_dzb[524288];
__device__ float g_alpha[4096];
__device__ float g_dsb[4096];
__device__ float g_dap[32768];
__device__ float g_mu[131072];
__device__ float g_m2[131072];
__device__ float g_dMu[131072];
__device__ float g_dE2[131072];
__device__ float g_gvec[8192];
__device__ float g_cat[262144];
__device__ float g_ep[1048576];
__device__ float g_cm[4096];
__device__ float g_tm[32768];
__device__ float g_meanT[4096];
__device__ float g_meanF[32768];
__device__ int   g_sc[4096];
__device__ int   g_st[4096];
__device__ int   g_rstep[4096];
__device__ int   g_cstep[32768];
__device__ float g_wtf2[73728];
__device__ float g_wtb2[73728];
__device__ float g_wtf3[294912];
__device__ float g_wtb3[294912];

// ---------- weight transposes ----------
__global__ void k_wt(const float* __restrict__ W, float* __restrict__ WTf,
                     float* __restrict__ WTb, int CIN, int COUT)
{
  int idx=blockIdx.x*256+threadIdx.x;
  int tot=CIN*COUT*9; if(idx>=tot) return;
  int k=idx%9, c=(idx/9)%CIN, o=idx/(9*CIN);
  float v=W[idx];
  int rf=(c>>3)*72 + k*8 + (c&7);
  WTf[(long)rf*COUT+o]=v;
  int rb=(o>>3)*72 + k*8 + (o&7);
  WTb[(long)rb*CIN+c]=v;
}

// ---------- conv1 fwd (CIN=1, coalesced stores, vectorized LDS) ----------
__global__ void __launch_bounds__(256) k_conv1(
    const float* __restrict__ in, const float* __restrict__ W,
    const float* __restrict__ bias, float* __restrict__ out)
{
  // x:(n,128,1024) -> h1:(n,64,64,512); k=3 s=2 pad lo0 hi1, relu
  __shared__ __align__(16) float ins[3][132];
  __shared__ __align__(16) float ws[9][64];
  __shared__ float bs[64];
  const int n=blockIdx.z, i=blockIdx.y, j0=blockIdx.x*64;
  const int tid=threadIdx.x, jt=tid&15, og=tid>>4;
  for(int idx=tid; idx<576; idx+=256){
    int o=idx/9, k=idx%9;
    ws[k][o]=W[idx];
  }
  if(tid<64) bs[tid]=bias[tid];
  for(int idx=tid; idx<3*130; idx+=256){
    int r=idx/130, col=idx%130;
    int gx=2*i+r, gy=2*j0+col;
    float v=0.f;
    if(gx<128 && gy<1024) v=in[((long)n*128+gx)*1024+gy];
    ins[r][col]=v;
  }
  __syncthreads();
  float acc[4][4];
#pragma unroll
  for(int o=0;o<4;o++)
#pragma unroll
  for(int e=0;e<4;e++) acc[o][e]=0.f;
#pragma unroll
  for(int r=0;r<3;r++){
    float v[9];
    *(float4*)v     = *(float4*)&ins[r][8*jt];
    *(float4*)(v+4) = *(float4*)&ins[r][8*jt+4];
    v[8]            = ins[r][8*jt+8];
#pragma unroll
    for(int kj=0;kj<3;kj++){
      float w[4];
      *(float4*)w = *(float4*)&ws[r*3+kj][og*4];
#pragma unroll
      for(int oo=0;oo<4;oo++)
#pragma unroll
      for(int e=0;e<4;e++)
        acc[oo][e]+=w[oo]*v[2*e+kj];
    }
  }
#pragma unroll
  for(int oo=0;oo<4;oo++){
    int o=og*4+oo;
    float bb=bs[o];
    float4 r;
    r.x=fmaxf(acc[oo][0]+bb,0.f); r.y=fmaxf(acc[oo][1]+bb,0.f);
    r.z=fmaxf(acc[oo][2]+bb,0.f); r.w=fmaxf(acc[oo][3]+bb,0.f);
    *(float4*)&out[(((long)n*64+o)*64+i)*512 + j0 + 4*jt]=r;
  }
}

// ---------- tf32 helpers ----------
__device__ __forceinline__ float to_tf32(float v){
  unsigned r; asm("cvt.rna.tf32.f32 %0, %1;" : "=r"(r) : "f"(v));
  return __uint_as_float(r);
}
__device__ __forceinline__ void mma_tf32(float* c4,
    unsigned a0,unsigned a1,unsigned a2,unsigned a3,unsigned b0,unsigned b1){
  asm volatile(
    "mma.sync.aligned.m16n8k8.row.col.f32.tf32.tf32.f32 "
    "{%0,%1,%2,%3},{%4,%5,%6,%7},{%8,%9},{%0,%1,%2,%3};"
    : "+f"(c4[0]),"+f"(c4[1]),"+f"(c4[2]),"+f"(c4[3])
    : "r"(a0),"r"(a1),"r"(a2),"r"(a3),"r"(b0),"r"(b1));
}

// ---------- tf32 mma conv fwd (SPLIT=3 pass1, SPLIT=1 pass2) ----------
template<int CIN,int COUT,int HIN,int WIN,int SPLIT>
__global__ void __launch_bounds__(256,2) k_cmma(
    const float* __restrict__ in, const float* __restrict__ WT,
    const float* __restrict__ bias, float* __restrict__ out)
{
  constexpr int HOUT=HIN/2, WOUT=WIN/2;
  constexpr int NJT=WOUT/128;
  constexpr int LD=136;
  extern __shared__ float sm[];
  float* ev = sm;
  float* od = sm + 24*LD;
  float* ws = sm + 48*LD;
  const int n=blockIdx.z, i=blockIdx.y;
  const int jt_=blockIdx.x%NJT, ot=blockIdx.x/NJT;
  const int j0=jt_*128, o0=ot*128;
  const int tid=threadIdx.x, wid=tid>>5, lane=tid&31;
  const int gid=lane>>2, tig=lane&3;
  const int m0=(wid&3)*32, n0w=(wid>>2)*64;
  float acc[2][8][4];
#pragma unroll
  for(int a=0;a<2;a++)
#pragma unroll
  for(int b=0;b<8;b++)
#pragma unroll
  for(int c=0;c<4;c++) acc[a][b][c]=0.f;

  for(int c0=0;c0<CIN;c0+=8){
    __syncthreads();
    for(int idx=tid; idx<8*3*129; idx+=256){
      int c=idx/387, rem=idx%387, r=rem/129, p=rem%129;
      int gx=2*i+r, gy=2*j0+2*p;
      float a=0.f,bv=0.f;
      if(gx<HIN && gy<WIN){
        const float2 s=*(const float2*)&in[(((long)n*CIN+c0+c)*HIN+gx)*WIN+gy];
        a=s.x; bv=s.y;
      }
      ev[(c*3+r)*LD+p]=a;
      od[(c*3+r)*LD+p]=bv;
    }
    {
      const float* wsrc = WT + (long)(c0>>3)*72*COUT + o0;
      for(int idx=tid; idx<72*32; idx+=256){
        int kk=idx>>5, o4=(idx&31)*4;
        float4 v=*(const float4*)&wsrc[(long)kk*COUT + o4];
        *(float4*)&ws[kk*LD + o4]=v;
      }
    }
    __syncthreads();
#pragma unroll
    for(int kc=0;kc<9;kc++){
      const int r=kc/3, kj=kc%3;
      const float* src = (kj==1)? od : ev;
      const int co = (kj==2)? 1:0;
      unsigned bh[8][2], bl[8][2];
#pragma unroll
      for(int f=0;f<8;f++){
        float v0 = src[(tig*3+r)*LD + n0w + f*8 + gid + co];
        float v1 = src[((tig+4)*3+r)*LD + n0w + f*8 + gid + co];
        float h0=to_tf32(v0), h1=to_tf32(v1);
        bh[f][0]=__float_as_uint(h0); bh[f][1]=__float_as_uint(h1);
        if(SPLIT==3){
          bl[f][0]=__float_as_uint(to_tf32(v0-h0));
          bl[f][1]=__float_as_uint(to_tf32(v1-h1));
        }
      }
#pragma unroll
      for(int mf=0;mf<2;mf++){
        float w0=ws[(kc*8+tig)*LD + m0+mf*16+gid];
        float w1=ws[(kc*8+tig)*LD + m0+mf*16+gid+8];
        float w2=ws[(kc*8+tig+4)*LD + m0+mf*16+gid];
        float w3=ws[(kc*8+tig+4)*LD + m0+mf*16+gid+8];
        float h0=to_tf32(w0),h1=to_tf32(w1),h2=to_tf32(w2),h3=to_tf32(w3);
        unsigned ah0=__float_as_uint(h0),ah1=__float_as_uint(h1),
                 ah2=__float_as_uint(h2),ah3=__float_as_uint(h3);
        unsigned al0=0,al1=0,al2=0,al3=0;
        if(SPLIT==3){
          al0=__float_as_uint(to_tf32(w0-h0)); al1=__float_as_uint(to_tf32(w1-h1));
          al2=__float_as_uint(to_tf32(w2-h2)); al3=__float_as_uint(to_tf32(w3-h3));
        }
#pragma unroll
        for(int f=0;f<8;f++){
          mma_tf32(acc[mf][f], ah0,ah1,ah2,ah3, bh[f][0],bh[f][1]);
          if(SPLIT==3){
            mma_tf32(acc[mf][f], ah0,ah1,ah2,ah3, bl[f][0],bl[f][1]);
            mma_tf32(acc[mf][f], al0,al1,al2,al3, bh[f][0],bh[f][1]);
          }
        }
      }
    }
  }
#pragma unroll
  for(int mf=0;mf<2;mf++){
    int oA=o0+m0+mf*16+gid, oB=oA+8;
    float bA=bias[oA], bB=bias[oB];
#pragma unroll
    for(int f=0;f<8;f++){
      int jj=j0 + n0w + f*8 + tig*2;
      long baseA=(((long)n*COUT+oA)*HOUT+i)*WOUT + jj;
      long baseB=(((long)n*COUT+oB)*HOUT+i)*WOUT + jj;
      float2 rA, rB;
      rA.x=fmaxf(acc[mf][f][0]+bA,0.f); rA.y=fmaxf(acc[mf][f][1]+bA,0.f);
      rB.x=fmaxf(acc[mf][f][2]+bB,0.f); rB.y=fmaxf(acc[mf][f][3]+bB,0.f);
      *(float2*)&out[baseA]=rA;
      *(float2*)&out[baseB]=rB;
    }
  }
}

// ---------- tf32 mma transposed-conv bwd ----------
template<int CIN,int COUT,int HOUT,int WOUT,int NT,int SPLIT>
__global__ void __launch_bounds__(256,2) k_cbmma(
    const float* __restrict__ dout, const float* __restrict__ WT,
    const float* __restrict__ act, float* __restrict__ din)
{
  constexpr int HIN=2*HOUT, WIN=2*WOUT;
  constexpr int LDW=CIN+8, LDD=NT/2+4, JL=NT/2+2;
  constexpr int NW_M=CIN/32;
  __shared__ float ws[72*LDW];
  __shared__ float dsA[8*LDD];
  __shared__ float dsB[8*LDD];
  const int n=blockIdx.z, x=blockIdx.y, y0=blockIdx.x*NT;
  const int tid=threadIdx.x, wid=tid>>5, lane=tid&31;
  const int gid=lane>>2, tig=lane&3;
  const int m0=(wid%NW_M)*32, n0=(wid/NW_M)*64;
  const bool xe=((x&1)==0);
  const int iA = xe ? (x>>1) : ((x-1)>>1);
  const int iB = (x>>1)-1;
  const bool hasB = xe && iB>=0;
  const int jb = y0/2 - 1;
  float acc_e[2][4][4], acc_o[2][4][4];
#pragma unroll
  for(int a=0;a<2;a++)
#pragma unroll
  for(int b=0;b<4;b++)
#pragma unroll
  for(int c=0;c<4;c++){acc_e[a][b][c]=0.f; acc_o[a][b][c]=0.f;}

  for(int o0=0;o0<COUT;o0+=8){
    __syncthreads();
    {
      const float* wsrc = WT + (long)(o0>>3)*72*CIN;
      for(int idx=tid; idx<72*(CIN/4); idx+=256){
        int r=idx/(CIN/4), c4=(idx%(CIN/4))*4;
        float4 v=*(const float4*)&wsrc[(long)r*CIN+c4];
        *(float4*)&ws[r*LDW+c4]=v;
      }
    }
    for(int idx=tid; idx<8*JL; idx+=256){
      int o=idx/JL, jl=idx%JL; int j=jb+jl;
      float a=0.f,bv=0.f;
      if(j>=0 && j<WOUT){
        long base=((long)n*COUT+o0+o)*HOUT;
        a = dout[(base+iA)*WOUT+j];
        if(hasB) bv = dout[(base+iB)*WOUT+j];
      }
      dsA[o*LDD+jl]=a; dsB[o*LDD+jl]=bv;
    }
    __syncthreads();

    auto proc = [&](const float* ds, const int tapBase){
      unsigned b1h[4][2], b0h[4][2], b1l[4][2], b0l[4][2];
#pragma unroll
      for(int f=0;f<4;f++){
        int cbase = n0/2 + f*8 + gid;
        float v1a = ds[tig*LDD + cbase + 1];
        float v1b = ds[(tig+4)*LDD + cbase + 1];
        float v0a = ds[tig*LDD + cbase];
        float v0b = ds[(tig+4)*LDD + cbase];
        float h1a=to_tf32(v1a), h1b=to_tf32(v1b);
        float h0a=to_tf32(v0a), h0b=to_tf32(v0b);
        b1h[f][0]=__float_as_uint(h1a); b1h[f][1]=__float_as_uint(h1b);
        b0h[f][0]=__float_as_uint(h0a); b0h[f][1]=__float_as_uint(h0b);
        if(SPLIT==3){
          b1l[f][0]=__float_as_uint(to_tf32(v1a-h1a));
          b1l[f][1]=__float_as_uint(to_tf32(v1b-h1b));
          b0l[f][0]=__float_as_uint(to_tf32(v0a-h0a));
          b0l[f][1]=__float_as_uint(to_tf32(v0b-h0b));
        }
      }
#pragma unroll
      for(int kj=0;kj<3;kj++){
        const int tap=tapBase+kj;
#pragma unroll
        for(int mf=0;mf<2;mf++){
          float w0=ws[(tap*8+tig)*LDW + m0+mf*16+gid];
          float w1=ws[(tap*8+tig)*LDW + m0+mf*16+gid+8];
          float w2=ws[(tap*8+tig+4)*LDW + m0+mf*16+gid];
          float w3=ws[(tap*8+tig+4)*LDW + m0+mf*16+gid+8];
          float h0=to_tf32(w0),h1=to_tf32(w1),h2=to_tf32(w2),h3=to_tf32(w3);
          unsigned ah0=__float_as_uint(h0),ah1=__float_as_uint(h1),
                   ah2=__float_as_uint(h2),ah3=__float_as_uint(h3);
          unsigned al0=0,al1=0,al2=0,al3=0;
          if(SPLIT==3){
            al0=__float_as_uint(to_tf32(w0-h0)); al1=__float_as_uint(to_tf32(w1-h1));
            al2=__float_as_uint(to_tf32(w2-h2)); al3=__float_as_uint(to_tf32(w3-h3));
          }
#pragma unroll
          for(int f=0;f<4;f++){
            float* c4 = (kj==1)? acc_o[mf][f] : acc_e[mf][f];
            const unsigned* bh = (kj==2)? b0h[f] : b1h[f];
            const unsigned* bl = (kj==2)? b0l[f] : b1l[f];
            mma_tf32(c4, ah0,ah1,ah2,ah3, bh[0],bh[1]);
            if(SPLIT==3){
              mma_tf32(c4, ah0,ah1,ah2,ah3, bl[0],bl[1]);
              mma_tf32(c4, al0,al1,al2,al3, bh[0],bh[1]);
            }
          }
        }
      }
    };
    proc(dsA, xe?0:3);
    if(hasB) proc(dsB, 6);
  }

#pragma unroll
  for(int mf=0;mf<2;mf++){
    int c0_=m0+mf*16+gid;
#pragma unroll
    for(int f=0;f<4;f++){
      int Y = y0 + n0 + 2*(f*8 + 2*tig);
      long b0i=(((long)n*CIN+c0_)*HIN+x)*WIN + Y;
      long b1i=(((long)n*CIN+c0_+8)*HIN+x)*WIN + Y;
      float2 m, r;
      m=*(const float2*)&act[b0i];
      r.x = m.x>0.f? acc_e[mf][f][0]:0.f; r.y = m.y>0.f? acc_o[mf][f][0]:0.f;
      *(float2*)&din[b0i]=r;
      m=*(const float2*)&act[b0i+2];
      r.x = m.x>0.f? acc_e[mf][f][1]:0.f; r.y = m.y>0.f? acc_o[mf][f][1]:0.f;
      *(float2*)&din[b0i+2]=r;
      m=*(const float2*)&act[b1i];
      r.x = m.x>0.f? acc_e[mf][f][2]:0.f; r.y = m.y>0.f? acc_o[mf][f][2]:0.f;
      *(float2*)&din[b1i]=r;
      m=*(const float2*)&act[b1i+2];
      r.x = m.x>0.f? acc_e[mf][f][3]:0.f; r.y = m.y>0.f? acc_o[mf][f][3]:0.f;
      *(float2*)&din[b1i+2]=r;
    }
  }
}

// ---------- conv1 data-grad -> |dx| ----------
__global__ void __launch_bounds__(256) k_bwd1(
    const float* __restrict__ dz1, const float* __restrict__ W1,
    float* __restrict__ fam)
{
  __shared__ float ws[576];
  __shared__ float dsm[8*2*260];
  const int n=blockIdx.z, x=blockIdx.y, y0=blockIdx.x*512;
  const int tid=threadIdx.x;
  for(int idx=tid; idx<576; idx+=256) ws[idx]=W1[idx];
  int iA,iB,kiA,kiB; bool hasB;
  if((x&1)==0){iA=x>>1;kiA=0;iB=iA-1;kiB=2;hasB=(iB>=0);}
  else{iA=(x-1)>>1;kiA=1;iB=0;kiB=0;hasB=false;}
  const int jbase=y0/2-1;
  float accE=0.f, accO=0.f;
  for(int o0=0;o0<64;o0+=8){
    __syncthreads();
    for(int idx=tid; idx<8*2*260; idx+=256){
      int o=idx/520, rs=(idx/260)&1, jj=idx%260;
      int j=jbase+jj; int ir=rs?iB:iA;
      float v=0.f;
      if(j>=0 && j<512 && (rs==0||hasB))
        v=dz1[(((long)n*64+o0+o)*64+ir)*512+j];
      dsm[idx]=v;
    }
    __syncthreads();
#pragma unroll
    for(int o=0;o<8;o++){
#pragma unroll
      for(int rs=0;rs<2;rs++){
        if(rs==1&&!hasB) break;
        int ki=rs?kiB:kiA;
        const float* wb=&ws[(o0+o)*9+ki*3];
        float vm=dsm[(o*2+rs)*260+tid], v0=dsm[(o*2+rs)*260+tid+1];
        accE+=wb[0]*v0+wb[2]*vm; accO+=wb[1]*v0;
      }
    }
  }
  long base=((long)n*128+x)*1024 + y0 + 2*tid;
  fam[base]=fabsf(accE); fam[base+1]=fabsf(accO);
}

// ---------- att partial GEMM (tf32 mma, split-K) ----------
template<int SPLIT>
__global__ void __launch_bounds__(256) k_attp_mma(
    const float* __restrict__ Wa, const float* __restrict__ feat,
    float* __restrict__ attp)
{
  constexpr int LDA=129, LDB=132;
  __shared__ float As[32*LDA];   // [k][h]
  __shared__ float Bs[32*LDB];   // [k][t]
  const int ks=blockIdx.x, b=blockIdx.y;
  const int tid=threadIdx.x, wid=tid>>5, lane=tid&31;
  const int gid=lane>>2, tig=lane&3;
  const int m0=(wid&3)*32, n0=(wid>>2)*64;
  const float* fb = feat + (long)b*524288;
  float acc[2][8][4];
#pragma unroll
  for(int a=0;a<2;a++)
#pragma unroll
  for(int bq=0;bq<8;bq++)
#pragma unroll
  for(int c=0;c<4;c++) acc[a][bq][c]=0.f;

  for(int k0=ks*512; k0<ks*512+512; k0+=32){
    __syncthreads();
    for(int idx=tid; idx<4096; idx+=256){
      int h=idx>>5, kk=idx&31;
      As[kk*LDA+h]=Wa[(long)h*4096+k0+kk];
    }
    for(int idx=tid; idx<4096; idx+=256){
      int kk=idx>>7, t=idx&127;
      Bs[kk*LDB+t]=fb[(long)(k0+kk)*128+t];
    }
    __syncthreads();
#pragma unroll
    for(int kc=0;kc<4;kc++){
      const int kb=kc*8;
      unsigned bh[8][2], bl[8][2];
#pragma unroll
      for(int f=0;f<8;f++){
        float v0=Bs[(kb+tig)*LDB + n0+f*8+gid];
        float v1=Bs[(kb+tig+4)*LDB + n0+f*8+gid];
        float h0=to_tf32(v0), h1=to_tf32(v1);
        bh[f][0]=__float_as_uint(h0); bh[f][1]=__float_as_uint(h1);
        if(SPLIT==3){
          bl[f][0]=__float_as_uint(to_tf32(v0-h0));
          bl[f][1]=__float_as_uint(to_tf32(v1-h1));
        }
      }
#pragma unroll
      for(int mf=0;mf<2;mf++){
        float w0=As[(kb+tig)*LDA + m0+mf*16+gid];
        float w1=As[(kb+tig)*LDA + m0+mf*16+gid+8];
        float w2=As[(kb+tig+4)*LDA + m0+mf*16+gid];
        float w3=As[(kb+tig+4)*LDA + m0+mf*16+gid+8];
        float h0=to_tf32(w0),h1=to_tf32(w1),h2=to_tf32(w2),h3=to_tf32(w3);
        unsigned ah0=__float_as_uint(h0),ah1=__float_as_uint(h1),
                 ah2=__float_as_uint(h2),ah3=__float_as_uint(h3);
        unsigned al0=0,al1=0,al2=0,al3=0;
        if(SPLIT==3){
          al0=__float_as_uint(to_tf32(w0-h0)); al1=__float_as_uint(to_tf32(w1-h1));
          al2=__float_as_uint(to_tf32(w2-h2)); al3=__float_as_uint(to_tf32(w3-h3));
        }
#pragma unroll
        for(int f=0;f<8;f++){
          mma_tf32(acc[mf][f], ah0,ah1,ah2,ah3, bh[f][0],bh[f][1]);
          if(SPLIT==3){
            mma_tf32(acc[mf][f], ah0,ah1,ah2,ah3, bl[f][0],bl[f][1]);
            mma_tf32(acc[mf][f], al0,al1,al2,al3, bh[f][0],bh[f][1]);
          }
        }
      }
    }
  }
#pragma unroll
  for(int mf=0;mf<2;mf++){
    int hA=m0+mf*16+gid, hB=hA+8;
#pragma unroll
    for(int f=0;f<8;f++){
      int t=n0+f*8+tig*2;
      float2 rA, rB;
      rA.x=acc[mf][f][0]; rA.y=acc[mf][f][1];
      rB.x=acc[mf][f][2]; rB.y=acc[mf][f][3];
      *(float2*)&attp[(long)ks*524288 + ((long)b*128+hA)*128+t]=rA;
      *(float2*)&attp[(long)ks*524288 + ((long)b*128+hB)*128+t]=rB;
    }
  }
}
__global__ void k_attf(const float* __restrict__ attp, const float* __restrict__ ba,
                       float* __restrict__ att)
{
  int i=blockIdx.x*256+threadIdx.x; if(i>=524288) return;
  int h=(i>>7)&127;
  float s=0.f;
#pragma unroll
  for(int ks=0;ks<8;ks++) s+=attp[(long)ks*524288+i];
  att[i]=tanhf(s+ba[h]);
}

// ---------- softmax ----------
__global__ void __launch_bounds__(128) k_salpha(
    const float* __restrict__ att, const float* __restrict__ va,
    float* __restrict__ alpha)
{
  __shared__ float vs[128], buf[128];
  const int b=blockIdx.x, t=threadIdx.x;
  vs[t]=va[t];
  __syncthreads();
  float s=0.f;
#pragma unroll 4
  for(int h=0;h<128;h++) s+=vs[h]*att[((long)b*128+h)*128+t];
  buf[t]=s; __syncthreads();
  for(int off=64;off;off>>=1){ if(t<off) buf[t]=fmaxf(buf[t],buf[t+off]); __syncthreads(); }
  float mx=buf[0]; __syncthreads();
  float e=expf(s-mx);
  buf[t]=e; __syncthreads();
  for(int off=64;off;off>>=1){ if(t<off) buf[t]+=buf[t+off]; __syncthreads(); }
  alpha[b*128+t]=e/buf[0];
}

// ---------- mu, m2 ----------
__global__ void k_mustats(const float* __restrict__ feat,
    const float* __restrict__ alpha, float* __restrict__ mu, float* __restrict__ m2)
{
  int w=(blockIdx.x*blockDim.x+threadIdx.x)>>5, lane=threadIdx.x&31;
  if(w>=131072) return;
  int b=w>>12;
  const float* fr=feat+(long)w*128;
  const float* ar=alpha+b*128;
  float s1=0.f,s2=0.f;
#pragma unroll
  for(int t=lane;t<128;t+=32){
    float a=ar[t], f=fr[t];
    s1+=a*f; s2+=a*f*f;
  }
  for(int o=16;o;o>>=1){ s1+=__shfl_down_sync(~0u,s1,o); s2+=__shfl_down_sync(~0u,s2,o); }
  if(!lane){ mu[w]=s1; m2[w]=s2; }
}

// ---------- gvec ----------
__global__ void k_gvec(const float* __restrict__ We,const float* __restrict__ Wc,
                       float* __restrict__ gvec)
{
  int w=(blockIdx.x*blockDim.x+threadIdx.x)>>5, lane=threadIdx.x&31;
  if(w>=8192) return;
  float s=0.f;
  for(int j=lane;j<256;j+=32) s+=We[(long)w*256+j]*(Wc[j*2+1]-Wc[j*2]);
  for(int o=16;o;o>>=1) s+=__shfl_down_sync(~0u,s,o);
  if(!lane) gvec[w]=s;
}

// ---------- dMu,dE2 ----------
__global__ void k_dcoef(const float* __restrict__ mu,const float* __restrict__ m2,
    const float* __restrict__ gvec, float* __restrict__ dMu,float* __restrict__ dE2)
{
  int i=blockIdx.x*256+threadIdx.x; if(i>=131072) return;
  int d=i&4095;
  float m=mu[i], v=m2[i]-m*m;
  float g2=gvec[4096+d];
  float dE=0.f, dM=gvec[d];
  if(v>1e-5f){ float sg=sqrtf(v); dE=0.5f*g2/sg; dM-=g2*m/sg; }
  dMu[i]=dM; dE2[i]=dE;
}

// ---------- dalpha ----------
__global__ void __launch_bounds__(128) k_dalp(
    const float* __restrict__ feat,const float* __restrict__ dMu,
    const float* __restrict__ dE2,float* __restrict__ part)
{
  const int ks=blockIdx.x, b=blockIdx.y, t=threadIdx.x;
  const float* fb=feat+(long)b*524288;
  const float* dm=dMu+b*4096; const float* de=dE2+b*4096;
  float acc=0.f;
  int d0=ks*512;
#pragma unroll 4
  for(int d=d0;d<d0+512;d++){
    float f=fb[(long)d*128+t];
    acc+=dm[d]*f+de[d]*f*f;
  }
  part[(ks*32+b)*128+t]=acc;
}
__global__ void __launch_bounds__(128) k_dalf(
    const float* __restrict__ part,const float* __restrict__ alpha,
    float* __restrict__ ds)
{
  const int b=blockIdx.x, t=threadIdx.x;
  float acc=0.f;
#pragma unroll
  for(int ks=0;ks<8;ks++) acc+=part[(ks*32+b)*128+t];
  __shared__ float buf[128];
  float a=alpha[b*128+t];
  buf[t]=a*acc; __syncthreads();
  for(int off=64;off;off>>=1){ if(t<off) buf[t]+=buf[t+off]; __syncthreads(); }
  ds[b*128+t]=a*(acc-buf[0]);
}

// ---------- dz ----------
__global__ void k_dz(const float* __restrict__ att,const float* __restrict__ ds,
    const float* __restrict__ va,float* __restrict__ dz)
{
  int i=blockIdx.x*256+threadIdx.x; if(i>=524288) return;
  int t=i&127, h=(i>>7)&127, b=i>>14;
  float a=att[i];
  dz[i]=va[h]*ds[b*128+t]*(1.f-a*a);
}

// ---------- dfeat (tf32 mma) + fused pointwise/mask epilogue ----------
template<int SPLIT>
__global__ void __launch_bounds__(256) k_dfeat_mma(
    const float* __restrict__ Wa, const float* __restrict__ dz,
    const float* __restrict__ feat, const float* __restrict__ alpha,
    const float* __restrict__ dMu, const float* __restrict__ dE2,
    float* __restrict__ dout3)
{
  constexpr int LDA=132, LDB=132;
  __shared__ float As[32*LDA];  // [k][d]
  __shared__ float Bs[32*LDB];  // [k][t]
  __shared__ float al[128];
  const int d0=blockIdx.x*128, b=blockIdx.y;
  const int tid=threadIdx.x, wid=tid>>5, lane=tid&31;
  const int gid=lane>>2, tig=lane&3;
  const int m0=(wid&3)*32, n0=(wid>>2)*64;
  if(tid<128) al[tid]=alpha[b*128+tid];
  float acc[2][8][4];
#pragma unroll
  for(int a=0;a<2;a++)
#pragma unroll
  for(int bq=0;bq<8;bq++)
#pragma unroll
  for(int c=0;c<4;c++) acc[a][bq][c]=0.f;

  for(int k0=0;k0<128;k0+=32){
    __syncthreads();
    for(int idx=tid; idx<4096; idx+=256){
      int kk=idx>>7, dd=idx&127;
      As[kk*LDA+dd]=Wa[(long)(k0+kk)*4096+d0+dd];
    }
    for(int idx=tid; idx<4096; idx+=256){
      int kk=idx>>7, t=idx&127;
      Bs[kk*LDB+t]=dz[((long)b*128+k0+kk)*128+t];
    }
    __syncthreads();
#pragma unroll
    for(int kc=0;kc<4;kc++){
      const int kb=kc*8;
      unsigned bh[8][2], bl[8][2];
#pragma unroll
      for(int f=0;f<8;f++){
        float v0=Bs[(kb+tig)*LDB + n0+f*8+gid];
        float v1=Bs[(kb+tig+4)*LDB + n0+f*8+gid];
        float h0=to_tf32(v0), h1=to_tf32(v1);
        bh[f][0]=__float_as_uint(h0); bh[f][1]=__float_as_uint(h1);
        if(SPLIT==3){
          bl[f][0]=__float_as_uint(to_tf32(v0-h0));
          bl[f][1]=__float_as_uint(to_tf32(v1-h1));
        }
      }
#pragma unroll
      for(int mf=0;mf<2;mf++){
        float w0=As[(kb+tig)*LDA + m0+mf*16+gid];
        float w1=As[(kb+tig)*LDA + m0+mf*16+gid+8];
        float w2=As[(kb+tig+4)*LDA + m0+mf*16+gid];
        float w3=As[(kb+tig+4)*LDA + m0+mf*16+gid+8];
        float h0=to_tf32(w0),h1=to_tf32(w1),h2=to_tf32(w2),h3=to_tf32(w3);
        unsigned ah0=__float_as_uint(h0),ah1=__float_as_uint(h1),
                 ah2=__float_as_uint(h2),ah3=__float_as_uint(h3);
        unsigned al0=0,al1=0,al2=0,al3=0;
        if(SPLIT==3){
          al0=__float_as_uint(to_tf32(w0-h0)); al1=__float_as_uint(to_tf32(w1-h1));
          al2=__float_as_uint(to_tf32(w2-h2)); al3=__float_as_uint(to_tf32(w3-h3));
        }
#pragma unroll
        for(int f=0;f<8;f++){
          mma_tf32(acc[mf][f], ah0,ah1,ah2,ah3, bh[f][0],bh[f][1]);
          if(SPLIT==3){
            mma_tf32(acc[mf][f], ah0,ah1,ah2,ah3, bl[f][0],bl[f][1]);
            mma_tf32(acc[mf][f], al0,al1,al2,al3, bh[f][0],bh[f][1]);
          }
        }
      }
    }
  }
#pragma unroll
  for(int mf=0;mf<2;mf++){
    int dA=d0+m0+mf*16+gid, dB=dA+8;
    float dmA=dMu[(long)b*4096+dA], deA=dE2[(long)b*4096+dA];
    float dmB=dMu[(long)b*4096+dB], deB=dE2[(long)b*4096+dB];
#pragma unroll
    for(int f=0;f<8;f++){
      int t=n0+f*8+tig*2;
      long fiA=((long)b*4096+dA)*128+t;
      long fiB=((long)b*4096+dB)*128+t;
      float2 fvA=*(const float2*)&feat[fiA];
      float2 fvB=*(const float2*)&feat[fiB];
      float2 rA, rB;
      rA.x = fvA.x>0.f? (acc[mf][f][0]+al[t]*(dmA+2.f*deA*fvA.x)) : 0.f;
      rA.y = fvA.y>0.f? (acc[mf][f][1]+al[t+1]*(dmA+2.f*deA*fvA.y)) : 0.f;
      rB.x = fvB.x>0.f? (acc[mf][f][2]+al[t]*(dmB+2.f*deB*fvB.x)) : 0.f;
      rB.y = fvB.y>0.f? (acc[mf][f][3]+al[t+1]*(dmB+2.f*deB*fvB.y)) : 0.f;
      *(float2*)&dout3[fiA]=rA;
      *(float2*)&dout3[fiB]=rB;
    }
  }
}

// ---------- row/col stats ----------
__global__ void k_rowstats(const float* __restrict__ fam,const float* __restrict__ x,
    float* __restrict__ cm,float* __restrict__ meanT)
{
  int w=(blockIdx.x*blockDim.x+threadIdx.x)>>5, lane=threadIdx.x&31;
  if(w>=4096) return;
  const float* fr=fam+(long)w*1024; const float* xr=x+(long)w*1024;
  float m=-1e30f, s=0.f;
  for(int t=lane;t<1024;t+=32){ m=fmaxf(m,fr[t]); s+=xr[t]; }
  for(int o=16;o;o>>=1){ m=fmaxf(m,__shfl_down_sync(~0u,m,o)); s+=__shfl_down_sync(~0u,s,o); }
  if(!lane){ cm[w]=m; meanT[w]=s*(1.f/1024.f); }
}
__global__ void k_colstats(const float* __restrict__ fam,const float* __restrict__ x,
    float* __restrict__ tm,float* __restrict__ meanF)
{
  int i=blockIdx.x*256+threadIdx.x; if(i>=32768) return;
  int b=i>>10, t=i&1023;
  const float* fb=fam+(long)b*131072+t; const float* xb=x+(long)b*131072+t;
  float m=-1e30f, s=0.f;
#pragma unroll 4
  for(int f=0;f<128;f++){ m=fmaxf(m,fb[f*1024]); s+=xb[f*1024]; }
  tm[i]=m; meanF[i]=s*(1.f/128.f);
}

// ---------- bitonic argsort ----------
template<int N>
__global__ void k_sort(const float* __restrict__ vals, int* __restrict__ idxout)
{
  __shared__ unsigned long long key[N];
  const int b=blockIdx.x, tid=threadIdx.x, TH=N/2;
  for(int i=tid;i<N;i+=TH){
    unsigned u=__float_as_uint(vals[b*N+i]);
    u = (u&0x80000000u)? ~u : (u|0x80000000u);
    key[i]=((unsigned long long)(~u)<<32)|(unsigned)i;
  }
  __syncthreads();
  for(int k=2;k<=N;k<<=1)
    for(int j=k>>1;j;j>>=1){
      for(int i=tid;i<N;i+=TH){
        int ixj=i^j;
        if(ixj>i){
          bool up=((i&k)==0);
          unsigned long long a=key[i],c=key[ixj];
          if((a>c)==up){ key[i]=c; key[ixj]=a; }
        }
      }
      __syncthreads();
    }
  for(int i=tid;i<128;i+=TH) idxout[b*128+i]=(int)(key[i]&0xFFFFFFFFu);
}

// ---------- RFM scan ----------
__global__ void k_rfm(const int* __restrict__ sc,const int* __restrict__ st,
    const int* __restrict__ mask_t,const int* __restrict__ s_t,
    const int* __restrict__ is_train,int* __restrict__ rstep,int* __restrict__ cstep)
{
  int b=threadIdx.x; if(b>=32) return;
  int* rs=rstep+b*128; int* cs=cstep+b*1024;
  for(int i=0;i<128;i++) rs[i]=-1;
  for(int i=0;i<1024;i++) cs[i]=-1;
  if(is_train && is_train[0]==0) return;
  int cnt=0;
  for(int s=0;s<128 && cnt<3;s++){
    int pc=sc[b*128+s], pt=st[b*128+s];
    if(rs[pc]!=-1||cs[pt]!=-1) continue;
    int mt=mask_t[b*128+s], ss=s_t[b*128+s];
    rs[pc]=s;
    int l=pt-ss; if(l<0)l=0;
    int r=pt+mt-ss; if(r>1024)r=1024;
    for(int t=l;t<r;t++) cs[t]=s;
    cnt++;
  }
}

// ---------- apply mask ----------
__global__ void k_apply(const float* __restrict__ x,const int* __restrict__ rstep,
    const int* __restrict__ cstep,const float* __restrict__ meanT,
    const float* __restrict__ meanF,float* __restrict__ xm)
{
  long i=(long)blockIdx.x*256+threadIdx.x; if(i>=4194304) return;
  int t=(int)(i&1023); int f=(int)((i>>10)&127); int b=(int)(i>>17);
  int rs=rstep[b*128+f], cs=cstep[b*1024+t];
  float v;
  if(rs<0&&cs<0) v=x[i];
  else v=(cs>=rs)? meanT[b*128+f] : meanF[b*1024+t];
  xm[i]=v;
}

// ---------- emb head ----------
__global__ void k_cat(const float* __restrict__ mu,const float* __restrict__ m2,
                      float* __restrict__ cat)
{
  int i=blockIdx.x*256+threadIdx.x; if(i>=131072) return;
  int b=i>>12, d=i&4095;
  float m=mu[i];
  cat[(long)b*8192+d]=m;
  cat[(long)b*8192+4096+d]=sqrtf(fmaxf(m2[i]-m*m,1e-5f));
}
__global__ void __launch_bounds__(256) k_embp(
    const float* __restrict__ cat,const float* __restrict__ We,
    float* __restrict__ part)
{
  __shared__ float cs[32][64];
  const int ks=blockIdx.x, j=threadIdx.x;
  for(int idx=j; idx<32*64; idx+=256){
    int b=idx>>6, ii=idx&63;
    cs[b][ii]=cat[(long)b*8192 + ks*64 + ii];
  }
  __syncthreads();
  float acc[32];
#pragma unroll
  for(int b=0;b<32;b++) acc[b]=0.f;
  for(int ii=0;ii<64;ii++){
    float w=We[((long)ks*64+ii)*256+j];
#pragma unroll
    for(int b=0;b<32;b++) acc[b]+=cs[b][ii]*w;
  }
#pragma unroll
  for(int b=0;b<32;b++) part[((long)ks*32+b)*256+j]=acc[b];
}
__global__ void __launch_bounds__(256) k_embf(
    const float* __restrict__ part,const float* __restrict__ be,
    const float* __restrict__ Wc,const float* __restrict__ bc,
    float* __restrict__ out)
{
  const int b=blockIdx.x, j=threadIdx.x;
  float s=be[j];
  for(int ks=0;ks<128;ks++) s+=part[((long)ks*32+b)*256+j];
  __shared__ float es[256];
  es[j]=s; __syncthreads();
  if(j<2){
    float acc=bc[j];
    for(int q=0;q<256;q++) acc+=es[q]*Wc[q*2+j];
    out[b*2+j]=acc;
  }
}

// ---------- host ----------
template<int SPLIT>
static void run_tail(const float* h3,const float* Wa,const float* ba,const float* va,
                     float* attp,float* att,float* alpha,float* mu,float* m2)
{
  k_attp_mma<SPLIT><<<dim3(8,32),256>>>(Wa,h3,attp);
  k_attf<<<2048,256>>>(attp,ba,att);
  k_salpha<<<32,128>>>(att,va,alpha);
  k_mustats<<<16384,256>>>(h3,alpha,mu,m2);
}

extern "C" void kernel_launch(void* const* d_in,const int* in_sizes,int n_in,
                              void* d_out,int out_size)
{
  const float* x =(const float*)d_in[0];
  const float* W1=(const float*)d_in[1]; const float* b1=(const float*)d_in[2];
  const float* W2=(const float*)d_in[3]; const float* b2=(const float*)d_in[4];
  const float* W3=(const float*)d_in[5]; const float* b3=(const float*)d_in[6];
  const float* Wa=(const float*)d_in[7]; const float* ba=(const float*)d_in[8];
  const float* va=(const float*)d_in[9];
  const float* We=(const float*)d_in[10]; const float* be=(const float*)d_in[11];
  const float* Wc=(const float*)d_in[12]; const float* bc=(const float*)d_in[13];
  const int* mask_t=(const int*)d_in[14]; const int* s_t=(const int*)d_in[15];
  const int* is_train = (n_in>16)? (const int*)d_in[16] : nullptr;
  float* out=(float*)d_out;

  float *h1,*h2,*h3,*d1,*d2,*d3,*fam,*xm,*att,*attp,*dz,*alpha,*ds,*dap,*mu,*m2,*dMu,*dE2,*gvec;
  float *cat,*ep,*cm,*tm,*meanT,*meanF,*wtf2,*wtb2,*wtf3,*wtb3;
  int *sc,*st,*rstep,*cstep;
  cudaGetSymbolAddress((void**)&h1,g_h1);   cudaGetSymbolAddress((void**)&h2,g_h2);
  cudaGetSymbolAddress((void**)&h3,g_h3);   cudaGetSymbolAddress((void**)&d1,g_d1);
  cudaGetSymbolAddress((void**)&d2,g_d2);   cudaGetSymbolAddress((void**)&d3,g_d3);
  cudaGetSymbolAddress((void**)&fam,g_fam); cudaGetSymbolAddress((void**)&xm,g_xm);
  cudaGetSymbolAddress((void**)&att,g_att); cudaGetSymbolAddress((void**)&attp,g_attp);
  cudaGetSymbolAddress((void**)&dz,g_dzb);
  cudaGetSymbolAddress((void**)&alpha,g_alpha); cudaGetSymbolAddress((void**)&ds,g_dsb);
  cudaGetSymbolAddress((void**)&dap,g_dap);
  cudaGetSymbolAddress((void**)&mu,g_mu);   cudaGetSymbolAddress((void**)&m2,g_m2);
  cudaGetSymbolAddress((void**)&dMu,g_dMu); cudaGetSymbolAddress((void**)&dE2,g_dE2);
  cudaGetSymbolAddress((void**)&gvec,g_gvec);
  cudaGetSymbolAddress((void**)&cat,g_cat); cudaGetSymbolAddress((void**)&ep,g_ep);
  cudaGetSymbolAddress((void**)&cm,g_cm);   cudaGetSymbolAddress((void**)&tm,g_tm);
  cudaGetSymbolAddress((void**)&meanT,g_meanT); cudaGetSymbolAddress((void**)&meanF,g_meanF);
  cudaGetSymbolAddress((void**)&sc,g_sc);   cudaGetSymbolAddress((void**)&st,g_st);
  cudaGetSymbolAddress((void**)&rstep,g_rstep); cudaGetSymbolAddress((void**)&cstep,g_cstep);
  cudaGetSymbolAddress((void**)&wtf2,g_wtf2); cudaGetSymbolAddress((void**)&wtb2,g_wtb2);
  cudaGetSymbolAddress((void**)&wtf3,g_wtf3); cudaGetSymbolAddress((void**)&wtb3,g_wtb3);

  const int MMA_SMEM = 120*136*4;
  cudaFuncSetAttribute(k_cmma<64,128,64,512,1>,  cudaFuncAttributeMaxDynamicSharedMemorySize, MMA_SMEM);
  cudaFuncSetAttribute(k_cmma<64,128,64,512,3>,  cudaFuncAttributeMaxDynamicSharedMemorySize, MMA_SMEM);
  cudaFuncSetAttribute(k_cmma<128,256,32,256,1>, cudaFuncAttributeMaxDynamicSharedMemorySize, MMA_SMEM);
  cudaFuncSetAttribute(k_cmma<128,256,32,256,3>, cudaFuncAttributeMaxDynamicSharedMemorySize, MMA_SMEM);

  // prep
  k_wt<<<288,256>>>(W2,wtf2,wtb2,64,128);
  k_wt<<<1152,256>>>(W3,wtf3,wtb3,128,256);
  k_gvec<<<1024,256>>>(We,Wc,gvec);
  // pass 1: forward convs MUST be 3xTF32 (R9 proved SPLIT=1 here flips the argsort)
  k_conv1<<<dim3(8,64,32),256>>>(x,W1,b1,h1);
  k_cmma<64,128,64,512,3><<<dim3(2,32,32),256,MMA_SMEM>>>(h1,wtf2,b2,h2);
  k_cmma<128,256,32,256,3><<<dim3(2,16,32),256,MMA_SMEM>>>(h2,wtf3,b3,h3);
  run_tail<1>(h3,Wa,ba,va,attp,att,alpha,mu,m2);
  // backward to input: single-tf32 (R8 proved additive fam noise is safe)
  k_dcoef<<<512,256>>>(mu,m2,gvec,dMu,dE2);
  k_dalp<<<dim3(8,32),128>>>(h3,dMu,dE2,dap);
  k_dalf<<<32,128>>>(dap,alpha,ds);
  k_dz<<<2048,256>>>(att,ds,va,dz);
  k_dfeat_mma<1><<<dim3(32,32),256>>>(Wa,dz,h3,alpha,dMu,dE2,d3);
  k_cbmma<128,256,16,128,128,1><<<dim3(2,32,32),256>>>(d3,wtb3,h2,d2);
  k_cbmma<64,128,32,256,256,1><<<dim3(2,64,32),256>>>(d2,wtb2,h1,d1);
  k_bwd1<<<dim3(2,128,32),256>>>(d1,W1,fam);
  // masking
  k_rowstats<<<512,256>>>(fam,x,cm,meanT);
  k_colstats<<<128,256>>>(fam,x,tm,meanF);
  k_sort<128><<<32,64>>>(cm,sc);
  k_sort<1024><<<32,512>>>(tm,st);
  k_rfm<<<1,32>>>(sc,st,mask_t,s_t,is_train,rstep,cstep);
  k_apply<<<16384,256>>>(x,rstep,cstep,meanT,meanF,xm);
  // pass 2 (single tf32: continuous output path)
  k_conv1<<<dim3(8,64,32),256>>>(xm,W1,b1,h1);
  k_cmma<64,128,64,512,1><<<dim3(2,32,32),256,MMA_SMEM>>>(h1,wtf2,b2,h2);
  k_cmma<128,256,32,256,1><<<dim3(2,16,32),256,MMA_SMEM>>>(h2,wtf3,b3,h3);
  run_tail<1>(h3,Wa,ba,va,attp,att,alpha,mu,m2);
  k_cat<<<512,256>>>(mu,m2,cat);
  k_embp<<<128,256>>>(cat,We,ep);
  k_embf<<<32,256>>>(ep,be,Wc,bc,out);
}

// round 12
// speedup vs baseline: 3.4291x; 1.0305x over previous
#include <cuda_runtime.h>
#include <math.h>

// ---------- static scratch ----------
__device__ float g_h1[67108864];
__device__ float g_h2[33554432];
__device__ float g_h3[16777216];
__device__ float g_d1[67108864];
__device__ float g_d2[33554432];
__device__ float g_d3[16777216];
__device__ float g_fam[4194304];
__device__ float g_xm[4194304];
__device__ float g_att[524288];
__device__ float g_attp[4194304];
__device__ float g_dzb[524288];
__device__ float g_alpha[4096];
__device__ float g_dsb[4096];
__device__ float g_dap[32768];
__device__ float g_mu[131072];
__device__ float g_m2[131072];
__device__ float g_dMu[131072];
__device__ float g_dE2[131072];
__device__ float g_gvec[8192];
__device__ float g_cat[262144];
__device__ float g_ep[1048576];
__device__ float g_cm[4096];
__device__ float g_tm[32768];
__device__ float g_meanT[4096];
__device__ float g_meanF[32768];
__device__ int   g_sc[4096];
__device__ int   g_st[4096];
__device__ int   g_rstep[4096];
__device__ int   g_cstep[32768];
__device__ float g_wtf2[73728];
__device__ float g_wtb2[73728];
__device__ float g_wtf3[294912];
__device__ float g_wtb3[294912];

// ---------- weight transposes ----------
__global__ void k_wt(const float* __restrict__ W, float* __restrict__ WTf,
                     float* __restrict__ WTb, int CIN, int COUT)
{
  int idx=blockIdx.x*256+threadIdx.x;
  int tot=CIN*COUT*9; if(idx>=tot) return;
  int k=idx%9, c=(idx/9)%CIN, o=idx/(9*CIN);
  float v=W[idx];
  int rf=(c>>3)*72 + k*8 + (c&7);
  WTf[(long)rf*COUT+o]=v;
  int rb=(o>>3)*72 + k*8 + (o&7);
  WTb[(long)rb*CIN+c]=v;
}

// ---------- conv1 fwd ----------
__global__ void __launch_bounds__(256) k_conv1(
    const float* __restrict__ in, const float* __restrict__ W,
    const float* __restrict__ bias, float* __restrict__ out)
{
  __shared__ __align__(16) float ins[3][132];
  __shared__ __align__(16) float ws[9][64];
  __shared__ float bs[64];
  const int n=blockIdx.z, i=blockIdx.y, j0=blockIdx.x*64;
  const int tid=threadIdx.x, jt=tid&15, og=tid>>4;
  for(int idx=tid; idx<576; idx+=256){
    int o=idx/9, k=idx%9;
    ws[k][o]=W[idx];
  }
  if(tid<64) bs[tid]=bias[tid];
  for(int idx=tid; idx<3*130; idx+=256){
    int r=idx/130, col=idx%130;
    int gx=2*i+r, gy=2*j0+col;
    float v=0.f;
    if(gx<128 && gy<1024) v=in[((long)n*128+gx)*1024+gy];
    ins[r][col]=v;
  }
  __syncthreads();
  float acc[4][4];
#pragma unroll
  for(int o=0;o<4;o++)
#pragma unroll
  for(int e=0;e<4;e++) acc[o][e]=0.f;
#pragma unroll
  for(int r=0;r<3;r++){
    float v[9];
    *(float4*)v     = *(float4*)&ins[r][8*jt];
    *(float4*)(v+4) = *(float4*)&ins[r][8*jt+4];
    v[8]            = ins[r][8*jt+8];
#pragma unroll
    for(int kj=0;kj<3;kj++){
      float w[4];
      *(float4*)w = *(float4*)&ws[r*3+kj][og*4];
#pragma unroll
      for(int oo=0;oo<4;oo++)
#pragma unroll
      for(int e=0;e<4;e++)
        acc[oo][e]+=w[oo]*v[2*e+kj];
    }
  }
#pragma unroll
  for(int oo=0;oo<4;oo++){
    int o=og*4+oo;
    float bb=bs[o];
    float4 r;
    r.x=fmaxf(acc[oo][0]+bb,0.f); r.y=fmaxf(acc[oo][1]+bb,0.f);
    r.z=fmaxf(acc[oo][2]+bb,0.f); r.w=fmaxf(acc[oo][3]+bb,0.f);
    *(float4*)&out[(((long)n*64+o)*64+i)*512 + j0 + 4*jt]=r;
  }
}

// ---------- tf32 helpers ----------
__device__ __forceinline__ float to_tf32(float v){
  unsigned r; asm("cvt.rna.tf32.f32 %0, %1;" : "=r"(r) : "f"(v));
  return __uint_as_float(r);
}
__device__ __forceinline__ void mma_tf32(float* c4,
    unsigned a0,unsigned a1,unsigned a2,unsigned a3,unsigned b0,unsigned b1){
  asm volatile(
    "mma.sync.aligned.m16n8k8.row.col.f32.tf32.tf32.f32 "
    "{%0,%1,%2,%3},{%4,%5,%6,%7},{%8,%9},{%0,%1,%2,%3};"
    : "+f"(c4[0]),"+f"(c4[1]),"+f"(c4[2]),"+f"(c4[3])
    : "r"(a0),"r"(a1),"r"(a2),"r"(a3),"r"(b0),"r"(b1));
}

// ---------- tf32 mma conv fwd; staging-side cvt (bit-identical to consumer cvt) ----------
template<int CIN,int COUT,int HIN,int WIN,int SPLIT>
__global__ void __launch_bounds__(256,2) k_cmma(
    const float* __restrict__ in, const float* __restrict__ WT,
    const float* __restrict__ bias, float* __restrict__ out)
{
  constexpr int HOUT=HIN/2, WOUT=WIN/2;
  constexpr int NJT=WOUT/128;
  constexpr int LD=136;
  constexpr int WOFF=(SPLIT==3)?96:48;
  extern __shared__ float sm[];
  float* evh = sm;
  float* odh = sm + 24*LD;
  float* evl = sm + 48*LD;   // S3 only
  float* odl = sm + 72*LD;   // S3 only
  float* ws  = sm + WOFF*LD;
  const int n=blockIdx.z, i=blockIdx.y;
  const int jt_=blockIdx.x%NJT, ot=blockIdx.x/NJT;
  const int j0=jt_*128, o0=ot*128;
  const int tid=threadIdx.x, wid=tid>>5, lane=tid&31;
  const int gid=lane>>2, tig=lane&3;
  const int m0=(wid&3)*32, n0w=(wid>>2)*64;
  float acc[2][8][4];
#pragma unroll
  for(int a=0;a<2;a++)
#pragma unroll
  for(int b=0;b<8;b++)
#pragma unroll
  for(int c=0;c<4;c++) acc[a][b][c]=0.f;

  for(int c0=0;c0<CIN;c0+=8){
    __syncthreads();
    for(int idx=tid; idx<8*3*129; idx+=256){
      int c=idx/387, rem=idx%387, r=rem/129, p=rem%129;
      int gx=2*i+r, gy=2*j0+2*p;
      float a=0.f,bv=0.f;
      if(gx<HIN && gy<WIN){
        const float2 s=*(const float2*)&in[(((long)n*CIN+c0+c)*HIN+gx)*WIN+gy];
        a=s.x; bv=s.y;
      }
      float ah=to_tf32(a), bh=to_tf32(bv);
      evh[(c*3+r)*LD+p]=ah;
      odh[(c*3+r)*LD+p]=bh;
      if(SPLIT==3){
        evl[(c*3+r)*LD+p]=to_tf32(a-ah);
        odl[(c*3+r)*LD+p]=to_tf32(bv-bh);
      }
    }
    {
      const float* wsrc = WT + (long)(c0>>3)*72*COUT + o0;
      for(int idx=tid; idx<72*32; idx+=256){
        int kk=idx>>5, o4=(idx&31)*4;
        float4 v=*(const float4*)&wsrc[(long)kk*COUT + o4];
        if(SPLIT==1){ v.x=to_tf32(v.x); v.y=to_tf32(v.y); v.z=to_tf32(v.z); v.w=to_tf32(v.w); }
        *(float4*)&ws[kk*LD + o4]=v;
      }
    }
    __syncthreads();
#pragma unroll
    for(int kc=0;kc<9;kc++){
      const int r=kc/3, kj=kc%3;
      const float* srch = (kj==1)? odh : evh;
      const float* srcl = (kj==1)? odl : evl;
      const int co = (kj==2)? 1:0;
      unsigned bh[8][2], bl[8][2];
#pragma unroll
      for(int f=0;f<8;f++){
        int i0=(tig*3+r)*LD + n0w + f*8 + gid + co;
        int i1=((tig+4)*3+r)*LD + n0w + f*8 + gid + co;
        bh[f][0]=__float_as_uint(srch[i0]);
        bh[f][1]=__float_as_uint(srch[i1]);
        if(SPLIT==3){
          bl[f][0]=__float_as_uint(srcl[i0]);
          bl[f][1]=__float_as_uint(srcl[i1]);
        }
      }
#pragma unroll
      for(int mf=0;mf<2;mf++){
        unsigned ah0,ah1,ah2,ah3,al0=0,al1=0,al2=0,al3=0;
        if(SPLIT==1){
          ah0=__float_as_uint(ws[(kc*8+tig)*LD + m0+mf*16+gid]);
          ah1=__float_as_uint(ws[(kc*8+tig)*LD + m0+mf*16+gid+8]);
          ah2=__float_as_uint(ws[(kc*8+tig+4)*LD + m0+mf*16+gid]);
          ah3=__float_as_uint(ws[(kc*8+tig+4)*LD + m0+mf*16+gid+8]);
        }else{
          float w0=ws[(kc*8+tig)*LD + m0+mf*16+gid];
          float w1=ws[(kc*8+tig)*LD + m0+mf*16+gid+8];
          float w2=ws[(kc*8+tig+4)*LD + m0+mf*16+gid];
          float w3=ws[(kc*8+tig+4)*LD + m0+mf*16+gid+8];
          float h0=to_tf32(w0),h1=to_tf32(w1),h2=to_tf32(w2),h3=to_tf32(w3);
          ah0=__float_as_uint(h0); ah1=__float_as_uint(h1);
          ah2=__float_as_uint(h2); ah3=__float_as_uint(h3);
          al0=__float_as_uint(to_tf32(w0-h0)); al1=__float_as_uint(to_tf32(w1-h1));
          al2=__float_as_uint(to_tf32(w2-h2)); al3=__float_as_uint(to_tf32(w3-h3));
        }
#pragma unroll
        for(int f=0;f<8;f++){
          mma_tf32(acc[mf][f], ah0,ah1,ah2,ah3, bh[f][0],bh[f][1]);
          if(SPLIT==3){
            mma_tf32(acc[mf][f], ah0,ah1,ah2,ah3, bl[f][0],bl[f][1]);
            mma_tf32(acc[mf][f], al0,al1,al2,al3, bh[f][0],bh[f][1]);
          }
        }
      }
    }
  }
#pragma unroll
  for(int mf=0;mf<2;mf++){
    int oA=o0+m0+mf*16+gid, oB=oA+8;
    float bA=bias[oA], bB=bias[oB];
#pragma unroll
    for(int f=0;f<8;f++){
      int jj=j0 + n0w + f*8 + tig*2;
      long baseA=(((long)n*COUT+oA)*HOUT+i)*WOUT + jj;
      long baseB=(((long)n*COUT+oB)*HOUT+i)*WOUT + jj;
      float2 rA, rB;
      rA.x=fmaxf(acc[mf][f][0]+bA,0.f); rA.y=fmaxf(acc[mf][f][1]+bA,0.f);
      rB.x=fmaxf(acc[mf][f][2]+bB,0.f); rB.y=fmaxf(acc[mf][f][3]+bB,0.f);
      *(float2*)&out[baseA]=rA;
      *(float2*)&out[baseB]=rB;
    }
  }
}

// ---------- tf32 mma transposed-conv bwd (S1 only; staging-side cvt) ----------
template<int CIN,int COUT,int HOUT,int WOUT,int NT>
__global__ void __launch_bounds__(256,2) k_cbmma(
    const float* __restrict__ dout, const float* __restrict__ WT,
    const float* __restrict__ act, float* __restrict__ din)
{
  constexpr int HIN=2*HOUT, WIN=2*WOUT;
  constexpr int LDW=CIN+8, LDD=NT/2+4, JL=NT/2+2;
  constexpr int NW_M=CIN/32;
  __shared__ float ws[72*LDW];
  __shared__ float dsA[8*LDD];
  __shared__ float dsB[8*LDD];
  const int n=blockIdx.z, x=blockIdx.y, y0=blockIdx.x*NT;
  const int tid=threadIdx.x, wid=tid>>5, lane=tid&31;
  const int gid=lane>>2, tig=lane&3;
  const int m0=(wid%NW_M)*32, n0=(wid/NW_M)*64;
  const bool xe=((x&1)==0);
  const int iA = xe ? (x>>1) : ((x-1)>>1);
  const int iB = (x>>1)-1;
  const bool hasB = xe && iB>=0;
  const int jb = y0/2 - 1;
  float acc_e[2][4][4], acc_o[2][4][4];
#pragma unroll
  for(int a=0;a<2;a++)
#pragma unroll
  for(int b=0;b<4;b++)
#pragma unroll
  for(int c=0;c<4;c++){acc_e[a][b][c]=0.f; acc_o[a][b][c]=0.f;}

  for(int o0=0;o0<COUT;o0+=8){
    __syncthreads();
    {
      const float* wsrc = WT + (long)(o0>>3)*72*CIN;
      for(int idx=tid; idx<72*(CIN/4); idx+=256){
        int r=idx/(CIN/4), c4=(idx%(CIN/4))*4;
        float4 v=*(const float4*)&wsrc[(long)r*CIN+c4];
        v.x=to_tf32(v.x); v.y=to_tf32(v.y); v.z=to_tf32(v.z); v.w=to_tf32(v.w);
        *(float4*)&ws[r*LDW+c4]=v;
      }
    }
    for(int idx=tid; idx<8*JL; idx+=256){
      int o=idx/JL, jl=idx%JL; int j=jb+jl;
      float a=0.f,bv=0.f;
      if(j>=0 && j<WOUT){
        long base=((long)n*COUT+o0+o)*HOUT;
        a = dout[(base+iA)*WOUT+j];
        if(hasB) bv = dout[(base+iB)*WOUT+j];
      }
      dsA[o*LDD+jl]=to_tf32(a); dsB[o*LDD+jl]=to_tf32(bv);
    }
    __syncthreads();

    auto proc = [&](const float* ds, const int tapBase){
      unsigned b1[4][2], b0[4][2];
#pragma unroll
      for(int f=0;f<4;f++){
        int cbase = n0/2 + f*8 + gid;
        b1[f][0]=__float_as_uint(ds[tig*LDD + cbase + 1]);
        b1[f][1]=__float_as_uint(ds[(tig+4)*LDD + cbase + 1]);
        b0[f][0]=__float_as_uint(ds[tig*LDD + cbase]);
        b0[f][1]=__float_as_uint(ds[(tig+4)*LDD + cbase]);
      }
#pragma unroll
      for(int kj=0;kj<3;kj++){
        const int tap=tapBase+kj;
#pragma unroll
        for(int mf=0;mf<2;mf++){
          unsigned a0=__float_as_uint(ws[(tap*8+tig)*LDW + m0+mf*16+gid]);
          unsigned a1=__float_as_uint(ws[(tap*8+tig)*LDW + m0+mf*16+gid+8]);
          unsigned a2=__float_as_uint(ws[(tap*8+tig+4)*LDW + m0+mf*16+gid]);
          unsigned a3=__float_as_uint(ws[(tap*8+tig+4)*LDW + m0+mf*16+gid+8]);
#pragma unroll
          for(int f=0;f<4;f++){
            float* c4 = (kj==1)? acc_o[mf][f] : acc_e[mf][f];
            const unsigned* bb = (kj==2)? b0[f] : b1[f];
            mma_tf32(c4, a0,a1,a2,a3, bb[0],bb[1]);
          }
        }
      }
    };
    proc(dsA, xe?0:3);
    if(hasB) proc(dsB, 6);
  }

#pragma unroll
  for(int mf=0;mf<2;mf++){
    int c0_=m0+mf*16+gid;
#pragma unroll
    for(int f=0;f<4;f++){
      int Y = y0 + n0 + 2*(f*8 + 2*tig);
      long b0i=(((long)n*CIN+c0_)*HIN+x)*WIN + Y;
      long b1i=(((long)n*CIN+c0_+8)*HIN+x)*WIN + Y;
      float2 m, r;
      m=*(const float2*)&act[b0i];
      r.x = m.x>0.f? acc_e[mf][f][0]:0.f; r.y = m.y>0.f? acc_o[mf][f][0]:0.f;
      *(float2*)&din[b0i]=r;
      m=*(const float2*)&act[b0i+2];
      r.x = m.x>0.f? acc_e[mf][f][1]:0.f; r.y = m.y>0.f? acc_o[mf][f][1]:0.f;
      *(float2*)&din[b0i+2]=r;
      m=*(const float2*)&act[b1i];
      r.x = m.x>0.f? acc_e[mf][f][2]:0.f; r.y = m.y>0.f? acc_o[mf][f][2]:0.f;
      *(float2*)&din[b1i]=r;
      m=*(const float2*)&act[b1i+2];
      r.x = m.x>0.f? acc_e[mf][f][3]:0.f; r.y = m.y>0.f? acc_o[mf][f][3]:0.f;
      *(float2*)&din[b1i+2]=r;
    }
  }
}

// ---------- conv1 data-grad -> |dx| ----------
__global__ void __launch_bounds__(256) k_bwd1(
    const float* __restrict__ dz1, const float* __restrict__ W1,
    float* __restrict__ fam)
{
  __shared__ float ws[576];
  __shared__ float dsm[8*2*260];
  const int n=blockIdx.z, x=blockIdx.y, y0=blockIdx.x*512;
  const int tid=threadIdx.x;
  for(int idx=tid; idx<576; idx+=256) ws[idx]=W1[idx];
  int iA,iB,kiA,kiB; bool hasB;
  if((x&1)==0){iA=x>>1;kiA=0;iB=iA-1;kiB=2;hasB=(iB>=0);}
  else{iA=(x-1)>>1;kiA=1;iB=0;kiB=0;hasB=false;}
  const int jbase=y0/2-1;
  float accE=0.f, accO=0.f;
  for(int o0=0;o0<64;o0+=8){
    __syncthreads();
    for(int idx=tid; idx<8*2*260; idx+=256){
      int o=idx/520, rs=(idx/260)&1, jj=idx%260;
      int j=jbase+jj; int ir=rs?iB:iA;
      float v=0.f;
      if(j>=0 && j<512 && (rs==0||hasB))
        v=dz1[(((long)n*64+o0+o)*64+ir)*512+j];
      dsm[idx]=v;
    }
    __syncthreads();
#pragma unroll
    for(int o=0;o<8;o++){
#pragma unroll
      for(int rs=0;rs<2;rs++){
        if(rs==1&&!hasB) break;
        int ki=rs?kiB:kiA;
        const float* wb=&ws[(o0+o)*9+ki*3];
        float vm=dsm[(o*2+rs)*260+tid], v0=dsm[(o*2+rs)*260+tid+1];
        accE+=wb[0]*v0+wb[2]*vm; accO+=wb[1]*v0;
      }
    }
  }
  long base=((long)n*128+x)*1024 + y0 + 2*tid;
  fam[base]=fabsf(accE); fam[base+1]=fabsf(accO);
}

// ---------- att partial GEMM (S1, staging-side cvt) ----------
__global__ void __launch_bounds__(256) k_attp(
    const float* __restrict__ Wa, const float* __restrict__ feat,
    float* __restrict__ attp)
{
  constexpr int LDA=129, LDB=132;
  __shared__ float As[32*LDA];
  __shared__ float Bs[32*LDB];
  const int ks=blockIdx.x, b=blockIdx.y;
  const int tid=threadIdx.x, wid=tid>>5, lane=tid&31;
  const int gid=lane>>2, tig=lane&3;
  const int m0=(wid&3)*32, n0=(wid>>2)*64;
  const float* fb = feat + (long)b*524288;
  float acc[2][8][4];
#pragma unroll
  for(int a=0;a<2;a++)
#pragma unroll
  for(int bq=0;bq<8;bq++)
#pragma unroll
  for(int c=0;c<4;c++) acc[a][bq][c]=0.f;

  for(int k0=ks*512; k0<ks*512+512; k0+=32){
    __syncthreads();
    for(int idx=tid; idx<4096; idx+=256){
      int h=idx>>5, kk=idx&31;
      As[kk*LDA+h]=to_tf32(Wa[(long)h*4096+k0+kk]);
    }
    for(int idx=tid; idx<4096; idx+=256){
      int kk=idx>>7, t=idx&127;
      Bs[kk*LDB+t]=to_tf32(fb[(long)(k0+kk)*128+t]);
    }
    __syncthreads();
#pragma unroll
    for(int kc=0;kc<4;kc++){
      const int kb=kc*8;
      unsigned bh[8][2];
#pragma unroll
      for(int f=0;f<8;f++){
        bh[f][0]=__float_as_uint(Bs[(kb+tig)*LDB + n0+f*8+gid]);
        bh[f][1]=__float_as_uint(Bs[(kb+tig+4)*LDB + n0+f*8+gid]);
      }
#pragma unroll
      for(int mf=0;mf<2;mf++){
        unsigned a0=__float_as_uint(As[(kb+tig)*LDA + m0+mf*16+gid]);
        unsigned a1=__float_as_uint(As[(kb+tig)*LDA + m0+mf*16+gid+8]);
        unsigned a2=__float_as_uint(As[(kb+tig+4)*LDA + m0+mf*16+gid]);
        unsigned a3=__float_as_uint(As[(kb+tig+4)*LDA + m0+mf*16+gid+8]);
#pragma unroll
        for(int f=0;f<8;f++)
          mma_tf32(acc[mf][f], a0,a1,a2,a3, bh[f][0],bh[f][1]);
      }
    }
  }
#pragma unroll
  for(int mf=0;mf<2;mf++){
    int hA=m0+mf*16+gid, hB=hA+8;
#pragma unroll
    for(int f=0;f<8;f++){
      int t=n0+f*8+tig*2;
      float2 rA, rB;
      rA.x=acc[mf][f][0]; rA.y=acc[mf][f][1];
      rB.x=acc[mf][f][2]; rB.y=acc[mf][f][3];
      *(float2*)&attp[(long)ks*524288 + ((long)b*128+hA)*128+t]=rA;
      *(float2*)&attp[(long)ks*524288 + ((long)b*128+hB)*128+t]=rB;
    }
  }
}
__global__ void k_attf(const float* __restrict__ attp, const float* __restrict__ ba,
                       float* __restrict__ att)
{
  int i=blockIdx.x*256+threadIdx.x; if(i>=524288) return;
  int h=(i>>7)&127;
  float s=0.f;
#pragma unroll
  for(int ks=0;ks<8;ks++) s+=attp[(long)ks*524288+i];
  att[i]=tanhf(s+ba[h]);
}

// ---------- softmax ----------
__global__ void __launch_bounds__(128) k_salpha(
    const float* __restrict__ att, const float* __restrict__ va,
    float* __restrict__ alpha)
{
  __shared__ float vs[128], buf[128];
  const int b=blockIdx.x, t=threadIdx.x;
  vs[t]=va[t];
  __syncthreads();
  float s=0.f;
#pragma unroll 4
  for(int h=0;h<128;h++) s+=vs[h]*att[((long)b*128+h)*128+t];
  buf[t]=s; __syncthreads();
  for(int off=64;off;off>>=1){ if(t<off) buf[t]=fmaxf(buf[t],buf[t+off]); __syncthreads(); }
  float mx=buf[0]; __syncthreads();
  float e=expf(s-mx);
  buf[t]=e; __syncthreads();
  for(int off=64;off;off>>=1){ if(t<off) buf[t]+=buf[t+off]; __syncthreads(); }
  alpha[b*128+t]=e/buf[0];
}

// ---------- mu, m2 ----------
__global__ void k_mustats(const float* __restrict__ feat,
    const float* __restrict__ alpha, float* __restrict__ mu, float* __restrict__ m2)
{
  int w=(blockIdx.x*blockDim.x+threadIdx.x)>>5, lane=threadIdx.x&31;
  if(w>=131072) return;
  int b=w>>12;
  const float* fr=feat+(long)w*128;
  const float* ar=alpha+b*128;
  float s1=0.f,s2=0.f;
#pragma unroll
  for(int t=lane;t<128;t+=32){
    float a=ar[t], f=fr[t];
    s1+=a*f; s2+=a*f*f;
  }
  for(int o=16;o;o>>=1){ s1+=__shfl_down_sync(~0u,s1,o); s2+=__shfl_down_sync(~0u,s2,o); }
  if(!lane){ mu[w]=s1; m2[w]=s2; }
}

// ---------- gvec ----------
__global__ void k_gvec(const float* __restrict__ We,const float* __restrict__ Wc,
                       float* __restrict__ gvec)
{
  int w=(blockIdx.x*blockDim.x+threadIdx.x)>>5, lane=threadIdx.x&31;
  if(w>=8192) return;
  float s=0.f;
  for(int j=lane;j<256;j+=32) s+=We[(long)w*256+j]*(Wc[j*2+1]-Wc[j*2]);
  for(int o=16;o;o>>=1) s+=__shfl_down_sync(~0u,s,o);
  if(!lane) gvec[w]=s;
}

// ---------- dMu,dE2 ----------
__global__ void k_dcoef(const float* __restrict__ mu,const float* __restrict__ m2,
    const float* __restrict__ gvec, float* __restrict__ dMu,float* __restrict__ dE2)
{
  int i=blockIdx.x*256+threadIdx.x; if(i>=131072) return;
  int d=i&4095;
  float m=mu[i], v=m2[i]-m*m;
  float g2=gvec[4096+d];
  float dE=0.f, dM=gvec[d];
  if(v>1e-5f){ float sg=sqrtf(v); dE=0.5f*g2/sg; dM-=g2*m/sg; }
  dMu[i]=dM; dE2[i]=dE;
}

// ---------- dalpha ----------
__global__ void __launch_bounds__(128) k_dalp(
    const float* __restrict__ feat,const float* __restrict__ dMu,
    const float* __restrict__ dE2,float* __restrict__ part)
{
  const int ks=blockIdx.x, b=blockIdx.y, t=threadIdx.x;
  const float* fb=feat+(long)b*524288;
  const float* dm=dMu+b*4096; const float* de=dE2+b*4096;
  float acc=0.f;
  int d0=ks*512;
#pragma unroll 4
  for(int d=d0;d<d0+512;d++){
    float f=fb[(long)d*128+t];
    acc+=dm[d]*f+de[d]*f*f;
  }
  part[(ks*32+b)*128+t]=acc;
}
__global__ void __launch_bounds__(128) k_dalf(
    const float* __restrict__ part,const float* __restrict__ alpha,
    float* __restrict__ ds)
{
  const int b=blockIdx.x, t=threadIdx.x;
  float acc=0.f;
#pragma unroll
  for(int ks=0;ks<8;ks++) acc+=part[(ks*32+b)*128+t];
  __shared__ float buf[128];
  float a=alpha[b*128+t];
  buf[t]=a*acc; __syncthreads();
  for(int off=64;off;off>>=1){ if(t<off) buf[t]+=buf[t+off]; __syncthreads(); }
  ds[b*128+t]=a*(acc-buf[0]);
}

// ---------- dz ----------
__global__ void k_dz(const float* __restrict__ att,const float* __restrict__ ds,
    const float* __restrict__ va,float* __restrict__ dz)
{
  int i=blockIdx.x*256+threadIdx.x; if(i>=524288) return;
  int t=i&127, h=(i>>7)&127, b=i>>14;
  float a=att[i];
  dz[i]=va[h]*ds[b*128+t]*(1.f-a*a);
}

// ---------- dfeat (S1, staging-side cvt) + fused epilogue ----------
__global__ void __launch_bounds__(256) k_dfeat(
    const float* __restrict__ Wa, const float* __restrict__ dz,
    const float* __restrict__ feat, const float* __restrict__ alpha,
    const float* __restrict__ dMu, const float* __restrict__ dE2,
    float* __restrict__ dout3)
{
  constexpr int LDA=132, LDB=132;
  __shared__ float As[32*LDA];
  __shared__ float Bs[32*LDB];
  __shared__ float al[128];
  const int d0=blockIdx.x*128, b=blockIdx.y;
  const int tid=threadIdx.x, wid=tid>>5, lane=tid&31;
  const int gid=lane>>2, tig=lane&3;
  const int m0=(wid&3)*32, n0=(wid>>2)*64;
  if(tid<128) al[tid]=alpha[b*128+tid];
  float acc[2][8][4];
#pragma unroll
  for(int a=0;a<2;a++)
#pragma unroll
  for(int bq=0;bq<8;bq++)
#pragma unroll
  for(int c=0;c<4;c++) acc[a][bq][c]=0.f;

  for(int k0=0;k0<128;k0+=32){
    __syncthreads();
    for(int idx=tid; idx<4096; idx+=256){
      int kk=idx>>7, dd=idx&127;
      As[kk*LDA+dd]=to_tf32(Wa[(long)(k0+kk)*4096+d0+dd]);
    }
    for(int idx=tid; idx<4096; idx+=256){
      int kk=idx>>7, t=idx&127;
      Bs[kk*LDB+t]=to_tf32(dz[((long)b*128+k0+kk)*128+t]);
    }
    __syncthreads();
#pragma unroll
    for(int kc=0;kc<4;kc++){
      const int kb=kc*8;
      unsigned bh[8][2];
#pragma unroll
      for(int f=0;f<8;f++){
        bh[f][0]=__float_as_uint(Bs[(kb+tig)*LDB + n0+f*8+gid]);
        bh[f][1]=__float_as_uint(Bs[(kb+tig+4)*LDB + n0+f*8+gid]);
      }
#pragma unroll
      for(int mf=0;mf<2;mf++){
        unsigned a0=__float_as_uint(As[(kb+tig)*LDA + m0+mf*16+gid]);
        unsigned a1=__float_as_uint(As[(kb+tig)*LDA + m0+mf*16+gid+8]);
        unsigned a2=__float_as_uint(As[(kb+tig+4)*LDA + m0+mf*16+gid]);
        unsigned a3=__float_as_uint(As[(kb+tig+4)*LDA + m0+mf*16+gid+8]);
#pragma unroll
        for(int f=0;f<8;f++)
          mma_tf32(acc[mf][f], a0,a1,a2,a3, bh[f][0],bh[f][1]);
      }
    }
  }
#pragma unroll
  for(int mf=0;mf<2;mf++){
    int dA=d0+m0+mf*16+gid, dB=dA+8;
    float dmA=dMu[(long)b*4096+dA], deA=dE2[(long)b*4096+dA];
    float dmB=dMu[(long)b*4096+dB], deB=dE2[(long)b*4096+dB];
#pragma unroll
    for(int f=0;f<8;f++){
      int t=n0+f*8+tig*2;
      long fiA=((long)b*4096+dA)*128+t;
      long fiB=((long)b*4096+dB)*128+t;
      float2 fvA=*(const float2*)&feat[fiA];
      float2 fvB=*(const float2*)&feat[fiB];
      float2 rA, rB;
      rA.x = fvA.x>0.f? (acc[mf][f][0]+al[t]*(dmA+2.f*deA*fvA.x)) : 0.f;
      rA.y = fvA.y>0.f? (acc[mf][f][1]+al[t+1]*(dmA+2.f*deA*fvA.y)) : 0.f;
      rB.x = fvB.x>0.f? (acc[mf][f][2]+al[t]*(dmB+2.f*deB*fvB.x)) : 0.f;
      rB.y = fvB.y>0.f? (acc[mf][f][3]+al[t+1]*(dmB+2.f*deB*fvB.y)) : 0.f;
      *(float2*)&dout3[fiA]=rA;
      *(float2*)&dout3[fiB]=rB;
    }
  }
}

// ---------- row/col stats ----------
__global__ void k_rowstats(const float* __restrict__ fam,const float* __restrict__ x,
    float* __restrict__ cm,float* __restrict__ meanT)
{
  int w=(blockIdx.x*blockDim.x+threadIdx.x)>>5, lane=threadIdx.x&31;
  if(w>=4096) return;
  const float* fr=fam+(long)w*1024; const float* xr=x+(long)w*1024;
  float m=-1e30f, s=0.f;
  for(int t=lane;t<1024;t+=32){ m=fmaxf(m,fr[t]); s+=xr[t]; }
  for(int o=16;o;o>>=1){ m=fmaxf(m,__shfl_down_sync(~0u,m,o)); s+=__shfl_down_sync(~0u,s,o); }
  if(!lane){ cm[w]=m; meanT[w]=s*(1.f/1024.f); }
}
__global__ void k_colstats(const float* __restrict__ fam,const float* __restrict__ x,
    float* __restrict__ tm,float* __restrict__ meanF)
{
  int i=blockIdx.x*256+threadIdx.x; if(i>=32768) return;
  int b=i>>10, t=i&1023;
  const float* fb=fam+(long)b*131072+t; const float* xb=x+(long)b*131072+t;
  float m=-1e30f, s=0.f;
#pragma unroll 4
  for(int f=0;f<128;f++){ m=fmaxf(m,fb[f*1024]); s+=xb[f*1024]; }
  tm[i]=m; meanF[i]=s*(1.f/128.f);
}

// ---------- bitonic argsort ----------
template<int N>
__global__ void k_sort(const float* __restrict__ vals, int* __restrict__ idxout)
{
  __shared__ unsigned long long key[N];
  const int b=blockIdx.x, tid=threadIdx.x, TH=N/2;
  for(int i=tid;i<N;i+=TH){
    unsigned u=__float_as_uint(vals[b*N+i]);
    u = (u&0x80000000u)? ~u : (u|0x80000000u);
    key[i]=((unsigned long long)(~u)<<32)|(unsigned)i;
  }
  __syncthreads();
  for(int k=2;k<=N;k<<=1)
    for(int j=k>>1;j;j>>=1){
      for(int i=tid;i<N;i+=TH){
        int ixj=i^j;
        if(ixj>i){
          bool up=((i&k)==0);
          unsigned long long a=key[i],c=key[ixj];
          if((a>c)==up){ key[i]=c; key[ixj]=a; }
        }
      }
      __syncthreads();
    }
  for(int i=tid;i<128;i+=TH) idxout[b*128+i]=(int)(key[i]&0xFFFFFFFFu);
}

// ---------- RFM scan ----------
__global__ void k_rfm(const int* __restrict__ sc,const int* __restrict__ st,
    const int* __restrict__ mask_t,const int* __restrict__ s_t,
    const int* __restrict__ is_train,int* __restrict__ rstep,int* __restrict__ cstep)
{
  int b=threadIdx.x; if(b>=32) return;
  int* rs=rstep+b*128; int* cs=cstep+b*1024;
  for(int i=0;i<128;i++) rs[i]=-1;
  for(int i=0;i<1024;i++) cs[i]=-1;
  if(is_train && is_train[0]==0) return;
  int cnt=0;
  for(int s=0;s<128 && cnt<3;s++){
    int pc=sc[b*128+s], pt=st[b*128+s];
    if(rs[pc]!=-1||cs[pt]!=-1) continue;
    int mt=mask_t[b*128+s], ss=s_t[b*128+s];
    rs[pc]=s;
    int l=pt-ss; if(l<0)l=0;
    int r=pt+mt-ss; if(r>1024)r=1024;
    for(int t=l;t<r;t++) cs[t]=s;
    cnt++;
  }
}

// ---------- apply mask ----------
__global__ void k_apply(const float* __restrict__ x,const int* __restrict__ rstep,
    const int* __restrict__ cstep,const float* __restrict__ meanT,
    const float* __restrict__ meanF,float* __restrict__ xm)
{
  long i=(long)blockIdx.x*256+threadIdx.x; if(i>=4194304) return;
  int t=(int)(i&1023); int f=(int)((i>>10)&127); int b=(int)(i>>17);
  int rs=rstep[b*128+f], cs=cstep[b*1024+t];
  float v;
  if(rs<0&&cs<0) v=x[i];
  else v=(cs>=rs)? meanT[b*128+f] : meanF[b*1024+t];
  xm[i]=v;
}

// ---------- emb head ----------
__global__ void k_cat(const float* __restrict__ mu,const float* __restrict__ m2,
                      float* __restrict__ cat)
{
  int i=blockIdx.x*256+threadIdx.x; if(i>=131072) return;
  int b=i>>12, d=i&4095;
  float m=mu[i];
  cat[(long)b*8192+d]=m;
  cat[(long)b*8192+4096+d]=sqrtf(fmaxf(m2[i]-m*m,1e-5f));
}
__global__ void __launch_bounds__(256) k_embp(
    const float* __restrict__ cat,const float* __restrict__ We,
    float* __restrict__ part)
{
  __shared__ float cs[32][64];
  const int ks=blockIdx.x, j=threadIdx.x;
  for(int idx=j; idx<32*64; idx+=256){
    int b=idx>>6, ii=idx&63;
    cs[b][ii]=cat[(long)b*8192 + ks*64 + ii];
  }
  __syncthreads();
  float acc[32];
#pragma unroll
  for(int b=0;b<32;b++) acc[b]=0.f;
  for(int ii=0;ii<64;ii++){
    float w=We[((long)ks*64+ii)*256+j];
#pragma unroll
    for(int b=0;b<32;b++) acc[b]+=cs[b][ii]*w;
  }
#pragma unroll
  for(int b=0;b<32;b++) part[((long)ks*32+b)*256+j]=acc[b];
}
__global__ void __launch_bounds__(256) k_embf(
    const float* __restrict__ part,const float* __restrict__ be,
    const float* __restrict__ Wc,const float* __restrict__ bc,
    float* __restrict__ out)
{
  const int b=blockIdx.x, j=threadIdx.x;
  float s=be[j];
  for(int ks=0;ks<128;ks++) s+=part[((long)ks*32+b)*256+j];
  __shared__ float es[256];
  es[j]=s; __syncthreads();
  if(j<2){
    float acc=bc[j];
    for(int q=0;q<256;q++) acc+=es[q]*Wc[q*2+j];
    out[b*2+j]=acc;
  }
}

// ---------- host ----------
static void run_tail(const float* h3,const float* Wa,const float* ba,const float* va,
                     float* attp,float* att,float* alpha,float* mu,float* m2)
{
  k_attp<<<dim3(8,32),256>>>(Wa,h3,attp);
  k_attf<<<2048,256>>>(attp,ba,att);
  k_salpha<<<32,128>>>(att,va,alpha);
  k_mustats<<<16384,256>>>(h3,alpha,mu,m2);
}

extern "C" void kernel_launch(void* const* d_in,const int* in_sizes,int n_in,
                              void* d_out,int out_size)
{
  const float* x =(const float*)d_in[0];
  const float* W1=(const float*)d_in[1]; const float* b1=(const float*)d_in[2];
  const float* W2=(const float*)d_in[3]; const float* b2=(const float*)d_in[4];
  const float* W3=(const float*)d_in[5]; const float* b3=(const float*)d_in[6];
  const float* Wa=(const float*)d_in[7]; const float* ba=(const float*)d_in[8];
  const float* va=(const float*)d_in[9];
  const float* We=(const float*)d_in[10]; const float* be=(const float*)d_in[11];
  const float* Wc=(const float*)d_in[12]; const float* bc=(const float*)d_in[13];
  const int* mask_t=(const int*)d_in[14]; const int* s_t=(const int*)d_in[15];
  const int* is_train = (n_in>16)? (const int*)d_in[16] : nullptr;
  float* out=(float*)d_out;

  float *h1,*h2,*h3,*d1,*d2,*d3,*fam,*xm,*att,*attp,*dz,*alpha,*ds,*dap,*mu,*m2,*dMu,*dE2,*gvec;
  float *cat,*ep,*cm,*tm,*meanT,*meanF,*wtf2,*wtb2,*wtf3,*wtb3;
  int *sc,*st,*rstep,*cstep;
  cudaGetSymbolAddress((void**)&h1,g_h1);   cudaGetSymbolAddress((void**)&h2,g_h2);
  cudaGetSymbolAddress((void**)&h3,g_h3);   cudaGetSymbolAddress((void**)&d1,g_d1);
  cudaGetSymbolAddress((void**)&d2,g_d2);   cudaGetSymbolAddress((void**)&d3,g_d3);
  cudaGetSymbolAddress((void**)&fam,g_fam); cudaGetSymbolAddress((void**)&xm,g_xm);
  cudaGetSymbolAddress((void**)&att,g_att); cudaGetSymbolAddress((void**)&attp,g_attp);
  cudaGetSymbolAddress((void**)&dz,g_dzb);
  cudaGetSymbolAddress((void**)&alpha,g_alpha); cudaGetSymbolAddress((void**)&ds,g_dsb);
  cudaGetSymbolAddress((void**)&dap,g_dap);
  cudaGetSymbolAddress((void**)&mu,g_mu);   cudaGetSymbolAddress((void**)&m2,g_m2);
  cudaGetSymbolAddress((void**)&dMu,g_dMu); cudaGetSymbolAddress((void**)&dE2,g_dE2);
  cudaGetSymbolAddress((void**)&gvec,g_gvec);
  cudaGetSymbolAddress((void**)&cat,g_cat); cudaGetSymbolAddress((void**)&ep,g_ep);
  cudaGetSymbolAddress((void**)&cm,g_cm);   cudaGetSymbolAddress((void**)&tm,g_tm);
  cudaGetSymbolAddress((void**)&meanT,g_meanT); cudaGetSymbolAddress((void**)&meanF,g_meanF);
  cudaGetSymbolAddress((void**)&sc,g_sc);   cudaGetSymbolAddress((void**)&st,g_st);
  cudaGetSymbolAddress((void**)&rstep,g_rstep); cudaGetSymbolAddress((void**)&cstep,g_cstep);
  cudaGetSymbolAddress((void**)&wtf2,g_wtf2); cudaGetSymbolAddress((void**)&wtb2,g_wtb2);
  cudaGetSymbolAddress((void**)&wtf3,g_wtf3); cudaGetSymbolAddress((void**)&wtb3,g_wtb3);

  const int SMEM1 = 120*136*4;   // S1: 48 input rows + 72 weight rows
  const int SMEM3 = 168*136*4;   // S3: 96 input rows (hi+lo) + 72 weight rows
  cudaFuncSetAttribute(k_cmma<64,128,64,512,1>,  cudaFuncAttributeMaxDynamicSharedMemorySize, SMEM1);
  cudaFuncSetAttribute(k_cmma<64,128,64,512,3>,  cudaFuncAttributeMaxDynamicSharedMemorySize, SMEM3);
  cudaFuncSetAttribute(k_cmma<128,256,32,256,1>, cudaFuncAttributeMaxDynamicSharedMemorySize, SMEM1);
  cudaFuncSetAttribute(k_cmma<128,256,32,256,3>, cudaFuncAttributeMaxDynamicSharedMemorySize, SMEM3);

  // prep
  k_wt<<<288,256>>>(W2,wtf2,wtb2,64,128);
  k_wt<<<1152,256>>>(W3,wtf3,wtb3,128,256);
  k_gvec<<<1024,256>>>(We,Wc,gvec);
  // pass 1: forward convs 3xTF32 (argsort-critical); staging-side hi/lo split
  k_conv1<<<dim3(8,64,32),256>>>(x,W1,b1,h1);
  k_cmma<64,128,64,512,3><<<dim3(2,32,32),256,SMEM3>>>(h1,wtf2,b2,h2);
  k_cmma<128,256,32,256,3><<<dim3(2,16,32),256,SMEM3>>>(h2,wtf3,b3,h3);
  run_tail(h3,Wa,ba,va,attp,att,alpha,mu,m2);
  // backward to input: single-tf32 (additive fam noise, proven safe)
  k_dcoef<<<512,256>>>(mu,m2,gvec,dMu,dE2);
  k_dalp<<<dim3(8,32),128>>>(h3,dMu,dE2,dap);
  k_dalf<<<32,128>>>(dap,alpha,ds);
  k_dz<<<2048,256>>>(att,ds,va,dz);
  k_dfeat<<<dim3(32,32),256>>>(Wa,dz,h3,alpha,dMu,dE2,d3);
  k_cbmma<128,256,16,128,128><<<dim3(2,32,32),256>>>(d3,wtb3,h2,d2);
  k_cbmma<64,128,32,256,256><<<dim3(2,64,32),256>>>(d2,wtb2,h1,d1);
  k_bwd1<<<dim3(2,128,32),256>>>(d1,W1,fam);
  // masking
  k_rowstats<<<512,256>>>(fam,x,cm,meanT);
  k_colstats<<<128,256>>>(fam,x,tm,meanF);
  k_sort<128><<<32,64>>>(cm,sc);
  k_sort<1024><<<32,512>>>(tm,st);
  k_rfm<<<1,32>>>(sc,st,mask_t,s_t,is_train,rstep,cstep);
  k_apply<<<16384,256>>>(x,rstep,cstep,meanT,meanF,xm);
  // pass 2 (single tf32)
  k_conv1<<<dim3(8,64,32),256>>>(xm,W1,b1,h1);
  k_cmma<64,128,64,512,1><<<dim3(2,32,32),256,SMEM1>>>(h1,wtf2,b2,h2);
  k_cmma<128,256,32,256,1><<<dim3(2,16,32),256,SMEM1>>>(h2,wtf3,b3,h3);
  run_tail(h3,Wa,ba,va,attp,att,alpha,mu,m2);
  k_cat<<<512,256>>>(mu,m2,cat);
  k_embp<<<128,256>>>(cat,We,ep);
  k_embf<<<32,256>>>(ep,be,Wc,bc,out);
}

// round 13
// speedup vs baseline: 3.5604x; 1.0383x over previous
#include <cuda_runtime.h>
#include <math.h>

// ---------- static scratch ----------
__device__ float g_h1[67108864];
__device__ float g_h2[33554432];
__device__ float g_h3[16777216];
__device__ float g_d1[67108864];
__device__ float g_d2[33554432];
__device__ float g_d3[16777216];
__device__ float g_fam[4194304];
__device__ float g_xm[4194304];
__device__ float g_att[524288];
__device__ float g_attp[4194304];
__device__ float g_alpha[4096];
__device__ float g_dsb[4096];
__device__ float g_dap[32768];
__device__ float g_mu[131072];
__device__ float g_m2[131072];
__device__ float g_dMu[131072];
__device__ float g_dE2[131072];
__device__ float g_gvec[8192];
__device__ float g_cat[262144];
__device__ float g_ep[1048576];
__device__ float g_cm[4096];
__device__ float g_tm[32768];
__device__ float g_meanT[4096];
__device__ float g_meanF[32768];
__device__ int   g_sc[4096];
__device__ int   g_st[4096];
__device__ int   g_rstep[4096];
__device__ int   g_cstep[32768];
__device__ float g_wtf2[73728];
__device__ float g_wtb2[73728];
__device__ float g_wtf3[294912];
__device__ float g_wtb3[294912];

// ---------- weight transposes ----------
__global__ void k_wt(const float* __restrict__ W, float* __restrict__ WTf,
                     float* __restrict__ WTb, int CIN, int COUT)
{
  int idx=blockIdx.x*256+threadIdx.x;
  int tot=CIN*COUT*9; if(idx>=tot) return;
  int k=idx%9, c=(idx/9)%CIN, o=idx/(9*CIN);
  float v=W[idx];
  int rf=(c>>3)*72 + k*8 + (c&7);
  WTf[(long)rf*COUT+o]=v;
  int rb=(o>>3)*72 + k*8 + (o&7);
  WTb[(long)rb*CIN+c]=v;
}

// ---------- conv1 fwd ----------
__global__ void __launch_bounds__(256) k_conv1(
    const float* __restrict__ in, const float* __restrict__ W,
    const float* __restrict__ bias, float* __restrict__ out)
{
  __shared__ __align__(16) float ins[3][132];
  __shared__ __align__(16) float ws[9][64];
  __shared__ float bs[64];
  const int n=blockIdx.z, i=blockIdx.y, j0=blockIdx.x*64;
  const int tid=threadIdx.x, jt=tid&15, og=tid>>4;
  for(int idx=tid; idx<576; idx+=256){
    int o=idx/9, k=idx%9;
    ws[k][o]=W[idx];
  }
  if(tid<64) bs[tid]=bias[tid];
  for(int idx=tid; idx<3*130; idx+=256){
    int r=idx/130, col=idx%130;
    int gx=2*i+r, gy=2*j0+col;
    float v=0.f;
    if(gx<128 && gy<1024) v=in[((long)n*128+gx)*1024+gy];
    ins[r][col]=v;
  }
  __syncthreads();
  float acc[4][4];
#pragma unroll
  for(int o=0;o<4;o++)
#pragma unroll
  for(int e=0;e<4;e++) acc[o][e]=0.f;
#pragma unroll
  for(int r=0;r<3;r++){
    float v[9];
    *(float4*)v     = *(float4*)&ins[r][8*jt];
    *(float4*)(v+4) = *(float4*)&ins[r][8*jt+4];
    v[8]            = ins[r][8*jt+8];
#pragma unroll
    for(int kj=0;kj<3;kj++){
      float w[4];
      *(float4*)w = *(float4*)&ws[r*3+kj][og*4];
#pragma unroll
      for(int oo=0;oo<4;oo++)
#pragma unroll
      for(int e=0;e<4;e++)
        acc[oo][e]+=w[oo]*v[2*e+kj];
    }
  }
#pragma unroll
  for(int oo=0;oo<4;oo++){
    int o=og*4+oo;
    float bb=bs[o];
    float4 r;
    r.x=fmaxf(acc[oo][0]+bb,0.f); r.y=fmaxf(acc[oo][1]+bb,0.f);
    r.z=fmaxf(acc[oo][2]+bb,0.f); r.w=fmaxf(acc[oo][3]+bb,0.f);
    *(float4*)&out[(((long)n*64+o)*64+i)*512 + j0 + 4*jt]=r;
  }
}

// ---------- tf32 helpers ----------
__device__ __forceinline__ float to_tf32(float v){
  unsigned r; asm("cvt.rna.tf32.f32 %0, %1;" : "=r"(r) : "f"(v));
  return __uint_as_float(r);
}
__device__ __forceinline__ void mma_tf32(float* c4,
    unsigned a0,unsigned a1,unsigned a2,unsigned a3,unsigned b0,unsigned b1){
  asm volatile(
    "mma.sync.aligned.m16n8k8.row.col.f32.tf32.tf32.f32 "
    "{%0,%1,%2,%3},{%4,%5,%6,%7},{%8,%9},{%0,%1,%2,%3};"
    : "+f"(c4[0]),"+f"(c4[1]),"+f"(c4[2]),"+f"(c4[3])
    : "r"(a0),"r"(a1),"r"(a2),"r"(a3),"r"(b0),"r"(b1));
}

// ---------- tf32 mma conv fwd; staging-side cvt ----------
template<int CIN,int COUT,int HIN,int WIN,int SPLIT>
__global__ void __launch_bounds__(256,2) k_cmma(
    const float* __restrict__ in, const float* __restrict__ WT,
    const float* __restrict__ bias, float* __restrict__ out)
{
  constexpr int HOUT=HIN/2, WOUT=WIN/2;
  constexpr int NJT=WOUT/128;
  constexpr int LD=136;
  constexpr int WOFF=(SPLIT==3)?96:48;
  extern __shared__ float sm[];
  float* evh = sm;
  float* odh = sm + 24*LD;
  float* evl = sm + 48*LD;
  float* odl = sm + 72*LD;
  float* ws  = sm + WOFF*LD;
  const int n=blockIdx.z, i=blockIdx.y;
  const int jt_=blockIdx.x%NJT, ot=blockIdx.x/NJT;
  const int j0=jt_*128, o0=ot*128;
  const int tid=threadIdx.x, wid=tid>>5, lane=tid&31;
  const int gid=lane>>2, tig=lane&3;
  const int m0=(wid&3)*32, n0w=(wid>>2)*64;
  float acc[2][8][4];
#pragma unroll
  for(int a=0;a<2;a++)
#pragma unroll
  for(int b=0;b<8;b++)
#pragma unroll
  for(int c=0;c<4;c++) acc[a][b][c]=0.f;

  for(int c0=0;c0<CIN;c0+=8){
    __syncthreads();
    for(int idx=tid; idx<8*3*129; idx+=256){
      int c=idx/387, rem=idx%387, r=rem/129, p=rem%129;
      int gx=2*i+r, gy=2*j0+2*p;
      float a=0.f,bv=0.f;
      if(gx<HIN && gy<WIN){
        const float2 s=*(const float2*)&in[(((long)n*CIN+c0+c)*HIN+gx)*WIN+gy];
        a=s.x; bv=s.y;
      }
      float ah=to_tf32(a), bh=to_tf32(bv);
      evh[(c*3+r)*LD+p]=ah;
      odh[(c*3+r)*LD+p]=bh;
      if(SPLIT==3){
        evl[(c*3+r)*LD+p]=to_tf32(a-ah);
        odl[(c*3+r)*LD+p]=to_tf32(bv-bh);
      }
    }
    {
      const float* wsrc = WT + (long)(c0>>3)*72*COUT + o0;
      for(int idx=tid; idx<72*32; idx+=256){
        int kk=idx>>5, o4=(idx&31)*4;
        float4 v=*(const float4*)&wsrc[(long)kk*COUT + o4];
        if(SPLIT==1){ v.x=to_tf32(v.x); v.y=to_tf32(v.y); v.z=to_tf32(v.z); v.w=to_tf32(v.w); }
        *(float4*)&ws[kk*LD + o4]=v;
      }
    }
    __syncthreads();
#pragma unroll
    for(int kc=0;kc<9;kc++){
      const int r=kc/3, kj=kc%3;
      const float* srch = (kj==1)? odh : evh;
      const float* srcl = (kj==1)? odl : evl;
      const int co = (kj==2)? 1:0;
      unsigned bh[8][2], bl[8][2];
#pragma unroll
      for(int f=0;f<8;f++){
        int i0=(tig*3+r)*LD + n0w + f*8 + gid + co;
        int i1=((tig+4)*3+r)*LD + n0w + f*8 + gid + co;
        bh[f][0]=__float_as_uint(srch[i0]);
        bh[f][1]=__float_as_uint(srch[i1]);
        if(SPLIT==3){
          bl[f][0]=__float_as_uint(srcl[i0]);
          bl[f][1]=__float_as_uint(srcl[i1]);
        }
      }
#pragma unroll
      for(int mf=0;mf<2;mf++){
        unsigned ah0,ah1,ah2,ah3,al0=0,al1=0,al2=0,al3=0;
        if(SPLIT==1){
          ah0=__float_as_uint(ws[(kc*8+tig)*LD + m0+mf*16+gid]);
          ah1=__float_as_uint(ws[(kc*8+tig)*LD + m0+mf*16+gid+8]);
          ah2=__float_as_uint(ws[(kc*8+tig+4)*LD + m0+mf*16+gid]);
          ah3=__float_as_uint(ws[(kc*8+tig+4)*LD + m0+mf*16+gid+8]);
        }else{
          float w0=ws[(kc*8+tig)*LD + m0+mf*16+gid];
          float w1=ws[(kc*8+tig)*LD + m0+mf*16+gid+8];
          float w2=ws[(kc*8+tig+4)*LD + m0+mf*16+gid];
          float w3=ws[(kc*8+tig+4)*LD + m0+mf*16+gid+8];
          float h0=to_tf32(w0),h1=to_tf32(w1),h2=to_tf32(w2),h3=to_tf32(w3);
          ah0=__float_as_uint(h0); ah1=__float_as_uint(h1);
          ah2=__float_as_uint(h2); ah3=__float_as_uint(h3);
          al0=__float_as_uint(to_tf32(w0-h0)); al1=__float_as_uint(to_tf32(w1-h1));
          al2=__float_as_uint(to_tf32(w2-h2)); al3=__float_as_uint(to_tf32(w3-h3));
        }
#pragma unroll
        for(int f=0;f<8;f++){
          mma_tf32(acc[mf][f], ah0,ah1,ah2,ah3, bh[f][0],bh[f][1]);
          if(SPLIT==3){
            mma_tf32(acc[mf][f], ah0,ah1,ah2,ah3, bl[f][0],bl[f][1]);
            mma_tf32(acc[mf][f], al0,al1,al2,al3, bh[f][0],bh[f][1]);
          }
        }
      }
    }
  }
#pragma unroll
  for(int mf=0;mf<2;mf++){
    int oA=o0+m0+mf*16+gid, oB=oA+8;
    float bA=bias[oA], bB=bias[oB];
#pragma unroll
    for(int f=0;f<8;f++){
      int jj=j0 + n0w + f*8 + tig*2;
      long baseA=(((long)n*COUT+oA)*HOUT+i)*WOUT + jj;
      long baseB=(((long)n*COUT+oB)*HOUT+i)*WOUT + jj;
      float2 rA, rB;
      rA.x=fmaxf(acc[mf][f][0]+bA,0.f); rA.y=fmaxf(acc[mf][f][1]+bA,0.f);
      rB.x=fmaxf(acc[mf][f][2]+bB,0.f); rB.y=fmaxf(acc[mf][f][3]+bB,0.f);
      *(float2*)&out[baseA]=rA;
      *(float2*)&out[baseB]=rB;
    }
  }
}

// ---------- tf32 mma transposed-conv bwd (S1, staging-side cvt) ----------
template<int CIN,int COUT,int HOUT,int WOUT,int NT>
__global__ void __launch_bounds__(256,2) k_cbmma(
    const float* __restrict__ dout, const float* __restrict__ WT,
    const float* __restrict__ act, float* __restrict__ din)
{
  constexpr int HIN=2*HOUT, WIN=2*WOUT;
  constexpr int LDW=CIN+8, LDD=NT/2+4, JL=NT/2+2;
  constexpr int NW_M=CIN/32;
  __shared__ float ws[72*LDW];
  __shared__ float dsA[8*LDD];
  __shared__ float dsB[8*LDD];
  const int n=blockIdx.z, x=blockIdx.y, y0=blockIdx.x*NT;
  const int tid=threadIdx.x, wid=tid>>5, lane=tid&31;
  const int gid=lane>>2, tig=lane&3;
  const int m0=(wid%NW_M)*32, n0=(wid/NW_M)*64;
  const bool xe=((x&1)==0);
  const int iA = xe ? (x>>1) : ((x-1)>>1);
  const int iB = (x>>1)-1;
  const bool hasB = xe && iB>=0;
  const int jb = y0/2 - 1;
  float acc_e[2][4][4], acc_o[2][4][4];
#pragma unroll
  for(int a=0;a<2;a++)
#pragma unroll
  for(int b=0;b<4;b++)
#pragma unroll
  for(int c=0;c<4;c++){acc_e[a][b][c]=0.f; acc_o[a][b][c]=0.f;}

  for(int o0=0;o0<COUT;o0+=8){
    __syncthreads();
    {
      const float* wsrc = WT + (long)(o0>>3)*72*CIN;
      for(int idx=tid; idx<72*(CIN/4); idx+=256){
        int r=idx/(CIN/4), c4=(idx%(CIN/4))*4;
        float4 v=*(const float4*)&wsrc[(long)r*CIN+c4];
        v.x=to_tf32(v.x); v.y=to_tf32(v.y); v.z=to_tf32(v.z); v.w=to_tf32(v.w);
        *(float4*)&ws[r*LDW+c4]=v;
      }
    }
    for(int idx=tid; idx<8*JL; idx+=256){
      int o=idx/JL, jl=idx%JL; int j=jb+jl;
      float a=0.f,bv=0.f;
      if(j>=0 && j<WOUT){
        long base=((long)n*COUT+o0+o)*HOUT;
        a = dout[(base+iA)*WOUT+j];
        if(hasB) bv = dout[(base+iB)*WOUT+j];
      }
      dsA[o*LDD+jl]=to_tf32(a); dsB[o*LDD+jl]=to_tf32(bv);
    }
    __syncthreads();

    auto proc = [&](const float* ds, const int tapBase){
      unsigned b1[4][2], b0[4][2];
#pragma unroll
      for(int f=0;f<4;f++){
        int cbase = n0/2 + f*8 + gid;
        b1[f][0]=__float_as_uint(ds[tig*LDD + cbase + 1]);
        b1[f][1]=__float_as_uint(ds[(tig+4)*LDD + cbase + 1]);
        b0[f][0]=__float_as_uint(ds[tig*LDD + cbase]);
        b0[f][1]=__float_as_uint(ds[(tig+4)*LDD + cbase]);
      }
#pragma unroll
      for(int kj=0;kj<3;kj++){
        const int tap=tapBase+kj;
#pragma unroll
        for(int mf=0;mf<2;mf++){
          unsigned a0=__float_as_uint(ws[(tap*8+tig)*LDW + m0+mf*16+gid]);
          unsigned a1=__float_as_uint(ws[(tap*8+tig)*LDW + m0+mf*16+gid+8]);
          unsigned a2=__float_as_uint(ws[(tap*8+tig+4)*LDW + m0+mf*16+gid]);
          unsigned a3=__float_as_uint(ws[(tap*8+tig+4)*LDW + m0+mf*16+gid+8]);
#pragma unroll
          for(int f=0;f<4;f++){
            float* c4 = (kj==1)? acc_o[mf][f] : acc_e[mf][f];
            const unsigned* bb = (kj==2)? b0[f] : b1[f];
            mma_tf32(c4, a0,a1,a2,a3, bb[0],bb[1]);
          }
        }
      }
    };
    proc(dsA, xe?0:3);
    if(hasB) proc(dsB, 6);
  }

#pragma unroll
  for(int mf=0;mf<2;mf++){
    int c0_=m0+mf*16+gid;
#pragma unroll
    for(int f=0;f<4;f++){
      int Y = y0 + n0 + 2*(f*8 + 2*tig);
      long b0i=(((long)n*CIN+c0_)*HIN+x)*WIN + Y;
      long b1i=(((long)n*CIN+c0_+8)*HIN+x)*WIN + Y;
      float2 m, r;
      m=*(const float2*)&act[b0i];
      r.x = m.x>0.f? acc_e[mf][f][0]:0.f; r.y = m.y>0.f? acc_o[mf][f][0]:0.f;
      *(float2*)&din[b0i]=r;
      m=*(const float2*)&act[b0i+2];
      r.x = m.x>0.f? acc_e[mf][f][1]:0.f; r.y = m.y>0.f? acc_o[mf][f][1]:0.f;
      *(float2*)&din[b0i+2]=r;
      m=*(const float2*)&act[b1i];
      r.x = m.x>0.f? acc_e[mf][f][2]:0.f; r.y = m.y>0.f? acc_o[mf][f][2]:0.f;
      *(float2*)&din[b1i]=r;
      m=*(const float2*)&act[b1i+2];
      r.x = m.x>0.f? acc_e[mf][f][3]:0.f; r.y = m.y>0.f? acc_o[mf][f][3]:0.f;
      *(float2*)&din[b1i+2]=r;
    }
  }
}

// ---------- conv1 data-grad -> |dx|, x-row-pair (shared staging) ----------
__global__ void __launch_bounds__(256) k_bwd1(
    const float* __restrict__ dz1, const float* __restrict__ W1,
    float* __restrict__ fam)
{
  __shared__ float ws[576];
  __shared__ float dsm[8*2*260];
  const int n=blockIdx.z, q=blockIdx.y, y0=blockIdx.x*512;
  const int tid=threadIdx.x;
  for(int idx=tid; idx<576; idx+=256) ws[idx]=W1[idx];
  const bool hasB=(q>0);
  const int jbase=y0/2-1;
  float aEE=0.f,aEO=0.f,aOE=0.f,aOO=0.f;
  for(int o0=0;o0<64;o0+=8){
    __syncthreads();
    for(int idx=tid; idx<8*2*260; idx+=256){
      int o=idx/520, rs=(idx/260)&1, jj=idx%260;
      int j=jbase+jj; int ir=rs? q-1 : q;
      float v=0.f;
      if(j>=0 && j<512 && (rs==0||hasB))
        v=dz1[(((long)n*64+o0+o)*64+ir)*512+j];
      dsm[idx]=v;
    }
    __syncthreads();
#pragma unroll
    for(int o=0;o<8;o++){
      const float* wb=&ws[(o0+o)*9];
      float vmA=dsm[(o*2)*260+tid], v0A=dsm[(o*2)*260+tid+1];
      // even x=2q: row q, tap ki=0
      aEE+=wb[0]*v0A+wb[2]*vmA; aEO+=wb[1]*v0A;
      // even x=2q: row q-1, tap ki=2
      if(hasB){
        float vmB=dsm[(o*2+1)*260+tid], v0B=dsm[(o*2+1)*260+tid+1];
        aEE+=wb[6]*v0B+wb[8]*vmB; aEO+=wb[7]*v0B;
      }
      // odd x=2q+1: row q, tap ki=1
      aOE+=wb[3]*v0A+wb[5]*vmA; aOO+=wb[4]*v0A;
    }
  }
  long base=((long)n*128+2*q)*1024 + y0 + 2*tid;
  fam[base]=fabsf(aEE);      fam[base+1]=fabsf(aEO);
  fam[base+1024]=fabsf(aOE); fam[base+1025]=fabsf(aOO);
}

// ---------- att partial GEMM (S1, staging-side cvt) ----------
__global__ void __launch_bounds__(256) k_attp(
    const float* __restrict__ Wa, const float* __restrict__ feat,
    float* __restrict__ attp)
{
  constexpr int LDA=129, LDB=132;
  __shared__ float As[32*LDA];
  __shared__ float Bs[32*LDB];
  const int ks=blockIdx.x, b=blockIdx.y;
  const int tid=threadIdx.x, wid=tid>>5, lane=tid&31;
  const int gid=lane>>2, tig=lane&3;
  const int m0=(wid&3)*32, n0=(wid>>2)*64;
  const float* fb = feat + (long)b*524288;
  float acc[2][8][4];
#pragma unroll
  for(int a=0;a<2;a++)
#pragma unroll
  for(int bq=0;bq<8;bq++)
#pragma unroll
  for(int c=0;c<4;c++) acc[a][bq][c]=0.f;

  for(int k0=ks*512; k0<ks*512+512; k0+=32){
    __syncthreads();
    for(int idx=tid; idx<4096; idx+=256){
      int h=idx>>5, kk=idx&31;
      As[kk*LDA+h]=to_tf32(Wa[(long)h*4096+k0+kk]);
    }
    for(int idx=tid; idx<4096; idx+=256){
      int kk=idx>>7, t=idx&127;
      Bs[kk*LDB+t]=to_tf32(fb[(long)(k0+kk)*128+t]);
    }
    __syncthreads();
#pragma unroll
    for(int kc=0;kc<4;kc++){
      const int kb=kc*8;
      unsigned bh[8][2];
#pragma unroll
      for(int f=0;f<8;f++){
        bh[f][0]=__float_as_uint(Bs[(kb+tig)*LDB + n0+f*8+gid]);
        bh[f][1]=__float_as_uint(Bs[(kb+tig+4)*LDB + n0+f*8+gid]);
      }
#pragma unroll
      for(int mf=0;mf<2;mf++){
        unsigned a0=__float_as_uint(As[(kb+tig)*LDA + m0+mf*16+gid]);
        unsigned a1=__float_as_uint(As[(kb+tig)*LDA + m0+mf*16+gid+8]);
        unsigned a2=__float_as_uint(As[(kb+tig+4)*LDA + m0+mf*16+gid]);
        unsigned a3=__float_as_uint(As[(kb+tig+4)*LDA + m0+mf*16+gid+8]);
#pragma unroll
        for(int f=0;f<8;f++)
          mma_tf32(acc[mf][f], a0,a1,a2,a3, bh[f][0],bh[f][1]);
      }
    }
  }
#pragma unroll
  for(int mf=0;mf<2;mf++){
    int hA=m0+mf*16+gid, hB=hA+8;
#pragma unroll
    for(int f=0;f<8;f++){
      int t=n0+f*8+tig*2;
      float2 rA, rB;
      rA.x=acc[mf][f][0]; rA.y=acc[mf][f][1];
      rB.x=acc[mf][f][2]; rB.y=acc[mf][f][3];
      *(float2*)&attp[(long)ks*524288 + ((long)b*128+hA)*128+t]=rA;
      *(float2*)&attp[(long)ks*524288 + ((long)b*128+hB)*128+t]=rB;
    }
  }
}
__global__ void k_attf(const float* __restrict__ attp, const float* __restrict__ ba,
                       float* __restrict__ att)
{
  int i=blockIdx.x*256+threadIdx.x; if(i>=524288) return;
  int h=(i>>7)&127;
  float s=0.f;
#pragma unroll
  for(int ks=0;ks<8;ks++) s+=attp[(long)ks*524288+i];
  att[i]=tanhf(s+ba[h]);
}

// ---------- softmax ----------
__global__ void __launch_bounds__(128) k_salpha(
    const float* __restrict__ att, const float* __restrict__ va,
    float* __restrict__ alpha)
{
  __shared__ float vs[128], buf[128];
  const int b=blockIdx.x, t=threadIdx.x;
  vs[t]=va[t];
  __syncthreads();
  float s=0.f;
#pragma unroll 4
  for(int h=0;h<128;h++) s+=vs[h]*att[((long)b*128+h)*128+t];
  buf[t]=s; __syncthreads();
  for(int off=64;off;off>>=1){ if(t<off) buf[t]=fmaxf(buf[t],buf[t+off]); __syncthreads(); }
  float mx=buf[0]; __syncthreads();
  float e=expf(s-mx);
  buf[t]=e; __syncthreads();
  for(int off=64;off;off>>=1){ if(t<off) buf[t]+=buf[t+off]; __syncthreads(); }
  alpha[b*128+t]=e/buf[0];
}

// ---------- mu, m2 ----------
__global__ void k_mustats(const float* __restrict__ feat,
    const float* __restrict__ alpha, float* __restrict__ mu, float* __restrict__ m2)
{
  int w=(blockIdx.x*blockDim.x+threadIdx.x)>>5, lane=threadIdx.x&31;
  if(w>=131072) return;
  int b=w>>12;
  const float* fr=feat+(long)w*128;
  const float* ar=alpha+b*128;
  float s1=0.f,s2=0.f;
#pragma unroll
  for(int t=lane;t<128;t+=32){
    float a=ar[t], f=fr[t];
    s1+=a*f; s2+=a*f*f;
  }
  for(int o=16;o;o>>=1){ s1+=__shfl_down_sync(~0u,s1,o); s2+=__shfl_down_sync(~0u,s2,o); }
  if(!lane){ mu[w]=s1; m2[w]=s2; }
}

// ---------- gvec ----------
__global__ void k_gvec(const float* __restrict__ We,const float* __restrict__ Wc,
                       float* __restrict__ gvec)
{
  int w=(blockIdx.x*blockDim.x+threadIdx.x)>>5, lane=threadIdx.x&31;
  if(w>=8192) return;
  float s=0.f;
  for(int j=lane;j<256;j+=32) s+=We[(long)w*256+j]*(Wc[j*2+1]-Wc[j*2]);
  for(int o=16;o;o>>=1) s+=__shfl_down_sync(~0u,s,o);
  if(!lane) gvec[w]=s;
}

// ---------- dMu,dE2 ----------
__global__ void k_dcoef(const float* __restrict__ mu,const float* __restrict__ m2,
    const float* __restrict__ gvec, float* __restrict__ dMu,float* __restrict__ dE2)
{
  int i=blockIdx.x*256+threadIdx.x; if(i>=131072) return;
  int d=i&4095;
  float m=mu[i], v=m2[i]-m*m;
  float g2=gvec[4096+d];
  float dE=0.f, dM=gvec[d];
  if(v>1e-5f){ float sg=sqrtf(v); dE=0.5f*g2/sg; dM-=g2*m/sg; }
  dMu[i]=dM; dE2[i]=dE;
}

// ---------- dalpha ----------
__global__ void __launch_bounds__(128) k_dalp(
    const float* __restrict__ feat,const float* __restrict__ dMu,
    const float* __restrict__ dE2,float* __restrict__ part)
{
  const int ks=blockIdx.x, b=blockIdx.y, t=threadIdx.x;
  const float* fb=feat+(long)b*524288;
  const float* dm=dMu+b*4096; const float* de=dE2+b*4096;
  float acc=0.f;
  int d0=ks*512;
#pragma unroll 4
  for(int d=d0;d<d0+512;d++){
    float f=fb[(long)d*128+t];
    acc+=dm[d]*f+de[d]*f*f;
  }
  part[(ks*32+b)*128+t]=acc;
}
__global__ void __launch_bounds__(128) k_dalf(
    const float* __restrict__ part,const float* __restrict__ alpha,
    float* __restrict__ ds)
{
  const int b=blockIdx.x, t=threadIdx.x;
  float acc=0.f;
#pragma unroll
  for(int ks=0;ks<8;ks++) acc+=part[(ks*32+b)*128+t];
  __shared__ float buf[128];
  float a=alpha[b*128+t];
  buf[t]=a*acc; __syncthreads();
  for(int off=64;off;off>>=1){ if(t<off) buf[t]+=buf[t+off]; __syncthreads(); }
  ds[b*128+t]=a*(acc-buf[0]);
}

// ---------- dfeat (S1, staging-side cvt; dz computed in-staging) ----------
__global__ void __launch_bounds__(256) k_dfeat(
    const float* __restrict__ Wa, const float* __restrict__ att,
    const float* __restrict__ va, const float* __restrict__ ds,
    const float* __restrict__ feat, const float* __restrict__ alpha,
    const float* __restrict__ dMu, const float* __restrict__ dE2,
    float* __restrict__ dout3)
{
  constexpr int LDA=132, LDB=132;
  __shared__ float As[32*LDA];
  __shared__ float Bs[32*LDB];
  __shared__ float al[128], vs[128], dsv[128];
  const int d0=blockIdx.x*128, b=blockIdx.y;
  const int tid=threadIdx.x, wid=tid>>5, lane=tid&31;
  const int gid=lane>>2, tig=lane&3;
  const int m0=(wid&3)*32, n0=(wid>>2)*64;
  if(tid<128){
    al[tid]=alpha[b*128+tid];
    vs[tid]=va[tid];
    dsv[tid]=ds[b*128+tid];
  }
  float acc[2][8][4];
#pragma unroll
  for(int a=0;a<2;a++)
#pragma unroll
  for(int bq=0;bq<8;bq++)
#pragma unroll
  for(int c=0;c<4;c++) acc[a][bq][c]=0.f;

  for(int k0=0;k0<128;k0+=32){
    __syncthreads();
    for(int idx=tid; idx<4096; idx+=256){
      int kk=idx>>7, dd=idx&127;
      As[kk*LDA+dd]=to_tf32(Wa[(long)(k0+kk)*4096+d0+dd]);
    }
    for(int idx=tid; idx<4096; idx+=256){
      int kk=idx>>7, t=idx&127;
      int h=k0+kk;
      float a=att[((long)b*128+h)*128+t];
      float dzv=vs[h]*dsv[t]*(1.f-a*a);
      Bs[kk*LDB+t]=to_tf32(dzv);
    }
    __syncthreads();
#pragma unroll
    for(int kc=0;kc<4;kc++){
      const int kb=kc*8;
      unsigned bh[8][2];
#pragma unroll
      for(int f=0;f<8;f++){
        bh[f][0]=__float_as_uint(Bs[(kb+tig)*LDB + n0+f*8+gid]);
        bh[f][1]=__float_as_uint(Bs[(kb+tig+4)*LDB + n0+f*8+gid]);
      }
#pragma unroll
      for(int mf=0;mf<2;mf++){
        unsigned a0=__float_as_uint(As[(kb+tig)*LDA + m0+mf*16+gid]);
        unsigned a1=__float_as_uint(As[(kb+tig)*LDA + m0+mf*16+gid+8]);
        unsigned a2=__float_as_uint(As[(kb+tig+4)*LDA + m0+mf*16+gid]);
        unsigned a3=__float_as_uint(As[(kb+tig+4)*LDA + m0+mf*16+gid+8]);
#pragma unroll
        for(int f=0;f<8;f++)
          mma_tf32(acc[mf][f], a0,a1,a2,a3, bh[f][0],bh[f][1]);
      }
    }
  }
#pragma unroll
  for(int mf=0;mf<2;mf++){
    int dA=d0+m0+mf*16+gid, dB=dA+8;
    float dmA=dMu[(long)b*4096+dA], deA=dE2[(long)b*4096+dA];
    float dmB=dMu[(long)b*4096+dB], deB=dE2[(long)b*4096+dB];
#pragma unroll
    for(int f=0;f<8;f++){
      int t=n0+f*8+tig*2;
      long fiA=((long)b*4096+dA)*128+t;
      long fiB=((long)b*4096+dB)*128+t;
      float2 fvA=*(const float2*)&feat[fiA];
      float2 fvB=*(const float2*)&feat[fiB];
      float2 rA, rB;
      rA.x = fvA.x>0.f? (acc[mf][f][0]+al[t]*(dmA+2.f*deA*fvA.x)) : 0.f;
      rA.y = fvA.y>0.f? (acc[mf][f][1]+al[t+1]*(dmA+2.f*deA*fvA.y)) : 0.f;
      rB.x = fvB.x>0.f? (acc[mf][f][2]+al[t]*(dmB+2.f*deB*fvB.x)) : 0.f;
      rB.y = fvB.y>0.f? (acc[mf][f][3]+al[t+1]*(dmB+2.f*deB*fvB.y)) : 0.f;
      *(float2*)&dout3[fiA]=rA;
      *(float2*)&dout3[fiB]=rB;
    }
  }
}

// ---------- row/col stats ----------
__global__ void k_rowstats(const float* __restrict__ fam,const float* __restrict__ x,
    float* __restrict__ cm,float* __restrict__ meanT)
{
  int w=(blockIdx.x*blockDim.x+threadIdx.x)>>5, lane=threadIdx.x&31;
  if(w>=4096) return;
  const float* fr=fam+(long)w*1024; const float* xr=x+(long)w*1024;
  float m=-1e30f, s=0.f;
  for(int t=lane;t<1024;t+=32){ m=fmaxf(m,fr[t]); s+=xr[t]; }
  for(int o=16;o;o>>=1){ m=fmaxf(m,__shfl_down_sync(~0u,m,o)); s+=__shfl_down_sync(~0u,s,o); }
  if(!lane){ cm[w]=m; meanT[w]=s*(1.f/1024.f); }
}
__global__ void k_colstats(const float* __restrict__ fam,const float* __restrict__ x,
    float* __restrict__ tm,float* __restrict__ meanF)
{
  int i=blockIdx.x*256+threadIdx.x; if(i>=32768) return;
  int b=i>>10, t=i&1023;
  const float* fb=fam+(long)b*131072+t; const float* xb=x+(long)b*131072+t;
  float m=-1e30f, s=0.f;
#pragma unroll 4
  for(int f=0;f<128;f++){ m=fmaxf(m,fb[f*1024]); s+=xb[f*1024]; }
  tm[i]=m; meanF[i]=s*(1.f/128.f);
}

// ---------- bitonic argsort ----------
template<int N>
__global__ void k_sort(const float* __restrict__ vals, int* __restrict__ idxout)
{
  __shared__ unsigned long long key[N];
  const int b=blockIdx.x, tid=threadIdx.x, TH=N/2;
  for(int i=tid;i<N;i+=TH){
    unsigned u=__float_as_uint(vals[b*N+i]);
    u = (u&0x80000000u)? ~u : (u|0x80000000u);
    key[i]=((unsigned long long)(~u)<<32)|(unsigned)i;
  }
  __syncthreads();
  for(int k=2;k<=N;k<<=1)
    for(int j=k>>1;j;j>>=1){
      for(int i=tid;i<N;i+=TH){
        int ixj=i^j;
        if(ixj>i){
          bool up=((i&k)==0);
          unsigned long long a=key[i],c=key[ixj];
          if((a>c)==up){ key[i]=c; key[ixj]=a; }
        }
      }
      __syncthreads();
    }
  for(int i=tid;i<128;i+=TH) idxout[b*128+i]=(int)(key[i]&0xFFFFFFFFu);
}

// ---------- RFM scan (parallel init, per-batch block) ----------
__global__ void k_rfm(const int* __restrict__ sc,const int* __restrict__ st,
    const int* __restrict__ mask_t,const int* __restrict__ s_t,
    const int* __restrict__ is_train,int* __restrict__ rstep,int* __restrict__ cstep)
{
  const int b=blockIdx.x, t=threadIdx.x;
  int* rs=rstep+b*128; int* cs=cstep+b*1024;
  rs[t]=-1;
  for(int i=t;i<1024;i+=128) cs[i]=-1;
  __syncthreads();
  if(t!=0) return;
  if(is_train && is_train[0]==0) return;
  int cnt=0;
  for(int s=0;s<128 && cnt<3;s++){
    int pc=sc[b*128+s], pt=st[b*128+s];
    if(rs[pc]!=-1||cs[pt]!=-1) continue;
    int mt=mask_t[b*128+s], ss=s_t[b*128+s];
    rs[pc]=s;
    int l=pt-ss; if(l<0)l=0;
    int r=pt+mt-ss; if(r>1024)r=1024;
    for(int tt=l;tt<r;tt++) cs[tt]=s;
    cnt++;
  }
}

// ---------- apply mask ----------
__global__ void k_apply(const float* __restrict__ x,const int* __restrict__ rstep,
    const int* __restrict__ cstep,const float* __restrict__ meanT,
    const float* __restrict__ meanF,float* __restrict__ xm)
{
  long i=(long)blockIdx.x*256+threadIdx.x; if(i>=4194304) return;
  int t=(int)(i&1023); int f=(int)((i>>10)&127); int b=(int)(i>>17);
  int rs=rstep[b*128+f], cs=cstep[b*1024+t];
  float v;
  if(rs<0&&cs<0) v=x[i];
  else v=(cs>=rs)? meanT[b*128+f] : meanF[b*1024+t];
  xm[i]=v;
}

// ---------- emb head ----------
__global__ void k_cat(const float* __restrict__ mu,const float* __restrict__ m2,
                      float* __restrict__ cat)
{
  int i=blockIdx.x*256+threadIdx.x; if(i>=131072) return;
  int b=i>>12, d=i&4095;
  float m=mu[i];
  cat[(long)b*8192+d]=m;
  cat[(long)b*8192+4096+d]=sqrtf(fmaxf(m2[i]-m*m,1e-5f));
}
__global__ void __launch_bounds__(256) k_embp(
    const float* __restrict__ cat,const float* __restrict__ We,
    float* __restrict__ part)
{
  __shared__ float cs[32][64];
  const int ks=blockIdx.x, j=threadIdx.x;
  for(int idx=j; idx<32*64; idx+=256){
    int b=idx>>6, ii=idx&63;
    cs[b][ii]=cat[(long)b*8192 + ks*64 + ii];
  }
  __syncthreads();
  float acc[32];
#pragma unroll
  for(int b=0;b<32;b++) acc[b]=0.f;
  for(int ii=0;ii<64;ii++){
    float w=We[((long)ks*64+ii)*256+j];
#pragma unroll
    for(int b=0;b<32;b++) acc[b]+=cs[b][ii]*w;
  }
#pragma unroll
  for(int b=0;b<32;b++) part[((long)ks*32+b)*256+j]=acc[b];
}
__global__ void __launch_bounds__(256) k_embf(
    const float* __restrict__ part,const float* __restrict__ be,
    const float* __restrict__ Wc,const float* __restrict__ bc,
    float* __restrict__ out)
{
  const int b=blockIdx.x, j=threadIdx.x;
  float s=be[j];
  for(int ks=0;ks<128;ks++) s+=part[((long)ks*32+b)*256+j];
  __shared__ float es[256];
  es[j]=s; __syncthreads();
  if(j<2){
    float acc=bc[j];
    for(int q=0;q<256;q++) acc+=es[q]*Wc[q*2+j];
    out[b*2+j]=acc;
  }
}

// ---------- host ----------
static void run_tail(const float* h3,const float* Wa,const float* ba,const float* va,
                     float* attp,float* att,float* alpha,float* mu,float* m2)
{
  k_attp<<<dim3(8,32),256>>>(Wa,h3,attp);
  k_attf<<<2048,256>>>(attp,ba,att);
  k_salpha<<<32,128>>>(att,va,alpha);
  k_mustats<<<16384,256>>>(h3,alpha,mu,m2);
}

extern "C" void kernel_launch(void* const* d_in,const int* in_sizes,int n_in,
                              void* d_out,int out_size)
{
  const float* x =(const float*)d_in[0];
  const float* W1=(const float*)d_in[1]; const float* b1=(const float*)d_in[2];
  const float* W2=(const float*)d_in[3]; const float* b2=(const float*)d_in[4];
  const float* W3=(const float*)d_in[5]; const float* b3=(const float*)d_in[6];
  const float* Wa=(const float*)d_in[7]; const float* ba=(const float*)d_in[8];
  const float* va=(const float*)d_in[9];
  const float* We=(const float*)d_in[10]; const float* be=(const float*)d_in[11];
  const float* Wc=(const float*)d_in[12]; const float* bc=(const float*)d_in[13];
  const int* mask_t=(const int*)d_in[14]; const int* s_t=(const int*)d_in[15];
  const int* is_train = (n_in>16)? (const int*)d_in[16] : nullptr;
  float* out=(float*)d_out;

  float *h1,*h2,*h3,*d1,*d2,*d3,*fam,*xm,*att,*attp,*alpha,*ds,*dap,*mu,*m2,*dMu,*dE2,*gvec;
  float *cat,*ep,*cm,*tm,*meanT,*meanF,*wtf2,*wtb2,*wtf3,*wtb3;
  int *sc,*st,*rstep,*cstep;
  cudaGetSymbolAddress((void**)&h1,g_h1);   cudaGetSymbolAddress((void**)&h2,g_h2);
  cudaGetSymbolAddress((void**)&h3,g_h3);   cudaGetSymbolAddress((void**)&d1,g_d1);
  cudaGetSymbolAddress((void**)&d2,g_d2);   cudaGetSymbolAddress((void**)&d3,g_d3);
  cudaGetSymbolAddress((void**)&fam,g_fam); cudaGetSymbolAddress((void**)&xm,g_xm);
  cudaGetSymbolAddress((void**)&att,g_att); cudaGetSymbolAddress((void**)&attp,g_attp);
  cudaGetSymbolAddress((void**)&alpha,g_alpha); cudaGetSymbolAddress((void**)&ds,g_dsb);
  cudaGetSymbolAddress((void**)&dap,g_dap);
  cudaGetSymbolAddress((void**)&mu,g_mu);   cudaGetSymbolAddress((void**)&m2,g_m2);
  cudaGetSymbolAddress((void**)&dMu,g_dMu); cudaGetSymbolAddress((void**)&dE2,g_dE2);
  cudaGetSymbolAddress((void**)&gvec,g_gvec);
  cudaGetSymbolAddress((void**)&cat,g_cat); cudaGetSymbolAddress((void**)&ep,g_ep);
  cudaGetSymbolAddress((void**)&cm,g_cm);   cudaGetSymbolAddress((void**)&tm,g_tm);
  cudaGetSymbolAddress((void**)&meanT,g_meanT); cudaGetSymbolAddress((void**)&meanF,g_meanF);
  cudaGetSymbolAddress((void**)&sc,g_sc);   cudaGetSymbolAddress((void**)&st,g_st);
  cudaGetSymbolAddress((void**)&rstep,g_rstep); cudaGetSymbolAddress((void**)&cstep,g_cstep);
  cudaGetSymbolAddress((void**)&wtf2,g_wtf2); cudaGetSymbolAddress((void**)&wtb2,g_wtb2);
  cudaGetSymbolAddress((void**)&wtf3,g_wtf3); cudaGetSymbolAddress((void**)&wtb3,g_wtb3);

  const int SMEM1 = 120*136*4;
  const int SMEM3 = 168*136*4;
  cudaFuncSetAttribute(k_cmma<64,128,64,512,1>,  cudaFuncAttributeMaxDynamicSharedMemorySize, SMEM1);
  cudaFuncSetAttribute(k_cmma<64,128,64,512,3>,  cudaFuncAttributeMaxDynamicSharedMemorySize, SMEM3);
  cudaFuncSetAttribute(k_cmma<128,256,32,256,1>, cudaFuncAttributeMaxDynamicSharedMemorySize, SMEM1);
  cudaFuncSetAttribute(k_cmma<128,256,32,256,3>, cudaFuncAttributeMaxDynamicSharedMemorySize, SMEM3);

  // prep
  k_wt<<<288,256>>>(W2,wtf2,wtb2,64,128);
  k_wt<<<1152,256>>>(W3,wtf3,wtb3,128,256);
  k_gvec<<<1024,256>>>(We,Wc,gvec);
  // pass 1: forward convs 3xTF32 (argsort-critical)
  k_conv1<<<dim3(8,64,32),256>>>(x,W1,b1,h1);
  k_cmma<64,128,64,512,3><<<dim3(2,32,32),256,SMEM3>>>(h1,wtf2,b2,h2);
  k_cmma<128,256,32,256,3><<<dim3(2,16,32),256,SMEM3>>>(h2,wtf3,b3,h3);
  run_tail(h3,Wa,ba,va,attp,att,alpha,mu,m2);
  // backward to input: single-tf32
  k_dcoef<<<512,256>>>(mu,m2,gvec,dMu,dE2);
  k_dalp<<<dim3(8,32),128>>>(h3,dMu,dE2,dap);
  k_dalf<<<32,128>>>(dap,alpha,ds);
  k_dfeat<<<dim3(32,32),256>>>(Wa,att,va,ds,h3,alpha,dMu,dE2,d3);
  k_cbmma<128,256,16,128,128><<<dim3(2,32,32),256>>>(d3,wtb3,h2,d2);
  k_cbmma<64,128,32,256,256><<<dim3(2,64,32),256>>>(d2,wtb2,h1,d1);
  k_bwd1<<<dim3(2,64,32),256>>>(d1,W1,fam);
  // masking
  k_rowstats<<<512,256>>>(fam,x,cm,meanT);
  k_colstats<<<128,256>>>(fam,x,tm,meanF);
  k_sort<128><<<32,64>>>(cm,sc);
  k_sort<1024><<<32,512>>>(tm,st);
  k_rfm<<<32,128>>>(sc,st,mask_t,s_t,is_train,rstep,cstep);
  k_apply<<<16384,256>>>(x,rstep,cstep,meanT,meanF,xm);
  // pass 2 (single tf32)
  k_conv1<<<dim3(8,64,32),256>>>(xm,W1,b1,h1);
  k_cmma<64,128,64,512,1><<<dim3(2,32,32),256,SMEM1>>>(h1,wtf2,b2,h2);
  k_cmma<128,256,32,256,1><<<dim3(2,16,32),256,SMEM1>>>(h2,wtf3,b3,h3);
  run_tail(h3,Wa,ba,va,attp,att,alpha,mu,m2);
  k_cat<<<512,256>>>(mu,m2,cat);
  k_embp<<<128,256>>>(cat,We,ep);
  k_embf<<<32,256>>>(ep,be,Wc,bc,out);
}